// round 1
// baseline (speedup 1.0000x reference)
#include <cuda_runtime.h>
#include <math.h>

#define Bb   2
#define Ls   2048
#define Dm   512
#define Hh   8
#define HDim 64
#define LcC  512
#define NSEL 8

// ---------------- scratch (allocation-free: __device__ globals) ----------------
static __device__ float g_q[Bb*Ls*Dm];
static __device__ float g_k[Bb*Ls*Dm];
static __device__ float g_v[Bb*Ls*Dm];
static __device__ float g_kcpre[Bb*LcC*Dm];
static __device__ float g_vc[Bb*LcC*Dm];
static __device__ float g_hid[Bb*LcC*Dm];
static __device__ float g_kc[Bb*LcC*Dm];
static __device__ float g_scores[(size_t)Bb*Hh*Ls*Ls];     // 256 MB dense scores
static __device__ float g_scoresg[(size_t)Bb*Hh*Ls*LcC];   // 64 MB global-path scores
static __device__ float g_outg[Bb*Ls*Dm];
static __device__ float g_outl[Bb*Ls*Dm];
static __device__ float g_comb[Bb*Ls*Dm];
static __device__ float g_imp[Bb*Hh*Ls];
static __device__ int   g_selidx[Bb*Hh*NSEL];

// ---------------- generic tiled SGEMM: C = A[MxK] @ W[KxN] + bias, opt exact GELU ----------------
__global__ void sgemm_bias_kernel(const float* __restrict__ A, const float* __restrict__ W,
                                  const float* __restrict__ bias, float* __restrict__ C,
                                  int M, int N, int K, int gelu)
{
    __shared__ float As[16][68];
    __shared__ float Ws[16][68];
    const int tid  = threadIdx.x;
    const int tr   = tid >> 4, tc = tid & 15;
    const int row0 = blockIdx.y * 64;
    const int col0 = blockIdx.x * 64;
    float acc[4][4] = {};

    for (int k0 = 0; k0 < K; k0 += 16) {
        { // A tile 64x16 -> As[k][m]
            int r = tid >> 2, c4 = tid & 3;
            float4 va = *(const float4*)&A[(size_t)(row0 + r)*K + k0 + c4*4];
            As[c4*4+0][r] = va.x; As[c4*4+1][r] = va.y;
            As[c4*4+2][r] = va.z; As[c4*4+3][r] = va.w;
        }
        { // W tile 16x64 -> Ws[k][n]
            int r = tid >> 4, c4 = tid & 15;
            float4 vw = *(const float4*)&W[(size_t)(k0 + r)*N + col0 + c4*4];
            *(float4*)&Ws[r][c4*4] = vw;
        }
        __syncthreads();
        #pragma unroll
        for (int kk = 0; kk < 16; kk++) {
            float a[4], w[4];
            *(float4*)a = *(const float4*)&As[kk][tr*4];
            *(float4*)w = *(const float4*)&Ws[kk][tc*4];
            #pragma unroll
            for (int i = 0; i < 4; i++)
                #pragma unroll
                for (int j = 0; j < 4; j++)
                    acc[i][j] = fmaf(a[i], w[j], acc[i][j]);
        }
        __syncthreads();
    }
    #pragma unroll
    for (int i = 0; i < 4; i++) {
        int m = row0 + tr*4 + i;
        float4 o;
        float* po = (float*)&o;
        #pragma unroll
        for (int j = 0; j < 4; j++) {
            int n = col0 + tc*4 + j;
            float val = acc[i][j] + bias[n];
            if (gelu) val = 0.5f * val * (1.0f + erff(val * 0.70710678118654752f));
            po[j] = val;
        }
        *(float4*)&C[(size_t)m*N + col0 + tc*4] = o;
    }
}

// ---------------- score tiles: S[bh,i,j] = scale * dot64(Q[b,i,h,:], Kp[b,j,h,:]) ----------------
// grid: (Lk/64, Ls/64, Bb*Hh)
__global__ void scores_kernel(const float* __restrict__ Qm, const float* __restrict__ Km,
                              float* __restrict__ S, int Lk, float scale)
{
    __shared__ float Qs[64][68];
    __shared__ float Ks[64][68];
    const int tid = threadIdx.x;
    const int bh  = blockIdx.z;
    const int b   = bh >> 3, h = bh & 7;
    const int i0  = blockIdx.y * 64, j0 = blockIdx.x * 64;
    const float* qb = Qm + ((size_t)b*Ls)*Dm + h*HDim;
    const float* kb = Km + ((size_t)b*Lk)*Dm + h*HDim;

    #pragma unroll
    for (int rep = 0; rep < 4; rep++) {
        int idx = tid + 256*rep;        // 0..1023 float4 slots
        int r = idx >> 4, c4 = idx & 15;
        float4 vq = *(const float4*)&qb[(size_t)(i0 + r)*Dm + c4*4];
        Qs[c4*4+0][r]=vq.x; Qs[c4*4+1][r]=vq.y; Qs[c4*4+2][r]=vq.z; Qs[c4*4+3][r]=vq.w;
        float4 vk = *(const float4*)&kb[(size_t)(j0 + r)*Dm + c4*4];
        Ks[c4*4+0][r]=vk.x; Ks[c4*4+1][r]=vk.y; Ks[c4*4+2][r]=vk.z; Ks[c4*4+3][r]=vk.w;
    }
    __syncthreads();

    const int tr = tid >> 4, tc = tid & 15;
    float acc[4][4] = {};
    #pragma unroll 8
    for (int d = 0; d < 64; d++) {
        float a[4], w[4];
        *(float4*)a = *(const float4*)&Qs[d][tr*4];
        *(float4*)w = *(const float4*)&Ks[d][tc*4];
        #pragma unroll
        for (int i = 0; i < 4; i++)
            #pragma unroll
            for (int j = 0; j < 4; j++)
                acc[i][j] = fmaf(a[i], w[j], acc[i][j]);
    }
    float* sp = S + ((size_t)bh*Ls + i0)*Lk + j0;
    #pragma unroll
    for (int i = 0; i < 4; i++) {
        float4 o;
        o.x = acc[i][0]*scale; o.y = acc[i][1]*scale;
        o.z = acc[i][2]*scale; o.w = acc[i][3]*scale;
        *(float4*)&sp[(size_t)(tr*4+i)*Lk + tc*4] = o;
    }
}

// ---------------- compress: mean over groups of 4 rows ----------------
__global__ void compress_kernel()
{
    int e = blockIdx.x*blockDim.x + threadIdx.x;   // over Bb*LcC*Dm
    if (e >= Bb*LcC*Dm) return;
    int b = e / (LcC*Dm);
    int r = e % (LcC*Dm);
    int m = r / Dm, d = r % Dm;
    size_t base = ((size_t)b*Ls + m*4)*Dm + d;
    g_kcpre[e] = 0.25f*(g_k[base] + g_k[base+Dm] + g_k[base+2*Dm] + g_k[base+3*Dm]);
    g_vc[e]    = 0.25f*(g_v[base] + g_v[base+Dm] + g_v[base+2*Dm] + g_v[base+3*Dm]);
}

// ---------------- importance: logsumexp - log(L) - mean, per dense-score row ----------------
__global__ void importance_kernel()
{
    int warp = (blockIdx.x*blockDim.x + threadIdx.x) >> 5;   // row over Bb*Hh*Ls
    int lane = threadIdx.x & 31;
    const float* row = g_scores + (size_t)warp * Ls;
    float m = -INFINITY, se = 0.f, s = 0.f;
    for (int j = lane; j < Ls; j += 32) {
        float x = row[j];
        s += x;
        if (x > m) { se = se * expf(m - x) + 1.f; m = x; }
        else       { se += expf(x - m); }
    }
    #pragma unroll
    for (int off = 16; off; off >>= 1) {
        float m2  = __shfl_xor_sync(0xFFFFFFFFu, m,  off);
        float se2 = __shfl_xor_sync(0xFFFFFFFFu, se, off);
        float s2  = __shfl_xor_sync(0xFFFFFFFFu, s,  off);
        float nm  = fmaxf(m, m2);
        se = se*expf(m - nm) + se2*expf(m2 - nm);
        m = nm; s += s2;
    }
    if (lane == 0)
        g_imp[warp] = m + logf(se) - logf((float)Ls) - s/(float)Ls;
}

// ---------------- top-8 per (b,h), ties -> smallest index (JAX semantics) ----------------
__global__ void topk_kernel()
{
    int bh = blockIdx.x;
    const float* imp = g_imp + bh*Ls;
    __shared__ float bv[256];
    __shared__ int   bi[256];
    __shared__ int   chosen[NSEL];
    int t = threadIdx.x;
    for (int itu = 0; itu < NSEL; itu++) {
        float best = -INFINITY; int bidx = 0x7FFFFFFF;
        for (int j = t; j < Ls; j += 256) {
            bool skip = false;
            for (int c = 0; c < itu; c++) if (chosen[c] == j) skip = true;
            if (skip) continue;
            float vv = imp[j];
            if (vv > best || (vv == best && j < bidx)) { best = vv; bidx = j; }
        }
        bv[t] = best; bi[t] = bidx;
        __syncthreads();
        for (int s2 = 128; s2; s2 >>= 1) {
            if (t < s2) {
                if (bv[t+s2] > bv[t] || (bv[t+s2] == bv[t] && bi[t+s2] < bi[t])) {
                    bv[t] = bv[t+s2]; bi[t] = bi[t+s2];
                }
            }
            __syncthreads();
        }
        if (t == 0) { chosen[itu] = bi[0]; g_selidx[bh*NSEL + itu] = bi[0]; }
        __syncthreads();
    }
}

// ---------------- global path: softmax over Lc + AV, warp per query ----------------
__global__ void attng_kernel()
{
    __shared__ float sp[8][LcC];
    int wl   = threadIdx.x >> 5;
    int lane = threadIdx.x & 31;
    int qg   = blockIdx.x*8 + wl;           // (b,h,i) flat
    int b = qg / (Hh*Ls);
    int r = qg % (Hh*Ls);
    int h = r / Ls, i = r % Ls;
    const float* row = g_scoresg + (size_t)qg * LcC;

    float m = -INFINITY;
    for (int j = lane; j < LcC; j += 32) m = fmaxf(m, row[j]);
    #pragma unroll
    for (int off = 16; off; off >>= 1) m = fmaxf(m, __shfl_xor_sync(0xFFFFFFFFu, m, off));
    float s = 0.f;
    for (int j = lane; j < LcC; j += 32) { float p = expf(row[j]-m); sp[wl][j] = p; s += p; }
    #pragma unroll
    for (int off = 16; off; off >>= 1) s += __shfl_xor_sync(0xFFFFFFFFu, s, off);
    __syncwarp();

    float inv = 1.f/s;
    float acc0 = 0.f, acc1 = 0.f;
    const float* vb = g_vc + ((size_t)b*LcC)*Dm + h*HDim;
    #pragma unroll 4
    for (int j = 0; j < LcC; j++) {
        float p = sp[wl][j];
        acc0 = fmaf(p, vb[(size_t)j*Dm + lane],      acc0);
        acc1 = fmaf(p, vb[(size_t)j*Dm + 32 + lane], acc1);
    }
    float* ob = g_outg + ((size_t)b*Ls + i)*Dm + h*HDim;
    ob[lane]      = acc0*inv;
    ob[32 + lane] = acc1*inv;
}

// ---------------- local path: band softmax + AV, warp per query ----------------
__global__ void attnl_kernel()
{
    __shared__ float sp[8][136];
    int wl   = threadIdx.x >> 5;
    int lane = threadIdx.x & 31;
    int qg   = blockIdx.x*8 + wl;
    int b = qg / (Hh*Ls);
    int r = qg % (Hh*Ls);
    int h = r / Ls, i = r % Ls;
    int j0 = (i - 64 > 0) ? i - 64 : 0;
    int j1 = (i + 64 < Ls-1) ? i + 64 : Ls-1;
    int n  = j1 - j0 + 1;
    const float* row = g_scores + (size_t)qg * Ls;

    float m = -INFINITY;
    for (int jj = lane; jj < n; jj += 32) m = fmaxf(m, row[j0+jj]);
    #pragma unroll
    for (int off = 16; off; off >>= 1) m = fmaxf(m, __shfl_xor_sync(0xFFFFFFFFu, m, off));
    float s = 0.f;
    for (int jj = lane; jj < n; jj += 32) { float p = expf(row[j0+jj]-m); sp[wl][jj] = p; s += p; }
    #pragma unroll
    for (int off = 16; off; off >>= 1) s += __shfl_xor_sync(0xFFFFFFFFu, s, off);
    __syncwarp();

    float inv = 1.f/s;
    float acc0 = 0.f, acc1 = 0.f;
    const float* vb = g_v + ((size_t)b*Ls + j0)*Dm + h*HDim;
    for (int jj = 0; jj < n; jj++) {
        float p = sp[wl][jj];
        acc0 = fmaf(p, vb[(size_t)jj*Dm + lane],      acc0);
        acc1 = fmaf(p, vb[(size_t)jj*Dm + 32 + lane], acc1);
    }
    float* ob = g_outl + ((size_t)b*Ls + i)*Dm + h*HDim;
    ob[lane]      = acc0*inv;
    ob[32 + lane] = acc1*inv;
}

// ---------------- combine: pw0*out_g + pw1*out_l ----------------
__global__ void combine_kernel(const float* __restrict__ pm)
{
    float a0 = pm[0], a1 = pm[1], a2 = pm[2];
    float mx = fmaxf(a0, fmaxf(a1, a2));
    float e0 = expf(a0-mx), e1 = expf(a1-mx), e2 = expf(a2-mx);
    float den = e0+e1+e2;
    float pw0 = e0/den, pw1 = e1/den;
    int e = blockIdx.x*blockDim.x + threadIdx.x;   // exactly Bb*Ls*Dm threads
    g_comb[e] = pw0*g_outg[e] + pw1*g_outl[e];
}

// ---------------- selection path: block per selected query, adds pw2*out_s into g_comb ----------------
__global__ void attns_kernel(const float* __restrict__ pm)
{
    __shared__ float p[Ls];
    __shared__ float red[256];
    int blk = blockIdx.x;                 // bh*NSEL + s
    int bh  = blk / NSEL, si = blk % NSEL;
    int b = bh >> 3, h = bh & 7;
    int qi = g_selidx[bh*NSEL + si];
    const float* row = g_scores + ((size_t)bh*Ls + qi)*Ls;
    int t = threadIdx.x;

    float m = -INFINITY;
    for (int j = t; j < Ls; j += 256) m = fmaxf(m, row[j]);
    red[t] = m; __syncthreads();
    for (int s2 = 128; s2; s2 >>= 1) { if (t < s2) red[t] = fmaxf(red[t], red[t+s2]); __syncthreads(); }
    m = red[0]; __syncthreads();

    float s = 0.f;
    for (int j = t; j < Ls; j += 256) { float e = expf(row[j]-m); p[j] = e; s += e; }
    red[t] = s; __syncthreads();
    for (int s2 = 128; s2; s2 >>= 1) { if (t < s2) red[t] += red[t+s2]; __syncthreads(); }
    s = red[0]; __syncthreads();

    int d = t & 63, qtr = t >> 6;
    const float* vb = g_v + ((size_t)b*Ls)*Dm + h*HDim + d;
    float acc = 0.f;
    for (int j = qtr*512; j < qtr*512 + 512; j++)
        acc = fmaf(p[j], vb[(size_t)j*Dm], acc);
    red[t] = acc; __syncthreads();

    if (t < 64) {
        float tot = red[t] + red[t+64] + red[t+128] + red[t+192];
        float a0 = pm[0], a1 = pm[1], a2 = pm[2];
        float mx = fmaxf(a0, fmaxf(a1, a2));
        float e0 = expf(a0-mx), e1 = expf(a1-mx), e2 = expf(a2-mx);
        float pw2 = e2/(e0+e1+e2);
        g_comb[((size_t)b*Ls + qi)*Dm + h*HDim + t] += pw2 * tot / s;
    }
}

// ---------------- launch ----------------
extern "C" void kernel_launch(void* const* d_in, const int* in_sizes, int n_in,
                              void* d_out, int out_size)
{
    const float* query = (const float*)d_in[0];
    const float* keyi  = (const float*)d_in[1];
    const float* vali  = (const float*)d_in[2];
    const float* Wq = (const float*)d_in[3];  const float* bq = (const float*)d_in[4];
    const float* Wk = (const float*)d_in[5];  const float* bk = (const float*)d_in[6];
    const float* Wv = (const float*)d_in[7];  const float* bv = (const float*)d_in[8];
    const float* Wo = (const float*)d_in[9];  const float* bo = (const float*)d_in[10];
    const float* Wc1 = (const float*)d_in[11]; const float* bc1 = (const float*)d_in[12];
    const float* Wc2 = (const float*)d_in[13]; const float* bc2 = (const float*)d_in[14];
    const float* pm  = (const float*)d_in[15];

    float *q, *k, *v, *kcpre, *hid, *kc, *scores, *scoresg, *comb;
    cudaGetSymbolAddress((void**)&q,      g_q);
    cudaGetSymbolAddress((void**)&k,      g_k);
    cudaGetSymbolAddress((void**)&v,      g_v);
    cudaGetSymbolAddress((void**)&kcpre,  g_kcpre);
    cudaGetSymbolAddress((void**)&hid,    g_hid);
    cudaGetSymbolAddress((void**)&kc,     g_kc);
    cudaGetSymbolAddress((void**)&scores, g_scores);
    cudaGetSymbolAddress((void**)&scoresg,g_scoresg);
    cudaGetSymbolAddress((void**)&comb,   g_comb);

    const float scale = 0.125f;   // 1/sqrt(64)

    // projections
    sgemm_bias_kernel<<<dim3(8,64), 256>>>(query, Wq, bq, q, Bb*Ls, Dm, Dm, 0);
    sgemm_bias_kernel<<<dim3(8,64), 256>>>(keyi,  Wk, bk, k, Bb*Ls, Dm, Dm, 0);
    sgemm_bias_kernel<<<dim3(8,64), 256>>>(vali,  Wv, bv, v, Bb*Ls, Dm, Dm, 0);

    // compression + MLP
    compress_kernel<<<2048, 256>>>();
    sgemm_bias_kernel<<<dim3(8,16), 256>>>(kcpre, Wc1, bc1, hid, Bb*LcC, Dm, Dm, 1);
    sgemm_bias_kernel<<<dim3(8,16), 256>>>(hid,   Wc2, bc2, kc,  Bb*LcC, Dm, Dm, 0);

    // score matrices
    scores_kernel<<<dim3(32,32,16), 256>>>(q, k,  scores,  Ls,  scale);
    scores_kernel<<<dim3(8, 32,16), 256>>>(q, kc, scoresg, LcC, scale);

    // selection bookkeeping
    importance_kernel<<<4096, 256>>>();
    topk_kernel<<<Bb*Hh, 256>>>();

    // attention paths
    attng_kernel<<<4096, 256>>>();
    attnl_kernel<<<4096, 256>>>();

    // mix + selection scatter-add
    combine_kernel<<<(Bb*Ls*Dm)/256, 256>>>(pm);
    attns_kernel<<<Bb*Hh*NSEL, 256>>>(pm);

    // output projection
    sgemm_bias_kernel<<<dim3(8,64), 256>>>(comb, Wo, bo, (float*)d_out, Bb*Ls, Dm, Dm, 0);
}

// round 2
// speedup vs baseline: 1.3525x; 1.3525x over previous
#include <cuda_runtime.h>
#include <math.h>

#define Bb   2
#define Ls   2048
#define Dm   512
#define Hh   8
#define HDim 64
#define LcC  512
#define NSEL 8

// ---------------- scratch (allocation-free: __device__ globals) ----------------
static __device__ float g_q[Bb*Ls*Dm];
static __device__ float g_k[Bb*Ls*Dm];
static __device__ float g_v[Bb*Ls*Dm];
static __device__ float g_kcpre[Bb*LcC*Dm];
static __device__ float g_vc[Bb*LcC*Dm];
static __device__ float g_hid[Bb*LcC*Dm];
static __device__ float g_kc[Bb*LcC*Dm];
static __device__ float g_scores[(size_t)Bb*Hh*Ls*Ls];     // 256 MB dense scores
static __device__ float g_scoresg[(size_t)Bb*Hh*Ls*LcC];   // 64 MB global-path scores
static __device__ float g_outg[Bb*Ls*Dm];
static __device__ float g_outl[Bb*Ls*Dm];
static __device__ float g_comb[Bb*Ls*Dm];
static __device__ float g_imp[Bb*Hh*Ls];
static __device__ int   g_selidx[Bb*Hh*NSEL];

// =========================================================================
// 128x128-tile SGEMM: C = A[MxK] @ W[KxN] + bias (opt exact GELU)
// 256 threads, 8x8 per thread (split 4+4 at +64), K-chunk 16, double buffer.
// =========================================================================
__global__ void sgemm128_kernel(const float* __restrict__ A, const float* __restrict__ W,
                                const float* __restrict__ bias, float* __restrict__ C,
                                int M, int N, int K, int gelu)
{
    __shared__ float As[2][16][132];
    __shared__ float Ws[2][16][132];
    const int tid = threadIdx.x;
    const int tr = tid >> 4, tc = tid & 15;
    const int row0 = blockIdx.y * 128, col0 = blockIdx.x * 128;

    const int arow0 = tid >> 2;           // slot = tid
    const int arow1 = (tid + 256) >> 2;   // slot = tid+256 (same c4)
    const int ac4   = tid & 3;
    const int wr0   = tid >> 5;
    const int wr1   = (tid + 256) >> 5;
    const int wc4   = tid & 31;

    // preload chunk 0
    {
        float4 va0 = *(const float4*)&A[(size_t)(row0 + arow0)*K + ac4*4];
        float4 va1 = *(const float4*)&A[(size_t)(row0 + arow1)*K + ac4*4];
        As[0][ac4*4+0][arow0] = va0.x; As[0][ac4*4+1][arow0] = va0.y;
        As[0][ac4*4+2][arow0] = va0.z; As[0][ac4*4+3][arow0] = va0.w;
        As[0][ac4*4+0][arow1] = va1.x; As[0][ac4*4+1][arow1] = va1.y;
        As[0][ac4*4+2][arow1] = va1.z; As[0][ac4*4+3][arow1] = va1.w;
        float4 vw0 = *(const float4*)&W[(size_t)wr0*N + col0 + wc4*4];
        float4 vw1 = *(const float4*)&W[(size_t)wr1*N + col0 + wc4*4];
        *(float4*)&Ws[0][wr0][wc4*4] = vw0;
        *(float4*)&Ws[0][wr1][wc4*4] = vw1;
    }
    __syncthreads();

    float acc[8][8] = {};
    const int nk = K >> 4;
    for (int kc = 0; kc < nk; kc++) {
        const int buf = kc & 1;
        float4 na0, na1, nw0, nw1;
        if (kc + 1 < nk) {
            int k0 = (kc + 1) * 16;
            na0 = *(const float4*)&A[(size_t)(row0 + arow0)*K + k0 + ac4*4];
            na1 = *(const float4*)&A[(size_t)(row0 + arow1)*K + k0 + ac4*4];
            nw0 = *(const float4*)&W[(size_t)(k0 + wr0)*N + col0 + wc4*4];
            nw1 = *(const float4*)&W[(size_t)(k0 + wr1)*N + col0 + wc4*4];
        }
        #pragma unroll
        for (int kk = 0; kk < 16; kk++) {
            float a[8], w[8];
            *(float4*)&a[0] = *(const float4*)&As[buf][kk][tr*4];
            *(float4*)&a[4] = *(const float4*)&As[buf][kk][64 + tr*4];
            *(float4*)&w[0] = *(const float4*)&Ws[buf][kk][tc*4];
            *(float4*)&w[4] = *(const float4*)&Ws[buf][kk][64 + tc*4];
            #pragma unroll
            for (int i = 0; i < 8; i++)
                #pragma unroll
                for (int j = 0; j < 8; j++)
                    acc[i][j] = fmaf(a[i], w[j], acc[i][j]);
        }
        if (kc + 1 < nk) {
            const int nb = buf ^ 1;
            As[nb][ac4*4+0][arow0] = na0.x; As[nb][ac4*4+1][arow0] = na0.y;
            As[nb][ac4*4+2][arow0] = na0.z; As[nb][ac4*4+3][arow0] = na0.w;
            As[nb][ac4*4+0][arow1] = na1.x; As[nb][ac4*4+1][arow1] = na1.y;
            As[nb][ac4*4+2][arow1] = na1.z; As[nb][ac4*4+3][arow1] = na1.w;
            *(float4*)&Ws[nb][wr0][wc4*4] = nw0;
            *(float4*)&Ws[nb][wr1][wc4*4] = nw1;
        }
        __syncthreads();
    }

    #pragma unroll
    for (int ig = 0; ig < 2; ig++)
        #pragma unroll
        for (int i = 0; i < 4; i++) {
            int r = row0 + ig*64 + tr*4 + i;
            #pragma unroll
            for (int jg = 0; jg < 2; jg++) {
                int c = col0 + jg*64 + tc*4;
                float4 o; float* po = (float*)&o;
                #pragma unroll
                for (int j = 0; j < 4; j++) {
                    float val = acc[ig*4+i][jg*4+j] + bias[c+j];
                    if (gelu) val = 0.5f * val * (1.0f + erff(val * 0.70710678118654752f));
                    po[j] = val;
                }
                *(float4*)&C[(size_t)r*N + c] = o;
            }
        }
}

// ---------------- legacy 64x64 SGEMM (used for the small MLP GEMMs) ----------------
__global__ void sgemm_bias_kernel(const float* __restrict__ A, const float* __restrict__ W,
                                  const float* __restrict__ bias, float* __restrict__ C,
                                  int M, int N, int K, int gelu)
{
    __shared__ float As[16][68];
    __shared__ float Ws[16][68];
    const int tid  = threadIdx.x;
    const int tr   = tid >> 4, tc = tid & 15;
    const int row0 = blockIdx.y * 64;
    const int col0 = blockIdx.x * 64;
    float acc[4][4] = {};

    for (int k0 = 0; k0 < K; k0 += 16) {
        {
            int r = tid >> 2, c4 = tid & 3;
            float4 va = *(const float4*)&A[(size_t)(row0 + r)*K + k0 + c4*4];
            As[c4*4+0][r] = va.x; As[c4*4+1][r] = va.y;
            As[c4*4+2][r] = va.z; As[c4*4+3][r] = va.w;
        }
        {
            int r = tid >> 4, c4 = tid & 15;
            float4 vw = *(const float4*)&W[(size_t)(k0 + r)*N + col0 + c4*4];
            *(float4*)&Ws[r][c4*4] = vw;
        }
        __syncthreads();
        #pragma unroll
        for (int kk = 0; kk < 16; kk++) {
            float a[4], w[4];
            *(float4*)a = *(const float4*)&As[kk][tr*4];
            *(float4*)w = *(const float4*)&Ws[kk][tc*4];
            #pragma unroll
            for (int i = 0; i < 4; i++)
                #pragma unroll
                for (int j = 0; j < 4; j++)
                    acc[i][j] = fmaf(a[i], w[j], acc[i][j]);
        }
        __syncthreads();
    }
    #pragma unroll
    for (int i = 0; i < 4; i++) {
        int m = row0 + tr*4 + i;
        float4 o; float* po = (float*)&o;
        #pragma unroll
        for (int j = 0; j < 4; j++) {
            int n = col0 + tc*4 + j;
            float val = acc[i][j] + bias[n];
            if (gelu) val = 0.5f * val * (1.0f + erff(val * 0.70710678118654752f));
            po[j] = val;
        }
        *(float4*)&C[(size_t)m*N + col0 + tc*4] = o;
    }
}

// =========================================================================
// 128x128-tile scores: S[bh,i,j] = scale * dot64(Q[b,i,h,:], K[b,j,h,:])
// grid (Lk/128, Ls/128, B*H), 256 threads, 8x8 per thread, K=64 in 2 chunks.
// =========================================================================
__global__ void scores128_kernel(const float* __restrict__ Qm, const float* __restrict__ Km,
                                 float* __restrict__ S, int Lk, float scale)
{
    __shared__ float Qs[32][132];
    __shared__ float Ks[32][132];
    const int tid = threadIdx.x;
    const int tr = tid >> 4, tc = tid & 15;
    const int bh = blockIdx.z;
    const int b  = bh >> 3, h = bh & 7;
    const int i0 = blockIdx.y * 128, j0 = blockIdx.x * 128;
    const float* qb = Qm + ((size_t)b*Ls)*Dm + h*HDim;
    const float* kb = Km + ((size_t)b*Lk)*Dm + h*HDim;

    float acc[8][8] = {};
    for (int kc = 0; kc < 2; kc++) {
        const int koff = kc * 32;
        #pragma unroll
        for (int rep = 0; rep < 4; rep++) {
            int slot = tid + 256*rep;
            int row = slot >> 3, c4 = slot & 7;
            float4 vq = *(const float4*)&qb[(size_t)(i0 + row)*Dm + koff + c4*4];
            Qs[c4*4+0][row] = vq.x; Qs[c4*4+1][row] = vq.y;
            Qs[c4*4+2][row] = vq.z; Qs[c4*4+3][row] = vq.w;
            float4 vk = *(const float4*)&kb[(size_t)(j0 + row)*Dm + koff + c4*4];
            Ks[c4*4+0][row] = vk.x; Ks[c4*4+1][row] = vk.y;
            Ks[c4*4+2][row] = vk.z; Ks[c4*4+3][row] = vk.w;
        }
        __syncthreads();
        #pragma unroll
        for (int kk = 0; kk < 32; kk++) {
            float a[8], w[8];
            *(float4*)&a[0] = *(const float4*)&Qs[kk][tr*4];
            *(float4*)&a[4] = *(const float4*)&Qs[kk][64 + tr*4];
            *(float4*)&w[0] = *(const float4*)&Ks[kk][tc*4];
            *(float4*)&w[4] = *(const float4*)&Ks[kk][64 + tc*4];
            #pragma unroll
            for (int i = 0; i < 8; i++)
                #pragma unroll
                for (int j = 0; j < 8; j++)
                    acc[i][j] = fmaf(a[i], w[j], acc[i][j]);
        }
        __syncthreads();
    }

    #pragma unroll
    for (int ig = 0; ig < 2; ig++)
        #pragma unroll
        for (int i = 0; i < 4; i++) {
            int r = i0 + ig*64 + tr*4 + i;
            #pragma unroll
            for (int jg = 0; jg < 2; jg++) {
                int c = j0 + jg*64 + tc*4;
                float4 o;
                o.x = acc[ig*4+i][jg*4+0]*scale; o.y = acc[ig*4+i][jg*4+1]*scale;
                o.z = acc[ig*4+i][jg*4+2]*scale; o.w = acc[ig*4+i][jg*4+3]*scale;
                *(float4*)&S[((size_t)bh*Ls + r)*Lk + c] = o;
            }
        }
}

// ---------------- compress: mean over groups of 4 rows (float4) ----------------
__global__ void compress_kernel()
{
    int e4 = blockIdx.x*blockDim.x + threadIdx.x;   // over Bb*LcC*Dm/4
    int b = e4 / (LcC*Dm/4);
    int r = e4 % (LcC*Dm/4);
    int m = r / (Dm/4), d4 = r % (Dm/4);
    const float4* k4 = (const float4*)g_k;
    const float4* v4 = (const float4*)g_v;
    size_t base = ((size_t)(b*Ls + m*4)*Dm)/4 + d4;
    float4 a = k4[base], bb = k4[base+128], c = k4[base+256], d = k4[base+384];
    float4 o;
    o.x = 0.25f*(a.x+bb.x+c.x+d.x); o.y = 0.25f*(a.y+bb.y+c.y+d.y);
    o.z = 0.25f*(a.z+bb.z+c.z+d.z); o.w = 0.25f*(a.w+bb.w+c.w+d.w);
    ((float4*)g_kcpre)[e4] = o;
    a = v4[base]; bb = v4[base+128]; c = v4[base+256]; d = v4[base+384];
    o.x = 0.25f*(a.x+bb.x+c.x+d.x); o.y = 0.25f*(a.y+bb.y+c.y+d.y);
    o.z = 0.25f*(a.z+bb.z+c.z+d.z); o.w = 0.25f*(a.w+bb.w+c.w+d.w);
    ((float4*)g_vc)[e4] = o;
}

// ---------------- importance: block per row, exact max + __expf lse ----------------
__global__ void importance_kernel()
{
    __shared__ float rmax[256], rsum[256];
    const int row = blockIdx.x;
    const float4* r4 = (const float4*)(g_scores + (size_t)row * Ls);
    const int t = threadIdx.x;
    float m = -INFINITY, s = 0.f;
    for (int idx = t; idx < Ls/4; idx += 256) {
        float4 v = r4[idx];
        m = fmaxf(m, fmaxf(fmaxf(v.x, v.y), fmaxf(v.z, v.w)));
        s += (v.x + v.y) + (v.z + v.w);
    }
    rmax[t] = m; rsum[t] = s; __syncthreads();
    for (int o = 128; o; o >>= 1) {
        if (t < o) { rmax[t] = fmaxf(rmax[t], rmax[t+o]); rsum[t] += rsum[t+o]; }
        __syncthreads();
    }
    m = rmax[0]; s = rsum[0];
    __syncthreads();
    float se = 0.f;
    for (int idx = t; idx < Ls/4; idx += 256) {
        float4 v = r4[idx];
        se += (__expf(v.x - m) + __expf(v.y - m)) + (__expf(v.z - m) + __expf(v.w - m));
    }
    rmax[t] = se; __syncthreads();
    for (int o = 128; o; o >>= 1) {
        if (t < o) rmax[t] += rmax[t+o];
        __syncthreads();
    }
    if (t == 0)
        g_imp[row] = m + logf(rmax[0]) - 7.6246189861593985f - s * (1.0f/2048.0f);
}

// ---------------- top-8 per (b,h), ties -> smallest index ----------------
__global__ void topk_kernel()
{
    int bh = blockIdx.x;
    const float* imp = g_imp + bh*Ls;
    __shared__ float bv[256];
    __shared__ int   bi[256];
    __shared__ int   chosen[NSEL];
    int t = threadIdx.x;
    for (int itu = 0; itu < NSEL; itu++) {
        float best = -INFINITY; int bidx = 0x7FFFFFFF;
        for (int j = t; j < Ls; j += 256) {
            bool skip = false;
            for (int c = 0; c < itu; c++) if (chosen[c] == j) skip = true;
            if (skip) continue;
            float vv = imp[j];
            if (vv > best || (vv == best && j < bidx)) { best = vv; bidx = j; }
        }
        bv[t] = best; bi[t] = bidx;
        __syncthreads();
        for (int s2 = 128; s2; s2 >>= 1) {
            if (t < s2) {
                if (bv[t+s2] > bv[t] || (bv[t+s2] == bv[t] && bi[t+s2] < bi[t])) {
                    bv[t] = bv[t+s2]; bi[t] = bi[t+s2];
                }
            }
            __syncthreads();
        }
        if (t == 0) { chosen[itu] = bi[0]; g_selidx[bh*NSEL + itu] = bi[0]; }
        __syncthreads();
    }
}

// =========================================================================
// global path: fused row-stats + tiled exp(S)@Vc.  grid (Ls/64, B*H)
// =========================================================================
__global__ void attng_kernel()
{
    __shared__ float Ps[64][68];
    __shared__ float Vs[64][68];
    __shared__ float ms[64], ssum[64];
    const int tid = threadIdx.x;
    const int wid = tid >> 5, lane = tid & 31;
    const int bh = blockIdx.y;
    const int b = bh >> 3, h = bh & 7;
    const int i0 = blockIdx.x * 64;
    const float* srow = g_scoresg + ((size_t)bh*Ls + i0) * LcC;

    // phase A: per-row max & sumexp (8 warps x 8 rows)
    for (int rr = 0; rr < 8; rr++) {
        int ii = wid*8 + rr;
        const float* r = srow + (size_t)ii * LcC;
        float m = -INFINITY;
        for (int j = lane; j < LcC; j += 32) m = fmaxf(m, r[j]);
        #pragma unroll
        for (int o = 16; o; o >>= 1) m = fmaxf(m, __shfl_xor_sync(0xFFFFFFFFu, m, o));
        float s = 0.f;
        for (int j = lane; j < LcC; j += 32) s += __expf(r[j] - m);
        #pragma unroll
        for (int o = 16; o; o >>= 1) s += __shfl_xor_sync(0xFFFFFFFFu, s, o);
        if (lane == 0) { ms[ii] = m; ssum[ii] = s; }
    }
    __syncthreads();

    const int tr = tid >> 4, tc = tid & 15;
    float acc[4][4] = {};
    for (int jb = 0; jb < LcC; jb += 64) {
        #pragma unroll
        for (int rep = 0; rep < 4; rep++) {
            int slot = tid + 256*rep;
            int row = slot >> 4, c4 = slot & 15;
            float4 v = *(const float4*)&srow[(size_t)row*LcC + jb + c4*4];
            float mi = ms[row];
            Ps[c4*4+0][row] = __expf(v.x - mi);
            Ps[c4*4+1][row] = __expf(v.y - mi);
            Ps[c4*4+2][row] = __expf(v.z - mi);
            Ps[c4*4+3][row] = __expf(v.w - mi);
            float4 vv = *(const float4*)&g_vc[((size_t)(b*LcC) + jb + row)*Dm + h*HDim + c4*4];
            *(float4*)&Vs[row][c4*4] = vv;
        }
        __syncthreads();
        #pragma unroll 8
        for (int jj = 0; jj < 64; jj++) {
            float a[4], w[4];
            *(float4*)a = *(const float4*)&Ps[jj][tr*4];
            *(float4*)w = *(const float4*)&Vs[jj][tc*4];
            #pragma unroll
            for (int i = 0; i < 4; i++)
                #pragma unroll
                for (int j = 0; j < 4; j++)
                    acc[i][j] = fmaf(a[i], w[j], acc[i][j]);
        }
        __syncthreads();
    }
    #pragma unroll
    for (int i = 0; i < 4; i++) {
        int ii = tr*4 + i;
        float inv = 1.0f / ssum[ii];
        float4 o;
        o.x = acc[i][0]*inv; o.y = acc[i][1]*inv; o.z = acc[i][2]*inv; o.w = acc[i][3]*inv;
        *(float4*)&g_outg[((size_t)(b*Ls) + i0 + ii)*Dm + h*HDim + tc*4] = o;
    }
}

// =========================================================================
// local path: band stats + tiled P@V over 3 chunks of 64.  grid (Ls/64, B*H)
// =========================================================================
__global__ void attnl_kernel()
{
    __shared__ float Ps[64][68];
    __shared__ float Vs[64][68];
    __shared__ float ms[64], ssum[64];
    const int tid = threadIdx.x;
    const int wid = tid >> 5, lane = tid & 31;
    const int bh = blockIdx.y;
    const int b = bh >> 3, h = bh & 7;
    const int i0 = blockIdx.x * 64;

    // phase A: band max & sumexp per row
    for (int rr = 0; rr < 8; rr++) {
        int ii = wid*8 + rr;
        int i  = i0 + ii;
        int jlo = (i - 64 > 0) ? i - 64 : 0;
        int jhi = (i + 64 < Ls-1) ? i + 64 : Ls-1;
        const float* r = g_scores + ((size_t)bh*Ls + i) * Ls;
        float m = -INFINITY;
        for (int j = jlo + lane; j <= jhi; j += 32) m = fmaxf(m, r[j]);
        #pragma unroll
        for (int o = 16; o; o >>= 1) m = fmaxf(m, __shfl_xor_sync(0xFFFFFFFFu, m, o));
        float s = 0.f;
        for (int j = jlo + lane; j <= jhi; j += 32) s += __expf(r[j] - m);
        #pragma unroll
        for (int o = 16; o; o >>= 1) s += __shfl_xor_sync(0xFFFFFFFFu, s, o);
        if (lane == 0) { ms[ii] = m; ssum[ii] = s; }
    }
    __syncthreads();

    const int tr = tid >> 4, tc = tid & 15;
    float acc[4][4] = {};
    for (int c = 0; c < 3; c++) {
        int jbase = i0 - 64 + c*64;
        #pragma unroll
        for (int rep = 0; rep < 4; rep++) {
            int slot = tid + 256*rep;
            int row = slot >> 4, c4 = slot & 15;
            int i = i0 + row;
            const float* srow = g_scores + ((size_t)bh*Ls + i) * Ls;
            float mi = ms[row];
            #pragma unroll
            for (int x = 0; x < 4; x++) {
                int j = jbase + c4*4 + x;
                float p = 0.f;
                if (j >= 0 && j < Ls && j >= i - 64 && j <= i + 64)
                    p = __expf(srow[j] - mi);
                Ps[c4*4+x][row] = p;
            }
            int jv = jbase + row;
            float4 vv;
            if (jv >= 0 && jv < Ls)
                vv = *(const float4*)&g_v[((size_t)(b*Ls) + jv)*Dm + h*HDim + c4*4];
            else
                vv = make_float4(0.f, 0.f, 0.f, 0.f);
            *(float4*)&Vs[row][c4*4] = vv;
        }
        __syncthreads();
        #pragma unroll 8
        for (int jj = 0; jj < 64; jj++) {
            float a[4], w[4];
            *(float4*)a = *(const float4*)&Ps[jj][tr*4];
            *(float4*)w = *(const float4*)&Vs[jj][tc*4];
            #pragma unroll
            for (int i = 0; i < 4; i++)
                #pragma unroll
                for (int j = 0; j < 4; j++)
                    acc[i][j] = fmaf(a[i], w[j], acc[i][j]);
        }
        __syncthreads();
    }
    #pragma unroll
    for (int i = 0; i < 4; i++) {
        int ii = tr*4 + i;
        float inv = 1.0f / ssum[ii];
        float4 o;
        o.x = acc[i][0]*inv; o.y = acc[i][1]*inv; o.z = acc[i][2]*inv; o.w = acc[i][3]*inv;
        *(float4*)&g_outl[((size_t)(b*Ls) + i0 + ii)*Dm + h*HDim + tc*4] = o;
    }
}

// ---------------- combine: pw0*out_g + pw1*out_l ----------------
__global__ void combine_kernel(const float* __restrict__ pm)
{
    float a0 = pm[0], a1 = pm[1], a2 = pm[2];
    float mx = fmaxf(a0, fmaxf(a1, a2));
    float e0 = expf(a0-mx), e1 = expf(a1-mx), e2 = expf(a2-mx);
    float den = e0+e1+e2;
    float pw0 = e0/den, pw1 = e1/den;
    int e = blockIdx.x*blockDim.x + threadIdx.x;
    g_comb[e] = pw0*g_outg[e] + pw1*g_outl[e];
}

// ---------------- selection path: block per selected query ----------------
__global__ void attns_kernel(const float* __restrict__ pm)
{
    __shared__ float p[Ls];
    __shared__ float red[256];
    int blk = blockIdx.x;
    int bh  = blk / NSEL, si = blk % NSEL;
    int b = bh >> 3, h = bh & 7;
    int qi = g_selidx[bh*NSEL + si];
    const float* row = g_scores + ((size_t)bh*Ls + qi)*Ls;
    int t = threadIdx.x;

    float m = -INFINITY;
    for (int j = t; j < Ls; j += 256) m = fmaxf(m, row[j]);
    red[t] = m; __syncthreads();
    for (int s2 = 128; s2; s2 >>= 1) { if (t < s2) red[t] = fmaxf(red[t], red[t+s2]); __syncthreads(); }
    m = red[0]; __syncthreads();

    float s = 0.f;
    for (int j = t; j < Ls; j += 256) { float e = __expf(row[j]-m); p[j] = e; s += e; }
    red[t] = s; __syncthreads();
    for (int s2 = 128; s2; s2 >>= 1) { if (t < s2) red[t] += red[t+s2]; __syncthreads(); }
    s = red[0]; __syncthreads();

    int d = t & 63, qtr = t >> 6;
    const float* vb = g_v + ((size_t)b*Ls)*Dm + h*HDim + d;
    float acc = 0.f;
    for (int j = qtr*512; j < qtr*512 + 512; j++)
        acc = fmaf(p[j], vb[(size_t)j*Dm], acc);
    red[t] = acc; __syncthreads();

    if (t < 64) {
        float tot = red[t] + red[t+64] + red[t+128] + red[t+192];
        float a0 = pm[0], a1 = pm[1], a2 = pm[2];
        float mx = fmaxf(a0, fmaxf(a1, a2));
        float e0 = expf(a0-mx), e1 = expf(a1-mx), e2 = expf(a2-mx);
        float pw2 = e2/(e0+e1+e2);
        g_comb[((size_t)b*Ls + qi)*Dm + h*HDim + t] += pw2 * tot / s;
    }
}

// ---------------- launch ----------------
extern "C" void kernel_launch(void* const* d_in, const int* in_sizes, int n_in,
                              void* d_out, int out_size)
{
    const float* query = (const float*)d_in[0];
    const float* keyi  = (const float*)d_in[1];
    const float* vali  = (const float*)d_in[2];
    const float* Wq = (const float*)d_in[3];  const float* bq = (const float*)d_in[4];
    const float* Wk = (const float*)d_in[5];  const float* bk = (const float*)d_in[6];
    const float* Wv = (const float*)d_in[7];  const float* bv = (const float*)d_in[8];
    const float* Wo = (const float*)d_in[9];  const float* bo = (const float*)d_in[10];
    const float* Wc1 = (const float*)d_in[11]; const float* bc1 = (const float*)d_in[12];
    const float* Wc2 = (const float*)d_in[13]; const float* bc2 = (const float*)d_in[14];
    const float* pm  = (const float*)d_in[15];

    float *q, *k, *v, *kcpre, *hid, *kc, *scores, *scoresg, *comb;
    cudaGetSymbolAddress((void**)&q,      g_q);
    cudaGetSymbolAddress((void**)&k,      g_k);
    cudaGetSymbolAddress((void**)&v,      g_v);
    cudaGetSymbolAddress((void**)&kcpre,  g_kcpre);
    cudaGetSymbolAddress((void**)&hid,    g_hid);
    cudaGetSymbolAddress((void**)&kc,     g_kc);
    cudaGetSymbolAddress((void**)&scores, g_scores);
    cudaGetSymbolAddress((void**)&scoresg,g_scoresg);
    cudaGetSymbolAddress((void**)&comb,   g_comb);

    const float scale = 0.125f;   // 1/sqrt(64)

    // projections (128x128 tiles)
    sgemm128_kernel<<<dim3(4,32), 256>>>(query, Wq, bq, q, Bb*Ls, Dm, Dm, 0);
    sgemm128_kernel<<<dim3(4,32), 256>>>(keyi,  Wk, bk, k, Bb*Ls, Dm, Dm, 0);
    sgemm128_kernel<<<dim3(4,32), 256>>>(vali,  Wv, bv, v, Bb*Ls, Dm, Dm, 0);

    // compression + MLP
    compress_kernel<<<512, 256>>>();
    sgemm_bias_kernel<<<dim3(8,16), 256>>>(kcpre, Wc1, bc1, hid, Bb*LcC, Dm, Dm, 1);
    sgemm_bias_kernel<<<dim3(8,16), 256>>>(hid,   Wc2, bc2, kc,  Bb*LcC, Dm, Dm, 0);

    // score matrices (128x128 tiles)
    scores128_kernel<<<dim3(16,16,16), 256>>>(q, k,  scores,  Ls,  scale);
    scores128_kernel<<<dim3(4, 16,16), 256>>>(q, kc, scoresg, LcC, scale);

    // selection bookkeeping
    importance_kernel<<<Bb*Hh*Ls, 256>>>();
    topk_kernel<<<Bb*Hh, 256>>>();

    // attention paths (GEMM-shaped)
    attng_kernel<<<dim3(32,16), 256>>>();
    attnl_kernel<<<dim3(32,16), 256>>>();

    // mix + selection scatter-add
    combine_kernel<<<(Bb*Ls*Dm)/256, 256>>>(pm);
    attns_kernel<<<Bb*Hh*NSEL, 256>>>(pm);

    // output projection
    sgemm128_kernel<<<dim3(4,32), 256>>>(comb, Wo, bo, (float*)d_out, Bb*Ls, Dm, Dm, 0);
}

// round 3
// speedup vs baseline: 1.4406x; 1.0651x over previous
#include <cuda_runtime.h>
#include <math.h>

#define Bb   2
#define Ls   2048
#define Dm   512
#define Hh   8
#define HDim 64
#define LcC  512
#define NSEL 8
#define NJT  16      // j-tiles of 128 in dense pass

// ---------------- scratch ----------------
static __device__ float g_q[Bb*Ls*Dm];
static __device__ float g_k[Bb*Ls*Dm];
static __device__ float g_v[Bb*Ls*Dm];
static __device__ float g_kcpre[Bb*LcC*Dm];
static __device__ float g_vc[Bb*LcC*Dm];
static __device__ float g_hid[Bb*LcC*Dm];
static __device__ float g_kc[Bb*LcC*Dm];
static __device__ float g_outg[Bb*Ls*Dm];
static __device__ float g_outl[Bb*Ls*Dm];
static __device__ float g_comb[Bb*Ls*Dm];
static __device__ float g_imp[Bb*Hh*Ls];
static __device__ int   g_selidx[Bb*Hh*NSEL];
static __device__ float g_pmax[Bb*Hh*Ls*NJT];
static __device__ float g_pse [Bb*Hh*Ls*NJT];
static __device__ float g_psum[Bb*Hh*Ls*NJT];

// =========================================================================
// 128x128 SGEMM body (256 thr, 8x8/thread, K-chunk 16, double buffered)
// =========================================================================
__device__ __forceinline__ void sgemm128_body(const float* __restrict__ A,
                                              const float* __restrict__ W,
                                              const float* __restrict__ bias,
                                              float* __restrict__ C,
                                              int N, int K, int gelu)
{
    __shared__ float As[2][16][132];
    __shared__ float Ws[2][16][132];
    const int tid = threadIdx.x;
    const int tr = tid >> 4, tc = tid & 15;
    const int row0 = blockIdx.y * 128, col0 = blockIdx.x * 128;

    const int arow0 = tid >> 2;
    const int arow1 = (tid + 256) >> 2;
    const int ac4   = tid & 3;
    const int wr0   = tid >> 5;
    const int wr1   = (tid + 256) >> 5;
    const int wc4   = tid & 31;

    {
        float4 va0 = *(const float4*)&A[(size_t)(row0 + arow0)*K + ac4*4];
        float4 va1 = *(const float4*)&A[(size_t)(row0 + arow1)*K + ac4*4];
        As[0][ac4*4+0][arow0] = va0.x; As[0][ac4*4+1][arow0] = va0.y;
        As[0][ac4*4+2][arow0] = va0.z; As[0][ac4*4+3][arow0] = va0.w;
        As[0][ac4*4+0][arow1] = va1.x; As[0][ac4*4+1][arow1] = va1.y;
        As[0][ac4*4+2][arow1] = va1.z; As[0][ac4*4+3][arow1] = va1.w;
        float4 vw0 = *(const float4*)&W[(size_t)wr0*N + col0 + wc4*4];
        float4 vw1 = *(const float4*)&W[(size_t)wr1*N + col0 + wc4*4];
        *(float4*)&Ws[0][wr0][wc4*4] = vw0;
        *(float4*)&Ws[0][wr1][wc4*4] = vw1;
    }
    __syncthreads();

    float acc[8][8] = {};
    const int nk = K >> 4;
    for (int kc = 0; kc < nk; kc++) {
        const int buf = kc & 1;
        float4 na0, na1, nw0, nw1;
        if (kc + 1 < nk) {
            int k0 = (kc + 1) * 16;
            na0 = *(const float4*)&A[(size_t)(row0 + arow0)*K + k0 + ac4*4];
            na1 = *(const float4*)&A[(size_t)(row0 + arow1)*K + k0 + ac4*4];
            nw0 = *(const float4*)&W[(size_t)(k0 + wr0)*N + col0 + wc4*4];
            nw1 = *(const float4*)&W[(size_t)(k0 + wr1)*N + col0 + wc4*4];
        }
        #pragma unroll
        for (int kk = 0; kk < 16; kk++) {
            float a[8], w[8];
            *(float4*)&a[0] = *(const float4*)&As[buf][kk][tr*4];
            *(float4*)&a[4] = *(const float4*)&As[buf][kk][64 + tr*4];
            *(float4*)&w[0] = *(const float4*)&Ws[buf][kk][tc*4];
            *(float4*)&w[4] = *(const float4*)&Ws[buf][kk][64 + tc*4];
            #pragma unroll
            for (int i = 0; i < 8; i++)
                #pragma unroll
                for (int j = 0; j < 8; j++)
                    acc[i][j] = fmaf(a[i], w[j], acc[i][j]);
        }
        if (kc + 1 < nk) {
            const int nb = buf ^ 1;
            As[nb][ac4*4+0][arow0] = na0.x; As[nb][ac4*4+1][arow0] = na0.y;
            As[nb][ac4*4+2][arow0] = na0.z; As[nb][ac4*4+3][arow0] = na0.w;
            As[nb][ac4*4+0][arow1] = na1.x; As[nb][ac4*4+1][arow1] = na1.y;
            As[nb][ac4*4+2][arow1] = na1.z; As[nb][ac4*4+3][arow1] = na1.w;
            *(float4*)&Ws[nb][wr0][wc4*4] = nw0;
            *(float4*)&Ws[nb][wr1][wc4*4] = nw1;
        }
        __syncthreads();
    }

    #pragma unroll
    for (int ig = 0; ig < 2; ig++)
        #pragma unroll
        for (int i = 0; i < 4; i++) {
            int r = row0 + ig*64 + tr*4 + i;
            #pragma unroll
            for (int jg = 0; jg < 2; jg++) {
                int c = col0 + jg*64 + tc*4;
                float4 o; float* po = (float*)&o;
                #pragma unroll
                for (int j = 0; j < 4; j++) {
                    float val = acc[ig*4+i][jg*4+j] + bias[c+j];
                    if (gelu) val = 0.5f * val * (1.0f + erff(val * 0.70710678118654752f));
                    po[j] = val;
                }
                *(float4*)&C[(size_t)r*N + c] = o;
            }
        }
}

__global__ void sgemm128_kernel(const float* __restrict__ A, const float* __restrict__ W,
                                const float* __restrict__ bias, float* __restrict__ C,
                                int N, int K, int gelu)
{
    sgemm128_body(A, W, bias, C, N, K, gelu);
}

// q/k/v projections in one launch (blockIdx.z selects triple)
__global__ void proj3_kernel(const float* A0, const float* A1, const float* A2,
                             const float* W0, const float* W1, const float* W2,
                             const float* b0, const float* b1, const float* b2,
                             float* C0, float* C1, float* C2)
{
    const float* A = blockIdx.z == 0 ? A0 : (blockIdx.z == 1 ? A1 : A2);
    const float* W = blockIdx.z == 0 ? W0 : (blockIdx.z == 1 ? W1 : W2);
    const float* b = blockIdx.z == 0 ? b0 : (blockIdx.z == 1 ? b1 : b2);
    float*       C = blockIdx.z == 0 ? C0 : (blockIdx.z == 1 ? C1 : C2);
    sgemm128_body(A, W, b, C, Dm, Dm, 0);
}

// ---------------- legacy 64x64 SGEMM (MLP) ----------------
__global__ void sgemm_bias_kernel(const float* __restrict__ A, const float* __restrict__ W,
                                  const float* __restrict__ bias, float* __restrict__ C,
                                  int N, int K, int gelu)
{
    __shared__ float As[16][68];
    __shared__ float Ws[16][68];
    const int tid  = threadIdx.x;
    const int tr   = tid >> 4, tc = tid & 15;
    const int row0 = blockIdx.y * 64;
    const int col0 = blockIdx.x * 64;
    float acc[4][4] = {};

    for (int k0 = 0; k0 < K; k0 += 16) {
        {
            int r = tid >> 2, c4 = tid & 3;
            float4 va = *(const float4*)&A[(size_t)(row0 + r)*K + k0 + c4*4];
            As[c4*4+0][r] = va.x; As[c4*4+1][r] = va.y;
            As[c4*4+2][r] = va.z; As[c4*4+3][r] = va.w;
        }
        {
            int r = tid >> 4, c4 = tid & 15;
            float4 vw = *(const float4*)&W[(size_t)(k0 + r)*N + col0 + c4*4];
            *(float4*)&Ws[r][c4*4] = vw;
        }
        __syncthreads();
        #pragma unroll
        for (int kk = 0; kk < 16; kk++) {
            float a[4], w[4];
            *(float4*)a = *(const float4*)&As[kk][tr*4];
            *(float4*)w = *(const float4*)&Ws[kk][tc*4];
            #pragma unroll
            for (int i = 0; i < 4; i++)
                #pragma unroll
                for (int j = 0; j < 4; j++)
                    acc[i][j] = fmaf(a[i], w[j], acc[i][j]);
        }
        __syncthreads();
    }
    #pragma unroll
    for (int i = 0; i < 4; i++) {
        int m = row0 + tr*4 + i;
        float4 o; float* po = (float*)&o;
        #pragma unroll
        for (int j = 0; j < 4; j++) {
            int n = col0 + tc*4 + j;
            float val = acc[i][j] + bias[n];
            if (gelu) val = 0.5f * val * (1.0f + erff(val * 0.70710678118654752f));
            po[j] = val;
        }
        *(float4*)&C[(size_t)m*N + col0 + tc*4] = o;
    }
}

// =========================================================================
// dense QK^T pass with fused per-row statistics — NO score materialization.
// grid (NJT, 16, 16); per block 128x128 tile; writes (max, sumexp, sum)
// partials per (row, jtile).
// =========================================================================
__global__ void scores_stats_kernel(const float* __restrict__ Qm, const float* __restrict__ Km,
                                    float scale)
{
    __shared__ float Qs[32][132];
    __shared__ float Ks[32][132];
    const int tid = threadIdx.x;
    const int tr = tid >> 4, tc = tid & 15;
    const int bh = blockIdx.z;
    const int b  = bh >> 3, h = bh & 7;
    const int i0 = blockIdx.y * 128, j0 = blockIdx.x * 128;
    const float* qb = Qm + ((size_t)b*Ls)*Dm + h*HDim;
    const float* kb = Km + ((size_t)b*Ls)*Dm + h*HDim;

    float acc[8][8] = {};
    for (int kc = 0; kc < 2; kc++) {
        const int koff = kc * 32;
        #pragma unroll
        for (int rep = 0; rep < 4; rep++) {
            int slot = tid + 256*rep;
            int row = slot >> 3, c4 = slot & 7;
            float4 vq = *(const float4*)&qb[(size_t)(i0 + row)*Dm + koff + c4*4];
            Qs[c4*4+0][row] = vq.x; Qs[c4*4+1][row] = vq.y;
            Qs[c4*4+2][row] = vq.z; Qs[c4*4+3][row] = vq.w;
            float4 vk = *(const float4*)&kb[(size_t)(j0 + row)*Dm + koff + c4*4];
            Ks[c4*4+0][row] = vk.x; Ks[c4*4+1][row] = vk.y;
            Ks[c4*4+2][row] = vk.z; Ks[c4*4+3][row] = vk.w;
        }
        __syncthreads();
        #pragma unroll
        for (int kk = 0; kk < 32; kk++) {
            float a[8], w[8];
            *(float4*)&a[0] = *(const float4*)&Qs[kk][tr*4];
            *(float4*)&a[4] = *(const float4*)&Qs[kk][64 + tr*4];
            *(float4*)&w[0] = *(const float4*)&Ks[kk][tc*4];
            *(float4*)&w[4] = *(const float4*)&Ks[kk][64 + tc*4];
            #pragma unroll
            for (int i = 0; i < 8; i++)
                #pragma unroll
                for (int j = 0; j < 8; j++)
                    acc[i][j] = fmaf(a[i], w[j], acc[i][j]);
        }
        __syncthreads();
    }

    // fused stats: per-thread 8 rows x 8 cols; reduce over the 16-lane row group.
    const int jt = blockIdx.x;
    #pragma unroll
    for (int r8 = 0; r8 < 8; r8++) {
        const int ig = r8 >> 2, i = r8 & 3;
        float rm = -INFINITY, rs = 0.f;
        #pragma unroll
        for (int c8 = 0; c8 < 8; c8++) {
            float x = acc[ig*4+i][c8] * scale;
            rm = fmaxf(rm, x);
            rs += x;
        }
        #pragma unroll
        for (int o = 8; o; o >>= 1) rm = fmaxf(rm, __shfl_xor_sync(0xFFFFFFFFu, rm, o));
        float se = 0.f;
        #pragma unroll
        for (int c8 = 0; c8 < 8; c8++)
            se += __expf(acc[ig*4+i][c8] * scale - rm);
        #pragma unroll
        for (int o = 8; o; o >>= 1) {
            se += __shfl_xor_sync(0xFFFFFFFFu, se, o);
            rs += __shfl_xor_sync(0xFFFFFFFFu, rs, o);
        }
        if (tc == 0) {
            int rowg = bh*Ls + i0 + ig*64 + tr*4 + i;
            g_pmax[(size_t)rowg*NJT + jt] = rm;
            g_pse [(size_t)rowg*NJT + jt] = se;
            g_psum[(size_t)rowg*NJT + jt] = rs;
        }
    }
}

// merge partials -> importance. 1 warp per row.
__global__ void impfinal_kernel()
{
    int warp = (blockIdx.x*blockDim.x + threadIdx.x) >> 5;
    int lane = threadIdx.x & 31;
    float pm = -INFINITY, pe = 0.f, ps = 0.f;
    if (lane < NJT) {
        pm = g_pmax[(size_t)warp*NJT + lane];
        pe = g_pse [(size_t)warp*NJT + lane];
        ps = g_psum[(size_t)warp*NJT + lane];
    }
    float m = pm;
    #pragma unroll
    for (int o = 8; o; o >>= 1) m = fmaxf(m, __shfl_xor_sync(0xFFFFFFFFu, m, o));
    float se = (lane < NJT) ? pe * __expf(pm - m) : 0.f;
    #pragma unroll
    for (int o = 8; o; o >>= 1) {
        se += __shfl_xor_sync(0xFFFFFFFFu, se, o);
        ps += __shfl_xor_sync(0xFFFFFFFFu, ps, o);
    }
    if (lane == 0)
        g_imp[warp] = m + logf(se) - 7.6246189861593985f - ps * (1.0f/2048.0f);
}

// ---------------- top-8 per (b,h), ties -> smallest index ----------------
__global__ void topk_kernel()
{
    int bh = blockIdx.x;
    const float* imp = g_imp + bh*Ls;
    __shared__ float bv[256];
    __shared__ int   bi[256];
    __shared__ int   chosen[NSEL];
    int t = threadIdx.x;
    for (int itu = 0; itu < NSEL; itu++) {
        float best = -INFINITY; int bidx = 0x7FFFFFFF;
        for (int j = t; j < Ls; j += 256) {
            bool skip = false;
            for (int c = 0; c < itu; c++) if (chosen[c] == j) skip = true;
            if (skip) continue;
            float vv = imp[j];
            if (vv > best || (vv == best && j < bidx)) { best = vv; bidx = j; }
        }
        bv[t] = best; bi[t] = bidx;
        __syncthreads();
        for (int s2 = 128; s2; s2 >>= 1) {
            if (t < s2) {
                if (bv[t+s2] > bv[t] || (bv[t+s2] == bv[t] && bi[t+s2] < bi[t])) {
                    bv[t] = bv[t+s2]; bi[t] = bi[t+s2];
                }
            }
            __syncthreads();
        }
        if (t == 0) { chosen[itu] = bi[0]; g_selidx[bh*NSEL + itu] = bi[0]; }
        __syncthreads();
    }
}

// =========================================================================
// flash attention tile kernel (64 q-rows/block, 64-wide KV chunks, online
// softmax). local=1 -> band mask w/ chunks centered at i0; local=0 -> full LK.
// dynamic smem: Qs[64][68] (d-major) | KsPs | Vs
// =========================================================================
extern __shared__ float fsm[];
__global__ void flash_kernel(const float* __restrict__ Qm, const float* __restrict__ Kc,
                             const float* __restrict__ Vc, float* __restrict__ Out,
                             int LK, int nchunks, int local)
{
    float* Qs = fsm;              // [d][row] stride 68
    float* KP = fsm + 64*68;      // K: [d][j] stride 68; later P: [row][col] stride 68
    float* Vs = fsm + 2*64*68;    // [j][d] stride 68
    const int tid = threadIdx.x;
    const int tr = tid >> 4, tc = tid & 15;
    const int bh = blockIdx.y;
    const int b = bh >> 3, h = bh & 7;
    const int i0 = blockIdx.x * 64;
    const float* qb = Qm + ((size_t)(b*Ls) + i0)*Dm + h*HDim;
    const float* kb = Kc + (size_t)(b*LK)*Dm + h*HDim;
    const float* vb = Vc + (size_t)(b*LK)*Dm + h*HDim;

    // load Q transposed
    #pragma unroll
    for (int rep = 0; rep < 4; rep++) {
        int slot = tid + 256*rep;
        int row = slot >> 4, c4 = slot & 15;
        float4 v = *(const float4*)&qb[(size_t)row*Dm + c4*4];
        Qs[(c4*4+0)*68 + row] = v.x; Qs[(c4*4+1)*68 + row] = v.y;
        Qs[(c4*4+2)*68 + row] = v.z; Qs[(c4*4+3)*68 + row] = v.w;
    }

    float acc[4][4] = {};
    float mrow[4] = {-INFINITY, -INFINITY, -INFINITY, -INFINITY};
    float lrow[4] = {};

    for (int c = 0; c < nchunks; c++) {
        int jbase = (local ? i0 - 64 : 0) + c*64;
        // load K chunk transposed (zero OOB)
        __syncthreads();
        #pragma unroll
        for (int rep = 0; rep < 4; rep++) {
            int slot = tid + 256*rep;
            int row = slot >> 4, c4 = slot & 15;
            int jg = jbase + row;
            float4 v = make_float4(0.f,0.f,0.f,0.f);
            if (jg >= 0 && jg < LK) v = *(const float4*)&kb[(size_t)jg*Dm + c4*4];
            KP[(c4*4+0)*68 + row] = v.x; KP[(c4*4+1)*68 + row] = v.y;
            KP[(c4*4+2)*68 + row] = v.z; KP[(c4*4+3)*68 + row] = v.w;
        }
        // load V chunk (natural, zero OOB)
        #pragma unroll
        for (int rep = 0; rep < 4; rep++) {
            int slot = tid + 256*rep;
            int row = slot >> 4, c4 = slot & 15;
            int jg = jbase + row;
            float4 v = make_float4(0.f,0.f,0.f,0.f);
            if (jg >= 0 && jg < LK) v = *(const float4*)&vb[(size_t)jg*Dm + c4*4];
            *(float4*)&Vs[row*68 + c4*4] = v;
        }
        __syncthreads();

        // S = Q K^T * scale (regs)
        float s[4][4] = {};
        #pragma unroll 8
        for (int d = 0; d < 64; d++) {
            float a[4], w[4];
            #pragma unroll
            for (int i = 0; i < 4; i++) a[i] = Qs[d*68 + tr*4 + i];
            #pragma unroll
            for (int j = 0; j < 4; j++) w[j] = KP[d*68 + tc*4 + j];
            #pragma unroll
            for (int i = 0; i < 4; i++)
                #pragma unroll
                for (int j = 0; j < 4; j++)
                    s[i][j] = fmaf(a[i], w[j], s[i][j]);
        }

        // online softmax update
        float cf[4];
        float p[4][4];
        #pragma unroll
        for (int i = 0; i < 4; i++) {
            int irow = i0 + tr*4 + i;
            float rm = -INFINITY;
            bool vmask[4];
            #pragma unroll
            for (int j = 0; j < 4; j++) {
                int jg = jbase + tc*4 + j;
                bool ok = (jg >= 0) && (jg < LK);
                if (local) ok = ok && (jg >= irow - 64) && (jg <= irow + 64);
                vmask[j] = ok;
                float x = s[i][j] * 0.125f;
                s[i][j] = x;
                if (ok) rm = fmaxf(rm, x);
            }
            #pragma unroll
            for (int o = 8; o; o >>= 1) rm = fmaxf(rm, __shfl_xor_sync(0xFFFFFFFFu, rm, o));
            float mnew = fmaxf(mrow[i], rm);
            cf[i] = (mnew == -INFINITY) ? 1.f : __expf(mrow[i] - mnew);
            mrow[i] = mnew;
            float ps = 0.f;
            #pragma unroll
            for (int j = 0; j < 4; j++) {
                float pv = (vmask[j] && mnew != -INFINITY) ? __expf(s[i][j] - mnew) : 0.f;
                p[i][j] = pv;
                ps += pv;
            }
            #pragma unroll
            for (int o = 8; o; o >>= 1) ps += __shfl_xor_sync(0xFFFFFFFFu, ps, o);
            lrow[i] = lrow[i]*cf[i] + ps;
            #pragma unroll
            for (int j = 0; j < 4; j++) acc[i][j] *= cf[i];
        }

        // write P into KP buffer (row-major), then PV
        __syncthreads();
        #pragma unroll
        for (int i = 0; i < 4; i++)
            *(float4*)&KP[(tr*4+i)*68 + tc*4] = *(float4*)&p[i][0];
        __syncthreads();

        #pragma unroll 4
        for (int jv = 0; jv < 64; jv++) {
            float a[4], w[4];
            #pragma unroll
            for (int i = 0; i < 4; i++) a[i] = KP[(tr*4+i)*68 + jv];
            #pragma unroll
            for (int j = 0; j < 4; j++) w[j] = Vs[jv*68 + tc*4 + j];
            #pragma unroll
            for (int i = 0; i < 4; i++)
                #pragma unroll
                for (int j = 0; j < 4; j++)
                    acc[i][j] = fmaf(a[i], w[j], acc[i][j]);
        }
    }

    #pragma unroll
    for (int i = 0; i < 4; i++) {
        float inv = 1.0f / lrow[i];
        float4 o;
        o.x = acc[i][0]*inv; o.y = acc[i][1]*inv;
        o.z = acc[i][2]*inv; o.w = acc[i][3]*inv;
        *(float4*)&Out[((size_t)(b*Ls) + i0 + tr*4 + i)*Dm + h*HDim + tc*4] = o;
    }
}

// ---------------- compress: mean over groups of 4 rows (float4) ----------------
__global__ void compress_kernel()
{
    int e4 = blockIdx.x*blockDim.x + threadIdx.x;
    int b = e4 / (LcC*Dm/4);
    int r = e4 % (LcC*Dm/4);
    int m = r / (Dm/4), d4 = r % (Dm/4);
    const float4* k4 = (const float4*)g_k;
    const float4* v4 = (const float4*)g_v;
    size_t base = ((size_t)(b*Ls + m*4)*Dm)/4 + d4;
    float4 a = k4[base], bb = k4[base+128], c = k4[base+256], d = k4[base+384];
    float4 o;
    o.x = 0.25f*(a.x+bb.x+c.x+d.x); o.y = 0.25f*(a.y+bb.y+c.y+d.y);
    o.z = 0.25f*(a.z+bb.z+c.z+d.z); o.w = 0.25f*(a.w+bb.w+c.w+d.w);
    ((float4*)g_kcpre)[e4] = o;
    a = v4[base]; bb = v4[base+128]; c = v4[base+256]; d = v4[base+384];
    o.x = 0.25f*(a.x+bb.x+c.x+d.x); o.y = 0.25f*(a.y+bb.y+c.y+d.y);
    o.z = 0.25f*(a.z+bb.z+c.z+d.z); o.w = 0.25f*(a.w+bb.w+c.w+d.w);
    ((float4*)g_vc)[e4] = o;
}

// ---------------- combine: pw0*out_g + pw1*out_l ----------------
__global__ void combine_kernel(const float* __restrict__ pm)
{
    float a0 = pm[0], a1 = pm[1], a2 = pm[2];
    float mx = fmaxf(a0, fmaxf(a1, a2));
    float e0 = expf(a0-mx), e1 = expf(a1-mx), e2 = expf(a2-mx);
    float den = e0+e1+e2;
    float pw0 = e0/den, pw1 = e1/den;
    int e = blockIdx.x*blockDim.x + threadIdx.x;
    g_comb[e] = pw0*g_outg[e] + pw1*g_outl[e];
}

// ---------------- selection path: recompute 1 row of scores + softmax*V ----------------
__global__ void attns_kernel(const float* __restrict__ pm)
{
    __shared__ float sc[Ls];
    __shared__ float qs[64];
    __shared__ float red[256];
    int blk = blockIdx.x;
    int bh  = blk / NSEL, si = blk % NSEL;
    int b = bh >> 3, h = bh & 7;
    int qi = g_selidx[bh*NSEL + si];
    int t = threadIdx.x;

    if (t < 16) {
        float4 v = *(const float4*)&g_q[((size_t)(b*Ls) + qi)*Dm + h*HDim + t*4];
        *(float4*)&qs[t*4] = v;
    }
    __syncthreads();

    // scores: 8 keys per thread
    const float* kb = g_k + ((size_t)(b*Ls))*Dm + h*HDim;
    for (int jj = 0; jj < 8; jj++) {
        int j = t*8 + jj;
        const float4* kr = (const float4*)&kb[(size_t)j*Dm];
        float dot = 0.f;
        #pragma unroll
        for (int d4 = 0; d4 < 16; d4++) {
            float4 kv = kr[d4];
            dot = fmaf(qs[d4*4+0], kv.x, dot);
            dot = fmaf(qs[d4*4+1], kv.y, dot);
            dot = fmaf(qs[d4*4+2], kv.z, dot);
            dot = fmaf(qs[d4*4+3], kv.w, dot);
        }
        sc[j] = dot * 0.125f;
    }
    __syncthreads();

    float m = -INFINITY;
    for (int j = t; j < Ls; j += 256) m = fmaxf(m, sc[j]);
    red[t] = m; __syncthreads();
    for (int s2 = 128; s2; s2 >>= 1) { if (t < s2) red[t] = fmaxf(red[t], red[t+s2]); __syncthreads(); }
    m = red[0]; __syncthreads();

    float s = 0.f;
    for (int j = t; j < Ls; j += 256) { float e = __expf(sc[j]-m); sc[j] = e; s += e; }
    red[t] = s; __syncthreads();
    for (int s2 = 128; s2; s2 >>= 1) { if (t < s2) red[t] += red[t+s2]; __syncthreads(); }
    s = red[0]; __syncthreads();

    int d = t & 63, qtr = t >> 6;
    const float* vb = g_v + ((size_t)b*Ls)*Dm + h*HDim + d;
    float acc = 0.f;
    for (int j = qtr*512; j < qtr*512 + 512; j++)
        acc = fmaf(sc[j], vb[(size_t)j*Dm], acc);
    red[t] = acc; __syncthreads();

    if (t < 64) {
        float tot = red[t] + red[t+64] + red[t+128] + red[t+192];
        float a0 = pm[0], a1 = pm[1], a2 = pm[2];
        float mx = fmaxf(a0, fmaxf(a1, a2));
        float e0 = expf(a0-mx), e1 = expf(a1-mx), e2 = expf(a2-mx);
        float pw2 = e2/(e0+e1+e2);
        g_comb[((size_t)b*Ls + qi)*Dm + h*HDim + t] += pw2 * tot / s;
    }
}

// ---------------- launch ----------------
extern "C" void kernel_launch(void* const* d_in, const int* in_sizes, int n_in,
                              void* d_out, int out_size)
{
    const float* query = (const float*)d_in[0];
    const float* keyi  = (const float*)d_in[1];
    const float* vali  = (const float*)d_in[2];
    const float* Wq = (const float*)d_in[3];  const float* bq = (const float*)d_in[4];
    const float* Wk = (const float*)d_in[5];  const float* bk = (const float*)d_in[6];
    const float* Wv = (const float*)d_in[7];  const float* bv = (const float*)d_in[8];
    const float* Wo = (const float*)d_in[9];  const float* bo = (const float*)d_in[10];
    const float* Wc1 = (const float*)d_in[11]; const float* bc1 = (const float*)d_in[12];
    const float* Wc2 = (const float*)d_in[13]; const float* bc2 = (const float*)d_in[14];
    const float* pm  = (const float*)d_in[15];

    float *q, *k, *v, *kcpre, *hid, *kc, *vc, *outg, *outl, *comb;
    cudaGetSymbolAddress((void**)&q,     g_q);
    cudaGetSymbolAddress((void**)&k,     g_k);
    cudaGetSymbolAddress((void**)&v,     g_v);
    cudaGetSymbolAddress((void**)&kcpre, g_kcpre);
    cudaGetSymbolAddress((void**)&hid,   g_hid);
    cudaGetSymbolAddress((void**)&kc,    g_kc);
    cudaGetSymbolAddress((void**)&vc,    g_vc);
    cudaGetSymbolAddress((void**)&outg,  g_outg);
    cudaGetSymbolAddress((void**)&outl,  g_outl);
    cudaGetSymbolAddress((void**)&comb,  g_comb);

    const int FLASH_SMEM = 3*64*68*4;
    cudaFuncSetAttribute(flash_kernel, cudaFuncAttributeMaxDynamicSharedMemorySize, FLASH_SMEM);

    // q/k/v projections in one launch
    proj3_kernel<<<dim3(4,32,3), 256>>>(query, keyi, vali, Wq, Wk, Wv, bq, bk, bv, q, k, v);

    // compression + MLP
    compress_kernel<<<512, 256>>>();
    sgemm_bias_kernel<<<dim3(8,16), 256>>>(kcpre, Wc1, bc1, hid, Dm, Dm, 1);
    sgemm_bias_kernel<<<dim3(8,16), 256>>>(hid,   Wc2, bc2, kc,  Dm, Dm, 0);

    // dense QK^T + fused row stats (no score tensor)
    scores_stats_kernel<<<dim3(NJT,16,16), 256>>>(q, k, 0.125f);
    impfinal_kernel<<<4096, 256>>>();
    topk_kernel<<<Bb*Hh, 256>>>();

    // attention paths (flash)
    flash_kernel<<<dim3(32,16), 256, FLASH_SMEM>>>(q, k,  v,  outl, Ls,  3, 1);
    flash_kernel<<<dim3(32,16), 256, FLASH_SMEM>>>(q, kc, vc, outg, LcC, 8, 0);

    // mix + selection scatter-add
    combine_kernel<<<(Bb*Ls*Dm)/256, 256>>>(pm);
    attns_kernel<<<Bb*Hh*NSEL, 256>>>(pm);

    // output projection
    sgemm128_kernel<<<dim3(4,32), 256>>>(comb, Wo, bo, (float*)d_out, Dm, Dm, 0);
}

// round 4
// speedup vs baseline: 1.6361x; 1.1357x over previous
#include <cuda_runtime.h>
#include <cuda_bf16.h>
#include <math.h>
#include <stdint.h>

#define Bb   2
#define Ls   2048
#define Dm   512
#define Hh   8
#define HDim 64
#define LcC  512
#define NSEL 8
#define NJT  16

// ---------------- fp32 scratch ----------------
static __device__ float g_q[Bb*Ls*Dm];
static __device__ float g_k[Bb*Ls*Dm];
static __device__ float g_v[Bb*Ls*Dm];
static __device__ float g_kcpre[Bb*LcC*Dm];
static __device__ float g_vc[Bb*LcC*Dm];
static __device__ float g_kc[Bb*LcC*Dm];
static __device__ float g_outg[Bb*Ls*Dm];
static __device__ float g_outl[Bb*Ls*Dm];
static __device__ float g_comb[Bb*Ls*Dm];
static __device__ float g_imp[Bb*Hh*Ls];
static __device__ int   g_selidx[Bb*Hh*NSEL];
static __device__ float g_pmax[Bb*Hh*Ls*NJT];
static __device__ float g_pse [Bb*Hh*Ls*NJT];
static __device__ float g_psum[Bb*Hh*Ls*NJT];

// ---------------- bf16 split scratch ----------------
static __device__ __nv_bfloat16 g_inh[3][Bb*Ls*Dm];
static __device__ __nv_bfloat16 g_inl[3][Bb*Ls*Dm];
static __device__ __nv_bfloat16 g_wth[6][Dm*Dm];   // transposed [N][K]
static __device__ __nv_bfloat16 g_wtl[6][Dm*Dm];
static __device__ __nv_bfloat16 g_qh[Bb*Ls*Dm], g_ql[Bb*Ls*Dm];
static __device__ __nv_bfloat16 g_kh[Bb*Ls*Dm], g_kl[Bb*Ls*Dm];
static __device__ __nv_bfloat16 g_kcpreh[Bb*LcC*Dm], g_kcprel[Bb*LcC*Dm];
static __device__ __nv_bfloat16 g_hidh[Bb*LcC*Dm], g_hidl[Bb*LcC*Dm];
static __device__ __nv_bfloat16 g_combh[Bb*Ls*Dm], g_combl[Bb*Ls*Dm];

__device__ __forceinline__ void bsplit(float x, __nv_bfloat16& h, __nv_bfloat16& l)
{
    h = __float2bfloat16(x);
    l = __float2bfloat16(x - __bfloat162float(h));
}

__device__ __forceinline__ void mma16816(float* c, const uint32_t* a, const uint32_t* b)
{
    asm volatile(
        "mma.sync.aligned.m16n8k16.row.col.f32.bf16.bf16.f32 "
        "{%0,%1,%2,%3}, {%4,%5,%6,%7}, {%8,%9}, {%0,%1,%2,%3};"
        : "+f"(c[0]), "+f"(c[1]), "+f"(c[2]), "+f"(c[3])
        : "r"(a[0]), "r"(a[1]), "r"(a[2]), "r"(a[3]), "r"(b[0]), "r"(b[1]));
}

// ---------------- prep: split inputs ----------------
__global__ void split_in_kernel(const float* x0, const float* x1, const float* x2)
{
    int z = blockIdx.y;
    const float* x = z == 0 ? x0 : (z == 1 ? x1 : x2);
    int i = blockIdx.x*blockDim.x + threadIdx.x;
    bsplit(x[i], g_inh[z][i], g_inl[z][i]);
}

// ---------------- prep: split + transpose a weight ----------------
__global__ void split_w_kernel(const float* w, int widx)
{
    __shared__ float tl[32][33];
    int tx = threadIdx.x, ty = threadIdx.y;          // 32 x 8
    int n0 = blockIdx.x*32, k0 = blockIdx.y*32;
    #pragma unroll
    for (int i = 0; i < 4; i++)
        tl[ty + i*8][tx] = w[(size_t)(k0 + ty + i*8)*Dm + n0 + tx];
    __syncthreads();
    #pragma unroll
    for (int i = 0; i < 4; i++) {
        float v = tl[tx][ty + i*8];
        size_t o = (size_t)(n0 + ty + i*8)*Dm + k0 + tx;
        bsplit(v, g_wth[widx][o], g_wtl[widx][o]);
    }
}

// =========================================================================
// bf16x3 tensor-core GEMM: C[M][N] = A[M][K] @ Bw^T + bias
// A given as hi/lo [M][K], Bw as hi/lo [N][K]. 128x128 tile, 256 thr,
// warps 2(M)x4(N), m16n8k16, double-buffered smem.
// =========================================================================
__device__ __forceinline__ void mma_gemm_body(
    const __nv_bfloat16* __restrict__ Ah, const __nv_bfloat16* __restrict__ Al,
    const __nv_bfloat16* __restrict__ Bh, const __nv_bfloat16* __restrict__ Bl,
    const float* __restrict__ bias, float* __restrict__ C,
    __nv_bfloat16* __restrict__ Ch, __nv_bfloat16* __restrict__ Cl,
    int N, int K, int gelu)
{
    __shared__ __nv_bfloat16 sAh[2][128*24], sAl[2][128*24];
    __shared__ __nv_bfloat16 sBh[2][128*24], sBl[2][128*24];
    const int tid = threadIdx.x;
    const int lane = tid & 31, warp = tid >> 5;
    const int wm = warp >> 2, wn = warp & 3;
    const int qr = lane >> 2, qc = (lane & 3)*2;
    const int row0 = blockIdx.y*128, col0 = blockIdx.x*128;
    const int half = tid >> 7, r = tid & 127;

    const __nv_bfloat16* As = half ? Al : Ah;
    const __nv_bfloat16* Bs = half ? Bl : Bh;

    // preload k-chunk 0
    {
        const uint4* pa = (const uint4*)(As + (size_t)(row0 + r)*K);
        const uint4* pb = (const uint4*)(Bs + (size_t)(col0 + r)*K);
        uint4 a0 = pa[0], a1 = pa[1], b0 = pb[0], b1 = pb[1];
        __nv_bfloat16* dA = half ? sAl[0] : sAh[0];
        __nv_bfloat16* dB = half ? sBl[0] : sBh[0];
        *(uint4*)&dA[r*24]     = a0; *(uint4*)&dA[r*24 + 8] = a1;
        *(uint4*)&dB[r*24]     = b0; *(uint4*)&dB[r*24 + 8] = b1;
    }
    __syncthreads();

    float acc[4][4][4] = {};
    const int nk = K >> 4;
    for (int kc = 0; kc < nk; kc++) {
        const int buf = kc & 1;
        uint4 na0, na1, nb0, nb1;
        if (kc + 1 < nk) {
            int k0 = (kc + 1)*16;
            const uint4* pa = (const uint4*)(As + (size_t)(row0 + r)*K + k0);
            const uint4* pb = (const uint4*)(Bs + (size_t)(col0 + r)*K + k0);
            na0 = pa[0]; na1 = pa[1]; nb0 = pb[0]; nb1 = pb[1];
        }

        const __nv_bfloat16* cAh = sAh[buf];
        const __nv_bfloat16* cAl = sAl[buf];
        const __nv_bfloat16* cBh = sBh[buf];
        const __nv_bfloat16* cBl = sBl[buf];

        uint32_t bh[4][2], bl[4][2];
        #pragma unroll
        for (int nt = 0; nt < 4; nt++) {
            int bo = (wn*32 + nt*8 + qr)*24 + qc;
            bh[nt][0] = *(const uint32_t*)&cBh[bo];
            bh[nt][1] = *(const uint32_t*)&cBh[bo + 8];
            bl[nt][0] = *(const uint32_t*)&cBl[bo];
            bl[nt][1] = *(const uint32_t*)&cBl[bo + 8];
        }
        #pragma unroll
        for (int mt = 0; mt < 4; mt++) {
            int ao = (wm*64 + mt*16 + qr)*24 + qc;
            uint32_t ah[4], al[4];
            ah[0] = *(const uint32_t*)&cAh[ao];
            ah[1] = *(const uint32_t*)&cAh[ao + 8*24];
            ah[2] = *(const uint32_t*)&cAh[ao + 8];
            ah[3] = *(const uint32_t*)&cAh[ao + 8*24 + 8];
            al[0] = *(const uint32_t*)&cAl[ao];
            al[1] = *(const uint32_t*)&cAl[ao + 8*24];
            al[2] = *(const uint32_t*)&cAl[ao + 8];
            al[3] = *(const uint32_t*)&cAl[ao + 8*24 + 8];
            #pragma unroll
            for (int nt = 0; nt < 4; nt++) {
                mma16816(acc[mt][nt], ah, bh[nt]);
                mma16816(acc[mt][nt], ah, bl[nt]);
                mma16816(acc[mt][nt], al, bh[nt]);
            }
        }

        if (kc + 1 < nk) {
            const int nb = buf ^ 1;
            __nv_bfloat16* dA = half ? sAl[nb] : sAh[nb];
            __nv_bfloat16* dB = half ? sBl[nb] : sBh[nb];
            *(uint4*)&dA[r*24]     = na0; *(uint4*)&dA[r*24 + 8] = na1;
            *(uint4*)&dB[r*24]     = nb0; *(uint4*)&dB[r*24 + 8] = nb1;
        }
        __syncthreads();
    }

    // epilogue
    #pragma unroll
    for (int mt = 0; mt < 4; mt++) {
        int gr = row0 + wm*64 + mt*16 + qr;
        #pragma unroll
        for (int nt = 0; nt < 4; nt++) {
            int gc = col0 + wn*32 + nt*8 + qc;
            float v0 = acc[mt][nt][0] + bias[gc];
            float v1 = acc[mt][nt][1] + bias[gc+1];
            float v2 = acc[mt][nt][2] + bias[gc];
            float v3 = acc[mt][nt][3] + bias[gc+1];
            if (gelu) {
                v0 = 0.5f*v0*(1.0f + erff(v0*0.70710678118654752f));
                v1 = 0.5f*v1*(1.0f + erff(v1*0.70710678118654752f));
                v2 = 0.5f*v2*(1.0f + erff(v2*0.70710678118654752f));
                v3 = 0.5f*v3*(1.0f + erff(v3*0.70710678118654752f));
            }
            if (C) {
                float2 p0 = make_float2(v0, v1), p1 = make_float2(v2, v3);
                *(float2*)&C[(size_t)gr*N + gc]     = p0;
                *(float2*)&C[(size_t)(gr+8)*N + gc] = p1;
            }
            if (Ch) {
                __nv_bfloat16 h0,l0,h1,l1,h2,l2,h3,l3;
                bsplit(v0,h0,l0); bsplit(v1,h1,l1); bsplit(v2,h2,l2); bsplit(v3,h3,l3);
                Ch[(size_t)gr*N + gc]   = h0; Ch[(size_t)gr*N + gc+1]   = h1;
                Cl[(size_t)gr*N + gc]   = l0; Cl[(size_t)gr*N + gc+1]   = l1;
                Ch[(size_t)(gr+8)*N+gc] = h2; Ch[(size_t)(gr+8)*N+gc+1] = h3;
                Cl[(size_t)(gr+8)*N+gc] = l2; Cl[(size_t)(gr+8)*N+gc+1] = l3;
            }
        }
    }
}

__global__ void __launch_bounds__(256, 1) mma_gemm_kernel(
    const __nv_bfloat16* Ah, const __nv_bfloat16* Al,
    const __nv_bfloat16* Bh, const __nv_bfloat16* Bl,
    const float* bias, float* C, __nv_bfloat16* Ch, __nv_bfloat16* Cl,
    int N, int K, int gelu)
{
    mma_gemm_body(Ah, Al, Bh, Bl, bias, C, Ch, Cl, N, K, gelu);
}

// q/k/v projections in one launch
__global__ void __launch_bounds__(256, 1) proj3_mma_kernel(
    const float* bq, const float* bk, const float* bv)
{
    int z = blockIdx.z;
    if (z == 0)
        mma_gemm_body(g_inh[0], g_inl[0], g_wth[0], g_wtl[0], bq, g_q, g_qh, g_ql, Dm, Dm, 0);
    else if (z == 1)
        mma_gemm_body(g_inh[1], g_inl[1], g_wth[1], g_wtl[1], bk, g_k, g_kh, g_kl, Dm, Dm, 0);
    else
        mma_gemm_body(g_inh[2], g_inl[2], g_wth[2], g_wtl[2], bv, g_v, nullptr, nullptr, Dm, Dm, 0);
}

// =========================================================================
// dense QK^T (bf16x3 mma) + fused row stats. grid (NJT, 16, B*H).
// A = Q[b,:,h*64..], B = K[b,:,h*64..], lda = Dm, Kdim = 64.
// =========================================================================
__global__ void __launch_bounds__(256, 1) scores_stats_mma_kernel(float scale)
{
    __shared__ __nv_bfloat16 sAh[128*24], sAl[128*24];
    __shared__ __nv_bfloat16 sBh[128*24], sBl[128*24];
    __shared__ float s4a[128][4], s4b[128][4], srm[128];

    const int tid = threadIdx.x;
    const int lane = tid & 31, warp = tid >> 5;
    const int wm = warp >> 2, wn = warp & 3;
    const int qr = lane >> 2, qc = (lane & 3)*2;
    const int bh = blockIdx.z;
    const int b = bh >> 3, h = bh & 7;
    const int i0 = blockIdx.y*128, j0 = blockIdx.x*128;
    const int half = tid >> 7, r = tid & 127;

    const __nv_bfloat16* Qs = (half ? g_ql : g_qh) + ((size_t)(b*Ls))*Dm + h*HDim;
    const __nv_bfloat16* Ks = (half ? g_kl : g_kh) + ((size_t)(b*Ls))*Dm + h*HDim;

    float acc[4][4][4] = {};
    for (int kc = 0; kc < 4; kc++) {
        int k0 = kc*16;
        {
            const uint4* pa = (const uint4*)(Qs + (size_t)(i0 + r)*Dm + k0);
            const uint4* pb = (const uint4*)(Ks + (size_t)(j0 + r)*Dm + k0);
            uint4 a0 = pa[0], a1 = pa[1], b0 = pb[0], b1 = pb[1];
            __nv_bfloat16* dA = half ? sAl : sAh;
            __nv_bfloat16* dB = half ? sBl : sBh;
            *(uint4*)&dA[r*24]     = a0; *(uint4*)&dA[r*24 + 8] = a1;
            *(uint4*)&dB[r*24]     = b0; *(uint4*)&dB[r*24 + 8] = b1;
        }
        __syncthreads();

        uint32_t bhf[4][2], blf[4][2];
        #pragma unroll
        for (int nt = 0; nt < 4; nt++) {
            int bo = (wn*32 + nt*8 + qr)*24 + qc;
            bhf[nt][0] = *(const uint32_t*)&sBh[bo];
            bhf[nt][1] = *(const uint32_t*)&sBh[bo + 8];
            blf[nt][0] = *(const uint32_t*)&sBl[bo];
            blf[nt][1] = *(const uint32_t*)&sBl[bo + 8];
        }
        #pragma unroll
        for (int mt = 0; mt < 4; mt++) {
            int ao = (wm*64 + mt*16 + qr)*24 + qc;
            uint32_t ah[4], al[4];
            ah[0] = *(const uint32_t*)&sAh[ao];
            ah[1] = *(const uint32_t*)&sAh[ao + 8*24];
            ah[2] = *(const uint32_t*)&sAh[ao + 8];
            ah[3] = *(const uint32_t*)&sAh[ao + 8*24 + 8];
            al[0] = *(const uint32_t*)&sAl[ao];
            al[1] = *(const uint32_t*)&sAl[ao + 8*24];
            al[2] = *(const uint32_t*)&sAl[ao + 8];
            al[3] = *(const uint32_t*)&sAl[ao + 8*24 + 8];
            #pragma unroll
            for (int nt = 0; nt < 4; nt++) {
                mma16816(acc[mt][nt], ah, bhf[nt]);
                mma16816(acc[mt][nt], ah, blf[nt]);
                mma16816(acc[mt][nt], al, bhf[nt]);
            }
        }
        __syncthreads();
    }

    // ---- fused stats over the 128-col j-tile ----
    // phase 1: per-row max
    #pragma unroll
    for (int mt = 0; mt < 4; mt++) {
        float m0 = -INFINITY, m1 = -INFINITY;
        #pragma unroll
        for (int nt = 0; nt < 4; nt++) {
            m0 = fmaxf(m0, fmaxf(acc[mt][nt][0], acc[mt][nt][1]));
            m1 = fmaxf(m1, fmaxf(acc[mt][nt][2], acc[mt][nt][3]));
        }
        m0 = fmaxf(m0, __shfl_xor_sync(0xFFFFFFFFu, m0, 1));
        m0 = fmaxf(m0, __shfl_xor_sync(0xFFFFFFFFu, m0, 2));
        m1 = fmaxf(m1, __shfl_xor_sync(0xFFFFFFFFu, m1, 1));
        m1 = fmaxf(m1, __shfl_xor_sync(0xFFFFFFFFu, m1, 2));
        if ((lane & 3) == 0) {
            s4a[wm*64 + mt*16 + qr][wn]     = m0;
            s4a[wm*64 + mt*16 + 8 + qr][wn] = m1;
        }
    }
    __syncthreads();
    if (tid < 128)
        srm[tid] = fmaxf(fmaxf(s4a[tid][0], s4a[tid][1]), fmaxf(s4a[tid][2], s4a[tid][3]));
    __syncthreads();

    // phase 2: sumexp (rel. row-tile-max, on scaled values) + raw sum
    #pragma unroll
    for (int mt = 0; mt < 4; mt++) {
        int lr0 = wm*64 + mt*16 + qr, lr1 = lr0 + 8;
        float rm0 = srm[lr0]*scale, rm1 = srm[lr1]*scale;
        float se0 = 0.f, se1 = 0.f, ss0 = 0.f, ss1 = 0.f;
        #pragma unroll
        for (int nt = 0; nt < 4; nt++) {
            float x0 = acc[mt][nt][0]*scale, x1 = acc[mt][nt][1]*scale;
            float x2 = acc[mt][nt][2]*scale, x3 = acc[mt][nt][3]*scale;
            se0 += __expf(x0 - rm0) + __expf(x1 - rm0);
            se1 += __expf(x2 - rm1) + __expf(x3 - rm1);
            ss0 += x0 + x1; ss1 += x2 + x3;
        }
        se0 += __shfl_xor_sync(0xFFFFFFFFu, se0, 1); se0 += __shfl_xor_sync(0xFFFFFFFFu, se0, 2);
        se1 += __shfl_xor_sync(0xFFFFFFFFu, se1, 1); se1 += __shfl_xor_sync(0xFFFFFFFFu, se1, 2);
        ss0 += __shfl_xor_sync(0xFFFFFFFFu, ss0, 1); ss0 += __shfl_xor_sync(0xFFFFFFFFu, ss0, 2);
        ss1 += __shfl_xor_sync(0xFFFFFFFFu, ss1, 1); ss1 += __shfl_xor_sync(0xFFFFFFFFu, ss1, 2);
        if ((lane & 3) == 0) {
            s4b[lr0][wn] = se0; s4b[lr1][wn] = se1;
            s4a[lr0][wn] = ss0; s4a[lr1][wn] = ss1;   // reuse s4a for sums
        }
    }
    __syncthreads();
    if (tid < 128) {
        int rowg = bh*Ls + i0 + tid;
        int jt = blockIdx.x;
        g_pmax[(size_t)rowg*NJT + jt] = srm[tid]*scale;
        g_pse [(size_t)rowg*NJT + jt] = s4b[tid][0]+s4b[tid][1]+s4b[tid][2]+s4b[tid][3];
        g_psum[(size_t)rowg*NJT + jt] = s4a[tid][0]+s4a[tid][1]+s4a[tid][2]+s4a[tid][3];
    }
}

// ---------------- compress: mean of 4 rows + split kcpre ----------------
__global__ void compress_kernel()
{
    int e4 = blockIdx.x*blockDim.x + threadIdx.x;
    int b = e4 / (LcC*Dm/4);
    int r = e4 % (LcC*Dm/4);
    int m = r / (Dm/4), d4 = r % (Dm/4);
    const float4* k4 = (const float4*)g_k;
    const float4* v4 = (const float4*)g_v;
    size_t base = ((size_t)(b*Ls + m*4)*Dm)/4 + d4;
    float4 a = k4[base], bb = k4[base+128], c = k4[base+256], d = k4[base+384];
    float4 o;
    o.x = 0.25f*(a.x+bb.x+c.x+d.x); o.y = 0.25f*(a.y+bb.y+c.y+d.y);
    o.z = 0.25f*(a.z+bb.z+c.z+d.z); o.w = 0.25f*(a.w+bb.w+c.w+d.w);
    ((float4*)g_kcpre)[e4] = o;
    bsplit(o.x, g_kcpreh[e4*4+0], g_kcprel[e4*4+0]);
    bsplit(o.y, g_kcpreh[e4*4+1], g_kcprel[e4*4+1]);
    bsplit(o.z, g_kcpreh[e4*4+2], g_kcprel[e4*4+2]);
    bsplit(o.w, g_kcpreh[e4*4+3], g_kcprel[e4*4+3]);
    a = v4[base]; bb = v4[base+128]; c = v4[base+256]; d = v4[base+384];
    o.x = 0.25f*(a.x+bb.x+c.x+d.x); o.y = 0.25f*(a.y+bb.y+c.y+d.y);
    o.z = 0.25f*(a.z+bb.z+c.z+d.z); o.w = 0.25f*(a.w+bb.w+c.w+d.w);
    ((float4*)g_vc)[e4] = o;
}

// ---------------- importance merge ----------------
__global__ void impfinal_kernel()
{
    int warp = (blockIdx.x*blockDim.x + threadIdx.x) >> 5;
    int lane = threadIdx.x & 31;
    float pm = -INFINITY, pe = 0.f, ps = 0.f;
    if (lane < NJT) {
        pm = g_pmax[(size_t)warp*NJT + lane];
        pe = g_pse [(size_t)warp*NJT + lane];
        ps = g_psum[(size_t)warp*NJT + lane];
    }
    float m = pm;
    #pragma unroll
    for (int o = 8; o; o >>= 1) m = fmaxf(m, __shfl_xor_sync(0xFFFFFFFFu, m, o));
    float se = (lane < NJT) ? pe * __expf(pm - m) : 0.f;
    #pragma unroll
    for (int o = 8; o; o >>= 1) {
        se += __shfl_xor_sync(0xFFFFFFFFu, se, o);
        ps += __shfl_xor_sync(0xFFFFFFFFu, ps, o);
    }
    if (lane == 0)
        g_imp[warp] = m + logf(se) - 7.6246189861593985f - ps * (1.0f/2048.0f);
}

// ---------------- top-8 ----------------
__global__ void topk_kernel()
{
    int bh = blockIdx.x;
    const float* imp = g_imp + bh*Ls;
    __shared__ float bv[256];
    __shared__ int   bi[256];
    __shared__ int   chosen[NSEL];
    int t = threadIdx.x;
    for (int itu = 0; itu < NSEL; itu++) {
        float best = -INFINITY; int bidx = 0x7FFFFFFF;
        for (int j = t; j < Ls; j += 256) {
            bool skip = false;
            for (int c = 0; c < itu; c++) if (chosen[c] == j) skip = true;
            if (skip) continue;
            float vv = imp[j];
            if (vv > best || (vv == best && j < bidx)) { best = vv; bidx = j; }
        }
        bv[t] = best; bi[t] = bidx;
        __syncthreads();
        for (int s2 = 128; s2; s2 >>= 1) {
            if (t < s2) {
                if (bv[t+s2] > bv[t] || (bv[t+s2] == bv[t] && bi[t+s2] < bi[t])) {
                    bv[t] = bv[t+s2]; bi[t] = bi[t+s2];
                }
            }
            __syncthreads();
        }
        if (t == 0) { chosen[itu] = bi[0]; g_selidx[bh*NSEL + itu] = bi[0]; }
        __syncthreads();
    }
}

// ---------------- flash tile kernel (fp32) ----------------
extern __shared__ float fsm[];
__global__ void flash_kernel(const float* __restrict__ Qm, const float* __restrict__ Kc,
                             const float* __restrict__ Vc, float* __restrict__ Out,
                             int LK, int nchunks, int local)
{
    float* Qs = fsm;
    float* KP = fsm + 64*68;
    float* Vs = fsm + 2*64*68;
    const int tid = threadIdx.x;
    const int tr = tid >> 4, tc = tid & 15;
    const int bh = blockIdx.y;
    const int b = bh >> 3, h = bh & 7;
    const int i0 = blockIdx.x * 64;
    const float* qb = Qm + ((size_t)(b*Ls) + i0)*Dm + h*HDim;
    const float* kb = Kc + (size_t)(b*LK)*Dm + h*HDim;
    const float* vb = Vc + (size_t)(b*LK)*Dm + h*HDim;

    #pragma unroll
    for (int rep = 0; rep < 4; rep++) {
        int slot = tid + 256*rep;
        int row = slot >> 4, c4 = slot & 15;
        float4 v = *(const float4*)&qb[(size_t)row*Dm + c4*4];
        Qs[(c4*4+0)*68 + row] = v.x; Qs[(c4*4+1)*68 + row] = v.y;
        Qs[(c4*4+2)*68 + row] = v.z; Qs[(c4*4+3)*68 + row] = v.w;
    }

    float acc[4][4] = {};
    float mrow[4] = {-INFINITY, -INFINITY, -INFINITY, -INFINITY};
    float lrow[4] = {};

    for (int c = 0; c < nchunks; c++) {
        int jbase = (local ? i0 - 64 : 0) + c*64;
        __syncthreads();
        #pragma unroll
        for (int rep = 0; rep < 4; rep++) {
            int slot = tid + 256*rep;
            int row = slot >> 4, c4 = slot & 15;
            int jg = jbase + row;
            float4 v = make_float4(0.f,0.f,0.f,0.f);
            if (jg >= 0 && jg < LK) v = *(const float4*)&kb[(size_t)jg*Dm + c4*4];
            KP[(c4*4+0)*68 + row] = v.x; KP[(c4*4+1)*68 + row] = v.y;
            KP[(c4*4+2)*68 + row] = v.z; KP[(c4*4+3)*68 + row] = v.w;
        }
        #pragma unroll
        for (int rep = 0; rep < 4; rep++) {
            int slot = tid + 256*rep;
            int row = slot >> 4, c4 = slot & 15;
            int jg = jbase + row;
            float4 v = make_float4(0.f,0.f,0.f,0.f);
            if (jg >= 0 && jg < LK) v = *(const float4*)&vb[(size_t)jg*Dm + c4*4];
            *(float4*)&Vs[row*68 + c4*4] = v;
        }
        __syncthreads();

        float s[4][4] = {};
        #pragma unroll 8
        for (int d = 0; d < 64; d++) {
            float a[4], w[4];
            #pragma unroll
            for (int i = 0; i < 4; i++) a[i] = Qs[d*68 + tr*4 + i];
            #pragma unroll
            for (int j = 0; j < 4; j++) w[j] = KP[d*68 + tc*4 + j];
            #pragma unroll
            for (int i = 0; i < 4; i++)
                #pragma unroll
                for (int j = 0; j < 4; j++)
                    s[i][j] = fmaf(a[i], w[j], s[i][j]);
        }

        float cf[4];
        float p[4][4];
        #pragma unroll
        for (int i = 0; i < 4; i++) {
            int irow = i0 + tr*4 + i;
            float rm = -INFINITY;
            bool vmask[4];
            #pragma unroll
            for (int j = 0; j < 4; j++) {
                int jg = jbase + tc*4 + j;
                bool ok = (jg >= 0) && (jg < LK);
                if (local) ok = ok && (jg >= irow - 64) && (jg <= irow + 64);
                vmask[j] = ok;
                float x = s[i][j] * 0.125f;
                s[i][j] = x;
                if (ok) rm = fmaxf(rm, x);
            }
            #pragma unroll
            for (int o = 8; o; o >>= 1) rm = fmaxf(rm, __shfl_xor_sync(0xFFFFFFFFu, rm, o));
            float mnew = fmaxf(mrow[i], rm);
            cf[i] = (mnew == -INFINITY) ? 1.f : __expf(mrow[i] - mnew);
            mrow[i] = mnew;
            float ps = 0.f;
            #pragma unroll
            for (int j = 0; j < 4; j++) {
                float pv = (vmask[j] && mnew != -INFINITY) ? __expf(s[i][j] - mnew) : 0.f;
                p[i][j] = pv;
                ps += pv;
            }
            #pragma unroll
            for (int o = 8; o; o >>= 1) ps += __shfl_xor_sync(0xFFFFFFFFu, ps, o);
            lrow[i] = lrow[i]*cf[i] + ps;
            #pragma unroll
            for (int j = 0; j < 4; j++) acc[i][j] *= cf[i];
        }

        __syncthreads();
        #pragma unroll
        for (int i = 0; i < 4; i++)
            *(float4*)&KP[(tr*4+i)*68 + tc*4] = *(float4*)&p[i][0];
        __syncthreads();

        #pragma unroll 4
        for (int jv = 0; jv < 64; jv++) {
            float a[4], w[4];
            #pragma unroll
            for (int i = 0; i < 4; i++) a[i] = KP[(tr*4+i)*68 + jv];
            #pragma unroll
            for (int j = 0; j < 4; j++) w[j] = Vs[jv*68 + tc*4 + j];
            #pragma unroll
            for (int i = 0; i < 4; i++)
                #pragma unroll
                for (int j = 0; j < 4; j++)
                    acc[i][j] = fmaf(a[i], w[j], acc[i][j]);
        }
    }

    #pragma unroll
    for (int i = 0; i < 4; i++) {
        float inv = 1.0f / lrow[i];
        float4 o;
        o.x = acc[i][0]*inv; o.y = acc[i][1]*inv;
        o.z = acc[i][2]*inv; o.w = acc[i][3]*inv;
        *(float4*)&Out[((size_t)(b*Ls) + i0 + tr*4 + i)*Dm + h*HDim + tc*4] = o;
    }
}

// ---------------- combine + split comb ----------------
__global__ void combine_kernel(const float* __restrict__ pm)
{
    float a0 = pm[0], a1 = pm[1], a2 = pm[2];
    float mx = fmaxf(a0, fmaxf(a1, a2));
    float e0 = expf(a0-mx), e1 = expf(a1-mx), e2 = expf(a2-mx);
    float den = e0+e1+e2;
    float pw0 = e0/den, pw1 = e1/den;
    int e = blockIdx.x*blockDim.x + threadIdx.x;
    float v = pw0*g_outg[e] + pw1*g_outl[e];
    g_comb[e] = v;
    bsplit(v, g_combh[e], g_combl[e]);
}

// ---------------- selection path ----------------
__global__ void attns_kernel(const float* __restrict__ pm)
{
    __shared__ float sc[Ls];
    __shared__ float qs[64];
    __shared__ float red[256];
    int blk = blockIdx.x;
    int bh  = blk / NSEL, si = blk % NSEL;
    int b = bh >> 3, h = bh & 7;
    int qi = g_selidx[bh*NSEL + si];
    int t = threadIdx.x;

    if (t < 16) {
        float4 v = *(const float4*)&g_q[((size_t)(b*Ls) + qi)*Dm + h*HDim + t*4];
        *(float4*)&qs[t*4] = v;
    }
    __syncthreads();

    const float* kb = g_k + ((size_t)(b*Ls))*Dm + h*HDim;
    for (int jj = 0; jj < 8; jj++) {
        int j = t*8 + jj;
        const float4* kr = (const float4*)&kb[(size_t)j*Dm];
        float dot = 0.f;
        #pragma unroll
        for (int d4 = 0; d4 < 16; d4++) {
            float4 kv = kr[d4];
            dot = fmaf(qs[d4*4+0], kv.x, dot);
            dot = fmaf(qs[d4*4+1], kv.y, dot);
            dot = fmaf(qs[d4*4+2], kv.z, dot);
            dot = fmaf(qs[d4*4+3], kv.w, dot);
        }
        sc[j] = dot * 0.125f;
    }
    __syncthreads();

    float m = -INFINITY;
    for (int j = t; j < Ls; j += 256) m = fmaxf(m, sc[j]);
    red[t] = m; __syncthreads();
    for (int s2 = 128; s2; s2 >>= 1) { if (t < s2) red[t] = fmaxf(red[t], red[t+s2]); __syncthreads(); }
    m = red[0]; __syncthreads();

    float s = 0.f;
    for (int j = t; j < Ls; j += 256) { float e = __expf(sc[j]-m); sc[j] = e; s += e; }
    red[t] = s; __syncthreads();
    for (int s2 = 128; s2; s2 >>= 1) { if (t < s2) red[t] += red[t+s2]; __syncthreads(); }
    s = red[0]; __syncthreads();

    int d = t & 63, qtr = t >> 6;
    const float* vb = g_v + ((size_t)b*Ls)*Dm + h*HDim + d;
    float acc = 0.f;
    for (int j = qtr*512; j < qtr*512 + 512; j++)
        acc = fmaf(sc[j], vb[(size_t)j*Dm], acc);
    red[t] = acc; __syncthreads();

    if (t < 64) {
        float tot = red[t] + red[t+64] + red[t+128] + red[t+192];
        float a0 = pm[0], a1 = pm[1], a2 = pm[2];
        float mx = fmaxf(a0, fmaxf(a1, a2));
        float e0 = expf(a0-mx), e1 = expf(a1-mx), e2 = expf(a2-mx);
        float pw2 = e2/(e0+e1+e2);
        size_t idx = ((size_t)b*Ls + qi)*Dm + h*HDim + t;
        float nv = g_comb[idx] + pw2 * tot / s;
        g_comb[idx] = nv;
        bsplit(nv, g_combh[idx], g_combl[idx]);
    }
}

// ---------------- launch ----------------
extern "C" void kernel_launch(void* const* d_in, const int* in_sizes, int n_in,
                              void* d_out, int out_size)
{
    const float* query = (const float*)d_in[0];
    const float* keyi  = (const float*)d_in[1];
    const float* vali  = (const float*)d_in[2];
    const float* Wq = (const float*)d_in[3];  const float* bq = (const float*)d_in[4];
    const float* Wk = (const float*)d_in[5];  const float* bk = (const float*)d_in[6];
    const float* Wv = (const float*)d_in[7];  const float* bv = (const float*)d_in[8];
    const float* Wo = (const float*)d_in[9];  const float* bo = (const float*)d_in[10];
    const float* Wc1 = (const float*)d_in[11]; const float* bc1 = (const float*)d_in[12];
    const float* Wc2 = (const float*)d_in[13]; const float* bc2 = (const float*)d_in[14];
    const float* pm  = (const float*)d_in[15];

    float *q, *k, *v, *kc, *vc, *outg, *outl, *comb;
    __nv_bfloat16 *kcpreh, *kcprel, *hidh, *hidl, *combh, *combl;
    __nv_bfloat16 *wth, *wtl;
    cudaGetSymbolAddress((void**)&q,     g_q);
    cudaGetSymbolAddress((void**)&k,     g_k);
    cudaGetSymbolAddress((void**)&v,     g_v);
    cudaGetSymbolAddress((void**)&kc,    g_kc);
    cudaGetSymbolAddress((void**)&vc,    g_vc);
    cudaGetSymbolAddress((void**)&outg,  g_outg);
    cudaGetSymbolAddress((void**)&outl,  g_outl);
    cudaGetSymbolAddress((void**)&comb,  g_comb);
    cudaGetSymbolAddress((void**)&kcpreh, g_kcpreh);
    cudaGetSymbolAddress((void**)&kcprel, g_kcprel);
    cudaGetSymbolAddress((void**)&hidh,  g_hidh);
    cudaGetSymbolAddress((void**)&hidl,  g_hidl);
    cudaGetSymbolAddress((void**)&combh, g_combh);
    cudaGetSymbolAddress((void**)&combl, g_combl);
    cudaGetSymbolAddress((void**)&wth,   g_wth);
    cudaGetSymbolAddress((void**)&wtl,   g_wtl);

    const int FLASH_SMEM = 3*64*68*4;
    cudaFuncSetAttribute(flash_kernel, cudaFuncAttributeMaxDynamicSharedMemorySize, FLASH_SMEM);

    // prep: splits
    split_in_kernel<<<dim3((Bb*Ls*Dm)/256, 3), 256>>>(query, keyi, vali);
    split_w_kernel<<<dim3(16,16), dim3(32,8)>>>(Wq,  0);
    split_w_kernel<<<dim3(16,16), dim3(32,8)>>>(Wk,  1);
    split_w_kernel<<<dim3(16,16), dim3(32,8)>>>(Wv,  2);
    split_w_kernel<<<dim3(16,16), dim3(32,8)>>>(Wo,  3);
    split_w_kernel<<<dim3(16,16), dim3(32,8)>>>(Wc1, 4);
    split_w_kernel<<<dim3(16,16), dim3(32,8)>>>(Wc2, 5);

    // projections (tensor core)
    proj3_mma_kernel<<<dim3(4,32,3), 256>>>(bq, bk, bv);

    // compression + MLP (tensor core)
    compress_kernel<<<512, 256>>>();
    mma_gemm_kernel<<<dim3(4,8), 256>>>(kcpreh, kcprel, wth + 4*(size_t)Dm*Dm, wtl + 4*(size_t)Dm*Dm,
                                        bc1, nullptr, hidh, hidl, Dm, Dm, 1);
    mma_gemm_kernel<<<dim3(4,8), 256>>>(hidh, hidl, wth + 5*(size_t)Dm*Dm, wtl + 5*(size_t)Dm*Dm,
                                        bc2, kc, nullptr, nullptr, Dm, Dm, 0);

    // dense QK^T + fused stats (tensor core)
    scores_stats_mma_kernel<<<dim3(NJT,16,16), 256>>>(0.125f);
    impfinal_kernel<<<4096, 256>>>();
    topk_kernel<<<Bb*Hh, 256>>>();

    // attention paths
    flash_kernel<<<dim3(32,16), 256, FLASH_SMEM>>>(q, k,  v,  outl, Ls,  3, 1);
    flash_kernel<<<dim3(32,16), 256, FLASH_SMEM>>>(q, kc, vc, outg, LcC, 8, 0);

    // mix + selection
    combine_kernel<<<(Bb*Ls*Dm)/256, 256>>>(pm);
    attns_kernel<<<Bb*Hh*NSEL, 256>>>(pm);

    // output projection (tensor core)
    mma_gemm_kernel<<<dim3(4,32), 256>>>(combh, combl, wth + 3*(size_t)Dm*Dm, wtl + 3*(size_t)Dm*Dm,
                                         bo, (float*)d_out, nullptr, nullptr, Dm, Dm, 0);
}

// round 5
// speedup vs baseline: 1.7727x; 1.0835x over previous
#include <cuda_runtime.h>
#include <cuda_bf16.h>
#include <math.h>
#include <stdint.h>

#define Bb   2
#define Ls   2048
#define Dm   512
#define Hh   8
#define HDim 64
#define LcC  512
#define NSEL 8
#define NJT  16

// ---------------- fp32 scratch ----------------
static __device__ float g_q[Bb*Ls*Dm];
static __device__ float g_k[Bb*Ls*Dm];
static __device__ float g_v[Bb*Ls*Dm];
static __device__ float g_outg[Bb*Ls*Dm];
static __device__ float g_outl[Bb*Ls*Dm];
static __device__ float g_comb[Bb*Ls*Dm];
static __device__ float g_imp[Bb*Hh*Ls];
static __device__ int   g_selidx[Bb*Hh*NSEL];
static __device__ float g_pmax[Bb*Hh*Ls*NJT];
static __device__ float g_pse [Bb*Hh*Ls*NJT];
static __device__ float g_psum[Bb*Hh*Ls*NJT];

// ---------------- bf16 split scratch ----------------
static __device__ __nv_bfloat16 g_inh[3][Bb*Ls*Dm];
static __device__ __nv_bfloat16 g_inl[3][Bb*Ls*Dm];
static __device__ __nv_bfloat16 g_wth[6][Dm*Dm];   // transposed [N][K]
static __device__ __nv_bfloat16 g_wtl[6][Dm*Dm];
static __device__ __nv_bfloat16 g_qh[Bb*Ls*Dm], g_ql[Bb*Ls*Dm];
static __device__ __nv_bfloat16 g_kh[Bb*Ls*Dm], g_kl[Bb*Ls*Dm];
static __device__ __nv_bfloat16 g_vh[Bb*Ls*Dm], g_vl[Bb*Ls*Dm];
static __device__ __nv_bfloat16 g_kch[Bb*LcC*Dm], g_kcl[Bb*LcC*Dm];
static __device__ __nv_bfloat16 g_vch[Bb*LcC*Dm], g_vcl[Bb*LcC*Dm];
static __device__ __nv_bfloat16 g_kcpreh[Bb*LcC*Dm], g_kcprel[Bb*LcC*Dm];
static __device__ __nv_bfloat16 g_hidh[Bb*LcC*Dm], g_hidl[Bb*LcC*Dm];
static __device__ __nv_bfloat16 g_combh[Bb*Ls*Dm], g_combl[Bb*Ls*Dm];

__device__ __forceinline__ void bsplit(float x, __nv_bfloat16& h, __nv_bfloat16& l)
{
    h = __float2bfloat16(x);
    l = __float2bfloat16(x - __bfloat162float(h));
}

__device__ __forceinline__ uint32_t packbf(float x, float y)
{
    __nv_bfloat162 t = __floats2bfloat162_rn(x, y);
    return *(uint32_t*)&t;
}

__device__ __forceinline__ void mma16816(float* c, const uint32_t* a, const uint32_t* b)
{
    asm volatile(
        "mma.sync.aligned.m16n8k16.row.col.f32.bf16.bf16.f32 "
        "{%0,%1,%2,%3}, {%4,%5,%6,%7}, {%8,%9}, {%0,%1,%2,%3};"
        : "+f"(c[0]), "+f"(c[1]), "+f"(c[2]), "+f"(c[3])
        : "r"(a[0]), "r"(a[1]), "r"(a[2]), "r"(a[3]), "r"(b[0]), "r"(b[1]));
}

// ---------------- prep: split inputs ----------------
__global__ void split_in_kernel(const float* x0, const float* x1, const float* x2)
{
    int z = blockIdx.y;
    const float* x = z == 0 ? x0 : (z == 1 ? x1 : x2);
    int i = blockIdx.x*blockDim.x + threadIdx.x;
    bsplit(x[i], g_inh[z][i], g_inl[z][i]);
}

// ---------------- prep: split + transpose all 6 weights in one launch ----------------
__global__ void split_w6_kernel(const float* w0, const float* w1, const float* w2,
                                const float* w3, const float* w4, const float* w5)
{
    __shared__ float tl[32][33];
    int widx = blockIdx.z;
    const float* w = widx==0?w0 : widx==1?w1 : widx==2?w2 : widx==3?w3 : widx==4?w4 : w5;
    int tx = threadIdx.x, ty = threadIdx.y;          // 32 x 8
    int n0 = blockIdx.x*32, k0 = blockIdx.y*32;
    #pragma unroll
    for (int i = 0; i < 4; i++)
        tl[ty + i*8][tx] = w[(size_t)(k0 + ty + i*8)*Dm + n0 + tx];
    __syncthreads();
    #pragma unroll
    for (int i = 0; i < 4; i++) {
        float v = tl[tx][ty + i*8];
        size_t o = (size_t)(n0 + ty + i*8)*Dm + k0 + tx;
        bsplit(v, g_wth[widx][o], g_wtl[widx][o]);
    }
}

// =========================================================================
// bf16x3 tensor-core GEMM: C[M][N] = A[M][K] @ Bw^T + bias
// =========================================================================
__device__ __forceinline__ void mma_gemm_body(
    const __nv_bfloat16* __restrict__ Ah, const __nv_bfloat16* __restrict__ Al,
    const __nv_bfloat16* __restrict__ Bh, const __nv_bfloat16* __restrict__ Bl,
    const float* __restrict__ bias, float* __restrict__ C,
    __nv_bfloat16* __restrict__ Ch, __nv_bfloat16* __restrict__ Cl,
    int N, int K, int gelu)
{
    __shared__ __nv_bfloat16 sAh[2][128*24], sAl[2][128*24];
    __shared__ __nv_bfloat16 sBh[2][128*24], sBl[2][128*24];
    const int tid = threadIdx.x;
    const int lane = tid & 31, warp = tid >> 5;
    const int wm = warp >> 2, wn = warp & 3;
    const int qr = lane >> 2, qc = (lane & 3)*2;
    const int row0 = blockIdx.y*128, col0 = blockIdx.x*128;
    const int half = tid >> 7, r = tid & 127;

    const __nv_bfloat16* As = half ? Al : Ah;
    const __nv_bfloat16* Bs = half ? Bl : Bh;

    {
        const uint4* pa = (const uint4*)(As + (size_t)(row0 + r)*K);
        const uint4* pb = (const uint4*)(Bs + (size_t)(col0 + r)*K);
        uint4 a0 = pa[0], a1 = pa[1], b0 = pb[0], b1 = pb[1];
        __nv_bfloat16* dA = half ? sAl[0] : sAh[0];
        __nv_bfloat16* dB = half ? sBl[0] : sBh[0];
        *(uint4*)&dA[r*24]     = a0; *(uint4*)&dA[r*24 + 8] = a1;
        *(uint4*)&dB[r*24]     = b0; *(uint4*)&dB[r*24 + 8] = b1;
    }
    __syncthreads();

    float acc[4][4][4] = {};
    const int nk = K >> 4;
    for (int kc = 0; kc < nk; kc++) {
        const int buf = kc & 1;
        uint4 na0, na1, nb0, nb1;
        if (kc + 1 < nk) {
            int k0 = (kc + 1)*16;
            const uint4* pa = (const uint4*)(As + (size_t)(row0 + r)*K + k0);
            const uint4* pb = (const uint4*)(Bs + (size_t)(col0 + r)*K + k0);
            na0 = pa[0]; na1 = pa[1]; nb0 = pb[0]; nb1 = pb[1];
        }

        const __nv_bfloat16* cAh = sAh[buf];
        const __nv_bfloat16* cAl = sAl[buf];
        const __nv_bfloat16* cBh = sBh[buf];
        const __nv_bfloat16* cBl = sBl[buf];

        uint32_t bh[4][2], bl[4][2];
        #pragma unroll
        for (int nt = 0; nt < 4; nt++) {
            int bo = (wn*32 + nt*8 + qr)*24 + qc;
            bh[nt][0] = *(const uint32_t*)&cBh[bo];
            bh[nt][1] = *(const uint32_t*)&cBh[bo + 8];
            bl[nt][0] = *(const uint32_t*)&cBl[bo];
            bl[nt][1] = *(const uint32_t*)&cBl[bo + 8];
        }
        #pragma unroll
        for (int mt = 0; mt < 4; mt++) {
            int ao = (wm*64 + mt*16 + qr)*24 + qc;
            uint32_t ah[4], al[4];
            ah[0] = *(const uint32_t*)&cAh[ao];
            ah[1] = *(const uint32_t*)&cAh[ao + 8*24];
            ah[2] = *(const uint32_t*)&cAh[ao + 8];
            ah[3] = *(const uint32_t*)&cAh[ao + 8*24 + 8];
            al[0] = *(const uint32_t*)&cAl[ao];
            al[1] = *(const uint32_t*)&cAl[ao + 8*24];
            al[2] = *(const uint32_t*)&cAl[ao + 8];
            al[3] = *(const uint32_t*)&cAl[ao + 8*24 + 8];
            #pragma unroll
            for (int nt = 0; nt < 4; nt++) {
                mma16816(acc[mt][nt], ah, bh[nt]);
                mma16816(acc[mt][nt], ah, bl[nt]);
                mma16816(acc[mt][nt], al, bh[nt]);
            }
        }

        if (kc + 1 < nk) {
            const int nb = buf ^ 1;
            __nv_bfloat16* dA = half ? sAl[nb] : sAh[nb];
            __nv_bfloat16* dB = half ? sBl[nb] : sBh[nb];
            *(uint4*)&dA[r*24]     = na0; *(uint4*)&dA[r*24 + 8] = na1;
            *(uint4*)&dB[r*24]     = nb0; *(uint4*)&dB[r*24 + 8] = nb1;
        }
        __syncthreads();
    }

    #pragma unroll
    for (int mt = 0; mt < 4; mt++) {
        int gr = row0 + wm*64 + mt*16 + qr;
        #pragma unroll
        for (int nt = 0; nt < 4; nt++) {
            int gc = col0 + wn*32 + nt*8 + qc;
            float v0 = acc[mt][nt][0] + bias[gc];
            float v1 = acc[mt][nt][1] + bias[gc+1];
            float v2 = acc[mt][nt][2] + bias[gc];
            float v3 = acc[mt][nt][3] + bias[gc+1];
            if (gelu) {
                v0 = 0.5f*v0*(1.0f + erff(v0*0.70710678118654752f));
                v1 = 0.5f*v1*(1.0f + erff(v1*0.70710678118654752f));
                v2 = 0.5f*v2*(1.0f + erff(v2*0.70710678118654752f));
                v3 = 0.5f*v3*(1.0f + erff(v3*0.70710678118654752f));
            }
            if (C) {
                float2 p0 = make_float2(v0, v1), p1 = make_float2(v2, v3);
                *(float2*)&C[(size_t)gr*N + gc]     = p0;
                *(float2*)&C[(size_t)(gr+8)*N + gc] = p1;
            }
            if (Ch) {
                __nv_bfloat16 h0,l0,h1,l1,h2,l2,h3,l3;
                bsplit(v0,h0,l0); bsplit(v1,h1,l1); bsplit(v2,h2,l2); bsplit(v3,h3,l3);
                Ch[(size_t)gr*N + gc]   = h0; Ch[(size_t)gr*N + gc+1]   = h1;
                Cl[(size_t)gr*N + gc]   = l0; Cl[(size_t)gr*N + gc+1]   = l1;
                Ch[(size_t)(gr+8)*N+gc] = h2; Ch[(size_t)(gr+8)*N+gc+1] = h3;
                Cl[(size_t)(gr+8)*N+gc] = l2; Cl[(size_t)(gr+8)*N+gc+1] = l3;
            }
        }
    }
}

__global__ void __launch_bounds__(256, 1) mma_gemm_kernel(
    const __nv_bfloat16* Ah, const __nv_bfloat16* Al,
    const __nv_bfloat16* Bh, const __nv_bfloat16* Bl,
    const float* bias, float* C, __nv_bfloat16* Ch, __nv_bfloat16* Cl,
    int N, int K, int gelu)
{
    mma_gemm_body(Ah, Al, Bh, Bl, bias, C, Ch, Cl, N, K, gelu);
}

__global__ void __launch_bounds__(256, 1) proj3_mma_kernel(
    const float* bq, const float* bk, const float* bv)
{
    int z = blockIdx.z;
    if (z == 0)
        mma_gemm_body(g_inh[0], g_inl[0], g_wth[0], g_wtl[0], bq, g_q, g_qh, g_ql, Dm, Dm, 0);
    else if (z == 1)
        mma_gemm_body(g_inh[1], g_inl[1], g_wth[1], g_wtl[1], bk, g_k, g_kh, g_kl, Dm, Dm, 0);
    else
        mma_gemm_body(g_inh[2], g_inl[2], g_wth[2], g_wtl[2], bv, g_v, g_vh, g_vl, Dm, Dm, 0);
}

// =========================================================================
// dense QK^T (bf16x3 mma) + fused row stats.
// =========================================================================
__global__ void __launch_bounds__(256, 1) scores_stats_mma_kernel(float scale)
{
    __shared__ __nv_bfloat16 sAh[128*24], sAl[128*24];
    __shared__ __nv_bfloat16 sBh[128*24], sBl[128*24];
    __shared__ float s4a[128][4], s4b[128][4], srm[128];

    const int tid = threadIdx.x;
    const int lane = tid & 31, warp = tid >> 5;
    const int wm = warp >> 2, wn = warp & 3;
    const int qr = lane >> 2, qc = (lane & 3)*2;
    const int bh = blockIdx.z;
    const int b = bh >> 3, h = bh & 7;
    const int i0 = blockIdx.y*128, j0 = blockIdx.x*128;
    const int half = tid >> 7, r = tid & 127;

    const __nv_bfloat16* Qs = (half ? g_ql : g_qh) + ((size_t)(b*Ls))*Dm + h*HDim;
    const __nv_bfloat16* Ks = (half ? g_kl : g_kh) + ((size_t)(b*Ls))*Dm + h*HDim;

    float acc[4][4][4] = {};
    for (int kc = 0; kc < 4; kc++) {
        int k0 = kc*16;
        {
            const uint4* pa = (const uint4*)(Qs + (size_t)(i0 + r)*Dm + k0);
            const uint4* pb = (const uint4*)(Ks + (size_t)(j0 + r)*Dm + k0);
            uint4 a0 = pa[0], a1 = pa[1], b0 = pb[0], b1 = pb[1];
            __nv_bfloat16* dA = half ? sAl : sAh;
            __nv_bfloat16* dB = half ? sBl : sBh;
            *(uint4*)&dA[r*24]     = a0; *(uint4*)&dA[r*24 + 8] = a1;
            *(uint4*)&dB[r*24]     = b0; *(uint4*)&dB[r*24 + 8] = b1;
        }
        __syncthreads();

        uint32_t bhf[4][2], blf[4][2];
        #pragma unroll
        for (int nt = 0; nt < 4; nt++) {
            int bo = (wn*32 + nt*8 + qr)*24 + qc;
            bhf[nt][0] = *(const uint32_t*)&sBh[bo];
            bhf[nt][1] = *(const uint32_t*)&sBh[bo + 8];
            blf[nt][0] = *(const uint32_t*)&sBl[bo];
            blf[nt][1] = *(const uint32_t*)&sBl[bo + 8];
        }
        #pragma unroll
        for (int mt = 0; mt < 4; mt++) {
            int ao = (wm*64 + mt*16 + qr)*24 + qc;
            uint32_t ah[4], al[4];
            ah[0] = *(const uint32_t*)&sAh[ao];
            ah[1] = *(const uint32_t*)&sAh[ao + 8*24];
            ah[2] = *(const uint32_t*)&sAh[ao + 8];
            ah[3] = *(const uint32_t*)&sAh[ao + 8*24 + 8];
            al[0] = *(const uint32_t*)&sAl[ao];
            al[1] = *(const uint32_t*)&sAl[ao + 8*24];
            al[2] = *(const uint32_t*)&sAl[ao + 8];
            al[3] = *(const uint32_t*)&sAl[ao + 8*24 + 8];
            #pragma unroll
            for (int nt = 0; nt < 4; nt++) {
                mma16816(acc[mt][nt], ah, bhf[nt]);
                mma16816(acc[mt][nt], ah, blf[nt]);
                mma16816(acc[mt][nt], al, bhf[nt]);
            }
        }
        __syncthreads();
    }

    #pragma unroll
    for (int mt = 0; mt < 4; mt++) {
        float m0 = -INFINITY, m1 = -INFINITY;
        #pragma unroll
        for (int nt = 0; nt < 4; nt++) {
            m0 = fmaxf(m0, fmaxf(acc[mt][nt][0], acc[mt][nt][1]));
            m1 = fmaxf(m1, fmaxf(acc[mt][nt][2], acc[mt][nt][3]));
        }
        m0 = fmaxf(m0, __shfl_xor_sync(0xFFFFFFFFu, m0, 1));
        m0 = fmaxf(m0, __shfl_xor_sync(0xFFFFFFFFu, m0, 2));
        m1 = fmaxf(m1, __shfl_xor_sync(0xFFFFFFFFu, m1, 1));
        m1 = fmaxf(m1, __shfl_xor_sync(0xFFFFFFFFu, m1, 2));
        if ((lane & 3) == 0) {
            s4a[wm*64 + mt*16 + qr][wn]     = m0;
            s4a[wm*64 + mt*16 + 8 + qr][wn] = m1;
        }
    }
    __syncthreads();
    if (tid < 128)
        srm[tid] = fmaxf(fmaxf(s4a[tid][0], s4a[tid][1]), fmaxf(s4a[tid][2], s4a[tid][3]));
    __syncthreads();

    #pragma unroll
    for (int mt = 0; mt < 4; mt++) {
        int lr0 = wm*64 + mt*16 + qr, lr1 = lr0 + 8;
        float rm0 = srm[lr0]*scale, rm1 = srm[lr1]*scale;
        float se0 = 0.f, se1 = 0.f, ss0 = 0.f, ss1 = 0.f;
        #pragma unroll
        for (int nt = 0; nt < 4; nt++) {
            float x0 = acc[mt][nt][0]*scale, x1 = acc[mt][nt][1]*scale;
            float x2 = acc[mt][nt][2]*scale, x3 = acc[mt][nt][3]*scale;
            se0 += __expf(x0 - rm0) + __expf(x1 - rm0);
            se1 += __expf(x2 - rm1) + __expf(x3 - rm1);
            ss0 += x0 + x1; ss1 += x2 + x3;
        }
        se0 += __shfl_xor_sync(0xFFFFFFFFu, se0, 1); se0 += __shfl_xor_sync(0xFFFFFFFFu, se0, 2);
        se1 += __shfl_xor_sync(0xFFFFFFFFu, se1, 1); se1 += __shfl_xor_sync(0xFFFFFFFFu, se1, 2);
        ss0 += __shfl_xor_sync(0xFFFFFFFFu, ss0, 1); ss0 += __shfl_xor_sync(0xFFFFFFFFu, ss0, 2);
        ss1 += __shfl_xor_sync(0xFFFFFFFFu, ss1, 1); ss1 += __shfl_xor_sync(0xFFFFFFFFu, ss1, 2);
        if ((lane & 3) == 0) {
            s4b[lr0][wn] = se0; s4b[lr1][wn] = se1;
            s4a[lr0][wn] = ss0; s4a[lr1][wn] = ss1;
        }
    }
    __syncthreads();
    if (tid < 128) {
        int rowg = bh*Ls + i0 + tid;
        int jt = blockIdx.x;
        g_pmax[(size_t)rowg*NJT + jt] = srm[tid]*scale;
        g_pse [(size_t)rowg*NJT + jt] = s4b[tid][0]+s4b[tid][1]+s4b[tid][2]+s4b[tid][3];
        g_psum[(size_t)rowg*NJT + jt] = s4a[tid][0]+s4a[tid][1]+s4a[tid][2]+s4a[tid][3];
    }
}

// ---------------- compress: mean of 4 rows -> splits ----------------
__global__ void compress_kernel()
{
    int e4 = blockIdx.x*blockDim.x + threadIdx.x;
    int b = e4 / (LcC*Dm/4);
    int r = e4 % (LcC*Dm/4);
    int m = r / (Dm/4), d4 = r % (Dm/4);
    const float4* k4 = (const float4*)g_k;
    const float4* v4 = (const float4*)g_v;
    size_t base = ((size_t)(b*Ls + m*4)*Dm)/4 + d4;
    float4 a = k4[base], bb = k4[base+128], c = k4[base+256], d = k4[base+384];
    float ox = 0.25f*(a.x+bb.x+c.x+d.x), oy = 0.25f*(a.y+bb.y+c.y+d.y);
    float oz = 0.25f*(a.z+bb.z+c.z+d.z), ow = 0.25f*(a.w+bb.w+c.w+d.w);
    bsplit(ox, g_kcpreh[e4*4+0], g_kcprel[e4*4+0]);
    bsplit(oy, g_kcpreh[e4*4+1], g_kcprel[e4*4+1]);
    bsplit(oz, g_kcpreh[e4*4+2], g_kcprel[e4*4+2]);
    bsplit(ow, g_kcpreh[e4*4+3], g_kcprel[e4*4+3]);
    a = v4[base]; bb = v4[base+128]; c = v4[base+256]; d = v4[base+384];
    ox = 0.25f*(a.x+bb.x+c.x+d.x); oy = 0.25f*(a.y+bb.y+c.y+d.y);
    oz = 0.25f*(a.z+bb.z+c.z+d.z); ow = 0.25f*(a.w+bb.w+c.w+d.w);
    bsplit(ox, g_vch[e4*4+0], g_vcl[e4*4+0]);
    bsplit(oy, g_vch[e4*4+1], g_vcl[e4*4+1]);
    bsplit(oz, g_vch[e4*4+2], g_vcl[e4*4+2]);
    bsplit(ow, g_vch[e4*4+3], g_vcl[e4*4+3]);
}

// ---------------- importance merge ----------------
__global__ void impfinal_kernel()
{
    int warp = (blockIdx.x*blockDim.x + threadIdx.x) >> 5;
    int lane = threadIdx.x & 31;
    float pm = -INFINITY, pe = 0.f, ps = 0.f;
    if (lane < NJT) {
        pm = g_pmax[(size_t)warp*NJT + lane];
        pe = g_pse [(size_t)warp*NJT + lane];
        ps = g_psum[(size_t)warp*NJT + lane];
    }
    float m = pm;
    #pragma unroll
    for (int o = 8; o; o >>= 1) m = fmaxf(m, __shfl_xor_sync(0xFFFFFFFFu, m, o));
    float se = (lane < NJT) ? pe * __expf(pm - m) : 0.f;
    #pragma unroll
    for (int o = 8; o; o >>= 1) {
        se += __shfl_xor_sync(0xFFFFFFFFu, se, o);
        ps += __shfl_xor_sync(0xFFFFFFFFu, ps, o);
    }
    if (lane == 0)
        g_imp[warp] = m + logf(se) - 7.6246189861593985f - ps * (1.0f/2048.0f);
}

// ---------------- top-8 ----------------
__global__ void topk_kernel()
{
    int bh = blockIdx.x;
    const float* imp = g_imp + bh*Ls;
    __shared__ float bv[256];
    __shared__ int   bi[256];
    __shared__ int   chosen[NSEL];
    int t = threadIdx.x;
    for (int itu = 0; itu < NSEL; itu++) {
        float best = -INFINITY; int bidx = 0x7FFFFFFF;
        for (int j = t; j < Ls; j += 256) {
            bool skip = false;
            for (int c = 0; c < itu; c++) if (chosen[c] == j) skip = true;
            if (skip) continue;
            float vv = imp[j];
            if (vv > best || (vv == best && j < bidx)) { best = vv; bidx = j; }
        }
        bv[t] = best; bi[t] = bidx;
        __syncthreads();
        for (int s2 = 128; s2; s2 >>= 1) {
            if (t < s2) {
                if (bv[t+s2] > bv[t] || (bv[t+s2] == bv[t] && bi[t+s2] < bi[t])) {
                    bv[t] = bv[t+s2]; bi[t] = bi[t+s2];
                }
            }
            __syncthreads();
        }
        if (t == 0) { chosen[itu] = bi[0]; g_selidx[bh*NSEL + itu] = bi[0]; }
        __syncthreads();
    }
}

// =========================================================================
// flash attention, bf16x3 tensor-core. 64 q-rows/block, 64-wide KV chunks.
// warps: 4 in M (wq), 2 in N (wn).  dynamic smem, see offsets.
// =========================================================================
extern __shared__ char fsm2[];
__global__ void __launch_bounds__(256, 1) flash_mma_kernel(
    const __nv_bfloat16* __restrict__ Qh, const __nv_bfloat16* __restrict__ Ql,
    const __nv_bfloat16* __restrict__ Kh, const __nv_bfloat16* __restrict__ Kl,
    const __nv_bfloat16* __restrict__ Vh, const __nv_bfloat16* __restrict__ Vl,
    float* __restrict__ Out, int LK, int nchunks, int local)
{
    __nv_bfloat16* sQh = (__nv_bfloat16*)fsm2;                 // [64][72]
    __nv_bfloat16* sQl = sQh + 64*72;
    __nv_bfloat16* sKh = sQl + 64*72;
    __nv_bfloat16* sKl = sKh + 64*72;
    __nv_bfloat16* sVh = sKl + 64*72;                           // [d][j] transposed
    __nv_bfloat16* sVl = sVh + 64*72;
    float* sM = (float*)(sVl + 64*72);                          // [64][2]
    float* sS = sM + 128;                                       // [64][2]
    float* sO = (float*)sKh;                                    // epilogue reuse [64][66]

    const int tid = threadIdx.x;
    const int lane = tid & 31, warp = tid >> 5;
    const int wq = warp >> 1, wn = warp & 1;
    const int qr = lane >> 2, qc = (lane & 3)*2;
    const int bh = blockIdx.y;
    const int b = bh >> 3, h = bh & 7;
    const int i0 = blockIdx.x*64;
    const size_t hoff = (size_t)h*HDim;

    // load Q tile (row-major [i][d])
    {
        int row = tid >> 2, c16 = (tid & 3)*16;
        const uint4* ph = (const uint4*)(Qh + ((size_t)(b*Ls) + i0 + row)*Dm + hoff + c16);
        const uint4* pl = (const uint4*)(Ql + ((size_t)(b*Ls) + i0 + row)*Dm + hoff + c16);
        uint4 h0 = ph[0], h1 = ph[1], l0 = pl[0], l1 = pl[1];
        *(uint4*)&sQh[row*72 + c16] = h0; *(uint4*)&sQh[row*72 + c16 + 8] = h1;
        *(uint4*)&sQl[row*72 + c16] = l0; *(uint4*)&sQl[row*72 + c16 + 8] = l1;
    }

    float accO[8][4] = {};
    float mr0 = -INFINITY, mr1 = -INFINITY;
    float lr0 = 0.f, lr1 = 0.f;
    const int ir0 = i0 + wq*16 + qr, ir1 = ir0 + 8;
    const int lrow0 = wq*16 + qr, lrow1 = lrow0 + 8;

    for (int c = 0; c < nchunks; c++) {
        int jbase = (local ? i0 - 64 : 0) + c*64;
        __syncthreads();
        // load K chunk [j][d]
        {
            int row = tid >> 2, c16 = (tid & 3)*16;
            int jg = jbase + row;
            uint4 h0 = {0,0,0,0}, h1 = {0,0,0,0}, l0 = {0,0,0,0}, l1 = {0,0,0,0};
            if (jg >= 0 && jg < LK) {
                const uint4* ph = (const uint4*)(Kh + ((size_t)(b*LK) + jg)*Dm + hoff + c16);
                const uint4* pl = (const uint4*)(Kl + ((size_t)(b*LK) + jg)*Dm + hoff + c16);
                h0 = ph[0]; h1 = ph[1]; l0 = pl[0]; l1 = pl[1];
            }
            *(uint4*)&sKh[row*72 + c16] = h0; *(uint4*)&sKh[row*72 + c16 + 8] = h1;
            *(uint4*)&sKl[row*72 + c16] = l0; *(uint4*)&sKl[row*72 + c16 + 8] = l1;
        }
        // load V chunk transposed -> [d][j]
        {
            int row = tid >> 2, d16 = (tid & 3)*16;
            int jg = jbase + row;
            uint4 h0 = {0,0,0,0}, h1 = {0,0,0,0}, l0 = {0,0,0,0}, l1 = {0,0,0,0};
            if (jg >= 0 && jg < LK) {
                const uint4* ph = (const uint4*)(Vh + ((size_t)(b*LK) + jg)*Dm + hoff + d16);
                const uint4* pl = (const uint4*)(Vl + ((size_t)(b*LK) + jg)*Dm + hoff + d16);
                h0 = ph[0]; h1 = ph[1]; l0 = pl[0]; l1 = pl[1];
            }
            const __nv_bfloat16* eh = (const __nv_bfloat16*)&h0;
            const __nv_bfloat16* el = (const __nv_bfloat16*)&l0;
            #pragma unroll
            for (int e = 0; e < 8; e++) {
                sVh[(d16 + e)*72 + row] = eh[e];
                sVl[(d16 + e)*72 + row] = el[e];
            }
            eh = (const __nv_bfloat16*)&h1; el = (const __nv_bfloat16*)&l1;
            #pragma unroll
            for (int e = 0; e < 8; e++) {
                sVh[(d16 + 8 + e)*72 + row] = eh[e];
                sVl[(d16 + 8 + e)*72 + row] = el[e];
            }
        }
        __syncthreads();

        // QK^T: s[nt][reg]
        float s[4][4] = {};
        #pragma unroll
        for (int kc = 0; kc < 4; kc++) {
            int ko = kc*16 + qc;
            int ar = wq*16 + qr;
            uint32_t ah[4], al[4];
            ah[0] = *(const uint32_t*)&sQh[ar*72 + ko];
            ah[1] = *(const uint32_t*)&sQh[(ar+8)*72 + ko];
            ah[2] = *(const uint32_t*)&sQh[ar*72 + ko + 8];
            ah[3] = *(const uint32_t*)&sQh[(ar+8)*72 + ko + 8];
            al[0] = *(const uint32_t*)&sQl[ar*72 + ko];
            al[1] = *(const uint32_t*)&sQl[(ar+8)*72 + ko];
            al[2] = *(const uint32_t*)&sQl[ar*72 + ko + 8];
            al[3] = *(const uint32_t*)&sQl[(ar+8)*72 + ko + 8];
            #pragma unroll
            for (int nt = 0; nt < 4; nt++) {
                int br = (wn*32 + nt*8 + qr)*72 + ko;
                uint32_t bhf[2], blf[2];
                bhf[0] = *(const uint32_t*)&sKh[br];
                bhf[1] = *(const uint32_t*)&sKh[br + 8];
                blf[0] = *(const uint32_t*)&sKl[br];
                blf[1] = *(const uint32_t*)&sKl[br + 8];
                mma16816(s[nt], ah, bhf);
                mma16816(s[nt], ah, blf);
                mma16816(s[nt], al, bhf);
            }
        }

        // scale + mask + chunk row max
        bool ok[4][4];
        float m0 = -INFINITY, m1 = -INFINITY;
        #pragma unroll
        for (int nt = 0; nt < 4; nt++) {
            int jc0 = jbase + wn*32 + nt*8 + qc;
            int jc1 = jc0 + 1;
            bool in0 = (jc0 >= 0) & (jc0 < LK);
            bool in1 = (jc1 >= 0) & (jc1 < LK);
            ok[nt][0] = in0 && (!local || (jc0 >= ir0-64 && jc0 <= ir0+64));
            ok[nt][1] = in1 && (!local || (jc1 >= ir0-64 && jc1 <= ir0+64));
            ok[nt][2] = in0 && (!local || (jc0 >= ir1-64 && jc0 <= ir1+64));
            ok[nt][3] = in1 && (!local || (jc1 >= ir1-64 && jc1 <= ir1+64));
            #pragma unroll
            for (int rg = 0; rg < 4; rg++) s[nt][rg] *= 0.125f;
            if (ok[nt][0]) m0 = fmaxf(m0, s[nt][0]);
            if (ok[nt][1]) m0 = fmaxf(m0, s[nt][1]);
            if (ok[nt][2]) m1 = fmaxf(m1, s[nt][2]);
            if (ok[nt][3]) m1 = fmaxf(m1, s[nt][3]);
        }
        m0 = fmaxf(m0, __shfl_xor_sync(0xFFFFFFFFu, m0, 1));
        m0 = fmaxf(m0, __shfl_xor_sync(0xFFFFFFFFu, m0, 2));
        m1 = fmaxf(m1, __shfl_xor_sync(0xFFFFFFFFu, m1, 1));
        m1 = fmaxf(m1, __shfl_xor_sync(0xFFFFFFFFu, m1, 2));
        if ((lane & 3) == 0) { sM[lrow0*2 + wn] = m0; sM[lrow1*2 + wn] = m1; }
        __syncthreads();
        float cm0 = fmaxf(sM[lrow0*2], sM[lrow0*2 + 1]);
        float cm1 = fmaxf(sM[lrow1*2], sM[lrow1*2 + 1]);
        float mn0 = fmaxf(mr0, cm0), mn1 = fmaxf(mr1, cm1);
        float cf0 = (mn0 == -INFINITY) ? 1.f : __expf(mr0 - mn0);
        float cf1 = (mn1 == -INFINITY) ? 1.f : __expf(mr1 - mn1);
        mr0 = mn0; mr1 = mn1;

        // P = exp(s - m), partial sums
        float ps0 = 0.f, ps1 = 0.f;
        #pragma unroll
        for (int nt = 0; nt < 4; nt++) {
            s[nt][0] = ok[nt][0] ? __expf(s[nt][0] - mn0) : 0.f;
            s[nt][1] = ok[nt][1] ? __expf(s[nt][1] - mn0) : 0.f;
            s[nt][2] = ok[nt][2] ? __expf(s[nt][2] - mn1) : 0.f;
            s[nt][3] = ok[nt][3] ? __expf(s[nt][3] - mn1) : 0.f;
            ps0 += s[nt][0] + s[nt][1];
            ps1 += s[nt][2] + s[nt][3];
        }
        ps0 += __shfl_xor_sync(0xFFFFFFFFu, ps0, 1); ps0 += __shfl_xor_sync(0xFFFFFFFFu, ps0, 2);
        ps1 += __shfl_xor_sync(0xFFFFFFFFu, ps1, 1); ps1 += __shfl_xor_sync(0xFFFFFFFFu, ps1, 2);
        if ((lane & 3) == 0) { sS[lrow0*2 + wn] = ps0; sS[lrow1*2 + wn] = ps1; }
        __syncthreads();
        lr0 = lr0*cf0 + sS[lrow0*2] + sS[lrow0*2 + 1];
        lr1 = lr1*cf1 + sS[lrow1*2] + sS[lrow1*2 + 1];

        // rescale accO
        #pragma unroll
        for (int ntd = 0; ntd < 8; ntd++) {
            accO[ntd][0] *= cf0; accO[ntd][1] *= cf0;
            accO[ntd][2] *= cf1; accO[ntd][3] *= cf1;
        }

        // PV: A = P (warp's 32 j-cols, 2 k16 chunks), B = V^T
        #pragma unroll
        for (int kch = 0; kch < 2; kch++) {
            int nt0 = kch*2, nt1 = kch*2 + 1;
            uint32_t pah[4], pal[4];
            {
                float p00 = s[nt0][0], p01 = s[nt0][1], p02 = s[nt0][2], p03 = s[nt0][3];
                float p10 = s[nt1][0], p11 = s[nt1][1], p12 = s[nt1][2], p13 = s[nt1][3];
                pah[0] = packbf(p00, p01); pah[1] = packbf(p02, p03);
                pah[2] = packbf(p10, p11); pah[3] = packbf(p12, p13);
                float q00 = p00 - __bfloat162float(__float2bfloat16(p00));
                float q01 = p01 - __bfloat162float(__float2bfloat16(p01));
                float q02 = p02 - __bfloat162float(__float2bfloat16(p02));
                float q03 = p03 - __bfloat162float(__float2bfloat16(p03));
                float q10 = p10 - __bfloat162float(__float2bfloat16(p10));
                float q11 = p11 - __bfloat162float(__float2bfloat16(p11));
                float q12 = p12 - __bfloat162float(__float2bfloat16(p12));
                float q13 = p13 - __bfloat162float(__float2bfloat16(p13));
                pal[0] = packbf(q00, q01); pal[1] = packbf(q02, q03);
                pal[2] = packbf(q10, q11); pal[3] = packbf(q12, q13);
            }
            int jb = wn*32 + kch*16 + qc;
            #pragma unroll
            for (int ntd = 0; ntd < 8; ntd++) {
                int vr = (ntd*8 + qr)*72 + jb;
                uint32_t bhf[2], blf[2];
                bhf[0] = *(const uint32_t*)&sVh[vr];
                bhf[1] = *(const uint32_t*)&sVh[vr + 8];
                blf[0] = *(const uint32_t*)&sVl[vr];
                blf[1] = *(const uint32_t*)&sVl[vr + 8];
                mma16816(accO[ntd], pah, bhf);
                mma16816(accO[ntd], pal, bhf);
                mma16816(accO[ntd], pah, blf);
            }
        }
    }

    // epilogue: sum wn halves via smem (reuse sK region), then write
    __syncthreads();
    if (wn == 1) {
        #pragma unroll
        for (int ntd = 0; ntd < 8; ntd++) {
            sO[lrow0*66 + ntd*8 + qc]     = accO[ntd][0];
            sO[lrow0*66 + ntd*8 + qc + 1] = accO[ntd][1];
            sO[lrow1*66 + ntd*8 + qc]     = accO[ntd][2];
            sO[lrow1*66 + ntd*8 + qc + 1] = accO[ntd][3];
        }
    }
    __syncthreads();
    if (wn == 0) {
        float inv0 = 1.0f/lr0, inv1 = 1.0f/lr1;
        #pragma unroll
        for (int ntd = 0; ntd < 8; ntd++) {
            float v0 = (accO[ntd][0] + sO[lrow0*66 + ntd*8 + qc])     * inv0;
            float v1 = (accO[ntd][1] + sO[lrow0*66 + ntd*8 + qc + 1]) * inv0;
            float v2 = (accO[ntd][2] + sO[lrow1*66 + ntd*8 + qc])     * inv1;
            float v3 = (accO[ntd][3] + sO[lrow1*66 + ntd*8 + qc + 1]) * inv1;
            *(float2*)&Out[((size_t)(b*Ls) + ir0)*Dm + hoff + ntd*8 + qc] = make_float2(v0, v1);
            *(float2*)&Out[((size_t)(b*Ls) + ir1)*Dm + hoff + ntd*8 + qc] = make_float2(v2, v3);
        }
    }
}

// ---------------- combine + split comb ----------------
__global__ void combine_kernel(const float* __restrict__ pm)
{
    float a0 = pm[0], a1 = pm[1], a2 = pm[2];
    float mx = fmaxf(a0, fmaxf(a1, a2));
    float e0 = expf(a0-mx), e1 = expf(a1-mx), e2 = expf(a2-mx);
    float den = e0+e1+e2;
    float pw0 = e0/den, pw1 = e1/den;
    int e = blockIdx.x*blockDim.x + threadIdx.x;
    float v = pw0*g_outg[e] + pw1*g_outl[e];
    g_comb[e] = v;
    bsplit(v, g_combh[e], g_combl[e]);
}

// ---------------- selection path ----------------
__global__ void attns_kernel(const float* __restrict__ pm)
{
    __shared__ float sc[Ls];
    __shared__ float qs[64];
    __shared__ float red[256];
    int blk = blockIdx.x;
    int bh  = blk / NSEL, si = blk % NSEL;
    int b = bh >> 3, h = bh & 7;
    int qi = g_selidx[bh*NSEL + si];
    int t = threadIdx.x;

    if (t < 16) {
        float4 v = *(const float4*)&g_q[((size_t)(b*Ls) + qi)*Dm + h*HDim + t*4];
        *(float4*)&qs[t*4] = v;
    }
    __syncthreads();

    const float* kb = g_k + ((size_t)(b*Ls))*Dm + h*HDim;
    for (int jj = 0; jj < 8; jj++) {
        int j = t*8 + jj;
        const float4* kr = (const float4*)&kb[(size_t)j*Dm];
        float dot = 0.f;
        #pragma unroll
        for (int d4 = 0; d4 < 16; d4++) {
            float4 kv = kr[d4];
            dot = fmaf(qs[d4*4+0], kv.x, dot);
            dot = fmaf(qs[d4*4+1], kv.y, dot);
            dot = fmaf(qs[d4*4+2], kv.z, dot);
            dot = fmaf(qs[d4*4+3], kv.w, dot);
        }
        sc[j] = dot * 0.125f;
    }
    __syncthreads();

    float m = -INFINITY;
    for (int j = t; j < Ls; j += 256) m = fmaxf(m, sc[j]);
    red[t] = m; __syncthreads();
    for (int s2 = 128; s2; s2 >>= 1) { if (t < s2) red[t] = fmaxf(red[t], red[t+s2]); __syncthreads(); }
    m = red[0]; __syncthreads();

    float s = 0.f;
    for (int j = t; j < Ls; j += 256) { float e = __expf(sc[j]-m); sc[j] = e; s += e; }
    red[t] = s; __syncthreads();
    for (int s2 = 128; s2; s2 >>= 1) { if (t < s2) red[t] += red[t+s2]; __syncthreads(); }
    s = red[0]; __syncthreads();

    int d = t & 63, qtr = t >> 6;
    const float* vb = g_v + ((size_t)b*Ls)*Dm + h*HDim + d;
    float acc = 0.f;
    for (int j = qtr*512; j < qtr*512 + 512; j++)
        acc = fmaf(sc[j], vb[(size_t)j*Dm], acc);
    red[t] = acc; __syncthreads();

    if (t < 64) {
        float tot = red[t] + red[t+64] + red[t+128] + red[t+192];
        float a0 = pm[0], a1 = pm[1], a2 = pm[2];
        float mx = fmaxf(a0, fmaxf(a1, a2));
        float e0 = expf(a0-mx), e1 = expf(a1-mx), e2 = expf(a2-mx);
        float pw2 = e2/(e0+e1+e2);
        size_t idx = ((size_t)b*Ls + qi)*Dm + h*HDim + t;
        float nv = g_comb[idx] + pw2 * tot / s;
        g_comb[idx] = nv;
        bsplit(nv, g_combh[idx], g_combl[idx]);
    }
}

// ---------------- launch ----------------
extern "C" void kernel_launch(void* const* d_in, const int* in_sizes, int n_in,
                              void* d_out, int out_size)
{
    const float* query = (const float*)d_in[0];
    const float* keyi  = (const float*)d_in[1];
    const float* vali  = (const float*)d_in[2];
    const float* Wq = (const float*)d_in[3];  const float* bq = (const float*)d_in[4];
    const float* Wk = (const float*)d_in[5];  const float* bk = (const float*)d_in[6];
    const float* Wv = (const float*)d_in[7];  const float* bv = (const float*)d_in[8];
    const float* Wo = (const float*)d_in[9];  const float* bo = (const float*)d_in[10];
    const float* Wc1 = (const float*)d_in[11]; const float* bc1 = (const float*)d_in[12];
    const float* Wc2 = (const float*)d_in[13]; const float* bc2 = (const float*)d_in[14];
    const float* pm  = (const float*)d_in[15];

    float *outg, *outl;
    __nv_bfloat16 *kcpreh, *kcprel, *hidh, *hidl, *combh, *combl, *wth, *wtl;
    __nv_bfloat16 *qh, *ql, *kh, *kl, *vh, *vl, *kch, *kcl, *vch, *vcl;
    cudaGetSymbolAddress((void**)&outg,  g_outg);
    cudaGetSymbolAddress((void**)&outl,  g_outl);
    cudaGetSymbolAddress((void**)&kcpreh, g_kcpreh);
    cudaGetSymbolAddress((void**)&kcprel, g_kcprel);
    cudaGetSymbolAddress((void**)&hidh,  g_hidh);
    cudaGetSymbolAddress((void**)&hidl,  g_hidl);
    cudaGetSymbolAddress((void**)&combh, g_combh);
    cudaGetSymbolAddress((void**)&combl, g_combl);
    cudaGetSymbolAddress((void**)&wth,   g_wth);
    cudaGetSymbolAddress((void**)&wtl,   g_wtl);
    cudaGetSymbolAddress((void**)&qh,    g_qh);
    cudaGetSymbolAddress((void**)&ql,    g_ql);
    cudaGetSymbolAddress((void**)&kh,    g_kh);
    cudaGetSymbolAddress((void**)&kl,    g_kl);
    cudaGetSymbolAddress((void**)&vh,    g_vh);
    cudaGetSymbolAddress((void**)&vl,    g_vl);
    cudaGetSymbolAddress((void**)&kch,   g_kch);
    cudaGetSymbolAddress((void**)&kcl,   g_kcl);
    cudaGetSymbolAddress((void**)&vch,   g_vch);
    cudaGetSymbolAddress((void**)&vcl,   g_vcl);

    const int FLASH_SMEM = 6*64*72*2 + 2*128*4;   // 56320 B
    cudaFuncSetAttribute(flash_mma_kernel, cudaFuncAttributeMaxDynamicSharedMemorySize, FLASH_SMEM);

    // prep
    split_in_kernel<<<dim3((Bb*Ls*Dm)/256, 3), 256>>>(query, keyi, vali);
    split_w6_kernel<<<dim3(16,16,6), dim3(32,8)>>>(Wq, Wk, Wv, Wo, Wc1, Wc2);

    // projections
    proj3_mma_kernel<<<dim3(4,32,3), 256>>>(bq, bk, bv);

    // compression + MLP
    compress_kernel<<<512, 256>>>();
    mma_gemm_kernel<<<dim3(4,8), 256>>>(kcpreh, kcprel, wth + 4*(size_t)Dm*Dm, wtl + 4*(size_t)Dm*Dm,
                                        bc1, nullptr, hidh, hidl, Dm, Dm, 1);
    mma_gemm_kernel<<<dim3(4,8), 256>>>(hidh, hidl, wth + 5*(size_t)Dm*Dm, wtl + 5*(size_t)Dm*Dm,
                                        bc2, nullptr, kch, kcl, Dm, Dm, 0);

    // dense QK^T + fused stats
    scores_stats_mma_kernel<<<dim3(NJT,16,16), 256>>>(0.125f);
    impfinal_kernel<<<4096, 256>>>();
    topk_kernel<<<Bb*Hh, 256>>>();

    // attention paths (tensor-core flash)
    flash_mma_kernel<<<dim3(32,16), 256, FLASH_SMEM>>>(qh, ql, kh, kl, vh, vl, outl, Ls,  3, 1);
    flash_mma_kernel<<<dim3(32,16), 256, FLASH_SMEM>>>(qh, ql, kch, kcl, vch, vcl, outg, LcC, 8, 0);

    // mix + selection
    combine_kernel<<<(Bb*Ls*Dm)/256, 256>>>(pm);
    attns_kernel<<<Bb*Hh*NSEL, 256>>>(pm);

    // output projection
    mma_gemm_kernel<<<dim3(4,32), 256>>>(combh, combl, wth + 3*(size_t)Dm*Dm, wtl + 3*(size_t)Dm*Dm,
                                         bo, (float*)d_out, nullptr, nullptr, Dm, Dm, 0);
}

// round 7
// speedup vs baseline: 1.9354x; 1.0918x over previous
#include <cuda_runtime.h>
#include <cuda_bf16.h>
#include <math.h>
#include <stdint.h>

#define Bb   2
#define Ls   2048
#define Dm   512
#define Hh   8
#define HDim 64
#define LcC  512
#define NSEL 8
#define NJT  16

// ---------------- fp32 scratch ----------------
static __device__ float g_q[Bb*Ls*Dm];
static __device__ float g_k[Bb*Ls*Dm];
static __device__ float g_v[Bb*Ls*Dm];
static __device__ float g_outg[Bb*Ls*Dm];
static __device__ float g_outl[Bb*Ls*Dm];
static __device__ float g_comb[Bb*Ls*Dm];
static __device__ float g_imp[Bb*Hh*Ls];
static __device__ int   g_selidx[Bb*Hh*NSEL];
static __device__ float g_pmax[Bb*Hh*Ls*NJT];
static __device__ float g_pse [Bb*Hh*Ls*NJT];
static __device__ float g_psum[Bb*Hh*Ls*NJT];

// ---------------- bf16 split scratch ----------------
static __device__ __nv_bfloat16 g_inh[3][Bb*Ls*Dm];
static __device__ __nv_bfloat16 g_inl[3][Bb*Ls*Dm];
static __device__ __nv_bfloat16 g_wth[6][Dm*Dm];   // transposed [N][K]
static __device__ __nv_bfloat16 g_wtl[6][Dm*Dm];
static __device__ __nv_bfloat16 g_qh[Bb*Ls*Dm], g_ql[Bb*Ls*Dm];
static __device__ __nv_bfloat16 g_kh[Bb*Ls*Dm], g_kl[Bb*Ls*Dm];
static __device__ __nv_bfloat16 g_vh[Bb*Ls*Dm], g_vl[Bb*Ls*Dm];
static __device__ __nv_bfloat16 g_kch[Bb*LcC*Dm], g_kcl[Bb*LcC*Dm];
static __device__ __nv_bfloat16 g_vch[Bb*LcC*Dm], g_vcl[Bb*LcC*Dm];
static __device__ __nv_bfloat16 g_kcpreh[Bb*LcC*Dm], g_kcprel[Bb*LcC*Dm];
static __device__ __nv_bfloat16 g_hidh[Bb*LcC*Dm], g_hidl[Bb*LcC*Dm];
static __device__ __nv_bfloat16 g_combh[Bb*Ls*Dm], g_combl[Bb*Ls*Dm];

__device__ __forceinline__ void bsplit(float x, __nv_bfloat16& h, __nv_bfloat16& l)
{
    h = __float2bfloat16(x);
    l = __float2bfloat16(x - __bfloat162float(h));
}

__device__ __forceinline__ uint32_t packbf(float x, float y)
{
    __nv_bfloat162 t = __floats2bfloat162_rn(x, y);
    return *(uint32_t*)&t;
}

__device__ __forceinline__ void mma16816(float* c, const uint32_t* a, const uint32_t* b)
{
    asm volatile(
        "mma.sync.aligned.m16n8k16.row.col.f32.bf16.bf16.f32 "
        "{%0,%1,%2,%3}, {%4,%5,%6,%7}, {%8,%9}, {%0,%1,%2,%3};"
        : "+f"(c[0]), "+f"(c[1]), "+f"(c[2]), "+f"(c[3])
        : "r"(a[0]), "r"(a[1]), "r"(a[2]), "r"(a[3]), "r"(b[0]), "r"(b[1]));
}

// ---------------- prep: split inputs ----------------
__global__ void split_in_kernel(const float* x0, const float* x1, const float* x2)
{
    int z = blockIdx.y;
    const float* x = z == 0 ? x0 : (z == 1 ? x1 : x2);
    int i = blockIdx.x*blockDim.x + threadIdx.x;
    bsplit(x[i], g_inh[z][i], g_inl[z][i]);
}

// ---------------- prep: split + transpose all 6 weights ----------------
__global__ void split_w6_kernel(const float* w0, const float* w1, const float* w2,
                                const float* w3, const float* w4, const float* w5)
{
    __shared__ float tl[32][33];
    int widx = blockIdx.z;
    const float* w = widx==0?w0 : widx==1?w1 : widx==2?w2 : widx==3?w3 : widx==4?w4 : w5;
    int tx = threadIdx.x, ty = threadIdx.y;
    int n0 = blockIdx.x*32, k0 = blockIdx.y*32;
    #pragma unroll
    for (int i = 0; i < 4; i++)
        tl[ty + i*8][tx] = w[(size_t)(k0 + ty + i*8)*Dm + n0 + tx];
    __syncthreads();
    #pragma unroll
    for (int i = 0; i < 4; i++) {
        float v = tl[tx][ty + i*8];
        size_t o = (size_t)(n0 + ty + i*8)*Dm + k0 + tx;
        bsplit(v, g_wth[widx][o], g_wtl[widx][o]);
    }
}

// =========================================================================
// bf16x3 tensor-core GEMM: C[M][N] = A[M][K] @ Bw^T + bias
// =========================================================================
__device__ __forceinline__ void mma_gemm_body(
    const __nv_bfloat16* __restrict__ Ah, const __nv_bfloat16* __restrict__ Al,
    const __nv_bfloat16* __restrict__ Bh, const __nv_bfloat16* __restrict__ Bl,
    const float* __restrict__ bias, float* __restrict__ C,
    __nv_bfloat16* __restrict__ Ch, __nv_bfloat16* __restrict__ Cl,
    int N, int K, int gelu)
{
    __shared__ __nv_bfloat16 sAh[2][128*24], sAl[2][128*24];
    __shared__ __nv_bfloat16 sBh[2][128*24], sBl[2][128*24];
    const int tid = threadIdx.x;
    const int lane = tid & 31, warp = tid >> 5;
    const int wm = warp >> 2, wn = warp & 3;
    const int qr = lane >> 2, qc = (lane & 3)*2;
    const int row0 = blockIdx.y*128, col0 = blockIdx.x*128;
    const int half = tid >> 7, r = tid & 127;

    const __nv_bfloat16* As = half ? Al : Ah;
    const __nv_bfloat16* Bs = half ? Bl : Bh;

    {
        const uint4* pa = (const uint4*)(As + (size_t)(row0 + r)*K);
        const uint4* pb = (const uint4*)(Bs + (size_t)(col0 + r)*K);
        uint4 a0 = pa[0], a1 = pa[1], b0 = pb[0], b1 = pb[1];
        __nv_bfloat16* dA = half ? sAl[0] : sAh[0];
        __nv_bfloat16* dB = half ? sBl[0] : sBh[0];
        *(uint4*)&dA[r*24]     = a0; *(uint4*)&dA[r*24 + 8] = a1;
        *(uint4*)&dB[r*24]     = b0; *(uint4*)&dB[r*24 + 8] = b1;
    }
    __syncthreads();

    float acc[4][4][4] = {};
    const int nk = K >> 4;
    for (int kc = 0; kc < nk; kc++) {
        const int buf = kc & 1;
        uint4 na0, na1, nb0, nb1;
        if (kc + 1 < nk) {
            int k0 = (kc + 1)*16;
            const uint4* pa = (const uint4*)(As + (size_t)(row0 + r)*K + k0);
            const uint4* pb = (const uint4*)(Bs + (size_t)(col0 + r)*K + k0);
            na0 = pa[0]; na1 = pa[1]; nb0 = pb[0]; nb1 = pb[1];
        }

        const __nv_bfloat16* cAh = sAh[buf];
        const __nv_bfloat16* cAl = sAl[buf];
        const __nv_bfloat16* cBh = sBh[buf];
        const __nv_bfloat16* cBl = sBl[buf];

        uint32_t bh[4][2], bl[4][2];
        #pragma unroll
        for (int nt = 0; nt < 4; nt++) {
            int bo = (wn*32 + nt*8 + qr)*24 + qc;
            bh[nt][0] = *(const uint32_t*)&cBh[bo];
            bh[nt][1] = *(const uint32_t*)&cBh[bo + 8];
            bl[nt][0] = *(const uint32_t*)&cBl[bo];
            bl[nt][1] = *(const uint32_t*)&cBl[bo + 8];
        }
        #pragma unroll
        for (int mt = 0; mt < 4; mt++) {
            int ao = (wm*64 + mt*16 + qr)*24 + qc;
            uint32_t ah[4], al[4];
            ah[0] = *(const uint32_t*)&cAh[ao];
            ah[1] = *(const uint32_t*)&cAh[ao + 8*24];
            ah[2] = *(const uint32_t*)&cAh[ao + 8];
            ah[3] = *(const uint32_t*)&cAh[ao + 8*24 + 8];
            al[0] = *(const uint32_t*)&cAl[ao];
            al[1] = *(const uint32_t*)&cAl[ao + 8*24];
            al[2] = *(const uint32_t*)&cAl[ao + 8];
            al[3] = *(const uint32_t*)&cAl[ao + 8*24 + 8];
            #pragma unroll
            for (int nt = 0; nt < 4; nt++) {
                mma16816(acc[mt][nt], ah, bh[nt]);
                mma16816(acc[mt][nt], ah, bl[nt]);
                mma16816(acc[mt][nt], al, bh[nt]);
            }
        }

        if (kc + 1 < nk) {
            const int nb = buf ^ 1;
            __nv_bfloat16* dA = half ? sAl[nb] : sAh[nb];
            __nv_bfloat16* dB = half ? sBl[nb] : sBh[nb];
            *(uint4*)&dA[r*24]     = na0; *(uint4*)&dA[r*24 + 8] = na1;
            *(uint4*)&dB[r*24]     = nb0; *(uint4*)&dB[r*24 + 8] = nb1;
        }
        __syncthreads();
    }

    #pragma unroll
    for (int mt = 0; mt < 4; mt++) {
        int gr = row0 + wm*64 + mt*16 + qr;
        #pragma unroll
        for (int nt = 0; nt < 4; nt++) {
            int gc = col0 + wn*32 + nt*8 + qc;
            float v0 = acc[mt][nt][0] + bias[gc];
            float v1 = acc[mt][nt][1] + bias[gc+1];
            float v2 = acc[mt][nt][2] + bias[gc];
            float v3 = acc[mt][nt][3] + bias[gc+1];
            if (gelu) {
                v0 = 0.5f*v0*(1.0f + erff(v0*0.70710678118654752f));
                v1 = 0.5f*v1*(1.0f + erff(v1*0.70710678118654752f));
                v2 = 0.5f*v2*(1.0f + erff(v2*0.70710678118654752f));
                v3 = 0.5f*v3*(1.0f + erff(v3*0.70710678118654752f));
            }
            if (C) {
                float2 p0 = make_float2(v0, v1), p1 = make_float2(v2, v3);
                *(float2*)&C[(size_t)gr*N + gc]     = p0;
                *(float2*)&C[(size_t)(gr+8)*N + gc] = p1;
            }
            if (Ch) {
                __nv_bfloat16 h0,l0,h1,l1,h2,l2,h3,l3;
                bsplit(v0,h0,l0); bsplit(v1,h1,l1); bsplit(v2,h2,l2); bsplit(v3,h3,l3);
                Ch[(size_t)gr*N + gc]   = h0; Ch[(size_t)gr*N + gc+1]   = h1;
                Cl[(size_t)gr*N + gc]   = l0; Cl[(size_t)gr*N + gc+1]   = l1;
                Ch[(size_t)(gr+8)*N+gc] = h2; Ch[(size_t)(gr+8)*N+gc+1] = h3;
                Cl[(size_t)(gr+8)*N+gc] = l2; Cl[(size_t)(gr+8)*N+gc+1] = l3;
            }
        }
    }
}

__global__ void __launch_bounds__(256, 2) mma_gemm_kernel(
    const __nv_bfloat16* Ah, const __nv_bfloat16* Al,
    const __nv_bfloat16* Bh, const __nv_bfloat16* Bl,
    const float* bias, float* C, __nv_bfloat16* Ch, __nv_bfloat16* Cl,
    int N, int K, int gelu)
{
    mma_gemm_body(Ah, Al, Bh, Bl, bias, C, Ch, Cl, N, K, gelu);
}

__global__ void __launch_bounds__(256, 2) proj3_mma_kernel(
    const float* bq, const float* bk, const float* bv)
{
    int z = blockIdx.z;
    if (z == 0)
        mma_gemm_body(g_inh[0], g_inl[0], g_wth[0], g_wtl[0], bq, g_q, g_qh, g_ql, Dm, Dm, 0);
    else if (z == 1)
        mma_gemm_body(g_inh[1], g_inl[1], g_wth[1], g_wtl[1], bk, g_k, g_kh, g_kl, Dm, Dm, 0);
    else
        mma_gemm_body(g_inh[2], g_inl[2], g_wth[2], g_wtl[2], bv, g_v, g_vh, g_vl, Dm, Dm, 0);
}

// =========================================================================
// dense QK^T (bf16x3 mma) + fused row stats.  Full-K smem residency:
// load all 4 tiles (128x64, stride 72) once, one sync, then 144 mma.
// dynamic smem 73728 B; grid (NJT, 16, B*H), 256 threads.
// =========================================================================
extern __shared__ __nv_bfloat16 scsm[];
__global__ void __launch_bounds__(256, 2) scores_stats_mma_kernel(float scale)
{
    __nv_bfloat16* sAh = scsm;
    __nv_bfloat16* sAl = scsm + 128*72;
    __nv_bfloat16* sBh = scsm + 2*128*72;
    __nv_bfloat16* sBl = scsm + 3*128*72;
    __shared__ float s4a[128][4], s4b[128][4], srm[128];

    const int tid = threadIdx.x;
    const int lane = tid & 31, warp = tid >> 5;
    const int wm = warp >> 2, wn = warp & 3;
    const int qr = lane >> 2, qc = (lane & 3)*2;
    const int bh = blockIdx.z;
    const int b = bh >> 3, h = bh & 7;
    const int i0 = blockIdx.y*128, j0 = blockIdx.x*128;

    const __nv_bfloat16* Qhp = g_qh + ((size_t)(b*Ls) + i0)*Dm + h*HDim;
    const __nv_bfloat16* Qlp = g_ql + ((size_t)(b*Ls) + i0)*Dm + h*HDim;
    const __nv_bfloat16* Khp = g_kh + ((size_t)(b*Ls) + j0)*Dm + h*HDim;
    const __nv_bfloat16* Klp = g_kl + ((size_t)(b*Ls) + j0)*Dm + h*HDim;

    // single load phase: 1024 uint4 slots per tile, 4 per thread per tile
    #pragma unroll
    for (int i = 0; i < 4; i++) {
        int slot = tid*4 + i;
        int row = slot >> 3, c = slot & 7;
        *(uint4*)&sAh[row*72 + c*8] = *(const uint4*)&Qhp[(size_t)row*Dm + c*8];
        *(uint4*)&sAl[row*72 + c*8] = *(const uint4*)&Qlp[(size_t)row*Dm + c*8];
        *(uint4*)&sBh[row*72 + c*8] = *(const uint4*)&Khp[(size_t)row*Dm + c*8];
        *(uint4*)&sBl[row*72 + c*8] = *(const uint4*)&Klp[(size_t)row*Dm + c*8];
    }
    __syncthreads();

    float acc[4][4][4] = {};
    #pragma unroll
    for (int kc = 0; kc < 4; kc++) {
        const int ko = kc*16 + qc;
        uint32_t bhf[4][2], blf[4][2];
        #pragma unroll
        for (int nt = 0; nt < 4; nt++) {
            int bo = (wn*32 + nt*8 + qr)*72 + ko;
            bhf[nt][0] = *(const uint32_t*)&sBh[bo];
            bhf[nt][1] = *(const uint32_t*)&sBh[bo + 8];
            blf[nt][0] = *(const uint32_t*)&sBl[bo];
            blf[nt][1] = *(const uint32_t*)&sBl[bo + 8];
        }
        #pragma unroll
        for (int mt = 0; mt < 4; mt++) {
            int ao = (wm*64 + mt*16 + qr)*72 + ko;
            uint32_t ah[4], al[4];
            ah[0] = *(const uint32_t*)&sAh[ao];
            ah[1] = *(const uint32_t*)&sAh[ao + 8*72];
            ah[2] = *(const uint32_t*)&sAh[ao + 8];
            ah[3] = *(const uint32_t*)&sAh[ao + 8*72 + 8];
            al[0] = *(const uint32_t*)&sAl[ao];
            al[1] = *(const uint32_t*)&sAl[ao + 8*72];
            al[2] = *(const uint32_t*)&sAl[ao + 8];
            al[3] = *(const uint32_t*)&sAl[ao + 8*72 + 8];
            #pragma unroll
            for (int nt = 0; nt < 4; nt++) {
                mma16816(acc[mt][nt], ah, bhf[nt]);
                mma16816(acc[mt][nt], ah, blf[nt]);
                mma16816(acc[mt][nt], al, bhf[nt]);
            }
        }
    }

    // ---- fused stats over the 128-col j-tile ----
    #pragma unroll
    for (int mt = 0; mt < 4; mt++) {
        float m0 = -INFINITY, m1 = -INFINITY;
        #pragma unroll
        for (int nt = 0; nt < 4; nt++) {
            m0 = fmaxf(m0, fmaxf(acc[mt][nt][0], acc[mt][nt][1]));
            m1 = fmaxf(m1, fmaxf(acc[mt][nt][2], acc[mt][nt][3]));
        }
        m0 = fmaxf(m0, __shfl_xor_sync(0xFFFFFFFFu, m0, 1));
        m0 = fmaxf(m0, __shfl_xor_sync(0xFFFFFFFFu, m0, 2));
        m1 = fmaxf(m1, __shfl_xor_sync(0xFFFFFFFFu, m1, 1));
        m1 = fmaxf(m1, __shfl_xor_sync(0xFFFFFFFFu, m1, 2));
        if ((lane & 3) == 0) {
            s4a[wm*64 + mt*16 + qr][wn]     = m0;
            s4a[wm*64 + mt*16 + 8 + qr][wn] = m1;
        }
    }
    __syncthreads();
    if (tid < 128)
        srm[tid] = fmaxf(fmaxf(s4a[tid][0], s4a[tid][1]), fmaxf(s4a[tid][2], s4a[tid][3]));
    __syncthreads();

    #pragma unroll
    for (int mt = 0; mt < 4; mt++) {
        int lr0 = wm*64 + mt*16 + qr, lr1 = lr0 + 8;
        float rm0 = srm[lr0]*scale, rm1 = srm[lr1]*scale;
        float se0 = 0.f, se1 = 0.f, ss0 = 0.f, ss1 = 0.f;
        #pragma unroll
        for (int nt = 0; nt < 4; nt++) {
            float x0 = acc[mt][nt][0]*scale, x1 = acc[mt][nt][1]*scale;
            float x2 = acc[mt][nt][2]*scale, x3 = acc[mt][nt][3]*scale;
            se0 += __expf(x0 - rm0) + __expf(x1 - rm0);
            se1 += __expf(x2 - rm1) + __expf(x3 - rm1);
            ss0 += x0 + x1; ss1 += x2 + x3;
        }
        se0 += __shfl_xor_sync(0xFFFFFFFFu, se0, 1); se0 += __shfl_xor_sync(0xFFFFFFFFu, se0, 2);
        se1 += __shfl_xor_sync(0xFFFFFFFFu, se1, 1); se1 += __shfl_xor_sync(0xFFFFFFFFu, se1, 2);
        ss0 += __shfl_xor_sync(0xFFFFFFFFu, ss0, 1); ss0 += __shfl_xor_sync(0xFFFFFFFFu, ss0, 2);
        ss1 += __shfl_xor_sync(0xFFFFFFFFu, ss1, 1); ss1 += __shfl_xor_sync(0xFFFFFFFFu, ss1, 2);
        if ((lane & 3) == 0) {
            s4b[lr0][wn] = se0; s4b[lr1][wn] = se1;
            s4a[lr0][wn] = ss0; s4a[lr1][wn] = ss1;
        }
    }
    __syncthreads();
    if (tid < 128) {
        int rowg = bh*Ls + i0 + tid;
        int jt = blockIdx.x;
        g_pmax[(size_t)rowg*NJT + jt] = srm[tid]*scale;
        g_pse [(size_t)rowg*NJT + jt] = s4b[tid][0]+s4b[tid][1]+s4b[tid][2]+s4b[tid][3];
        g_psum[(size_t)rowg*NJT + jt] = s4a[tid][0]+s4a[tid][1]+s4a[tid][2]+s4a[tid][3];
    }
}

// ---------------- compress: mean of 4 rows -> splits ----------------
__global__ void compress_kernel()
{
    int e4 = blockIdx.x*blockDim.x + threadIdx.x;
    int b = e4 / (LcC*Dm/4);
    int r = e4 % (LcC*Dm/4);
    int m = r / (Dm/4), d4 = r % (Dm/4);
    const float4* k4 = (const float4*)g_k;
    const float4* v4 = (const float4*)g_v;
    size_t base = ((size_t)(b*Ls + m*4)*Dm)/4 + d4;
    float4 a = k4[base], bb = k4[base+128], c = k4[base+256], d = k4[base+384];
    float ox = 0.25f*(a.x+bb.x+c.x+d.x), oy = 0.25f*(a.y+bb.y+c.y+d.y);
    float oz = 0.25f*(a.z+bb.z+c.z+d.z), ow = 0.25f*(a.w+bb.w+c.w+d.w);
    bsplit(ox, g_kcpreh[e4*4+0], g_kcprel[e4*4+0]);
    bsplit(oy, g_kcpreh[e4*4+1], g_kcprel[e4*4+1]);
    bsplit(oz, g_kcpreh[e4*4+2], g_kcprel[e4*4+2]);
    bsplit(ow, g_kcpreh[e4*4+3], g_kcprel[e4*4+3]);
    a = v4[base]; bb = v4[base+128]; c = v4[base+256]; d = v4[base+384];
    ox = 0.25f*(a.x+bb.x+c.x+d.x); oy = 0.25f*(a.y+bb.y+c.y+d.y);
    oz = 0.25f*(a.z+bb.z+c.z+d.z); ow = 0.25f*(a.w+bb.w+c.w+d.w);
    bsplit(ox, g_vch[e4*4+0], g_vcl[e4*4+0]);
    bsplit(oy, g_vch[e4*4+1], g_vcl[e4*4+1]);
    bsplit(oz, g_vch[e4*4+2], g_vcl[e4*4+2]);
    bsplit(ow, g_vch[e4*4+3], g_vcl[e4*4+3]);
}

// ---------------- importance merge ----------------
__global__ void impfinal_kernel()
{
    int warp = (blockIdx.x*blockDim.x + threadIdx.x) >> 5;
    int lane = threadIdx.x & 31;
    float pm = -INFINITY, pe = 0.f, ps = 0.f;
    if (lane < NJT) {
        pm = g_pmax[(size_t)warp*NJT + lane];
        pe = g_pse [(size_t)warp*NJT + lane];
        ps = g_psum[(size_t)warp*NJT + lane];
    }
    float m = pm;
    #pragma unroll
    for (int o = 8; o; o >>= 1) m = fmaxf(m, __shfl_xor_sync(0xFFFFFFFFu, m, o));
    float se = (lane < NJT) ? pe * __expf(pm - m) : 0.f;
    #pragma unroll
    for (int o = 8; o; o >>= 1) {
        se += __shfl_xor_sync(0xFFFFFFFFu, se, o);
        ps += __shfl_xor_sync(0xFFFFFFFFu, ps, o);
    }
    if (lane == 0)
        g_imp[warp] = m + logf(se) - 7.6246189861593985f - ps * (1.0f/2048.0f);
}

// ---------------- top-8 ----------------
__global__ void topk_kernel()
{
    int bh = blockIdx.x;
    const float* imp = g_imp + bh*Ls;
    __shared__ float bv[256];
    __shared__ int   bi[256];
    __shared__ int   chosen[NSEL];
    int t = threadIdx.x;
    for (int itu = 0; itu < NSEL; itu++) {
        float best = -INFINITY; int bidx = 0x7FFFFFFF;
        for (int j = t; j < Ls; j += 256) {
            bool skip = false;
            for (int c = 0; c < itu; c++) if (chosen[c] == j) skip = true;
            if (skip) continue;
            float vv = imp[j];
            if (vv > best || (vv == best && j < bidx)) { best = vv; bidx = j; }
        }
        bv[t] = best; bi[t] = bidx;
        __syncthreads();
        for (int s2 = 128; s2; s2 >>= 1) {
            if (t < s2) {
                if (bv[t+s2] > bv[t] || (bv[t+s2] == bv[t] && bi[t+s2] < bi[t])) {
                    bv[t] = bv[t+s2]; bi[t] = bi[t+s2];
                }
            }
            __syncthreads();
        }
        if (t == 0) { chosen[itu] = bi[0]; g_selidx[bh*NSEL + itu] = bi[0]; }
        __syncthreads();
    }
}

// =========================================================================
// flash attention, bf16x3 legacy mma
// =========================================================================
extern __shared__ char fsm2[];
__global__ void __launch_bounds__(256, 2) flash_mma_kernel(
    const __nv_bfloat16* __restrict__ Qh, const __nv_bfloat16* __restrict__ Ql,
    const __nv_bfloat16* __restrict__ Kh, const __nv_bfloat16* __restrict__ Kl,
    const __nv_bfloat16* __restrict__ Vh, const __nv_bfloat16* __restrict__ Vl,
    float* __restrict__ Out, int LK, int nchunks, int local)
{
    __nv_bfloat16* sQh = (__nv_bfloat16*)fsm2;
    __nv_bfloat16* sQl = sQh + 64*72;
    __nv_bfloat16* sKh = sQl + 64*72;
    __nv_bfloat16* sKl = sKh + 64*72;
    __nv_bfloat16* sVh = sKl + 64*72;
    __nv_bfloat16* sVl = sVh + 64*72;
    float* sM = (float*)(sVl + 64*72);
    float* sS = sM + 128;
    float* sO = (float*)sKh;

    const int tid = threadIdx.x;
    const int lane = tid & 31, warp = tid >> 5;
    const int wq = warp >> 1, wn = warp & 1;
    const int qr = lane >> 2, qc = (lane & 3)*2;
    const int bh = blockIdx.y;
    const int b = bh >> 3, h = bh & 7;
    const int i0 = blockIdx.x*64;
    const size_t hoff = (size_t)h*HDim;

    {
        int row = tid >> 2, c16 = (tid & 3)*16;
        const uint4* ph = (const uint4*)(Qh + ((size_t)(b*Ls) + i0 + row)*Dm + hoff + c16);
        const uint4* pl = (const uint4*)(Ql + ((size_t)(b*Ls) + i0 + row)*Dm + hoff + c16);
        uint4 h0 = ph[0], h1 = ph[1], l0 = pl[0], l1 = pl[1];
        *(uint4*)&sQh[row*72 + c16] = h0; *(uint4*)&sQh[row*72 + c16 + 8] = h1;
        *(uint4*)&sQl[row*72 + c16] = l0; *(uint4*)&sQl[row*72 + c16 + 8] = l1;
    }

    float accO[8][4] = {};
    float mr0 = -INFINITY, mr1 = -INFINITY;
    float lr0 = 0.f, lr1 = 0.f;
    const int ir0 = i0 + wq*16 + qr, ir1 = ir0 + 8;
    const int lrow0 = wq*16 + qr, lrow1 = lrow0 + 8;

    for (int c = 0; c < nchunks; c++) {
        int jbase = (local ? i0 - 64 : 0) + c*64;
        __syncthreads();
        {
            int row = tid >> 2, c16 = (tid & 3)*16;
            int jg = jbase + row;
            uint4 h0 = {0,0,0,0}, h1 = {0,0,0,0}, l0 = {0,0,0,0}, l1 = {0,0,0,0};
            if (jg >= 0 && jg < LK) {
                const uint4* ph = (const uint4*)(Kh + ((size_t)(b*LK) + jg)*Dm + hoff + c16);
                const uint4* pl = (const uint4*)(Kl + ((size_t)(b*LK) + jg)*Dm + hoff + c16);
                h0 = ph[0]; h1 = ph[1]; l0 = pl[0]; l1 = pl[1];
            }
            *(uint4*)&sKh[row*72 + c16] = h0; *(uint4*)&sKh[row*72 + c16 + 8] = h1;
            *(uint4*)&sKl[row*72 + c16] = l0; *(uint4*)&sKl[row*72 + c16 + 8] = l1;
        }
        {
            int row = tid >> 2, d16 = (tid & 3)*16;
            int jg = jbase + row;
            uint4 h0 = {0,0,0,0}, h1 = {0,0,0,0}, l0 = {0,0,0,0}, l1 = {0,0,0,0};
            if (jg >= 0 && jg < LK) {
                const uint4* ph = (const uint4*)(Vh + ((size_t)(b*LK) + jg)*Dm + hoff + d16);
                const uint4* pl = (const uint4*)(Vl + ((size_t)(b*LK) + jg)*Dm + hoff + d16);
                h0 = ph[0]; h1 = ph[1]; l0 = pl[0]; l1 = pl[1];
            }
            const __nv_bfloat16* eh = (const __nv_bfloat16*)&h0;
            const __nv_bfloat16* el = (const __nv_bfloat16*)&l0;
            #pragma unroll
            for (int e = 0; e < 8; e++) {
                sVh[(d16 + e)*72 + row] = eh[e];
                sVl[(d16 + e)*72 + row] = el[e];
            }
            eh = (const __nv_bfloat16*)&h1; el = (const __nv_bfloat16*)&l1;
            #pragma unroll
            for (int e = 0; e < 8; e++) {
                sVh[(d16 + 8 + e)*72 + row] = eh[e];
                sVl[(d16 + 8 + e)*72 + row] = el[e];
            }
        }
        __syncthreads();

        float s[4][4] = {};
        #pragma unroll
        for (int kc = 0; kc < 4; kc++) {
            int ko = kc*16 + qc;
            int ar = wq*16 + qr;
            uint32_t ah[4], al[4];
            ah[0] = *(const uint32_t*)&sQh[ar*72 + ko];
            ah[1] = *(const uint32_t*)&sQh[(ar+8)*72 + ko];
            ah[2] = *(const uint32_t*)&sQh[ar*72 + ko + 8];
            ah[3] = *(const uint32_t*)&sQh[(ar+8)*72 + ko + 8];
            al[0] = *(const uint32_t*)&sQl[ar*72 + ko];
            al[1] = *(const uint32_t*)&sQl[(ar+8)*72 + ko];
            al[2] = *(const uint32_t*)&sQl[ar*72 + ko + 8];
            al[3] = *(const uint32_t*)&sQl[(ar+8)*72 + ko + 8];
            #pragma unroll
            for (int nt = 0; nt < 4; nt++) {
                int br = (wn*32 + nt*8 + qr)*72 + ko;
                uint32_t bhf[2], blf[2];
                bhf[0] = *(const uint32_t*)&sKh[br];
                bhf[1] = *(const uint32_t*)&sKh[br + 8];
                blf[0] = *(const uint32_t*)&sKl[br];
                blf[1] = *(const uint32_t*)&sKl[br + 8];
                mma16816(s[nt], ah, bhf);
                mma16816(s[nt], ah, blf);
                mma16816(s[nt], al, bhf);
            }
        }

        bool ok[4][4];
        float m0 = -INFINITY, m1 = -INFINITY;
        #pragma unroll
        for (int nt = 0; nt < 4; nt++) {
            int jc0 = jbase + wn*32 + nt*8 + qc;
            int jc1 = jc0 + 1;
            bool in0 = (jc0 >= 0) & (jc0 < LK);
            bool in1 = (jc1 >= 0) & (jc1 < LK);
            ok[nt][0] = in0 && (!local || (jc0 >= ir0-64 && jc0 <= ir0+64));
            ok[nt][1] = in1 && (!local || (jc1 >= ir0-64 && jc1 <= ir0+64));
            ok[nt][2] = in0 && (!local || (jc0 >= ir1-64 && jc0 <= ir1+64));
            ok[nt][3] = in1 && (!local || (jc1 >= ir1-64 && jc1 <= ir1+64));
            #pragma unroll
            for (int rg = 0; rg < 4; rg++) s[nt][rg] *= 0.125f;
            if (ok[nt][0]) m0 = fmaxf(m0, s[nt][0]);
            if (ok[nt][1]) m0 = fmaxf(m0, s[nt][1]);
            if (ok[nt][2]) m1 = fmaxf(m1, s[nt][2]);
            if (ok[nt][3]) m1 = fmaxf(m1, s[nt][3]);
        }
        m0 = fmaxf(m0, __shfl_xor_sync(0xFFFFFFFFu, m0, 1));
        m0 = fmaxf(m0, __shfl_xor_sync(0xFFFFFFFFu, m0, 2));
        m1 = fmaxf(m1, __shfl_xor_sync(0xFFFFFFFFu, m1, 1));
        m1 = fmaxf(m1, __shfl_xor_sync(0xFFFFFFFFu, m1, 2));
        if ((lane & 3) == 0) { sM[lrow0*2 + wn] = m0; sM[lrow1*2 + wn] = m1; }
        __syncthreads();
        float cm0 = fmaxf(sM[lrow0*2], sM[lrow0*2 + 1]);
        float cm1 = fmaxf(sM[lrow1*2], sM[lrow1*2 + 1]);
        float mn0 = fmaxf(mr0, cm0), mn1 = fmaxf(mr1, cm1);
        float cf0 = (mn0 == -INFINITY) ? 1.f : __expf(mr0 - mn0);
        float cf1 = (mn1 == -INFINITY) ? 1.f : __expf(mr1 - mn1);
        mr0 = mn0; mr1 = mn1;

        float ps0 = 0.f, ps1 = 0.f;
        #pragma unroll
        for (int nt = 0; nt < 4; nt++) {
            s[nt][0] = ok[nt][0] ? __expf(s[nt][0] - mn0) : 0.f;
            s[nt][1] = ok[nt][1] ? __expf(s[nt][1] - mn0) : 0.f;
            s[nt][2] = ok[nt][2] ? __expf(s[nt][2] - mn1) : 0.f;
            s[nt][3] = ok[nt][3] ? __expf(s[nt][3] - mn1) : 0.f;
            ps0 += s[nt][0] + s[nt][1];
            ps1 += s[nt][2] + s[nt][3];
        }
        ps0 += __shfl_xor_sync(0xFFFFFFFFu, ps0, 1); ps0 += __shfl_xor_sync(0xFFFFFFFFu, ps0, 2);
        ps1 += __shfl_xor_sync(0xFFFFFFFFu, ps1, 1); ps1 += __shfl_xor_sync(0xFFFFFFFFu, ps1, 2);
        if ((lane & 3) == 0) { sS[lrow0*2 + wn] = ps0; sS[lrow1*2 + wn] = ps1; }
        __syncthreads();
        lr0 = lr0*cf0 + sS[lrow0*2] + sS[lrow0*2 + 1];
        lr1 = lr1*cf1 + sS[lrow1*2] + sS[lrow1*2 + 1];

        #pragma unroll
        for (int ntd = 0; ntd < 8; ntd++) {
            accO[ntd][0] *= cf0; accO[ntd][1] *= cf0;
            accO[ntd][2] *= cf1; accO[ntd][3] *= cf1;
        }

        #pragma unroll
        for (int kch = 0; kch < 2; kch++) {
            int nt0 = kch*2, nt1 = kch*2 + 1;
            uint32_t pah[4], pal[4];
            {
                float p00 = s[nt0][0], p01 = s[nt0][1], p02 = s[nt0][2], p03 = s[nt0][3];
                float p10 = s[nt1][0], p11 = s[nt1][1], p12 = s[nt1][2], p13 = s[nt1][3];
                pah[0] = packbf(p00, p01); pah[1] = packbf(p02, p03);
                pah[2] = packbf(p10, p11); pah[3] = packbf(p12, p13);
                float q00 = p00 - __bfloat162float(__float2bfloat16(p00));
                float q01 = p01 - __bfloat162float(__float2bfloat16(p01));
                float q02 = p02 - __bfloat162float(__float2bfloat16(p02));
                float q03 = p03 - __bfloat162float(__float2bfloat16(p03));
                float q10 = p10 - __bfloat162float(__float2bfloat16(p10));
                float q11 = p11 - __bfloat162float(__float2bfloat16(p11));
                float q12 = p12 - __bfloat162float(__float2bfloat16(p12));
                float q13 = p13 - __bfloat162float(__float2bfloat16(p13));
                pal[0] = packbf(q00, q01); pal[1] = packbf(q02, q03);
                pal[2] = packbf(q10, q11); pal[3] = packbf(q12, q13);
            }
            int jb = wn*32 + kch*16 + qc;
            #pragma unroll
            for (int ntd = 0; ntd < 8; ntd++) {
                int vr = (ntd*8 + qr)*72 + jb;
                uint32_t bhf[2], blf[2];
                bhf[0] = *(const uint32_t*)&sVh[vr];
                bhf[1] = *(const uint32_t*)&sVh[vr + 8];
                blf[0] = *(const uint32_t*)&sVl[vr];
                blf[1] = *(const uint32_t*)&sVl[vr + 8];
                mma16816(accO[ntd], pah, bhf);
                mma16816(accO[ntd], pal, bhf);
                mma16816(accO[ntd], pah, blf);
            }
        }
    }

    __syncthreads();
    if (wn == 1) {
        #pragma unroll
        for (int ntd = 0; ntd < 8; ntd++) {
            sO[lrow0*66 + ntd*8 + qc]     = accO[ntd][0];
            sO[lrow0*66 + ntd*8 + qc + 1] = accO[ntd][1];
            sO[lrow1*66 + ntd*8 + qc]     = accO[ntd][2];
            sO[lrow1*66 + ntd*8 + qc + 1] = accO[ntd][3];
        }
    }
    __syncthreads();
    if (wn == 0) {
        float inv0 = 1.0f/lr0, inv1 = 1.0f/lr1;
        #pragma unroll
        for (int ntd = 0; ntd < 8; ntd++) {
            float v0 = (accO[ntd][0] + sO[lrow0*66 + ntd*8 + qc])     * inv0;
            float v1 = (accO[ntd][1] + sO[lrow0*66 + ntd*8 + qc + 1]) * inv0;
            float v2 = (accO[ntd][2] + sO[lrow1*66 + ntd*8 + qc])     * inv1;
            float v3 = (accO[ntd][3] + sO[lrow1*66 + ntd*8 + qc + 1]) * inv1;
            *(float2*)&Out[((size_t)(b*Ls) + ir0)*Dm + hoff + ntd*8 + qc] = make_float2(v0, v1);
            *(float2*)&Out[((size_t)(b*Ls) + ir1)*Dm + hoff + ntd*8 + qc] = make_float2(v2, v3);
        }
    }
}

// ---------------- combine + split comb ----------------
__global__ void combine_kernel(const float* __restrict__ pm)
{
    float a0 = pm[0], a1 = pm[1], a2 = pm[2];
    float mx = fmaxf(a0, fmaxf(a1, a2));
    float e0 = expf(a0-mx), e1 = expf(a1-mx), e2 = expf(a2-mx);
    float den = e0+e1+e2;
    float pw0 = e0/den, pw1 = e1/den;
    int e = blockIdx.x*blockDim.x + threadIdx.x;
    float v = pw0*g_outg[e] + pw1*g_outl[e];
    g_comb[e] = v;
    bsplit(v, g_combh[e], g_combl[e]);
}

// ---------------- selection path ----------------
__global__ void attns_kernel(const float* __restrict__ pm)
{
    __shared__ float sc[Ls];
    __shared__ float qs[64];
    __shared__ float red[256];
    int blk = blockIdx.x;
    int bh  = blk / NSEL, si = blk % NSEL;
    int b = bh >> 3, h = bh & 7;
    int qi = g_selidx[bh*NSEL + si];
    int t = threadIdx.x;

    if (t < 16) {
        float4 v = *(const float4*)&g_q[((size_t)(b*Ls) + qi)*Dm + h*HDim + t*4];
        *(float4*)&qs[t*4] = v;
    }
    __syncthreads();

    const float* kb = g_k + ((size_t)(b*Ls))*Dm + h*HDim;
    for (int jj = 0; jj < 8; jj++) {
        int j = t*8 + jj;
        const float4* kr = (const float4*)&kb[(size_t)j*Dm];
        float dot = 0.f;
        #pragma unroll
        for (int d4 = 0; d4 < 16; d4++) {
            float4 kv = kr[d4];
            dot = fmaf(qs[d4*4+0], kv.x, dot);
            dot = fmaf(qs[d4*4+1], kv.y, dot);
            dot = fmaf(qs[d4*4+2], kv.z, dot);
            dot = fmaf(qs[d4*4+3], kv.w, dot);
        }
        sc[j] = dot * 0.125f;
    }
    __syncthreads();

    float m = -INFINITY;
    for (int j = t; j < Ls; j += 256) m = fmaxf(m, sc[j]);
    red[t] = m; __syncthreads();
    for (int s2 = 128; s2; s2 >>= 1) { if (t < s2) red[t] = fmaxf(red[t], red[t+s2]); __syncthreads(); }
    m = red[0]; __syncthreads();

    float s = 0.f;
    for (int j = t; j < Ls; j += 256) { float e = __expf(sc[j]-m); sc[j] = e; s += e; }
    red[t] = s; __syncthreads();
    for (int s2 = 128; s2; s2 >>= 1) { if (t < s2) red[t] += red[t+s2]; __syncthreads(); }
    s = red[0]; __syncthreads();

    int d = t & 63, qtr = t >> 6;
    const float* vb = g_v + ((size_t)b*Ls)*Dm + h*HDim + d;
    float acc = 0.f;
    for (int j = qtr*512; j < qtr*512 + 512; j++)
        acc = fmaf(sc[j], vb[(size_t)j*Dm], acc);
    red[t] = acc; __syncthreads();

    if (t < 64) {
        float tot = red[t] + red[t+64] + red[t+128] + red[t+192];
        float a0 = pm[0], a1 = pm[1], a2 = pm[2];
        float mx = fmaxf(a0, fmaxf(a1, a2));
        float e0 = expf(a0-mx), e1 = expf(a1-mx), e2 = expf(a2-mx);
        float pw2 = e2/(e0+e1+e2);
        size_t idx = ((size_t)b*Ls + qi)*Dm + h*HDim + t;
        float nv = g_comb[idx] + pw2 * tot / s;
        g_comb[idx] = nv;
        bsplit(nv, g_combh[idx], g_combl[idx]);
    }
}

// ---------------- launch ----------------
extern "C" void kernel_launch(void* const* d_in, const int* in_sizes, int n_in,
                              void* d_out, int out_size)
{
    const float* query = (const float*)d_in[0];
    const float* keyi  = (const float*)d_in[1];
    const float* vali  = (const float*)d_in[2];
    const float* Wq = (const float*)d_in[3];  const float* bq = (const float*)d_in[4];
    const float* Wk = (const float*)d_in[5];  const float* bk = (const float*)d_in[6];
    const float* Wv = (const float*)d_in[7];  const float* bv = (const float*)d_in[8];
    const float* Wo = (const float*)d_in[9];  const float* bo = (const float*)d_in[10];
    const float* Wc1 = (const float*)d_in[11]; const float* bc1 = (const float*)d_in[12];
    const float* Wc2 = (const float*)d_in[13]; const float* bc2 = (const float*)d_in[14];
    const float* pm  = (const float*)d_in[15];

    float *outg, *outl;
    __nv_bfloat16 *kcpreh, *kcprel, *hidh, *hidl, *combh, *combl, *wth, *wtl;
    __nv_bfloat16 *qh, *ql, *kh, *kl, *vh, *vl, *kch, *kcl, *vch, *vcl;
    cudaGetSymbolAddress((void**)&outg,  g_outg);
    cudaGetSymbolAddress((void**)&outl,  g_outl);
    cudaGetSymbolAddress((void**)&kcpreh, g_kcpreh);
    cudaGetSymbolAddress((void**)&kcprel, g_kcprel);
    cudaGetSymbolAddress((void**)&hidh,  g_hidh);
    cudaGetSymbolAddress((void**)&hidl,  g_hidl);
    cudaGetSymbolAddress((void**)&combh, g_combh);
    cudaGetSymbolAddress((void**)&combl, g_combl);
    cudaGetSymbolAddress((void**)&wth,   g_wth);
    cudaGetSymbolAddress((void**)&wtl,   g_wtl);
    cudaGetSymbolAddress((void**)&qh,    g_qh);
    cudaGetSymbolAddress((void**)&ql,    g_ql);
    cudaGetSymbolAddress((void**)&kh,    g_kh);
    cudaGetSymbolAddress((void**)&kl,    g_kl);
    cudaGetSymbolAddress((void**)&vh,    g_vh);
    cudaGetSymbolAddress((void**)&vl,    g_vl);
    cudaGetSymbolAddress((void**)&kch,   g_kch);
    cudaGetSymbolAddress((void**)&kcl,   g_kcl);
    cudaGetSymbolAddress((void**)&vch,   g_vch);
    cudaGetSymbolAddress((void**)&vcl,   g_vcl);

    const int FLASH_SMEM = 6*64*72*2 + 2*128*4;
    const int SCORES_SMEM = 4*128*72*2;   // 73728
    cudaFuncSetAttribute(flash_mma_kernel, cudaFuncAttributeMaxDynamicSharedMemorySize, FLASH_SMEM);
    cudaFuncSetAttribute(scores_stats_mma_kernel, cudaFuncAttributeMaxDynamicSharedMemorySize, SCORES_SMEM);

    // prep
    split_in_kernel<<<dim3((Bb*Ls*Dm)/256, 3), 256>>>(query, keyi, vali);
    split_w6_kernel<<<dim3(16,16,6), dim3(32,8)>>>(Wq, Wk, Wv, Wo, Wc1, Wc2);

    // projections
    proj3_mma_kernel<<<dim3(4,32,3), 256>>>(bq, bk, bv);

    // compression + MLP
    compress_kernel<<<512, 256>>>();
    mma_gemm_kernel<<<dim3(4,8), 256>>>(kcpreh, kcprel, wth + 4*(size_t)Dm*Dm, wtl + 4*(size_t)Dm*Dm,
                                        bc1, nullptr, hidh, hidl, Dm, Dm, 1);
    mma_gemm_kernel<<<dim3(4,8), 256>>>(hidh, hidl, wth + 5*(size_t)Dm*Dm, wtl + 5*(size_t)Dm*Dm,
                                        bc2, nullptr, kch, kcl, Dm, Dm, 0);

    // dense QK^T + fused stats
    scores_stats_mma_kernel<<<dim3(NJT,16,16), 256, SCORES_SMEM>>>(0.125f);
    impfinal_kernel<<<4096, 256>>>();
    topk_kernel<<<Bb*Hh, 256>>>();

    // attention paths
    flash_mma_kernel<<<dim3(32,16), 256, FLASH_SMEM>>>(qh, ql, kh, kl, vh, vl, outl, Ls,  3, 1);
    flash_mma_kernel<<<dim3(32,16), 256, FLASH_SMEM>>>(qh, ql, kch, kcl, vch, vcl, outg, LcC, 8, 0);

    // mix + selection
    combine_kernel<<<(Bb*Ls*Dm)/256, 256>>>(pm);
    attns_kernel<<<Bb*Hh*NSEL, 256>>>(pm);

    // output projection
    mma_gemm_kernel<<<dim3(4,32), 256>>>(combh, combl, wth + 3*(size_t)Dm*Dm, wtl + 3*(size_t)Dm*Dm,
                                         bo, (float*)d_out, nullptr, nullptr, Dm, Dm, 0);
}

// round 8
// speedup vs baseline: 2.0849x; 1.0773x over previous
#include <cuda_runtime.h>
#include <cuda_bf16.h>
#include <math.h>
#include <stdint.h>

#define Bb   2
#define Ls   2048
#define Dm   512
#define Hh   8
#define HDim 64
#define LcC  512
#define NSEL 8
#define NJT  16

// ---------------- fp32 scratch ----------------
static __device__ float g_q[Bb*Ls*Dm];
static __device__ float g_k[Bb*Ls*Dm];
static __device__ float g_v[Bb*Ls*Dm];
static __device__ float g_outg[Bb*Ls*Dm];
static __device__ float g_outl[Bb*Ls*Dm];
static __device__ float g_comb[Bb*Ls*Dm];
static __device__ float g_imp[Bb*Hh*Ls];
static __device__ int   g_selidx[Bb*Hh*NSEL];
static __device__ float g_pmax[Bb*Hh*Ls*NJT];
static __device__ float g_pse [Bb*Hh*Ls*NJT];
static __device__ float g_psum[Bb*Hh*Ls*NJT];

// ---------------- bf16 split scratch ----------------
static __device__ __nv_bfloat16 g_inh[3][Bb*Ls*Dm];
static __device__ __nv_bfloat16 g_inl[3][Bb*Ls*Dm];
static __device__ __nv_bfloat16 g_wth[6][Dm*Dm];   // transposed [N][K]
static __device__ __nv_bfloat16 g_wtl[6][Dm*Dm];
static __device__ __nv_bfloat16 g_qh[Bb*Ls*Dm], g_ql[Bb*Ls*Dm];
static __device__ __nv_bfloat16 g_kh[Bb*Ls*Dm], g_kl[Bb*Ls*Dm];
static __device__ __nv_bfloat16 g_vh[Bb*Ls*Dm], g_vl[Bb*Ls*Dm];
static __device__ __nv_bfloat16 g_kch[Bb*LcC*Dm], g_kcl[Bb*LcC*Dm];
static __device__ __nv_bfloat16 g_vch[Bb*LcC*Dm], g_vcl[Bb*LcC*Dm];
static __device__ __nv_bfloat16 g_kcpreh[Bb*LcC*Dm], g_kcprel[Bb*LcC*Dm];
static __device__ __nv_bfloat16 g_hidh[Bb*LcC*Dm], g_hidl[Bb*LcC*Dm];
static __device__ __nv_bfloat16 g_combh[Bb*Ls*Dm], g_combl[Bb*Ls*Dm];

__device__ __forceinline__ void bsplit(float x, __nv_bfloat16& h, __nv_bfloat16& l)
{
    h = __float2bfloat16(x);
    l = __float2bfloat16(x - __bfloat162float(h));
}

__device__ __forceinline__ uint32_t packbf(float x, float y)
{
    __nv_bfloat162 t = __floats2bfloat162_rn(x, y);
    return *(uint32_t*)&t;
}

__device__ __forceinline__ void mma16816(float* c, const uint32_t* a, const uint32_t* b)
{
    asm volatile(
        "mma.sync.aligned.m16n8k16.row.col.f32.bf16.bf16.f32 "
        "{%0,%1,%2,%3}, {%4,%5,%6,%7}, {%8,%9}, {%0,%1,%2,%3};"
        : "+f"(c[0]), "+f"(c[1]), "+f"(c[2]), "+f"(c[3])
        : "r"(a[0]), "r"(a[1]), "r"(a[2]), "r"(a[3]), "r"(b[0]), "r"(b[1]));
}

__device__ __forceinline__ uint32_t smem_u32(const void* p)
{
    uint32_t a;
    asm("{ .reg .u64 t; cvta.to.shared.u64 t, %1; cvt.u32.u64 %0, t; }" : "=r"(a) : "l"(p));
    return a;
}

__device__ __forceinline__ void ldmx4(uint32_t* r, uint32_t a)
{
    asm volatile("ldmatrix.sync.aligned.m8n8.x4.shared.b16 {%0,%1,%2,%3}, [%4];"
        : "=r"(r[0]), "=r"(r[1]), "=r"(r[2]), "=r"(r[3]) : "r"(a));
}
__device__ __forceinline__ void ldmx4t(uint32_t* r, uint32_t a)
{
    asm volatile("ldmatrix.sync.aligned.m8n8.x4.trans.shared.b16 {%0,%1,%2,%3}, [%4];"
        : "=r"(r[0]), "=r"(r[1]), "=r"(r[2]), "=r"(r[3]) : "r"(a));
}

// ---------------- prep: split inputs ----------------
__global__ void split_in_kernel(const float* x0, const float* x1, const float* x2)
{
    int z = blockIdx.y;
    const float* x = z == 0 ? x0 : (z == 1 ? x1 : x2);
    int i = blockIdx.x*blockDim.x + threadIdx.x;
    bsplit(x[i], g_inh[z][i], g_inl[z][i]);
}

// ---------------- prep: split + transpose all 6 weights ----------------
__global__ void split_w6_kernel(const float* w0, const float* w1, const float* w2,
                                const float* w3, const float* w4, const float* w5)
{
    __shared__ float tl[32][33];
    int widx = blockIdx.z;
    const float* w = widx==0?w0 : widx==1?w1 : widx==2?w2 : widx==3?w3 : widx==4?w4 : w5;
    int tx = threadIdx.x, ty = threadIdx.y;
    int n0 = blockIdx.x*32, k0 = blockIdx.y*32;
    #pragma unroll
    for (int i = 0; i < 4; i++)
        tl[ty + i*8][tx] = w[(size_t)(k0 + ty + i*8)*Dm + n0 + tx];
    __syncthreads();
    #pragma unroll
    for (int i = 0; i < 4; i++) {
        float v = tl[tx][ty + i*8];
        size_t o = (size_t)(n0 + ty + i*8)*Dm + k0 + tx;
        bsplit(v, g_wth[widx][o], g_wtl[widx][o]);
    }
}

// =========================================================================
// bf16x3 tensor-core GEMM: C[M][N] = A[M][K] @ Bw^T + bias (unchanged)
// =========================================================================
__device__ __forceinline__ void mma_gemm_body(
    const __nv_bfloat16* __restrict__ Ah, const __nv_bfloat16* __restrict__ Al,
    const __nv_bfloat16* __restrict__ Bh, const __nv_bfloat16* __restrict__ Bl,
    const float* __restrict__ bias, float* __restrict__ C,
    __nv_bfloat16* __restrict__ Ch, __nv_bfloat16* __restrict__ Cl,
    int N, int K, int gelu)
{
    __shared__ __nv_bfloat16 sAh[2][128*24], sAl[2][128*24];
    __shared__ __nv_bfloat16 sBh[2][128*24], sBl[2][128*24];
    const int tid = threadIdx.x;
    const int lane = tid & 31, warp = tid >> 5;
    const int wm = warp >> 2, wn = warp & 3;
    const int qr = lane >> 2, qc = (lane & 3)*2;
    const int row0 = blockIdx.y*128, col0 = blockIdx.x*128;
    const int half = tid >> 7, r = tid & 127;

    const __nv_bfloat16* As = half ? Al : Ah;
    const __nv_bfloat16* Bs = half ? Bl : Bh;

    {
        const uint4* pa = (const uint4*)(As + (size_t)(row0 + r)*K);
        const uint4* pb = (const uint4*)(Bs + (size_t)(col0 + r)*K);
        uint4 a0 = pa[0], a1 = pa[1], b0 = pb[0], b1 = pb[1];
        __nv_bfloat16* dA = half ? sAl[0] : sAh[0];
        __nv_bfloat16* dB = half ? sBl[0] : sBh[0];
        *(uint4*)&dA[r*24]     = a0; *(uint4*)&dA[r*24 + 8] = a1;
        *(uint4*)&dB[r*24]     = b0; *(uint4*)&dB[r*24 + 8] = b1;
    }
    __syncthreads();

    float acc[4][4][4] = {};
    const int nk = K >> 4;
    for (int kc = 0; kc < nk; kc++) {
        const int buf = kc & 1;
        uint4 na0, na1, nb0, nb1;
        if (kc + 1 < nk) {
            int k0 = (kc + 1)*16;
            const uint4* pa = (const uint4*)(As + (size_t)(row0 + r)*K + k0);
            const uint4* pb = (const uint4*)(Bs + (size_t)(col0 + r)*K + k0);
            na0 = pa[0]; na1 = pa[1]; nb0 = pb[0]; nb1 = pb[1];
        }

        const __nv_bfloat16* cAh = sAh[buf];
        const __nv_bfloat16* cAl = sAl[buf];
        const __nv_bfloat16* cBh = sBh[buf];
        const __nv_bfloat16* cBl = sBl[buf];

        uint32_t bh[4][2], bl[4][2];
        #pragma unroll
        for (int nt = 0; nt < 4; nt++) {
            int bo = (wn*32 + nt*8 + qr)*24 + qc;
            bh[nt][0] = *(const uint32_t*)&cBh[bo];
            bh[nt][1] = *(const uint32_t*)&cBh[bo + 8];
            bl[nt][0] = *(const uint32_t*)&cBl[bo];
            bl[nt][1] = *(const uint32_t*)&cBl[bo + 8];
        }
        #pragma unroll
        for (int mt = 0; mt < 4; mt++) {
            int ao = (wm*64 + mt*16 + qr)*24 + qc;
            uint32_t ah[4], al[4];
            ah[0] = *(const uint32_t*)&cAh[ao];
            ah[1] = *(const uint32_t*)&cAh[ao + 8*24];
            ah[2] = *(const uint32_t*)&cAh[ao + 8];
            ah[3] = *(const uint32_t*)&cAh[ao + 8*24 + 8];
            al[0] = *(const uint32_t*)&cAl[ao];
            al[1] = *(const uint32_t*)&cAl[ao + 8*24];
            al[2] = *(const uint32_t*)&cAl[ao + 8];
            al[3] = *(const uint32_t*)&cAl[ao + 8*24 + 8];
            #pragma unroll
            for (int nt = 0; nt < 4; nt++) {
                mma16816(acc[mt][nt], ah, bh[nt]);
                mma16816(acc[mt][nt], ah, bl[nt]);
                mma16816(acc[mt][nt], al, bh[nt]);
            }
        }

        if (kc + 1 < nk) {
            const int nb = buf ^ 1;
            __nv_bfloat16* dA = half ? sAl[nb] : sAh[nb];
            __nv_bfloat16* dB = half ? sBl[nb] : sBh[nb];
            *(uint4*)&dA[r*24]     = na0; *(uint4*)&dA[r*24 + 8] = na1;
            *(uint4*)&dB[r*24]     = nb0; *(uint4*)&dB[r*24 + 8] = nb1;
        }
        __syncthreads();
    }

    #pragma unroll
    for (int mt = 0; mt < 4; mt++) {
        int gr = row0 + wm*64 + mt*16 + qr;
        #pragma unroll
        for (int nt = 0; nt < 4; nt++) {
            int gc = col0 + wn*32 + nt*8 + qc;
            float v0 = acc[mt][nt][0] + bias[gc];
            float v1 = acc[mt][nt][1] + bias[gc+1];
            float v2 = acc[mt][nt][2] + bias[gc];
            float v3 = acc[mt][nt][3] + bias[gc+1];
            if (gelu) {
                v0 = 0.5f*v0*(1.0f + erff(v0*0.70710678118654752f));
                v1 = 0.5f*v1*(1.0f + erff(v1*0.70710678118654752f));
                v2 = 0.5f*v2*(1.0f + erff(v2*0.70710678118654752f));
                v3 = 0.5f*v3*(1.0f + erff(v3*0.70710678118654752f));
            }
            if (C) {
                float2 p0 = make_float2(v0, v1), p1 = make_float2(v2, v3);
                *(float2*)&C[(size_t)gr*N + gc]     = p0;
                *(float2*)&C[(size_t)(gr+8)*N + gc] = p1;
            }
            if (Ch) {
                __nv_bfloat16 h0,l0,h1,l1,h2,l2,h3,l3;
                bsplit(v0,h0,l0); bsplit(v1,h1,l1); bsplit(v2,h2,l2); bsplit(v3,h3,l3);
                Ch[(size_t)gr*N + gc]   = h0; Ch[(size_t)gr*N + gc+1]   = h1;
                Cl[(size_t)gr*N + gc]   = l0; Cl[(size_t)gr*N + gc+1]   = l1;
                Ch[(size_t)(gr+8)*N+gc] = h2; Ch[(size_t)(gr+8)*N+gc+1] = h3;
                Cl[(size_t)(gr+8)*N+gc] = l2; Cl[(size_t)(gr+8)*N+gc+1] = l3;
            }
        }
    }
}

__global__ void __launch_bounds__(256, 2) mma_gemm_kernel(
    const __nv_bfloat16* Ah, const __nv_bfloat16* Al,
    const __nv_bfloat16* Bh, const __nv_bfloat16* Bl,
    const float* bias, float* C, __nv_bfloat16* Ch, __nv_bfloat16* Cl,
    int N, int K, int gelu)
{
    mma_gemm_body(Ah, Al, Bh, Bl, bias, C, Ch, Cl, N, K, gelu);
}

__global__ void __launch_bounds__(256, 2) proj3_mma_kernel(
    const float* bq, const float* bk, const float* bv)
{
    int z = blockIdx.z;
    if (z == 0)
        mma_gemm_body(g_inh[0], g_inl[0], g_wth[0], g_wtl[0], bq, g_q, g_qh, g_ql, Dm, Dm, 0);
    else if (z == 1)
        mma_gemm_body(g_inh[1], g_inl[1], g_wth[1], g_wtl[1], bk, g_k, g_kh, g_kl, Dm, Dm, 0);
    else
        mma_gemm_body(g_inh[2], g_inl[2], g_wth[2], g_wtl[2], bv, g_v, g_vh, g_vl, Dm, Dm, 0);
}

// =========================================================================
// dense QK^T (bf16x3 mma) + fused row stats, ldmatrix fragments.
// dynamic smem 73728 B; grid (NJT, 16, B*H), 256 threads.
// =========================================================================
extern __shared__ __nv_bfloat16 scsm[];
__global__ void __launch_bounds__(256, 2) scores_stats_mma_kernel(float scale)
{
    __nv_bfloat16* sAh = scsm;
    __nv_bfloat16* sAl = scsm + 128*72;
    __nv_bfloat16* sBh = scsm + 2*128*72;
    __nv_bfloat16* sBl = scsm + 3*128*72;
    __shared__ float s4a[128][4], s4b[128][4], srm[128];

    const int tid = threadIdx.x;
    const int lane = tid & 31, warp = tid >> 5;
    const int wm = warp >> 2, wn = warp & 3;
    const int qr = lane >> 2;
    const int bh = blockIdx.z;
    const int b = bh >> 3, h = bh & 7;
    const int i0 = blockIdx.y*128, j0 = blockIdx.x*128;

    const __nv_bfloat16* Qhp = g_qh + ((size_t)(b*Ls) + i0)*Dm + h*HDim;
    const __nv_bfloat16* Qlp = g_ql + ((size_t)(b*Ls) + i0)*Dm + h*HDim;
    const __nv_bfloat16* Khp = g_kh + ((size_t)(b*Ls) + j0)*Dm + h*HDim;
    const __nv_bfloat16* Klp = g_kl + ((size_t)(b*Ls) + j0)*Dm + h*HDim;

    #pragma unroll
    for (int i = 0; i < 4; i++) {
        int slot = tid*4 + i;
        int row = slot >> 3, c = slot & 7;
        *(uint4*)&sAh[row*72 + c*8] = *(const uint4*)&Qhp[(size_t)row*Dm + c*8];
        *(uint4*)&sAl[row*72 + c*8] = *(const uint4*)&Qlp[(size_t)row*Dm + c*8];
        *(uint4*)&sBh[row*72 + c*8] = *(const uint4*)&Khp[(size_t)row*Dm + c*8];
        *(uint4*)&sBl[row*72 + c*8] = *(const uint4*)&Klp[(size_t)row*Dm + c*8];
    }
    __syncthreads();

    // ldmatrix lane addressing: row part (lane&15), k-half part (lane>>4)*8
    const uint32_t sc0 = smem_u32(scsm);
    const uint32_t aAh = sc0, aAl = sc0 + 128*72*2, aBh = sc0 + 2*128*72*2, aBl = sc0 + 3*128*72*2;
    const int lrow = lane & 15, lkh = (lane >> 4)*8;

    float acc[4][4][4] = {};
    #pragma unroll
    for (int kc = 0; kc < 4; kc++) {
        const int ko = kc*16;
        uint32_t Bh4[2][4], Bl4[2][4];
        #pragma unroll
        for (int ntp = 0; ntp < 2; ntp++) {
            uint32_t off = ((wn*32 + ntp*16 + lrow)*72 + ko + lkh)*2;
            ldmx4(Bh4[ntp], aBh + off);
            ldmx4(Bl4[ntp], aBl + off);
        }
        #pragma unroll
        for (int mt = 0; mt < 4; mt++) {
            uint32_t offA = ((wm*64 + mt*16 + lrow)*72 + ko + lkh)*2;
            uint32_t ah[4], al[4];
            ldmx4(ah, aAh + offA);
            ldmx4(al, aAl + offA);
            #pragma unroll
            for (int nt = 0; nt < 4; nt++) {
                uint32_t bhf[2] = { Bh4[nt>>1][nt&1], Bh4[nt>>1][(nt&1)+2] };
                uint32_t blf[2] = { Bl4[nt>>1][nt&1], Bl4[nt>>1][(nt&1)+2] };
                mma16816(acc[mt][nt], ah, bhf);
                mma16816(acc[mt][nt], ah, blf);
                mma16816(acc[mt][nt], al, bhf);
            }
        }
    }

    // ---- fused stats over the 128-col j-tile ----
    #pragma unroll
    for (int mt = 0; mt < 4; mt++) {
        float m0 = -INFINITY, m1 = -INFINITY;
        #pragma unroll
        for (int nt = 0; nt < 4; nt++) {
            m0 = fmaxf(m0, fmaxf(acc[mt][nt][0], acc[mt][nt][1]));
            m1 = fmaxf(m1, fmaxf(acc[mt][nt][2], acc[mt][nt][3]));
        }
        m0 = fmaxf(m0, __shfl_xor_sync(0xFFFFFFFFu, m0, 1));
        m0 = fmaxf(m0, __shfl_xor_sync(0xFFFFFFFFu, m0, 2));
        m1 = fmaxf(m1, __shfl_xor_sync(0xFFFFFFFFu, m1, 1));
        m1 = fmaxf(m1, __shfl_xor_sync(0xFFFFFFFFu, m1, 2));
        if ((lane & 3) == 0) {
            s4a[wm*64 + mt*16 + qr][wn]     = m0;
            s4a[wm*64 + mt*16 + 8 + qr][wn] = m1;
        }
    }
    __syncthreads();
    if (tid < 128)
        srm[tid] = fmaxf(fmaxf(s4a[tid][0], s4a[tid][1]), fmaxf(s4a[tid][2], s4a[tid][3]));
    __syncthreads();

    #pragma unroll
    for (int mt = 0; mt < 4; mt++) {
        int lr0 = wm*64 + mt*16 + qr, lr1 = lr0 + 8;
        float rm0 = srm[lr0]*scale, rm1 = srm[lr1]*scale;
        float se0 = 0.f, se1 = 0.f, ss0 = 0.f, ss1 = 0.f;
        #pragma unroll
        for (int nt = 0; nt < 4; nt++) {
            float x0 = acc[mt][nt][0]*scale, x1 = acc[mt][nt][1]*scale;
            float x2 = acc[mt][nt][2]*scale, x3 = acc[mt][nt][3]*scale;
            se0 += __expf(x0 - rm0) + __expf(x1 - rm0);
            se1 += __expf(x2 - rm1) + __expf(x3 - rm1);
            ss0 += x0 + x1; ss1 += x2 + x3;
        }
        se0 += __shfl_xor_sync(0xFFFFFFFFu, se0, 1); se0 += __shfl_xor_sync(0xFFFFFFFFu, se0, 2);
        se1 += __shfl_xor_sync(0xFFFFFFFFu, se1, 1); se1 += __shfl_xor_sync(0xFFFFFFFFu, se1, 2);
        ss0 += __shfl_xor_sync(0xFFFFFFFFu, ss0, 1); ss0 += __shfl_xor_sync(0xFFFFFFFFu, ss0, 2);
        ss1 += __shfl_xor_sync(0xFFFFFFFFu, ss1, 1); ss1 += __shfl_xor_sync(0xFFFFFFFFu, ss1, 2);
        if ((lane & 3) == 0) {
            s4b[lr0][wn] = se0; s4b[lr1][wn] = se1;
            s4a[lr0][wn] = ss0; s4a[lr1][wn] = ss1;
        }
    }
    __syncthreads();
    if (tid < 128) {
        int rowg = bh*Ls + i0 + tid;
        int jt = blockIdx.x;
        g_pmax[(size_t)rowg*NJT + jt] = srm[tid]*scale;
        g_pse [(size_t)rowg*NJT + jt] = s4b[tid][0]+s4b[tid][1]+s4b[tid][2]+s4b[tid][3];
        g_psum[(size_t)rowg*NJT + jt] = s4a[tid][0]+s4a[tid][1]+s4a[tid][2]+s4a[tid][3];
    }
}

// ---------------- compress: mean of 4 rows -> splits ----------------
__global__ void compress_kernel()
{
    int e4 = blockIdx.x*blockDim.x + threadIdx.x;
    int b = e4 / (LcC*Dm/4);
    int r = e4 % (LcC*Dm/4);
    int m = r / (Dm/4), d4 = r % (Dm/4);
    const float4* k4 = (const float4*)g_k;
    const float4* v4 = (const float4*)g_v;
    size_t base = ((size_t)(b*Ls + m*4)*Dm)/4 + d4;
    float4 a = k4[base], bb = k4[base+128], c = k4[base+256], d = k4[base+384];
    float ox = 0.25f*(a.x+bb.x+c.x+d.x), oy = 0.25f*(a.y+bb.y+c.y+d.y);
    float oz = 0.25f*(a.z+bb.z+c.z+d.z), ow = 0.25f*(a.w+bb.w+c.w+d.w);
    bsplit(ox, g_kcpreh[e4*4+0], g_kcprel[e4*4+0]);
    bsplit(oy, g_kcpreh[e4*4+1], g_kcprel[e4*4+1]);
    bsplit(oz, g_kcpreh[e4*4+2], g_kcprel[e4*4+2]);
    bsplit(ow, g_kcpreh[e4*4+3], g_kcprel[e4*4+3]);
    a = v4[base]; bb = v4[base+128]; c = v4[base+256]; d = v4[base+384];
    ox = 0.25f*(a.x+bb.x+c.x+d.x); oy = 0.25f*(a.y+bb.y+c.y+d.y);
    oz = 0.25f*(a.z+bb.z+c.z+d.z); ow = 0.25f*(a.w+bb.w+c.w+d.w);
    bsplit(ox, g_vch[e4*4+0], g_vcl[e4*4+0]);
    bsplit(oy, g_vch[e4*4+1], g_vcl[e4*4+1]);
    bsplit(oz, g_vch[e4*4+2], g_vcl[e4*4+2]);
    bsplit(ow, g_vch[e4*4+3], g_vcl[e4*4+3]);
}

// ---------------- importance merge ----------------
__global__ void impfinal_kernel()
{
    int warp = (blockIdx.x*blockDim.x + threadIdx.x) >> 5;
    int lane = threadIdx.x & 31;
    float pm = -INFINITY, pe = 0.f, ps = 0.f;
    if (lane < NJT) {
        pm = g_pmax[(size_t)warp*NJT + lane];
        pe = g_pse [(size_t)warp*NJT + lane];
        ps = g_psum[(size_t)warp*NJT + lane];
    }
    float m = pm;
    #pragma unroll
    for (int o = 8; o; o >>= 1) m = fmaxf(m, __shfl_xor_sync(0xFFFFFFFFu, m, o));
    float se = (lane < NJT) ? pe * __expf(pm - m) : 0.f;
    #pragma unroll
    for (int o = 8; o; o >>= 1) {
        se += __shfl_xor_sync(0xFFFFFFFFu, se, o);
        ps += __shfl_xor_sync(0xFFFFFFFFu, ps, o);
    }
    if (lane == 0)
        g_imp[warp] = m + logf(se) - 7.6246189861593985f - ps * (1.0f/2048.0f);
}

// ---------------- top-8 ----------------
__global__ void topk_kernel()
{
    int bh = blockIdx.x;
    const float* imp = g_imp + bh*Ls;
    __shared__ float bv[256];
    __shared__ int   bi[256];
    __shared__ int   chosen[NSEL];
    int t = threadIdx.x;
    for (int itu = 0; itu < NSEL; itu++) {
        float best = -INFINITY; int bidx = 0x7FFFFFFF;
        for (int j = t; j < Ls; j += 256) {
            bool skip = false;
            for (int c = 0; c < itu; c++) if (chosen[c] == j) skip = true;
            if (skip) continue;
            float vv = imp[j];
            if (vv > best || (vv == best && j < bidx)) { best = vv; bidx = j; }
        }
        bv[t] = best; bi[t] = bidx;
        __syncthreads();
        for (int s2 = 128; s2; s2 >>= 1) {
            if (t < s2) {
                if (bv[t+s2] > bv[t] || (bv[t+s2] == bv[t] && bi[t+s2] < bi[t])) {
                    bv[t] = bv[t+s2]; bi[t] = bi[t+s2];
                }
            }
            __syncthreads();
        }
        if (t == 0) { chosen[itu] = bi[0]; g_selidx[bh*NSEL + itu] = bi[0]; }
        __syncthreads();
    }
}

// =========================================================================
// fused flash attention (z=0 local band, z=1 global/compressed), bf16x3 mma,
// ldmatrix fragments, V natural layout + ldmatrix.trans for PV.
// =========================================================================
extern __shared__ char fsm2[];
__global__ void __launch_bounds__(256, 2) flash_mma_kernel(
    const __nv_bfloat16* __restrict__ Qh, const __nv_bfloat16* __restrict__ Ql,
    const __nv_bfloat16* __restrict__ Khg, const __nv_bfloat16* __restrict__ Klg,
    const __nv_bfloat16* __restrict__ Vhg, const __nv_bfloat16* __restrict__ Vlg,
    const __nv_bfloat16* __restrict__ Khc, const __nv_bfloat16* __restrict__ Klc,
    const __nv_bfloat16* __restrict__ Vhc, const __nv_bfloat16* __restrict__ Vlc,
    float* __restrict__ OutL, float* __restrict__ OutG)
{
    __nv_bfloat16* sQh = (__nv_bfloat16*)fsm2;  // [64][72]
    __nv_bfloat16* sQl = sQh + 64*72;
    __nv_bfloat16* sKh = sQl + 64*72;
    __nv_bfloat16* sKl = sKh + 64*72;
    __nv_bfloat16* sVh = sKl + 64*72;           // natural [j][d]
    __nv_bfloat16* sVl = sVh + 64*72;
    float* sM = (float*)(sVl + 64*72);
    float* sS = sM + 128;
    float* sO = (float*)sKh;                     // epilogue reuse [64][66]

    const int z = blockIdx.z;
    const __nv_bfloat16* Kh = z ? Khc : Khg;
    const __nv_bfloat16* Kl = z ? Klc : Klg;
    const __nv_bfloat16* Vh = z ? Vhc : Vhg;
    const __nv_bfloat16* Vl = z ? Vlc : Vlg;
    float* Out = z ? OutG : OutL;
    const int LK = z ? LcC : Ls;
    const int nchunks = z ? 8 : 3;
    const int local = z ? 0 : 1;

    const int tid = threadIdx.x;
    const int lane = tid & 31, warp = tid >> 5;
    const int wq = warp >> 1, wn = warp & 1;
    const int qr = lane >> 2, qc = (lane & 3)*2;
    const int bh = blockIdx.y;
    const int b = bh >> 3, h = bh & 7;
    const int i0 = blockIdx.x*64;
    const size_t hoff = (size_t)h*HDim;

    const uint32_t sb = smem_u32(fsm2);
    const uint32_t aQh = sb, aQl = sb + 9216, aKh = sb + 18432, aKl = sb + 27648;
    const uint32_t aVh = sb + 36864, aVl = sb + 46080;
    const int lrow = lane & 15, lkh = (lane >> 4)*8;

    // load Q tile (row-major [i][d])
    {
        int row = tid >> 2, c16 = (tid & 3)*16;
        const uint4* ph = (const uint4*)(Qh + ((size_t)(b*Ls) + i0 + row)*Dm + hoff + c16);
        const uint4* pl = (const uint4*)(Ql + ((size_t)(b*Ls) + i0 + row)*Dm + hoff + c16);
        uint4 h0 = ph[0], h1 = ph[1], l0 = pl[0], l1 = pl[1];
        *(uint4*)&sQh[row*72 + c16] = h0; *(uint4*)&sQh[row*72 + c16 + 8] = h1;
        *(uint4*)&sQl[row*72 + c16] = l0; *(uint4*)&sQl[row*72 + c16 + 8] = l1;
    }

    float accO[8][4] = {};
    float mr0 = -INFINITY, mr1 = -INFINITY;
    float lr0 = 0.f, lr1 = 0.f;
    const int ir0 = i0 + wq*16 + qr, ir1 = ir0 + 8;
    const int lrow0 = wq*16 + qr, lrow1 = lrow0 + 8;

    for (int c = 0; c < nchunks; c++) {
        int jbase = (local ? i0 - 64 : 0) + c*64;
        __syncthreads();
        // load K and V chunks [j][d], vectorized
        {
            int row = tid >> 2, c16 = (tid & 3)*16;
            int jg = jbase + row;
            uint4 kh0 = {0,0,0,0}, kh1 = {0,0,0,0}, kl0 = {0,0,0,0}, kl1 = {0,0,0,0};
            uint4 vh0 = {0,0,0,0}, vh1 = {0,0,0,0}, vl0 = {0,0,0,0}, vl1 = {0,0,0,0};
            if (jg >= 0 && jg < LK) {
                const uint4* ph = (const uint4*)(Kh + ((size_t)(b*LK) + jg)*Dm + hoff + c16);
                const uint4* pl = (const uint4*)(Kl + ((size_t)(b*LK) + jg)*Dm + hoff + c16);
                kh0 = ph[0]; kh1 = ph[1]; kl0 = pl[0]; kl1 = pl[1];
                ph = (const uint4*)(Vh + ((size_t)(b*LK) + jg)*Dm + hoff + c16);
                pl = (const uint4*)(Vl + ((size_t)(b*LK) + jg)*Dm + hoff + c16);
                vh0 = ph[0]; vh1 = ph[1]; vl0 = pl[0]; vl1 = pl[1];
            }
            *(uint4*)&sKh[row*72 + c16] = kh0; *(uint4*)&sKh[row*72 + c16 + 8] = kh1;
            *(uint4*)&sKl[row*72 + c16] = kl0; *(uint4*)&sKl[row*72 + c16 + 8] = kl1;
            *(uint4*)&sVh[row*72 + c16] = vh0; *(uint4*)&sVh[row*72 + c16 + 8] = vh1;
            *(uint4*)&sVl[row*72 + c16] = vl0; *(uint4*)&sVl[row*72 + c16 + 8] = vl1;
        }
        __syncthreads();

        // QK^T via ldmatrix fragments
        float s[4][4] = {};
        #pragma unroll
        for (int kc = 0; kc < 4; kc++) {
            int ko = kc*16;
            uint32_t offA = ((wq*16 + lrow)*72 + ko + lkh)*2;
            uint32_t ah[4], al[4];
            ldmx4(ah, aQh + offA);
            ldmx4(al, aQl + offA);
            #pragma unroll
            for (int ntp = 0; ntp < 2; ntp++) {
                uint32_t offB = ((wn*32 + ntp*16 + lrow)*72 + ko + lkh)*2;
                uint32_t kh4[4], kl4[4];
                ldmx4(kh4, aKh + offB);
                ldmx4(kl4, aKl + offB);
                uint32_t bhf0[2] = { kh4[0], kh4[2] }, bhf1[2] = { kh4[1], kh4[3] };
                uint32_t blf0[2] = { kl4[0], kl4[2] }, blf1[2] = { kl4[1], kl4[3] };
                mma16816(s[ntp*2],   ah, bhf0);
                mma16816(s[ntp*2],   ah, blf0);
                mma16816(s[ntp*2],   al, bhf0);
                mma16816(s[ntp*2+1], ah, bhf1);
                mma16816(s[ntp*2+1], ah, blf1);
                mma16816(s[ntp*2+1], al, bhf1);
            }
        }

        // scale + mask + chunk row max
        bool ok[4][4];
        float m0 = -INFINITY, m1 = -INFINITY;
        #pragma unroll
        for (int nt = 0; nt < 4; nt++) {
            int jc0 = jbase + wn*32 + nt*8 + qc;
            int jc1 = jc0 + 1;
            bool in0 = (jc0 >= 0) & (jc0 < LK);
            bool in1 = (jc1 >= 0) & (jc1 < LK);
            ok[nt][0] = in0 && (!local || (jc0 >= ir0-64 && jc0 <= ir0+64));
            ok[nt][1] = in1 && (!local || (jc1 >= ir0-64 && jc1 <= ir0+64));
            ok[nt][2] = in0 && (!local || (jc0 >= ir1-64 && jc0 <= ir1+64));
            ok[nt][3] = in1 && (!local || (jc1 >= ir1-64 && jc1 <= ir1+64));
            #pragma unroll
            for (int rg = 0; rg < 4; rg++) s[nt][rg] *= 0.125f;
            if (ok[nt][0]) m0 = fmaxf(m0, s[nt][0]);
            if (ok[nt][1]) m0 = fmaxf(m0, s[nt][1]);
            if (ok[nt][2]) m1 = fmaxf(m1, s[nt][2]);
            if (ok[nt][3]) m1 = fmaxf(m1, s[nt][3]);
        }
        m0 = fmaxf(m0, __shfl_xor_sync(0xFFFFFFFFu, m0, 1));
        m0 = fmaxf(m0, __shfl_xor_sync(0xFFFFFFFFu, m0, 2));
        m1 = fmaxf(m1, __shfl_xor_sync(0xFFFFFFFFu, m1, 1));
        m1 = fmaxf(m1, __shfl_xor_sync(0xFFFFFFFFu, m1, 2));
        if ((lane & 3) == 0) { sM[lrow0*2 + wn] = m0; sM[lrow1*2 + wn] = m1; }
        __syncthreads();
        float cm0 = fmaxf(sM[lrow0*2], sM[lrow0*2 + 1]);
        float cm1 = fmaxf(sM[lrow1*2], sM[lrow1*2 + 1]);
        float mn0 = fmaxf(mr0, cm0), mn1 = fmaxf(mr1, cm1);
        float cf0 = (mn0 == -INFINITY) ? 1.f : __expf(mr0 - mn0);
        float cf1 = (mn1 == -INFINITY) ? 1.f : __expf(mr1 - mn1);
        mr0 = mn0; mr1 = mn1;

        // P = exp(s - m), partial sums
        float ps0 = 0.f, ps1 = 0.f;
        #pragma unroll
        for (int nt = 0; nt < 4; nt++) {
            s[nt][0] = ok[nt][0] ? __expf(s[nt][0] - mn0) : 0.f;
            s[nt][1] = ok[nt][1] ? __expf(s[nt][1] - mn0) : 0.f;
            s[nt][2] = ok[nt][2] ? __expf(s[nt][2] - mn1) : 0.f;
            s[nt][3] = ok[nt][3] ? __expf(s[nt][3] - mn1) : 0.f;
            ps0 += s[nt][0] + s[nt][1];
            ps1 += s[nt][2] + s[nt][3];
        }
        ps0 += __shfl_xor_sync(0xFFFFFFFFu, ps0, 1); ps0 += __shfl_xor_sync(0xFFFFFFFFu, ps0, 2);
        ps1 += __shfl_xor_sync(0xFFFFFFFFu, ps1, 1); ps1 += __shfl_xor_sync(0xFFFFFFFFu, ps1, 2);
        if ((lane & 3) == 0) { sS[lrow0*2 + wn] = ps0; sS[lrow1*2 + wn] = ps1; }
        __syncthreads();
        lr0 = lr0*cf0 + sS[lrow0*2] + sS[lrow0*2 + 1];
        lr1 = lr1*cf1 + sS[lrow1*2] + sS[lrow1*2 + 1];

        #pragma unroll
        for (int ntd = 0; ntd < 8; ntd++) {
            accO[ntd][0] *= cf0; accO[ntd][1] *= cf0;
            accO[ntd][2] *= cf1; accO[ntd][3] *= cf1;
        }

        // PV: A = P (warp's 32 j-cols, 2 k16 chunks), B = V via ldmatrix.trans
        #pragma unroll
        for (int kch = 0; kch < 2; kch++) {
            int nt0 = kch*2, nt1 = kch*2 + 1;
            uint32_t pah[4], pal[4];
            {
                float p00 = s[nt0][0], p01 = s[nt0][1], p02 = s[nt0][2], p03 = s[nt0][3];
                float p10 = s[nt1][0], p11 = s[nt1][1], p12 = s[nt1][2], p13 = s[nt1][3];
                pah[0] = packbf(p00, p01); pah[1] = packbf(p02, p03);
                pah[2] = packbf(p10, p11); pah[3] = packbf(p12, p13);
                float q00 = p00 - __bfloat162float(__float2bfloat16(p00));
                float q01 = p01 - __bfloat162float(__float2bfloat16(p01));
                float q02 = p02 - __bfloat162float(__float2bfloat16(p02));
                float q03 = p03 - __bfloat162float(__float2bfloat16(p03));
                float q10 = p10 - __bfloat162float(__float2bfloat16(p10));
                float q11 = p11 - __bfloat162float(__float2bfloat16(p11));
                float q12 = p12 - __bfloat162float(__float2bfloat16(p12));
                float q13 = p13 - __bfloat162float(__float2bfloat16(p13));
                pal[0] = packbf(q00, q01); pal[1] = packbf(q02, q03);
                pal[2] = packbf(q10, q11); pal[3] = packbf(q12, q13);
            }
            const int jo = wn*32 + kch*16;
            #pragma unroll
            for (int ntp = 0; ntp < 4; ntp++) {
                uint32_t offV = ((jo + lrow)*72 + ntp*16 + lkh)*2;
                uint32_t vh4[4], vl4[4];
                ldmx4t(vh4, aVh + offV);
                ldmx4t(vl4, aVl + offV);
                // vh4 = { b0(ntd), b1(ntd), b0(ntd+1), b1(ntd+1) }, ntd = ntp*2
                mma16816(accO[ntp*2],   pah, &vh4[0]);
                mma16816(accO[ntp*2],   pal, &vh4[0]);
                mma16816(accO[ntp*2],   pah, &vl4[0]);
                mma16816(accO[ntp*2+1], pah, &vh4[2]);
                mma16816(accO[ntp*2+1], pal, &vh4[2]);
                mma16816(accO[ntp*2+1], pah, &vl4[2]);
            }
        }
    }

    // epilogue: sum wn halves via smem (reuse sK region), then write
    __syncthreads();
    if (wn == 1) {
        #pragma unroll
        for (int ntd = 0; ntd < 8; ntd++) {
            sO[lrow0*66 + ntd*8 + qc]     = accO[ntd][0];
            sO[lrow0*66 + ntd*8 + qc + 1] = accO[ntd][1];
            sO[lrow1*66 + ntd*8 + qc]     = accO[ntd][2];
            sO[lrow1*66 + ntd*8 + qc + 1] = accO[ntd][3];
        }
    }
    __syncthreads();
    if (wn == 0) {
        float inv0 = 1.0f/lr0, inv1 = 1.0f/lr1;
        #pragma unroll
        for (int ntd = 0; ntd < 8; ntd++) {
            float v0 = (accO[ntd][0] + sO[lrow0*66 + ntd*8 + qc])     * inv0;
            float v1 = (accO[ntd][1] + sO[lrow0*66 + ntd*8 + qc + 1]) * inv0;
            float v2 = (accO[ntd][2] + sO[lrow1*66 + ntd*8 + qc])     * inv1;
            float v3 = (accO[ntd][3] + sO[lrow1*66 + ntd*8 + qc + 1]) * inv1;
            *(float2*)&Out[((size_t)(b*Ls) + ir0)*Dm + hoff + ntd*8 + qc] = make_float2(v0, v1);
            *(float2*)&Out[((size_t)(b*Ls) + ir1)*Dm + hoff + ntd*8 + qc] = make_float2(v2, v3);
        }
    }
}

// ---------------- combine + split comb ----------------
__global__ void combine_kernel(const float* __restrict__ pm)
{
    float a0 = pm[0], a1 = pm[1], a2 = pm[2];
    float mx = fmaxf(a0, fmaxf(a1, a2));
    float e0 = expf(a0-mx), e1 = expf(a1-mx), e2 = expf(a2-mx);
    float den = e0+e1+e2;
    float pw0 = e0/den, pw1 = e1/den;
    int e = blockIdx.x*blockDim.x + threadIdx.x;
    float v = pw0*g_outg[e] + pw1*g_outl[e];
    g_comb[e] = v;
    bsplit(v, g_combh[e], g_combl[e]);
}

// ---------------- selection path ----------------
__global__ void attns_kernel(const float* __restrict__ pm)
{
    __shared__ float sc[Ls];
    __shared__ float qs[64];
    __shared__ float red[256];
    int blk = blockIdx.x;
    int bh  = blk / NSEL, si = blk % NSEL;
    int b = bh >> 3, h = bh & 7;
    int qi = g_selidx[bh*NSEL + si];
    int t = threadIdx.x;

    if (t < 16) {
        float4 v = *(const float4*)&g_q[((size_t)(b*Ls) + qi)*Dm + h*HDim + t*4];
        *(float4*)&qs[t*4] = v;
    }
    __syncthreads();

    const float* kb = g_k + ((size_t)(b*Ls))*Dm + h*HDim;
    for (int jj = 0; jj < 8; jj++) {
        int j = t*8 + jj;
        const float4* kr = (const float4*)&kb[(size_t)j*Dm];
        float dot = 0.f;
        #pragma unroll
        for (int d4 = 0; d4 < 16; d4++) {
            float4 kv = kr[d4];
            dot = fmaf(qs[d4*4+0], kv.x, dot);
            dot = fmaf(qs[d4*4+1], kv.y, dot);
            dot = fmaf(qs[d4*4+2], kv.z, dot);
            dot = fmaf(qs[d4*4+3], kv.w, dot);
        }
        sc[j] = dot * 0.125f;
    }
    __syncthreads();

    float m = -INFINITY;
    for (int j = t; j < Ls; j += 256) m = fmaxf(m, sc[j]);
    red[t] = m; __syncthreads();
    for (int s2 = 128; s2; s2 >>= 1) { if (t < s2) red[t] = fmaxf(red[t], red[t+s2]); __syncthreads(); }
    m = red[0]; __syncthreads();

    float s = 0.f;
    for (int j = t; j < Ls; j += 256) { float e = __expf(sc[j]-m); sc[j] = e; s += e; }
    red[t] = s; __syncthreads();
    for (int s2 = 128; s2; s2 >>= 1) { if (t < s2) red[t] += red[t+s2]; __syncthreads(); }
    s = red[0]; __syncthreads();

    int d = t & 63, qtr = t >> 6;
    const float* vb = g_v + ((size_t)b*Ls)*Dm + h*HDim + d;
    float acc = 0.f;
    for (int j = qtr*512; j < qtr*512 + 512; j++)
        acc = fmaf(sc[j], vb[(size_t)j*Dm], acc);
    red[t] = acc; __syncthreads();

    if (t < 64) {
        float tot = red[t] + red[t+64] + red[t+128] + red[t+192];
        float a0 = pm[0], a1 = pm[1], a2 = pm[2];
        float mx = fmaxf(a0, fmaxf(a1, a2));
        float e0 = expf(a0-mx), e1 = expf(a1-mx), e2 = expf(a2-mx);
        float pw2 = e2/(e0+e1+e2);
        size_t idx = ((size_t)b*Ls + qi)*Dm + h*HDim + t;
        float nv = g_comb[idx] + pw2 * tot / s;
        g_comb[idx] = nv;
        bsplit(nv, g_combh[idx], g_combl[idx]);
    }
}

// ---------------- launch ----------------
extern "C" void kernel_launch(void* const* d_in, const int* in_sizes, int n_in,
                              void* d_out, int out_size)
{
    const float* query = (const float*)d_in[0];
    const float* keyi  = (const float*)d_in[1];
    const float* vali  = (const float*)d_in[2];
    const float* Wq = (const float*)d_in[3];  const float* bq = (const float*)d_in[4];
    const float* Wk = (const float*)d_in[5];  const float* bk = (const float*)d_in[6];
    const float* Wv = (const float*)d_in[7];  const float* bv = (const float*)d_in[8];
    const float* Wo = (const float*)d_in[9];  const float* bo = (const float*)d_in[10];
    const float* Wc1 = (const float*)d_in[11]; const float* bc1 = (const float*)d_in[12];
    const float* Wc2 = (const float*)d_in[13]; const float* bc2 = (const float*)d_in[14];
    const float* pm  = (const float*)d_in[15];

    float *outg, *outl;
    __nv_bfloat16 *kcpreh, *kcprel, *hidh, *hidl, *combh, *combl, *wth, *wtl;
    __nv_bfloat16 *qh, *ql, *kh, *kl, *vh, *vl, *kch, *kcl, *vch, *vcl;
    cudaGetSymbolAddress((void**)&outg,  g_outg);
    cudaGetSymbolAddress((void**)&outl,  g_outl);
    cudaGetSymbolAddress((void**)&kcpreh, g_kcpreh);
    cudaGetSymbolAddress((void**)&kcprel, g_kcprel);
    cudaGetSymbolAddress((void**)&hidh,  g_hidh);
    cudaGetSymbolAddress((void**)&hidl,  g_hidl);
    cudaGetSymbolAddress((void**)&combh, g_combh);
    cudaGetSymbolAddress((void**)&combl, g_combl);
    cudaGetSymbolAddress((void**)&wth,   g_wth);
    cudaGetSymbolAddress((void**)&wtl,   g_wtl);
    cudaGetSymbolAddress((void**)&qh,    g_qh);
    cudaGetSymbolAddress((void**)&ql,    g_ql);
    cudaGetSymbolAddress((void**)&kh,    g_kh);
    cudaGetSymbolAddress((void**)&kl,    g_kl);
    cudaGetSymbolAddress((void**)&vh,    g_vh);
    cudaGetSymbolAddress((void**)&vl,    g_vl);
    cudaGetSymbolAddress((void**)&kch,   g_kch);
    cudaGetSymbolAddress((void**)&kcl,   g_kcl);
    cudaGetSymbolAddress((void**)&vch,   g_vch);
    cudaGetSymbolAddress((void**)&vcl,   g_vcl);

    const int FLASH_SMEM = 6*64*72*2 + 2*128*4;
    const int SCORES_SMEM = 4*128*72*2;   // 73728
    cudaFuncSetAttribute(flash_mma_kernel, cudaFuncAttributeMaxDynamicSharedMemorySize, FLASH_SMEM);
    cudaFuncSetAttribute(scores_stats_mma_kernel, cudaFuncAttributeMaxDynamicSharedMemorySize, SCORES_SMEM);

    // prep
    split_in_kernel<<<dim3((Bb*Ls*Dm)/256, 3), 256>>>(query, keyi, vali);
    split_w6_kernel<<<dim3(16,16,6), dim3(32,8)>>>(Wq, Wk, Wv, Wo, Wc1, Wc2);

    // projections
    proj3_mma_kernel<<<dim3(4,32,3), 256>>>(bq, bk, bv);

    // compression + MLP
    compress_kernel<<<512, 256>>>();
    mma_gemm_kernel<<<dim3(4,8), 256>>>(kcpreh, kcprel, wth + 4*(size_t)Dm*Dm, wtl + 4*(size_t)Dm*Dm,
                                        bc1, nullptr, hidh, hidl, Dm, Dm, 1);
    mma_gemm_kernel<<<dim3(4,8), 256>>>(hidh, hidl, wth + 5*(size_t)Dm*Dm, wtl + 5*(size_t)Dm*Dm,
                                        bc2, nullptr, kch, kcl, Dm, Dm, 0);

    // dense QK^T + fused stats
    scores_stats_mma_kernel<<<dim3(NJT,16,16), 256, SCORES_SMEM>>>(0.125f);
    impfinal_kernel<<<4096, 256>>>();
    topk_kernel<<<Bb*Hh, 256>>>();

    // attention paths (fused local+global)
    flash_mma_kernel<<<dim3(32,16,2), 256, FLASH_SMEM>>>(
        qh, ql, kh, kl, vh, vl, kch, kcl, vch, vcl, outl, outg);

    // mix + selection
    combine_kernel<<<(Bb*Ls*Dm)/256, 256>>>(pm);
    attns_kernel<<<Bb*Hh*NSEL, 256>>>(pm);

    // output projection
    mma_gemm_kernel<<<dim3(4,32), 256>>>(combh, combl, wth + 3*(size_t)Dm*Dm, wtl + 3*(size_t)Dm*Dm,
                                         bo, (float*)d_out, nullptr, nullptr, Dm, Dm, 0);
}

// round 9
// speedup vs baseline: 2.1587x; 1.0354x over previous
#include <cuda_runtime.h>
#include <cuda_bf16.h>
#include <math.h>
#include <stdint.h>

#define Bb   2
#define Ls   2048
#define Dm   512
#define Hh   8
#define HDim 64
#define LcC  512
#define NSEL 8
#define NJT  16

// ---------------- fp32 scratch ----------------
static __device__ float g_q[Bb*Ls*Dm];
static __device__ float g_k[Bb*Ls*Dm];
static __device__ float g_v[Bb*Ls*Dm];
static __device__ float g_outg[Bb*Ls*Dm];
static __device__ float g_outl[Bb*Ls*Dm];
static __device__ float g_comb[Bb*Ls*Dm];
static __device__ float g_imp[Bb*Hh*Ls];
static __device__ int   g_selidx[Bb*Hh*NSEL];
static __device__ float g_pmax[Bb*Hh*Ls*NJT];
static __device__ float g_pse [Bb*Hh*Ls*NJT];
static __device__ float g_psum[Bb*Hh*Ls*NJT];

// ---------------- bf16 split scratch ----------------
static __device__ __nv_bfloat16 g_inh[3][Bb*Ls*Dm];
static __device__ __nv_bfloat16 g_inl[3][Bb*Ls*Dm];
static __device__ __nv_bfloat16 g_wth[6][Dm*Dm];   // transposed [N][K]
static __device__ __nv_bfloat16 g_wtl[6][Dm*Dm];
static __device__ __nv_bfloat16 g_qh[Bb*Ls*Dm], g_ql[Bb*Ls*Dm];
static __device__ __nv_bfloat16 g_kh[Bb*Ls*Dm], g_kl[Bb*Ls*Dm];
static __device__ __nv_bfloat16 g_vh[Bb*Ls*Dm], g_vl[Bb*Ls*Dm];
static __device__ __nv_bfloat16 g_kch[Bb*LcC*Dm], g_kcl[Bb*LcC*Dm];
static __device__ __nv_bfloat16 g_vch[Bb*LcC*Dm], g_vcl[Bb*LcC*Dm];
static __device__ __nv_bfloat16 g_kcpreh[Bb*LcC*Dm], g_kcprel[Bb*LcC*Dm];
static __device__ __nv_bfloat16 g_hidh[Bb*LcC*Dm], g_hidl[Bb*LcC*Dm];
static __device__ __nv_bfloat16 g_combh[Bb*Ls*Dm], g_combl[Bb*Ls*Dm];

__device__ __forceinline__ void bsplit(float x, __nv_bfloat16& h, __nv_bfloat16& l)
{
    h = __float2bfloat16(x);
    l = __float2bfloat16(x - __bfloat162float(h));
}

__device__ __forceinline__ uint32_t packbf(float x, float y)
{
    __nv_bfloat162 t = __floats2bfloat162_rn(x, y);
    return *(uint32_t*)&t;
}

__device__ __forceinline__ void mma16816(float* c, const uint32_t* a, const uint32_t* b)
{
    asm volatile(
        "mma.sync.aligned.m16n8k16.row.col.f32.bf16.bf16.f32 "
        "{%0,%1,%2,%3}, {%4,%5,%6,%7}, {%8,%9}, {%0,%1,%2,%3};"
        : "+f"(c[0]), "+f"(c[1]), "+f"(c[2]), "+f"(c[3])
        : "r"(a[0]), "r"(a[1]), "r"(a[2]), "r"(a[3]), "r"(b[0]), "r"(b[1]));
}

__device__ __forceinline__ uint32_t smem_u32(const void* p)
{
    uint32_t a;
    asm("{ .reg .u64 t; cvta.to.shared.u64 t, %1; cvt.u32.u64 %0, t; }" : "=r"(a) : "l"(p));
    return a;
}

__device__ __forceinline__ void ldmx4(uint32_t* r, uint32_t a)
{
    asm volatile("ldmatrix.sync.aligned.m8n8.x4.shared.b16 {%0,%1,%2,%3}, [%4];"
        : "=r"(r[0]), "=r"(r[1]), "=r"(r[2]), "=r"(r[3]) : "r"(a));
}
__device__ __forceinline__ void ldmx4t(uint32_t* r, uint32_t a)
{
    asm volatile("ldmatrix.sync.aligned.m8n8.x4.trans.shared.b16 {%0,%1,%2,%3}, [%4];"
        : "=r"(r[0]), "=r"(r[1]), "=r"(r[2]), "=r"(r[3]) : "r"(a));
}

// ---------------- prep: split inputs ----------------
__global__ void split_in_kernel(const float* x0, const float* x1, const float* x2)
{
    int z = blockIdx.y;
    const float* x = z == 0 ? x0 : (z == 1 ? x1 : x2);
    int i = blockIdx.x*blockDim.x + threadIdx.x;
    bsplit(x[i], g_inh[z][i], g_inl[z][i]);
}

// ---------------- prep: split + transpose all 6 weights ----------------
__global__ void split_w6_kernel(const float* w0, const float* w1, const float* w2,
                                const float* w3, const float* w4, const float* w5)
{
    __shared__ float tl[32][33];
    int widx = blockIdx.z;
    const float* w = widx==0?w0 : widx==1?w1 : widx==2?w2 : widx==3?w3 : widx==4?w4 : w5;
    int tx = threadIdx.x, ty = threadIdx.y;
    int n0 = blockIdx.x*32, k0 = blockIdx.y*32;
    #pragma unroll
    for (int i = 0; i < 4; i++)
        tl[ty + i*8][tx] = w[(size_t)(k0 + ty + i*8)*Dm + n0 + tx];
    __syncthreads();
    #pragma unroll
    for (int i = 0; i < 4; i++) {
        float v = tl[tx][ty + i*8];
        size_t o = (size_t)(n0 + ty + i*8)*Dm + k0 + tx;
        bsplit(v, g_wth[widx][o], g_wtl[widx][o]);
    }
}

// =========================================================================
// bf16x3 tensor-core GEMM: C[M][N] = A[M][K] @ Bw^T + bias, ldmatrix frags
// =========================================================================
__device__ __forceinline__ void mma_gemm_body(
    const __nv_bfloat16* __restrict__ Ah, const __nv_bfloat16* __restrict__ Al,
    const __nv_bfloat16* __restrict__ Bh, const __nv_bfloat16* __restrict__ Bl,
    const float* __restrict__ bias, float* __restrict__ C,
    __nv_bfloat16* __restrict__ Ch, __nv_bfloat16* __restrict__ Cl,
    int N, int K, int gelu)
{
    __shared__ __nv_bfloat16 sAh[2][128*24], sAl[2][128*24];
    __shared__ __nv_bfloat16 sBh[2][128*24], sBl[2][128*24];
    const int tid = threadIdx.x;
    const int lane = tid & 31, warp = tid >> 5;
    const int wm = warp >> 2, wn = warp & 3;
    const int qr = lane >> 2, qc = (lane & 3)*2;
    const int lrow = lane & 15, lkh = (lane >> 4)*8;
    const int row0 = blockIdx.y*128, col0 = blockIdx.x*128;
    const int half = tid >> 7, r = tid & 127;

    const __nv_bfloat16* As = half ? Al : Ah;
    const __nv_bfloat16* Bs = half ? Bl : Bh;

    {
        const uint4* pa = (const uint4*)(As + (size_t)(row0 + r)*K);
        const uint4* pb = (const uint4*)(Bs + (size_t)(col0 + r)*K);
        uint4 a0 = pa[0], a1 = pa[1], b0 = pb[0], b1 = pb[1];
        __nv_bfloat16* dA = half ? sAl[0] : sAh[0];
        __nv_bfloat16* dB = half ? sBl[0] : sBh[0];
        *(uint4*)&dA[r*24]     = a0; *(uint4*)&dA[r*24 + 8] = a1;
        *(uint4*)&dB[r*24]     = b0; *(uint4*)&dB[r*24 + 8] = b1;
    }
    __syncthreads();

    float acc[4][4][4] = {};
    const int nk = K >> 4;
    for (int kc = 0; kc < nk; kc++) {
        const int buf = kc & 1;
        uint4 na0, na1, nb0, nb1;
        if (kc + 1 < nk) {
            int k0 = (kc + 1)*16;
            const uint4* pa = (const uint4*)(As + (size_t)(row0 + r)*K + k0);
            const uint4* pb = (const uint4*)(Bs + (size_t)(col0 + r)*K + k0);
            na0 = pa[0]; na1 = pa[1]; nb0 = pb[0]; nb1 = pb[1];
        }

        const uint32_t cAh = smem_u32(&sAh[buf][0]);
        const uint32_t cAl = smem_u32(&sAl[buf][0]);
        const uint32_t cBh = smem_u32(&sBh[buf][0]);
        const uint32_t cBl = smem_u32(&sBl[buf][0]);

        uint32_t bh[4][2], bl[4][2];
        #pragma unroll
        for (int ntp = 0; ntp < 2; ntp++) {
            uint32_t off = (uint32_t)(((wn*32 + ntp*16 + lrow)*24 + lkh)*2);
            uint32_t t4[4], u4[4];
            ldmx4(t4, cBh + off);
            ldmx4(u4, cBl + off);
            bh[ntp*2][0]   = t4[0]; bh[ntp*2][1]   = t4[2];
            bh[ntp*2+1][0] = t4[1]; bh[ntp*2+1][1] = t4[3];
            bl[ntp*2][0]   = u4[0]; bl[ntp*2][1]   = u4[2];
            bl[ntp*2+1][0] = u4[1]; bl[ntp*2+1][1] = u4[3];
        }
        #pragma unroll
        for (int mt = 0; mt < 4; mt++) {
            uint32_t offA = (uint32_t)(((wm*64 + mt*16 + lrow)*24 + lkh)*2);
            uint32_t ah[4], al[4];
            ldmx4(ah, cAh + offA);
            ldmx4(al, cAl + offA);
            #pragma unroll
            for (int nt = 0; nt < 4; nt++) {
                mma16816(acc[mt][nt], ah, bh[nt]);
                mma16816(acc[mt][nt], ah, bl[nt]);
                mma16816(acc[mt][nt], al, bh[nt]);
            }
        }

        if (kc + 1 < nk) {
            const int nb = buf ^ 1;
            __nv_bfloat16* dA = half ? sAl[nb] : sAh[nb];
            __nv_bfloat16* dB = half ? sBl[nb] : sBh[nb];
            *(uint4*)&dA[r*24]     = na0; *(uint4*)&dA[r*24 + 8] = na1;
            *(uint4*)&dB[r*24]     = nb0; *(uint4*)&dB[r*24 + 8] = nb1;
        }
        __syncthreads();
    }

    #pragma unroll
    for (int mt = 0; mt < 4; mt++) {
        int gr = row0 + wm*64 + mt*16 + qr;
        #pragma unroll
        for (int nt = 0; nt < 4; nt++) {
            int gc = col0 + wn*32 + nt*8 + qc;
            float v0 = acc[mt][nt][0] + bias[gc];
            float v1 = acc[mt][nt][1] + bias[gc+1];
            float v2 = acc[mt][nt][2] + bias[gc];
            float v3 = acc[mt][nt][3] + bias[gc+1];
            if (gelu) {
                v0 = 0.5f*v0*(1.0f + erff(v0*0.70710678118654752f));
                v1 = 0.5f*v1*(1.0f + erff(v1*0.70710678118654752f));
                v2 = 0.5f*v2*(1.0f + erff(v2*0.70710678118654752f));
                v3 = 0.5f*v3*(1.0f + erff(v3*0.70710678118654752f));
            }
            if (C) {
                float2 p0 = make_float2(v0, v1), p1 = make_float2(v2, v3);
                *(float2*)&C[(size_t)gr*N + gc]     = p0;
                *(float2*)&C[(size_t)(gr+8)*N + gc] = p1;
            }
            if (Ch) {
                __nv_bfloat16 h0,l0,h1,l1,h2,l2,h3,l3;
                bsplit(v0,h0,l0); bsplit(v1,h1,l1); bsplit(v2,h2,l2); bsplit(v3,h3,l3);
                Ch[(size_t)gr*N + gc]   = h0; Ch[(size_t)gr*N + gc+1]   = h1;
                Cl[(size_t)gr*N + gc]   = l0; Cl[(size_t)gr*N + gc+1]   = l1;
                Ch[(size_t)(gr+8)*N+gc] = h2; Ch[(size_t)(gr+8)*N+gc+1] = h3;
                Cl[(size_t)(gr+8)*N+gc] = l2; Cl[(size_t)(gr+8)*N+gc+1] = l3;
            }
        }
    }
}

__global__ void __launch_bounds__(256, 2) mma_gemm_kernel(
    const __nv_bfloat16* Ah, const __nv_bfloat16* Al,
    const __nv_bfloat16* Bh, const __nv_bfloat16* Bl,
    const float* bias, float* C, __nv_bfloat16* Ch, __nv_bfloat16* Cl,
    int N, int K, int gelu)
{
    mma_gemm_body(Ah, Al, Bh, Bl, bias, C, Ch, Cl, N, K, gelu);
}

__global__ void __launch_bounds__(256, 2) proj3_mma_kernel(
    const float* bq, const float* bk, const float* bv)
{
    int z = blockIdx.z;
    if (z == 0)
        mma_gemm_body(g_inh[0], g_inl[0], g_wth[0], g_wtl[0], bq, g_q, g_qh, g_ql, Dm, Dm, 0);
    else if (z == 1)
        mma_gemm_body(g_inh[1], g_inl[1], g_wth[1], g_wtl[1], bk, g_k, g_kh, g_kl, Dm, Dm, 0);
    else
        mma_gemm_body(g_inh[2], g_inl[2], g_wth[2], g_wtl[2], bv, g_v, g_vh, g_vl, Dm, Dm, 0);
}

// =========================================================================
// dense QK^T (bf16x3 mma) + fused row stats, ldmatrix fragments (unchanged)
// =========================================================================
extern __shared__ __nv_bfloat16 scsm[];
__global__ void __launch_bounds__(256, 2) scores_stats_mma_kernel(float scale)
{
    __nv_bfloat16* sAh = scsm;
    __nv_bfloat16* sAl = scsm + 128*72;
    __nv_bfloat16* sBh = scsm + 2*128*72;
    __nv_bfloat16* sBl = scsm + 3*128*72;
    __shared__ float s4a[128][4], s4b[128][4], srm[128];

    const int tid = threadIdx.x;
    const int lane = tid & 31, warp = tid >> 5;
    const int wm = warp >> 2, wn = warp & 3;
    const int qr = lane >> 2;
    const int bh = blockIdx.z;
    const int b = bh >> 3, h = bh & 7;
    const int i0 = blockIdx.y*128, j0 = blockIdx.x*128;

    const __nv_bfloat16* Qhp = g_qh + ((size_t)(b*Ls) + i0)*Dm + h*HDim;
    const __nv_bfloat16* Qlp = g_ql + ((size_t)(b*Ls) + i0)*Dm + h*HDim;
    const __nv_bfloat16* Khp = g_kh + ((size_t)(b*Ls) + j0)*Dm + h*HDim;
    const __nv_bfloat16* Klp = g_kl + ((size_t)(b*Ls) + j0)*Dm + h*HDim;

    #pragma unroll
    for (int i = 0; i < 4; i++) {
        int slot = tid*4 + i;
        int row = slot >> 3, c = slot & 7;
        *(uint4*)&sAh[row*72 + c*8] = *(const uint4*)&Qhp[(size_t)row*Dm + c*8];
        *(uint4*)&sAl[row*72 + c*8] = *(const uint4*)&Qlp[(size_t)row*Dm + c*8];
        *(uint4*)&sBh[row*72 + c*8] = *(const uint4*)&Khp[(size_t)row*Dm + c*8];
        *(uint4*)&sBl[row*72 + c*8] = *(const uint4*)&Klp[(size_t)row*Dm + c*8];
    }
    __syncthreads();

    const uint32_t sc0 = smem_u32(scsm);
    const uint32_t aAh = sc0, aAl = sc0 + 128*72*2, aBh = sc0 + 2*128*72*2, aBl = sc0 + 3*128*72*2;
    const int lrow = lane & 15, lkh = (lane >> 4)*8;

    float acc[4][4][4] = {};
    #pragma unroll
    for (int kc = 0; kc < 4; kc++) {
        const int ko = kc*16;
        uint32_t Bh4[2][4], Bl4[2][4];
        #pragma unroll
        for (int ntp = 0; ntp < 2; ntp++) {
            uint32_t off = ((wn*32 + ntp*16 + lrow)*72 + ko + lkh)*2;
            ldmx4(Bh4[ntp], aBh + off);
            ldmx4(Bl4[ntp], aBl + off);
        }
        #pragma unroll
        for (int mt = 0; mt < 4; mt++) {
            uint32_t offA = ((wm*64 + mt*16 + lrow)*72 + ko + lkh)*2;
            uint32_t ah[4], al[4];
            ldmx4(ah, aAh + offA);
            ldmx4(al, aAl + offA);
            #pragma unroll
            for (int nt = 0; nt < 4; nt++) {
                uint32_t bhf[2] = { Bh4[nt>>1][nt&1], Bh4[nt>>1][(nt&1)+2] };
                uint32_t blf[2] = { Bl4[nt>>1][nt&1], Bl4[nt>>1][(nt&1)+2] };
                mma16816(acc[mt][nt], ah, bhf);
                mma16816(acc[mt][nt], ah, blf);
                mma16816(acc[mt][nt], al, bhf);
            }
        }
    }

    #pragma unroll
    for (int mt = 0; mt < 4; mt++) {
        float m0 = -INFINITY, m1 = -INFINITY;
        #pragma unroll
        for (int nt = 0; nt < 4; nt++) {
            m0 = fmaxf(m0, fmaxf(acc[mt][nt][0], acc[mt][nt][1]));
            m1 = fmaxf(m1, fmaxf(acc[mt][nt][2], acc[mt][nt][3]));
        }
        m0 = fmaxf(m0, __shfl_xor_sync(0xFFFFFFFFu, m0, 1));
        m0 = fmaxf(m0, __shfl_xor_sync(0xFFFFFFFFu, m0, 2));
        m1 = fmaxf(m1, __shfl_xor_sync(0xFFFFFFFFu, m1, 1));
        m1 = fmaxf(m1, __shfl_xor_sync(0xFFFFFFFFu, m1, 2));
        if ((lane & 3) == 0) {
            s4a[wm*64 + mt*16 + qr][wn]     = m0;
            s4a[wm*64 + mt*16 + 8 + qr][wn] = m1;
        }
    }
    __syncthreads();
    if (tid < 128)
        srm[tid] = fmaxf(fmaxf(s4a[tid][0], s4a[tid][1]), fmaxf(s4a[tid][2], s4a[tid][3]));
    __syncthreads();

    #pragma unroll
    for (int mt = 0; mt < 4; mt++) {
        int lr0 = wm*64 + mt*16 + qr, lr1 = lr0 + 8;
        float rm0 = srm[lr0]*scale, rm1 = srm[lr1]*scale;
        float se0 = 0.f, se1 = 0.f, ss0 = 0.f, ss1 = 0.f;
        #pragma unroll
        for (int nt = 0; nt < 4; nt++) {
            float x0 = acc[mt][nt][0]*scale, x1 = acc[mt][nt][1]*scale;
            float x2 = acc[mt][nt][2]*scale, x3 = acc[mt][nt][3]*scale;
            se0 += __expf(x0 - rm0) + __expf(x1 - rm0);
            se1 += __expf(x2 - rm1) + __expf(x3 - rm1);
            ss0 += x0 + x1; ss1 += x2 + x3;
        }
        se0 += __shfl_xor_sync(0xFFFFFFFFu, se0, 1); se0 += __shfl_xor_sync(0xFFFFFFFFu, se0, 2);
        se1 += __shfl_xor_sync(0xFFFFFFFFu, se1, 1); se1 += __shfl_xor_sync(0xFFFFFFFFu, se1, 2);
        ss0 += __shfl_xor_sync(0xFFFFFFFFu, ss0, 1); ss0 += __shfl_xor_sync(0xFFFFFFFFu, ss0, 2);
        ss1 += __shfl_xor_sync(0xFFFFFFFFu, ss1, 1); ss1 += __shfl_xor_sync(0xFFFFFFFFu, ss1, 2);
        if ((lane & 3) == 0) {
            s4b[lr0][wn] = se0; s4b[lr1][wn] = se1;
            s4a[lr0][wn] = ss0; s4a[lr1][wn] = ss1;
        }
    }
    __syncthreads();
    if (tid < 128) {
        int rowg = bh*Ls + i0 + tid;
        int jt = blockIdx.x;
        g_pmax[(size_t)rowg*NJT + jt] = srm[tid]*scale;
        g_pse [(size_t)rowg*NJT + jt] = s4b[tid][0]+s4b[tid][1]+s4b[tid][2]+s4b[tid][3];
        g_psum[(size_t)rowg*NJT + jt] = s4a[tid][0]+s4a[tid][1]+s4a[tid][2]+s4a[tid][3];
    }
}

// ---------------- compress: mean of 4 rows -> splits ----------------
__global__ void compress_kernel()
{
    int e4 = blockIdx.x*blockDim.x + threadIdx.x;
    int b = e4 / (LcC*Dm/4);
    int r = e4 % (LcC*Dm/4);
    int m = r / (Dm/4), d4 = r % (Dm/4);
    const float4* k4 = (const float4*)g_k;
    const float4* v4 = (const float4*)g_v;
    size_t base = ((size_t)(b*Ls + m*4)*Dm)/4 + d4;
    float4 a = k4[base], bb = k4[base+128], c = k4[base+256], d = k4[base+384];
    float ox = 0.25f*(a.x+bb.x+c.x+d.x), oy = 0.25f*(a.y+bb.y+c.y+d.y);
    float oz = 0.25f*(a.z+bb.z+c.z+d.z), ow = 0.25f*(a.w+bb.w+c.w+d.w);
    bsplit(ox, g_kcpreh[e4*4+0], g_kcprel[e4*4+0]);
    bsplit(oy, g_kcpreh[e4*4+1], g_kcprel[e4*4+1]);
    bsplit(oz, g_kcpreh[e4*4+2], g_kcprel[e4*4+2]);
    bsplit(ow, g_kcpreh[e4*4+3], g_kcprel[e4*4+3]);
    a = v4[base]; bb = v4[base+128]; c = v4[base+256]; d = v4[base+384];
    ox = 0.25f*(a.x+bb.x+c.x+d.x); oy = 0.25f*(a.y+bb.y+c.y+d.y);
    oz = 0.25f*(a.z+bb.z+c.z+d.z); ow = 0.25f*(a.w+bb.w+c.w+d.w);
    bsplit(ox, g_vch[e4*4+0], g_vcl[e4*4+0]);
    bsplit(oy, g_vch[e4*4+1], g_vcl[e4*4+1]);
    bsplit(oz, g_vch[e4*4+2], g_vcl[e4*4+2]);
    bsplit(ow, g_vch[e4*4+3], g_vcl[e4*4+3]);
}

// ---------------- importance merge ----------------
__global__ void impfinal_kernel()
{
    int warp = (blockIdx.x*blockDim.x + threadIdx.x) >> 5;
    int lane = threadIdx.x & 31;
    float pm = -INFINITY, pe = 0.f, ps = 0.f;
    if (lane < NJT) {
        pm = g_pmax[(size_t)warp*NJT + lane];
        pe = g_pse [(size_t)warp*NJT + lane];
        ps = g_psum[(size_t)warp*NJT + lane];
    }
    float m = pm;
    #pragma unroll
    for (int o = 8; o; o >>= 1) m = fmaxf(m, __shfl_xor_sync(0xFFFFFFFFu, m, o));
    float se = (lane < NJT) ? pe * __expf(pm - m) : 0.f;
    #pragma unroll
    for (int o = 8; o; o >>= 1) {
        se += __shfl_xor_sync(0xFFFFFFFFu, se, o);
        ps += __shfl_xor_sync(0xFFFFFFFFu, ps, o);
    }
    if (lane == 0)
        g_imp[warp] = m + logf(se) - 7.6246189861593985f - ps * (1.0f/2048.0f);
}

// ---------------- top-8 ----------------
__global__ void topk_kernel()
{
    int bh = blockIdx.x;
    const float* imp = g_imp + bh*Ls;
    __shared__ float bv[256];
    __shared__ int   bi[256];
    __shared__ int   chosen[NSEL];
    int t = threadIdx.x;
    for (int itu = 0; itu < NSEL; itu++) {
        float best = -INFINITY; int bidx = 0x7FFFFFFF;
        for (int j = t; j < Ls; j += 256) {
            bool skip = false;
            for (int c = 0; c < itu; c++) if (chosen[c] == j) skip = true;
            if (skip) continue;
            float vv = imp[j];
            if (vv > best || (vv == best && j < bidx)) { best = vv; bidx = j; }
        }
        bv[t] = best; bi[t] = bidx;
        __syncthreads();
        for (int s2 = 128; s2; s2 >>= 1) {
            if (t < s2) {
                if (bv[t+s2] > bv[t] || (bv[t+s2] == bv[t] && bi[t+s2] < bi[t])) {
                    bv[t] = bv[t+s2]; bi[t] = bi[t+s2];
                }
            }
            __syncthreads();
        }
        if (t == 0) { chosen[itu] = bi[0]; g_selidx[bh*NSEL + itu] = bi[0]; }
        __syncthreads();
    }
}

// =========================================================================
// fused flash attention, 128-row Q tiles, 8 warps all in M.
// z=0 local band, z=1 global/compressed. grid (16, 16, 2), 256 threads.
// smem: Qh[128][72] Ql | Kh[64][72] Kl | Vh[64][72] Vl  = 73728 B
// =========================================================================
extern __shared__ char fsm2[];
__global__ void __launch_bounds__(256, 2) flash_mma_kernel(
    const __nv_bfloat16* __restrict__ Qh, const __nv_bfloat16* __restrict__ Ql,
    const __nv_bfloat16* __restrict__ Khg, const __nv_bfloat16* __restrict__ Klg,
    const __nv_bfloat16* __restrict__ Vhg, const __nv_bfloat16* __restrict__ Vlg,
    const __nv_bfloat16* __restrict__ Khc, const __nv_bfloat16* __restrict__ Klc,
    const __nv_bfloat16* __restrict__ Vhc, const __nv_bfloat16* __restrict__ Vlc,
    float* __restrict__ OutL, float* __restrict__ OutG)
{
    __nv_bfloat16* sQh = (__nv_bfloat16*)fsm2;   // [128][72]
    __nv_bfloat16* sQl = sQh + 128*72;
    __nv_bfloat16* sKh = sQl + 128*72;           // [64][72]
    __nv_bfloat16* sKl = sKh + 64*72;
    __nv_bfloat16* sVh = sKl + 64*72;            // natural [j][d]
    __nv_bfloat16* sVl = sVh + 64*72;

    const int z = blockIdx.z;
    const __nv_bfloat16* Kh = z ? Khc : Khg;
    const __nv_bfloat16* Kl = z ? Klc : Klg;
    const __nv_bfloat16* Vh = z ? Vhc : Vhg;
    const __nv_bfloat16* Vl = z ? Vlc : Vlg;
    float* Out = z ? OutG : OutL;
    const int LK = z ? LcC : Ls;
    const int nchunks = z ? 8 : 4;
    const int local = z ? 0 : 1;

    const int tid = threadIdx.x;
    const int lane = tid & 31, w = tid >> 5;
    const int qr = lane >> 2, qc = (lane & 3)*2;
    const int lrow = lane & 15, lkh = (lane >> 4)*8;
    const int bh = blockIdx.y;
    const int b = bh >> 3, h = bh & 7;
    const int i0 = blockIdx.x*128;
    const size_t hoff = (size_t)h*HDim;

    const uint32_t sb = smem_u32(fsm2);
    const uint32_t aQh = sb, aQl = sb + 18432;
    const uint32_t aKh = sb + 36864, aKl = sb + 46080;
    const uint32_t aVh = sb + 55296, aVl = sb + 64512;

    // load Q tile (row-major [i][d]): 128 rows, 2 threads/row
    {
        int row = tid >> 1, part = (tid & 1)*32;
        const uint4* ph = (const uint4*)(Qh + ((size_t)(b*Ls) + i0 + row)*Dm + hoff + part);
        const uint4* pl = (const uint4*)(Ql + ((size_t)(b*Ls) + i0 + row)*Dm + hoff + part);
        #pragma unroll
        for (int j = 0; j < 4; j++) {
            *(uint4*)&sQh[row*72 + part + j*8] = ph[j];
            *(uint4*)&sQl[row*72 + part + j*8] = pl[j];
        }
    }

    float accO[8][4] = {};
    float mr0 = -INFINITY, mr1 = -INFINITY;
    float lr0 = 0.f, lr1 = 0.f;
    const int ir0 = i0 + w*16 + qr, ir1 = ir0 + 8;

    for (int c = 0; c < nchunks; c++) {
        int jbase = (local ? i0 - 64 : 0) + c*64;
        __syncthreads();
        // load K and V chunks [j][d], vectorized
        {
            int row = tid >> 2, c16 = (tid & 3)*16;
            int jg = jbase + row;
            uint4 kh0 = {0,0,0,0}, kh1 = {0,0,0,0}, kl0 = {0,0,0,0}, kl1 = {0,0,0,0};
            uint4 vh0 = {0,0,0,0}, vh1 = {0,0,0,0}, vl0 = {0,0,0,0}, vl1 = {0,0,0,0};
            if (jg >= 0 && jg < LK) {
                const uint4* ph = (const uint4*)(Kh + ((size_t)(b*LK) + jg)*Dm + hoff + c16);
                const uint4* pl = (const uint4*)(Kl + ((size_t)(b*LK) + jg)*Dm + hoff + c16);
                kh0 = ph[0]; kh1 = ph[1]; kl0 = pl[0]; kl1 = pl[1];
                ph = (const uint4*)(Vh + ((size_t)(b*LK) + jg)*Dm + hoff + c16);
                pl = (const uint4*)(Vl + ((size_t)(b*LK) + jg)*Dm + hoff + c16);
                vh0 = ph[0]; vh1 = ph[1]; vl0 = pl[0]; vl1 = pl[1];
            }
            *(uint4*)&sKh[row*72 + c16] = kh0; *(uint4*)&sKh[row*72 + c16 + 8] = kh1;
            *(uint4*)&sKl[row*72 + c16] = kl0; *(uint4*)&sKl[row*72 + c16 + 8] = kl1;
            *(uint4*)&sVh[row*72 + c16] = vh0; *(uint4*)&sVh[row*72 + c16 + 8] = vh1;
            *(uint4*)&sVl[row*72 + c16] = vl0; *(uint4*)&sVl[row*72 + c16 + 8] = vl1;
        }
        __syncthreads();

        // QK^T: warp owns its 16 rows x all 64 cols  (8 n-tiles)
        float s[8][4] = {};
        #pragma unroll
        for (int kc = 0; kc < 4; kc++) {
            int ko = kc*16;
            uint32_t offA = ((w*16 + lrow)*72 + ko + lkh)*2;
            uint32_t ah[4], al[4];
            ldmx4(ah, aQh + offA);
            ldmx4(al, aQl + offA);
            #pragma unroll
            for (int ntp = 0; ntp < 4; ntp++) {
                uint32_t offB = ((ntp*16 + lrow)*72 + ko + lkh)*2;
                uint32_t kh4[4], kl4[4];
                ldmx4(kh4, aKh + offB);
                ldmx4(kl4, aKl + offB);
                uint32_t bhf0[2] = { kh4[0], kh4[2] }, bhf1[2] = { kh4[1], kh4[3] };
                uint32_t blf0[2] = { kl4[0], kl4[2] }, blf1[2] = { kl4[1], kl4[3] };
                mma16816(s[ntp*2],   ah, bhf0);
                mma16816(s[ntp*2],   ah, blf0);
                mma16816(s[ntp*2],   al, bhf0);
                mma16816(s[ntp*2+1], ah, bhf1);
                mma16816(s[ntp*2+1], ah, blf1);
                mma16816(s[ntp*2+1], al, bhf1);
            }
        }

        // scale + mask + row max (whole row inside quad — no smem)
        float m0 = -INFINITY, m1 = -INFINITY;
        #pragma unroll
        for (int nt = 0; nt < 8; nt++) {
            int jc0 = jbase + nt*8 + qc;
            int jc1 = jc0 + 1;
            #pragma unroll
            for (int rg = 0; rg < 4; rg++) s[nt][rg] *= 0.125f;
            bool ok00 = true, ok01 = true, ok10 = true, ok11 = true;
            if (local) {
                ok00 = (jc0 >= 0) & (jc0 < LK) & (jc0 >= ir0-64) & (jc0 <= ir0+64);
                ok01 = (jc1 >= 0) & (jc1 < LK) & (jc1 >= ir0-64) & (jc1 <= ir0+64);
                ok10 = (jc0 >= 0) & (jc0 < LK) & (jc0 >= ir1-64) & (jc0 <= ir1+64);
                ok11 = (jc1 >= 0) & (jc1 < LK) & (jc1 >= ir1-64) & (jc1 <= ir1+64);
            }
            if (ok00) m0 = fmaxf(m0, s[nt][0]);
            if (ok01) m0 = fmaxf(m0, s[nt][1]);
            if (ok10) m1 = fmaxf(m1, s[nt][2]);
            if (ok11) m1 = fmaxf(m1, s[nt][3]);
        }
        m0 = fmaxf(m0, __shfl_xor_sync(0xFFFFFFFFu, m0, 1));
        m0 = fmaxf(m0, __shfl_xor_sync(0xFFFFFFFFu, m0, 2));
        m1 = fmaxf(m1, __shfl_xor_sync(0xFFFFFFFFu, m1, 1));
        m1 = fmaxf(m1, __shfl_xor_sync(0xFFFFFFFFu, m1, 2));
        float mn0 = fmaxf(mr0, m0), mn1 = fmaxf(mr1, m1);
        float cf0 = (mn0 == -INFINITY) ? 1.f : __expf(mr0 - mn0);
        float cf1 = (mn1 == -INFINITY) ? 1.f : __expf(mr1 - mn1);
        mr0 = mn0; mr1 = mn1;

        // P = exp(s - m), row sums (quad shuffles only)
        float ps0 = 0.f, ps1 = 0.f;
        #pragma unroll
        for (int nt = 0; nt < 8; nt++) {
            int jc0 = jbase + nt*8 + qc;
            int jc1 = jc0 + 1;
            bool ok00 = true, ok01 = true, ok10 = true, ok11 = true;
            if (local) {
                ok00 = (jc0 >= 0) & (jc0 < LK) & (jc0 >= ir0-64) & (jc0 <= ir0+64);
                ok01 = (jc1 >= 0) & (jc1 < LK) & (jc1 >= ir0-64) & (jc1 <= ir0+64);
                ok10 = (jc0 >= 0) & (jc0 < LK) & (jc0 >= ir1-64) & (jc0 <= ir1+64);
                ok11 = (jc1 >= 0) & (jc1 < LK) & (jc1 >= ir1-64) & (jc1 <= ir1+64);
            }
            s[nt][0] = ok00 ? __expf(s[nt][0] - mn0) : 0.f;
            s[nt][1] = ok01 ? __expf(s[nt][1] - mn0) : 0.f;
            s[nt][2] = ok10 ? __expf(s[nt][2] - mn1) : 0.f;
            s[nt][3] = ok11 ? __expf(s[nt][3] - mn1) : 0.f;
            ps0 += s[nt][0] + s[nt][1];
            ps1 += s[nt][2] + s[nt][3];
        }
        ps0 += __shfl_xor_sync(0xFFFFFFFFu, ps0, 1); ps0 += __shfl_xor_sync(0xFFFFFFFFu, ps0, 2);
        ps1 += __shfl_xor_sync(0xFFFFFFFFu, ps1, 1); ps1 += __shfl_xor_sync(0xFFFFFFFFu, ps1, 2);
        lr0 = lr0*cf0 + ps0;
        lr1 = lr1*cf1 + ps1;

        // rescale accO
        #pragma unroll
        for (int ntd = 0; ntd < 8; ntd++) {
            accO[ntd][0] *= cf0; accO[ntd][1] *= cf0;
            accO[ntd][2] *= cf1; accO[ntd][3] *= cf1;
        }

        // PV: A = P (4 k16 chunks over 64 j), B = V via ldmatrix.trans
        #pragma unroll
        for (int kch = 0; kch < 4; kch++) {
            int nt0 = kch*2, nt1 = kch*2 + 1;
            uint32_t pah[4], pal[4];
            {
                float p00 = s[nt0][0], p01 = s[nt0][1], p02 = s[nt0][2], p03 = s[nt0][3];
                float p10 = s[nt1][0], p11 = s[nt1][1], p12 = s[nt1][2], p13 = s[nt1][3];
                pah[0] = packbf(p00, p01); pah[1] = packbf(p02, p03);
                pah[2] = packbf(p10, p11); pah[3] = packbf(p12, p13);
                float q00 = p00 - __bfloat162float(__float2bfloat16(p00));
                float q01 = p01 - __bfloat162float(__float2bfloat16(p01));
                float q02 = p02 - __bfloat162float(__float2bfloat16(p02));
                float q03 = p03 - __bfloat162float(__float2bfloat16(p03));
                float q10 = p10 - __bfloat162float(__float2bfloat16(p10));
                float q11 = p11 - __bfloat162float(__float2bfloat16(p11));
                float q12 = p12 - __bfloat162float(__float2bfloat16(p12));
                float q13 = p13 - __bfloat162float(__float2bfloat16(p13));
                pal[0] = packbf(q00, q01); pal[1] = packbf(q02, q03);
                pal[2] = packbf(q10, q11); pal[3] = packbf(q12, q13);
            }
            const int jo = kch*16;
            #pragma unroll
            for (int ntp = 0; ntp < 4; ntp++) {
                uint32_t offV = ((jo + lrow)*72 + ntp*16 + lkh)*2;
                uint32_t vh4[4], vl4[4];
                ldmx4t(vh4, aVh + offV);
                ldmx4t(vl4, aVl + offV);
                mma16816(accO[ntp*2],   pah, &vh4[0]);
                mma16816(accO[ntp*2],   pal, &vh4[0]);
                mma16816(accO[ntp*2],   pah, &vl4[0]);
                mma16816(accO[ntp*2+1], pah, &vh4[2]);
                mma16816(accO[ntp*2+1], pal, &vh4[2]);
                mma16816(accO[ntp*2+1], pah, &vl4[2]);
            }
        }
    }

    // epilogue: direct write (no cross-warp reduction needed)
    float inv0 = 1.0f/lr0, inv1 = 1.0f/lr1;
    #pragma unroll
    for (int ntd = 0; ntd < 8; ntd++) {
        *(float2*)&Out[((size_t)(b*Ls) + ir0)*Dm + hoff + ntd*8 + qc] =
            make_float2(accO[ntd][0]*inv0, accO[ntd][1]*inv0);
        *(float2*)&Out[((size_t)(b*Ls) + ir1)*Dm + hoff + ntd*8 + qc] =
            make_float2(accO[ntd][2]*inv1, accO[ntd][3]*inv1);
    }
}

// ---------------- combine + split comb ----------------
__global__ void combine_kernel(const float* __restrict__ pm)
{
    float a0 = pm[0], a1 = pm[1], a2 = pm[2];
    float mx = fmaxf(a0, fmaxf(a1, a2));
    float e0 = expf(a0-mx), e1 = expf(a1-mx), e2 = expf(a2-mx);
    float den = e0+e1+e2;
    float pw0 = e0/den, pw1 = e1/den;
    int e = blockIdx.x*blockDim.x + threadIdx.x;
    float v = pw0*g_outg[e] + pw1*g_outl[e];
    g_comb[e] = v;
    bsplit(v, g_combh[e], g_combl[e]);
}

// ---------------- selection path ----------------
__global__ void attns_kernel(const float* __restrict__ pm)
{
    __shared__ float sc[Ls];
    __shared__ float qs[64];
    __shared__ float red[256];
    int blk = blockIdx.x;
    int bh  = blk / NSEL, si = blk % NSEL;
    int b = bh >> 3, h = bh & 7;
    int qi = g_selidx[bh*NSEL + si];
    int t = threadIdx.x;

    if (t < 16) {
        float4 v = *(const float4*)&g_q[((size_t)(b*Ls) + qi)*Dm + h*HDim + t*4];
        *(float4*)&qs[t*4] = v;
    }
    __syncthreads();

    const float* kb = g_k + ((size_t)(b*Ls))*Dm + h*HDim;
    for (int jj = 0; jj < 8; jj++) {
        int j = t*8 + jj;
        const float4* kr = (const float4*)&kb[(size_t)j*Dm];
        float dot = 0.f;
        #pragma unroll
        for (int d4 = 0; d4 < 16; d4++) {
            float4 kv = kr[d4];
            dot = fmaf(qs[d4*4+0], kv.x, dot);
            dot = fmaf(qs[d4*4+1], kv.y, dot);
            dot = fmaf(qs[d4*4+2], kv.z, dot);
            dot = fmaf(qs[d4*4+3], kv.w, dot);
        }
        sc[j] = dot * 0.125f;
    }
    __syncthreads();

    float m = -INFINITY;
    for (int j = t; j < Ls; j += 256) m = fmaxf(m, sc[j]);
    red[t] = m; __syncthreads();
    for (int s2 = 128; s2; s2 >>= 1) { if (t < s2) red[t] = fmaxf(red[t], red[t+s2]); __syncthreads(); }
    m = red[0]; __syncthreads();

    float s = 0.f;
    for (int j = t; j < Ls; j += 256) { float e = __expf(sc[j]-m); sc[j] = e; s += e; }
    red[t] = s; __syncthreads();
    for (int s2 = 128; s2; s2 >>= 1) { if (t < s2) red[t] += red[t+s2]; __syncthreads(); }
    s = red[0]; __syncthreads();

    int d = t & 63, qtr = t >> 6;
    const float* vb = g_v + ((size_t)b*Ls)*Dm + h*HDim + d;
    float acc = 0.f;
    for (int j = qtr*512; j < qtr*512 + 512; j++)
        acc = fmaf(sc[j], vb[(size_t)j*Dm], acc);
    red[t] = acc; __syncthreads();

    if (t < 64) {
        float tot = red[t] + red[t+64] + red[t+128] + red[t+192];
        float a0 = pm[0], a1 = pm[1], a2 = pm[2];
        float mx = fmaxf(a0, fmaxf(a1, a2));
        float e0 = expf(a0-mx), e1 = expf(a1-mx), e2 = expf(a2-mx);
        float pw2 = e2/(e0+e1+e2);
        size_t idx = ((size_t)b*Ls + qi)*Dm + h*HDim + t;
        float nv = g_comb[idx] + pw2 * tot / s;
        g_comb[idx] = nv;
        bsplit(nv, g_combh[idx], g_combl[idx]);
    }
}

// ---------------- launch ----------------
extern "C" void kernel_launch(void* const* d_in, const int* in_sizes, int n_in,
                              void* d_out, int out_size)
{
    const float* query = (const float*)d_in[0];
    const float* keyi  = (const float*)d_in[1];
    const float* vali  = (const float*)d_in[2];
    const float* Wq = (const float*)d_in[3];  const float* bq = (const float*)d_in[4];
    const float* Wk = (const float*)d_in[5];  const float* bk = (const float*)d_in[6];
    const float* Wv = (const float*)d_in[7];  const float* bv = (const float*)d_in[8];
    const float* Wo = (const float*)d_in[9];  const float* bo = (const float*)d_in[10];
    const float* Wc1 = (const float*)d_in[11]; const float* bc1 = (const float*)d_in[12];
    const float* Wc2 = (const float*)d_in[13]; const float* bc2 = (const float*)d_in[14];
    const float* pm  = (const float*)d_in[15];

    float *outg, *outl;
    __nv_bfloat16 *kcpreh, *kcprel, *hidh, *hidl, *combh, *combl, *wth, *wtl;
    __nv_bfloat16 *qh, *ql, *kh, *kl, *vh, *vl, *kch, *kcl, *vch, *vcl;
    cudaGetSymbolAddress((void**)&outg,  g_outg);
    cudaGetSymbolAddress((void**)&outl,  g_outl);
    cudaGetSymbolAddress((void**)&kcpreh, g_kcpreh);
    cudaGetSymbolAddress((void**)&kcprel, g_kcprel);
    cudaGetSymbolAddress((void**)&hidh,  g_hidh);
    cudaGetSymbolAddress((void**)&hidl,  g_hidl);
    cudaGetSymbolAddress((void**)&combh, g_combh);
    cudaGetSymbolAddress((void**)&combl, g_combl);
    cudaGetSymbolAddress((void**)&wth,   g_wth);
    cudaGetSymbolAddress((void**)&wtl,   g_wtl);
    cudaGetSymbolAddress((void**)&qh,    g_qh);
    cudaGetSymbolAddress((void**)&ql,    g_ql);
    cudaGetSymbolAddress((void**)&kh,    g_kh);
    cudaGetSymbolAddress((void**)&kl,    g_kl);
    cudaGetSymbolAddress((void**)&vh,    g_vh);
    cudaGetSymbolAddress((void**)&vl,    g_vl);
    cudaGetSymbolAddress((void**)&kch,   g_kch);
    cudaGetSymbolAddress((void**)&kcl,   g_kcl);
    cudaGetSymbolAddress((void**)&vch,   g_vch);
    cudaGetSymbolAddress((void**)&vcl,   g_vcl);

    const int FLASH_SMEM = (2*128*72 + 4*64*72)*2;   // 73728
    const int SCORES_SMEM = 4*128*72*2;              // 73728
    cudaFuncSetAttribute(flash_mma_kernel, cudaFuncAttributeMaxDynamicSharedMemorySize, FLASH_SMEM);
    cudaFuncSetAttribute(scores_stats_mma_kernel, cudaFuncAttributeMaxDynamicSharedMemorySize, SCORES_SMEM);

    // prep
    split_in_kernel<<<dim3((Bb*Ls*Dm)/256, 3), 256>>>(query, keyi, vali);
    split_w6_kernel<<<dim3(16,16,6), dim3(32,8)>>>(Wq, Wk, Wv, Wo, Wc1, Wc2);

    // projections
    proj3_mma_kernel<<<dim3(4,32,3), 256>>>(bq, bk, bv);

    // compression + MLP
    compress_kernel<<<512, 256>>>();
    mma_gemm_kernel<<<dim3(4,8), 256>>>(kcpreh, kcprel, wth + 4*(size_t)Dm*Dm, wtl + 4*(size_t)Dm*Dm,
                                        bc1, nullptr, hidh, hidl, Dm, Dm, 1);
    mma_gemm_kernel<<<dim3(4,8), 256>>>(hidh, hidl, wth + 5*(size_t)Dm*Dm, wtl + 5*(size_t)Dm*Dm,
                                        bc2, nullptr, kch, kcl, Dm, Dm, 0);

    // dense QK^T + fused stats
    scores_stats_mma_kernel<<<dim3(NJT,16,16), 256, SCORES_SMEM>>>(0.125f);
    impfinal_kernel<<<4096, 256>>>();
    topk_kernel<<<Bb*Hh, 256>>>();

    // attention paths (fused local+global, 128-row Q tiles)
    flash_mma_kernel<<<dim3(16,16,2), 256, FLASH_SMEM>>>(
        qh, ql, kh, kl, vh, vl, kch, kcl, vch, vcl, outl, outg);

    // mix + selection
    combine_kernel<<<(Bb*Ls*Dm)/256, 256>>>(pm);
    attns_kernel<<<Bb*Hh*NSEL, 256>>>(pm);

    // output projection
    mma_gemm_kernel<<<dim3(4,32), 256>>>(combh, combl, wth + 3*(size_t)Dm*Dm, wtl + 3*(size_t)Dm*Dm,
                                         bo, (float*)d_out, nullptr, nullptr, Dm, Dm, 0);
}

// round 10
// speedup vs baseline: 2.3129x; 1.0714x over previous
#include <cuda_runtime.h>
#include <cuda_bf16.h>
#include <math.h>
#include <stdint.h>

#define Bb   2
#define Ls   2048
#define Dm   512
#define Hh   8
#define HDim 64
#define LcC  512
#define NSEL 8
#define NJT  16

// ---------------- fp32 scratch ----------------
static __device__ float g_q[Bb*Ls*Dm];
static __device__ float g_k[Bb*Ls*Dm];
static __device__ float g_v[Bb*Ls*Dm];
static __device__ float g_outg[Bb*Ls*Dm];
static __device__ float g_outl[Bb*Ls*Dm];
static __device__ float g_comb[Bb*Ls*Dm];
static __device__ float g_imp[Bb*Hh*Ls];
static __device__ int   g_selidx[Bb*Hh*NSEL];
static __device__ float g_pmax[Bb*Hh*Ls*NJT];
static __device__ float g_pse [Bb*Hh*Ls*NJT];
static __device__ float g_psum[Bb*Hh*Ls*NJT];

// ---------------- bf16 split scratch ----------------
static __device__ __nv_bfloat16 g_wth[6][Dm*Dm];   // transposed [N][K]
static __device__ __nv_bfloat16 g_wtl[6][Dm*Dm];
static __device__ __nv_bfloat16 g_qh[Bb*Ls*Dm], g_ql[Bb*Ls*Dm];
static __device__ __nv_bfloat16 g_kh[Bb*Ls*Dm], g_kl[Bb*Ls*Dm];
static __device__ __nv_bfloat16 g_vh[Bb*Ls*Dm], g_vl[Bb*Ls*Dm];
static __device__ __nv_bfloat16 g_kch[Bb*LcC*Dm], g_kcl[Bb*LcC*Dm];
static __device__ __nv_bfloat16 g_vch[Bb*LcC*Dm], g_vcl[Bb*LcC*Dm];
static __device__ __nv_bfloat16 g_kcpreh[Bb*LcC*Dm], g_kcprel[Bb*LcC*Dm];
static __device__ __nv_bfloat16 g_hidh[Bb*LcC*Dm], g_hidl[Bb*LcC*Dm];
static __device__ __nv_bfloat16 g_combh[Bb*Ls*Dm], g_combl[Bb*Ls*Dm];

__device__ __forceinline__ void bsplit(float x, __nv_bfloat16& h, __nv_bfloat16& l)
{
    h = __float2bfloat16(x);
    l = __float2bfloat16(x - __bfloat162float(h));
}

__device__ __forceinline__ uint32_t packbf(float x, float y)
{
    __nv_bfloat162 t = __floats2bfloat162_rn(x, y);
    return *(uint32_t*)&t;
}

// split two floats -> packed hi pair + packed lo pair (bit-identical to bsplit)
__device__ __forceinline__ void split2(float a, float b, uint32_t& h2, uint32_t& l2)
{
    __nv_bfloat16 ha = __float2bfloat16(a), hb = __float2bfloat16(b);
    float la = a - __bfloat162float(ha), lb = b - __bfloat162float(hb);
    __nv_bfloat162 hp; hp.x = ha; hp.y = hb;
    h2 = *(uint32_t*)&hp;
    l2 = packbf(la, lb);
}

__device__ __forceinline__ void mma16816(float* c, const uint32_t* a, const uint32_t* b)
{
    asm volatile(
        "mma.sync.aligned.m16n8k16.row.col.f32.bf16.bf16.f32 "
        "{%0,%1,%2,%3}, {%4,%5,%6,%7}, {%8,%9}, {%0,%1,%2,%3};"
        : "+f"(c[0]), "+f"(c[1]), "+f"(c[2]), "+f"(c[3])
        : "r"(a[0]), "r"(a[1]), "r"(a[2]), "r"(a[3]), "r"(b[0]), "r"(b[1]));
}

__device__ __forceinline__ uint32_t smem_u32(const void* p)
{
    uint32_t a;
    asm("{ .reg .u64 t; cvta.to.shared.u64 t, %1; cvt.u32.u64 %0, t; }" : "=r"(a) : "l"(p));
    return a;
}

__device__ __forceinline__ void ldmx4(uint32_t* r, uint32_t a)
{
    asm volatile("ldmatrix.sync.aligned.m8n8.x4.shared.b16 {%0,%1,%2,%3}, [%4];"
        : "=r"(r[0]), "=r"(r[1]), "=r"(r[2]), "=r"(r[3]) : "r"(a));
}
__device__ __forceinline__ void ldmx4t(uint32_t* r, uint32_t a)
{
    asm volatile("ldmatrix.sync.aligned.m8n8.x4.trans.shared.b16 {%0,%1,%2,%3}, [%4];"
        : "=r"(r[0]), "=r"(r[1]), "=r"(r[2]), "=r"(r[3]) : "r"(a));
}

// ---------------- prep: split + transpose all 6 weights ----------------
__global__ void split_w6_kernel(const float* w0, const float* w1, const float* w2,
                                const float* w3, const float* w4, const float* w5)
{
    __shared__ float tl[32][33];
    int widx = blockIdx.z;
    const float* w = widx==0?w0 : widx==1?w1 : widx==2?w2 : widx==3?w3 : widx==4?w4 : w5;
    int tx = threadIdx.x, ty = threadIdx.y;
    int n0 = blockIdx.x*32, k0 = blockIdx.y*32;
    #pragma unroll
    for (int i = 0; i < 4; i++)
        tl[ty + i*8][tx] = w[(size_t)(k0 + ty + i*8)*Dm + n0 + tx];
    __syncthreads();
    #pragma unroll
    for (int i = 0; i < 4; i++) {
        float v = tl[tx][ty + i*8];
        size_t o = (size_t)(n0 + ty + i*8)*Dm + k0 + tx;
        bsplit(v, g_wth[widx][o], g_wtl[widx][o]);
    }
}

// =========================================================================
// bf16x3 tensor-core GEMM (bf16 A inputs): C = A @ Bw^T + bias
// =========================================================================
__device__ __forceinline__ void mma_gemm_body(
    const __nv_bfloat16* __restrict__ Ah, const __nv_bfloat16* __restrict__ Al,
    const __nv_bfloat16* __restrict__ Bh, const __nv_bfloat16* __restrict__ Bl,
    const float* __restrict__ bias, float* __restrict__ C,
    __nv_bfloat16* __restrict__ Ch, __nv_bfloat16* __restrict__ Cl,
    int N, int K, int gelu)
{
    __shared__ __nv_bfloat16 sAh[2][128*24], sAl[2][128*24];
    __shared__ __nv_bfloat16 sBh[2][128*24], sBl[2][128*24];
    const int tid = threadIdx.x;
    const int lane = tid & 31, warp = tid >> 5;
    const int wm = warp >> 2, wn = warp & 3;
    const int qr = lane >> 2, qc = (lane & 3)*2;
    const int lrow = lane & 15, lkh = (lane >> 4)*8;
    const int row0 = blockIdx.y*128, col0 = blockIdx.x*128;
    const int half = tid >> 7, r = tid & 127;

    const __nv_bfloat16* As = half ? Al : Ah;
    const __nv_bfloat16* Bs = half ? Bl : Bh;

    {
        const uint4* pa = (const uint4*)(As + (size_t)(row0 + r)*K);
        const uint4* pb = (const uint4*)(Bs + (size_t)(col0 + r)*K);
        uint4 a0 = pa[0], a1 = pa[1], b0 = pb[0], b1 = pb[1];
        __nv_bfloat16* dA = half ? sAl[0] : sAh[0];
        __nv_bfloat16* dB = half ? sBl[0] : sBh[0];
        *(uint4*)&dA[r*24]     = a0; *(uint4*)&dA[r*24 + 8] = a1;
        *(uint4*)&dB[r*24]     = b0; *(uint4*)&dB[r*24 + 8] = b1;
    }
    __syncthreads();

    float acc[4][4][4] = {};
    const int nk = K >> 4;
    for (int kc = 0; kc < nk; kc++) {
        const int buf = kc & 1;
        uint4 na0, na1, nb0, nb1;
        if (kc + 1 < nk) {
            int k0 = (kc + 1)*16;
            const uint4* pa = (const uint4*)(As + (size_t)(row0 + r)*K + k0);
            const uint4* pb = (const uint4*)(Bs + (size_t)(col0 + r)*K + k0);
            na0 = pa[0]; na1 = pa[1]; nb0 = pb[0]; nb1 = pb[1];
        }

        const uint32_t cAh = smem_u32(&sAh[buf][0]);
        const uint32_t cAl = smem_u32(&sAl[buf][0]);
        const uint32_t cBh = smem_u32(&sBh[buf][0]);
        const uint32_t cBl = smem_u32(&sBl[buf][0]);

        uint32_t bh[4][2], bl[4][2];
        #pragma unroll
        for (int ntp = 0; ntp < 2; ntp++) {
            uint32_t off = (uint32_t)(((wn*32 + ntp*16 + lrow)*24 + lkh)*2);
            uint32_t t4[4], u4[4];
            ldmx4(t4, cBh + off);
            ldmx4(u4, cBl + off);
            bh[ntp*2][0]   = t4[0]; bh[ntp*2][1]   = t4[2];
            bh[ntp*2+1][0] = t4[1]; bh[ntp*2+1][1] = t4[3];
            bl[ntp*2][0]   = u4[0]; bl[ntp*2][1]   = u4[2];
            bl[ntp*2+1][0] = u4[1]; bl[ntp*2+1][1] = u4[3];
        }
        #pragma unroll
        for (int mt = 0; mt < 4; mt++) {
            uint32_t offA = (uint32_t)(((wm*64 + mt*16 + lrow)*24 + lkh)*2);
            uint32_t ah[4], al[4];
            ldmx4(ah, cAh + offA);
            ldmx4(al, cAl + offA);
            #pragma unroll
            for (int nt = 0; nt < 4; nt++) {
                mma16816(acc[mt][nt], ah, bh[nt]);
                mma16816(acc[mt][nt], ah, bl[nt]);
                mma16816(acc[mt][nt], al, bh[nt]);
            }
        }

        if (kc + 1 < nk) {
            const int nb = buf ^ 1;
            __nv_bfloat16* dA = half ? sAl[nb] : sAh[nb];
            __nv_bfloat16* dB = half ? sBl[nb] : sBh[nb];
            *(uint4*)&dA[r*24]     = na0; *(uint4*)&dA[r*24 + 8] = na1;
            *(uint4*)&dB[r*24]     = nb0; *(uint4*)&dB[r*24 + 8] = nb1;
        }
        __syncthreads();
    }

    #pragma unroll
    for (int mt = 0; mt < 4; mt++) {
        int gr = row0 + wm*64 + mt*16 + qr;
        #pragma unroll
        for (int nt = 0; nt < 4; nt++) {
            int gc = col0 + wn*32 + nt*8 + qc;
            float v0 = acc[mt][nt][0] + bias[gc];
            float v1 = acc[mt][nt][1] + bias[gc+1];
            float v2 = acc[mt][nt][2] + bias[gc];
            float v3 = acc[mt][nt][3] + bias[gc+1];
            if (gelu) {
                v0 = 0.5f*v0*(1.0f + erff(v0*0.70710678118654752f));
                v1 = 0.5f*v1*(1.0f + erff(v1*0.70710678118654752f));
                v2 = 0.5f*v2*(1.0f + erff(v2*0.70710678118654752f));
                v3 = 0.5f*v3*(1.0f + erff(v3*0.70710678118654752f));
            }
            if (C) {
                float2 p0 = make_float2(v0, v1), p1 = make_float2(v2, v3);
                *(float2*)&C[(size_t)gr*N + gc]     = p0;
                *(float2*)&C[(size_t)(gr+8)*N + gc] = p1;
            }
            if (Ch) {
                uint32_t h01, l01, h23, l23;
                split2(v0, v1, h01, l01);
                split2(v2, v3, h23, l23);
                *(uint32_t*)&Ch[(size_t)gr*N + gc]     = h01;
                *(uint32_t*)&Cl[(size_t)gr*N + gc]     = l01;
                *(uint32_t*)&Ch[(size_t)(gr+8)*N + gc] = h23;
                *(uint32_t*)&Cl[(size_t)(gr+8)*N + gc] = l23;
            }
        }
    }
}

__global__ void __launch_bounds__(256, 2) mma_gemm_kernel(
    const __nv_bfloat16* Ah, const __nv_bfloat16* Al,
    const __nv_bfloat16* Bh, const __nv_bfloat16* Bl,
    const float* bias, float* C, __nv_bfloat16* Ch, __nv_bfloat16* Cl,
    int N, int K, int gelu)
{
    mma_gemm_body(Ah, Al, Bh, Bl, bias, C, Ch, Cl, N, K, gelu);
}

// =========================================================================
// bf16x3 GEMM with fused fp32->hi/lo A conversion (projections).
// half==0 threads stage A (fp32 load + split); half==1 threads stage B hi+lo.
// =========================================================================
__device__ __forceinline__ void mma_gemm_f32A_body(
    const float* __restrict__ Afp,
    const __nv_bfloat16* __restrict__ Bh, const __nv_bfloat16* __restrict__ Bl,
    const float* __restrict__ bias, float* __restrict__ C,
    __nv_bfloat16* __restrict__ Ch, __nv_bfloat16* __restrict__ Cl,
    int N, int K)
{
    __shared__ __nv_bfloat16 sAh[2][128*24], sAl[2][128*24];
    __shared__ __nv_bfloat16 sBh[2][128*24], sBl[2][128*24];
    const int tid = threadIdx.x;
    const int lane = tid & 31, warp = tid >> 5;
    const int wm = warp >> 2, wn = warp & 3;
    const int qr = lane >> 2, qc = (lane & 3)*2;
    const int lrow = lane & 15, lkh = (lane >> 4)*8;
    const int row0 = blockIdx.y*128, col0 = blockIdx.x*128;
    const int half = tid >> 7, r = tid & 127;

    // stage k-chunk 0
    if (half == 0) {
        const float4* pa = (const float4*)(Afp + (size_t)(row0 + r)*K);
        float4 f0 = pa[0], f1 = pa[1], f2 = pa[2], f3 = pa[3];
        float fv[16] = {f0.x,f0.y,f0.z,f0.w, f1.x,f1.y,f1.z,f1.w,
                        f2.x,f2.y,f2.z,f2.w, f3.x,f3.y,f3.z,f3.w};
        #pragma unroll
        for (int c2 = 0; c2 < 8; c2++) {
            uint32_t h2, l2;
            split2(fv[c2*2], fv[c2*2+1], h2, l2);
            *(uint32_t*)&sAh[0][r*24 + c2*2] = h2;
            *(uint32_t*)&sAl[0][r*24 + c2*2] = l2;
        }
    } else {
        const uint4* pbh = (const uint4*)(Bh + (size_t)(col0 + r)*K);
        const uint4* pbl = (const uint4*)(Bl + (size_t)(col0 + r)*K);
        uint4 b0 = pbh[0], b1 = pbh[1], c0 = pbl[0], c1 = pbl[1];
        *(uint4*)&sBh[0][r*24]     = b0; *(uint4*)&sBh[0][r*24 + 8] = b1;
        *(uint4*)&sBl[0][r*24]     = c0; *(uint4*)&sBl[0][r*24 + 8] = c1;
    }
    __syncthreads();

    float acc[4][4][4] = {};
    const int nk = K >> 4;
    for (int kc = 0; kc < nk; kc++) {
        const int buf = kc & 1;
        float nfv[16];
        uint4 nb0, nb1, nc0, nc1;
        if (kc + 1 < nk) {
            int k0 = (kc + 1)*16;
            if (half == 0) {
                const float4* pa = (const float4*)(Afp + (size_t)(row0 + r)*K + k0);
                float4 f0 = pa[0], f1 = pa[1], f2 = pa[2], f3 = pa[3];
                nfv[0]=f0.x; nfv[1]=f0.y; nfv[2]=f0.z; nfv[3]=f0.w;
                nfv[4]=f1.x; nfv[5]=f1.y; nfv[6]=f1.z; nfv[7]=f1.w;
                nfv[8]=f2.x; nfv[9]=f2.y; nfv[10]=f2.z; nfv[11]=f2.w;
                nfv[12]=f3.x; nfv[13]=f3.y; nfv[14]=f3.z; nfv[15]=f3.w;
            } else {
                const uint4* pbh = (const uint4*)(Bh + (size_t)(col0 + r)*K + k0);
                const uint4* pbl = (const uint4*)(Bl + (size_t)(col0 + r)*K + k0);
                nb0 = pbh[0]; nb1 = pbh[1]; nc0 = pbl[0]; nc1 = pbl[1];
            }
        }

        const uint32_t cAh = smem_u32(&sAh[buf][0]);
        const uint32_t cAl = smem_u32(&sAl[buf][0]);
        const uint32_t cBh = smem_u32(&sBh[buf][0]);
        const uint32_t cBl = smem_u32(&sBl[buf][0]);

        uint32_t bh[4][2], bl[4][2];
        #pragma unroll
        for (int ntp = 0; ntp < 2; ntp++) {
            uint32_t off = (uint32_t)(((wn*32 + ntp*16 + lrow)*24 + lkh)*2);
            uint32_t t4[4], u4[4];
            ldmx4(t4, cBh + off);
            ldmx4(u4, cBl + off);
            bh[ntp*2][0]   = t4[0]; bh[ntp*2][1]   = t4[2];
            bh[ntp*2+1][0] = t4[1]; bh[ntp*2+1][1] = t4[3];
            bl[ntp*2][0]   = u4[0]; bl[ntp*2][1]   = u4[2];
            bl[ntp*2+1][0] = u4[1]; bl[ntp*2+1][1] = u4[3];
        }
        #pragma unroll
        for (int mt = 0; mt < 4; mt++) {
            uint32_t offA = (uint32_t)(((wm*64 + mt*16 + lrow)*24 + lkh)*2);
            uint32_t ah[4], al[4];
            ldmx4(ah, cAh + offA);
            ldmx4(al, cAl + offA);
            #pragma unroll
            for (int nt = 0; nt < 4; nt++) {
                mma16816(acc[mt][nt], ah, bh[nt]);
                mma16816(acc[mt][nt], ah, bl[nt]);
                mma16816(acc[mt][nt], al, bh[nt]);
            }
        }

        if (kc + 1 < nk) {
            const int nb = buf ^ 1;
            if (half == 0) {
                #pragma unroll
                for (int c2 = 0; c2 < 8; c2++) {
                    uint32_t h2, l2;
                    split2(nfv[c2*2], nfv[c2*2+1], h2, l2);
                    *(uint32_t*)&sAh[nb][r*24 + c2*2] = h2;
                    *(uint32_t*)&sAl[nb][r*24 + c2*2] = l2;
                }
            } else {
                *(uint4*)&sBh[nb][r*24]     = nb0; *(uint4*)&sBh[nb][r*24 + 8] = nb1;
                *(uint4*)&sBl[nb][r*24]     = nc0; *(uint4*)&sBl[nb][r*24 + 8] = nc1;
            }
        }
        __syncthreads();
    }

    #pragma unroll
    for (int mt = 0; mt < 4; mt++) {
        int gr = row0 + wm*64 + mt*16 + qr;
        #pragma unroll
        for (int nt = 0; nt < 4; nt++) {
            int gc = col0 + wn*32 + nt*8 + qc;
            float v0 = acc[mt][nt][0] + bias[gc];
            float v1 = acc[mt][nt][1] + bias[gc+1];
            float v2 = acc[mt][nt][2] + bias[gc];
            float v3 = acc[mt][nt][3] + bias[gc+1];
            if (C) {
                *(float2*)&C[(size_t)gr*N + gc]     = make_float2(v0, v1);
                *(float2*)&C[(size_t)(gr+8)*N + gc] = make_float2(v2, v3);
            }
            if (Ch) {
                uint32_t h01, l01, h23, l23;
                split2(v0, v1, h01, l01);
                split2(v2, v3, h23, l23);
                *(uint32_t*)&Ch[(size_t)gr*N + gc]     = h01;
                *(uint32_t*)&Cl[(size_t)gr*N + gc]     = l01;
                *(uint32_t*)&Ch[(size_t)(gr+8)*N + gc] = h23;
                *(uint32_t*)&Cl[(size_t)(gr+8)*N + gc] = l23;
            }
        }
    }
}

__global__ void __launch_bounds__(256, 2) proj3_mma_kernel(
    const float* q_in, const float* k_in, const float* v_in,
    const float* bq, const float* bk, const float* bv)
{
    int z = blockIdx.z;
    if (z == 0)
        mma_gemm_f32A_body(q_in, g_wth[0], g_wtl[0], bq, g_q, g_qh, g_ql, Dm, Dm);
    else if (z == 1)
        mma_gemm_f32A_body(k_in, g_wth[1], g_wtl[1], bk, g_k, g_kh, g_kl, Dm, Dm);
    else
        mma_gemm_f32A_body(v_in, g_wth[2], g_wtl[2], bv, g_v, g_vh, g_vl, Dm, Dm);
}

// =========================================================================
// dense QK^T (bf16x3 mma) + fused row stats, ldmatrix fragments (unchanged)
// =========================================================================
extern __shared__ __nv_bfloat16 scsm[];
__global__ void __launch_bounds__(256, 2) scores_stats_mma_kernel(float scale)
{
    __nv_bfloat16* sAh = scsm;
    __nv_bfloat16* sAl = scsm + 128*72;
    __nv_bfloat16* sBh = scsm + 2*128*72;
    __nv_bfloat16* sBl = scsm + 3*128*72;
    __shared__ float s4a[128][4], s4b[128][4], srm[128];

    const int tid = threadIdx.x;
    const int lane = tid & 31, warp = tid >> 5;
    const int wm = warp >> 2, wn = warp & 3;
    const int qr = lane >> 2;
    const int bh = blockIdx.z;
    const int b = bh >> 3, h = bh & 7;
    const int i0 = blockIdx.y*128, j0 = blockIdx.x*128;

    const __nv_bfloat16* Qhp = g_qh + ((size_t)(b*Ls) + i0)*Dm + h*HDim;
    const __nv_bfloat16* Qlp = g_ql + ((size_t)(b*Ls) + i0)*Dm + h*HDim;
    const __nv_bfloat16* Khp = g_kh + ((size_t)(b*Ls) + j0)*Dm + h*HDim;
    const __nv_bfloat16* Klp = g_kl + ((size_t)(b*Ls) + j0)*Dm + h*HDim;

    #pragma unroll
    for (int i = 0; i < 4; i++) {
        int slot = tid*4 + i;
        int row = slot >> 3, c = slot & 7;
        *(uint4*)&sAh[row*72 + c*8] = *(const uint4*)&Qhp[(size_t)row*Dm + c*8];
        *(uint4*)&sAl[row*72 + c*8] = *(const uint4*)&Qlp[(size_t)row*Dm + c*8];
        *(uint4*)&sBh[row*72 + c*8] = *(const uint4*)&Khp[(size_t)row*Dm + c*8];
        *(uint4*)&sBl[row*72 + c*8] = *(const uint4*)&Klp[(size_t)row*Dm + c*8];
    }
    __syncthreads();

    const uint32_t sc0 = smem_u32(scsm);
    const uint32_t aAh = sc0, aAl = sc0 + 128*72*2, aBh = sc0 + 2*128*72*2, aBl = sc0 + 3*128*72*2;
    const int lrow = lane & 15, lkh = (lane >> 4)*8;

    float acc[4][4][4] = {};
    #pragma unroll
    for (int kc = 0; kc < 4; kc++) {
        const int ko = kc*16;
        uint32_t Bh4[2][4], Bl4[2][4];
        #pragma unroll
        for (int ntp = 0; ntp < 2; ntp++) {
            uint32_t off = ((wn*32 + ntp*16 + lrow)*72 + ko + lkh)*2;
            ldmx4(Bh4[ntp], aBh + off);
            ldmx4(Bl4[ntp], aBl + off);
        }
        #pragma unroll
        for (int mt = 0; mt < 4; mt++) {
            uint32_t offA = ((wm*64 + mt*16 + lrow)*72 + ko + lkh)*2;
            uint32_t ah[4], al[4];
            ldmx4(ah, aAh + offA);
            ldmx4(al, aAl + offA);
            #pragma unroll
            for (int nt = 0; nt < 4; nt++) {
                uint32_t bhf[2] = { Bh4[nt>>1][nt&1], Bh4[nt>>1][(nt&1)+2] };
                uint32_t blf[2] = { Bl4[nt>>1][nt&1], Bl4[nt>>1][(nt&1)+2] };
                mma16816(acc[mt][nt], ah, bhf);
                mma16816(acc[mt][nt], ah, blf);
                mma16816(acc[mt][nt], al, bhf);
            }
        }
    }

    #pragma unroll
    for (int mt = 0; mt < 4; mt++) {
        float m0 = -INFINITY, m1 = -INFINITY;
        #pragma unroll
        for (int nt = 0; nt < 4; nt++) {
            m0 = fmaxf(m0, fmaxf(acc[mt][nt][0], acc[mt][nt][1]));
            m1 = fmaxf(m1, fmaxf(acc[mt][nt][2], acc[mt][nt][3]));
        }
        m0 = fmaxf(m0, __shfl_xor_sync(0xFFFFFFFFu, m0, 1));
        m0 = fmaxf(m0, __shfl_xor_sync(0xFFFFFFFFu, m0, 2));
        m1 = fmaxf(m1, __shfl_xor_sync(0xFFFFFFFFu, m1, 1));
        m1 = fmaxf(m1, __shfl_xor_sync(0xFFFFFFFFu, m1, 2));
        if ((lane & 3) == 0) {
            s4a[wm*64 + mt*16 + qr][wn]     = m0;
            s4a[wm*64 + mt*16 + 8 + qr][wn] = m1;
        }
    }
    __syncthreads();
    if (tid < 128)
        srm[tid] = fmaxf(fmaxf(s4a[tid][0], s4a[tid][1]), fmaxf(s4a[tid][2], s4a[tid][3]));
    __syncthreads();

    #pragma unroll
    for (int mt = 0; mt < 4; mt++) {
        int lr0 = wm*64 + mt*16 + qr, lr1 = lr0 + 8;
        float rm0 = srm[lr0]*scale, rm1 = srm[lr1]*scale;
        float se0 = 0.f, se1 = 0.f, ss0 = 0.f, ss1 = 0.f;
        #pragma unroll
        for (int nt = 0; nt < 4; nt++) {
            float x0 = acc[mt][nt][0]*scale, x1 = acc[mt][nt][1]*scale;
            float x2 = acc[mt][nt][2]*scale, x3 = acc[mt][nt][3]*scale;
            se0 += __expf(x0 - rm0) + __expf(x1 - rm0);
            se1 += __expf(x2 - rm1) + __expf(x3 - rm1);
            ss0 += x0 + x1; ss1 += x2 + x3;
        }
        se0 += __shfl_xor_sync(0xFFFFFFFFu, se0, 1); se0 += __shfl_xor_sync(0xFFFFFFFFu, se0, 2);
        se1 += __shfl_xor_sync(0xFFFFFFFFu, se1, 1); se1 += __shfl_xor_sync(0xFFFFFFFFu, se1, 2);
        ss0 += __shfl_xor_sync(0xFFFFFFFFu, ss0, 1); ss0 += __shfl_xor_sync(0xFFFFFFFFu, ss0, 2);
        ss1 += __shfl_xor_sync(0xFFFFFFFFu, ss1, 1); ss1 += __shfl_xor_sync(0xFFFFFFFFu, ss1, 2);
        if ((lane & 3) == 0) {
            s4b[lr0][wn] = se0; s4b[lr1][wn] = se1;
            s4a[lr0][wn] = ss0; s4a[lr1][wn] = ss1;
        }
    }
    __syncthreads();
    if (tid < 128) {
        int rowg = bh*Ls + i0 + tid;
        int jt = blockIdx.x;
        g_pmax[(size_t)rowg*NJT + jt] = srm[tid]*scale;
        g_pse [(size_t)rowg*NJT + jt] = s4b[tid][0]+s4b[tid][1]+s4b[tid][2]+s4b[tid][3];
        g_psum[(size_t)rowg*NJT + jt] = s4a[tid][0]+s4a[tid][1]+s4a[tid][2]+s4a[tid][3];
    }
}

// ---------------- compress: mean of 4 rows -> splits ----------------
__global__ void compress_kernel()
{
    int e4 = blockIdx.x*blockDim.x + threadIdx.x;
    int b = e4 / (LcC*Dm/4);
    int r = e4 % (LcC*Dm/4);
    int m = r / (Dm/4), d4 = r % (Dm/4);
    const float4* k4 = (const float4*)g_k;
    const float4* v4 = (const float4*)g_v;
    size_t base = ((size_t)(b*Ls + m*4)*Dm)/4 + d4;
    float4 a = k4[base], bb = k4[base+128], c = k4[base+256], d = k4[base+384];
    float ox = 0.25f*(a.x+bb.x+c.x+d.x), oy = 0.25f*(a.y+bb.y+c.y+d.y);
    float oz = 0.25f*(a.z+bb.z+c.z+d.z), ow = 0.25f*(a.w+bb.w+c.w+d.w);
    bsplit(ox, g_kcpreh[e4*4+0], g_kcprel[e4*4+0]);
    bsplit(oy, g_kcpreh[e4*4+1], g_kcprel[e4*4+1]);
    bsplit(oz, g_kcpreh[e4*4+2], g_kcprel[e4*4+2]);
    bsplit(ow, g_kcpreh[e4*4+3], g_kcprel[e4*4+3]);
    a = v4[base]; bb = v4[base+128]; c = v4[base+256]; d = v4[base+384];
    ox = 0.25f*(a.x+bb.x+c.x+d.x); oy = 0.25f*(a.y+bb.y+c.y+d.y);
    oz = 0.25f*(a.z+bb.z+c.z+d.z); ow = 0.25f*(a.w+bb.w+c.w+d.w);
    bsplit(ox, g_vch[e4*4+0], g_vcl[e4*4+0]);
    bsplit(oy, g_vch[e4*4+1], g_vcl[e4*4+1]);
    bsplit(oz, g_vch[e4*4+2], g_vcl[e4*4+2]);
    bsplit(ow, g_vch[e4*4+3], g_vcl[e4*4+3]);
}

// ---------------- importance merge ----------------
__global__ void impfinal_kernel()
{
    int warp = (blockIdx.x*blockDim.x + threadIdx.x) >> 5;
    int lane = threadIdx.x & 31;
    float pm = -INFINITY, pe = 0.f, ps = 0.f;
    if (lane < NJT) {
        pm = g_pmax[(size_t)warp*NJT + lane];
        pe = g_pse [(size_t)warp*NJT + lane];
        ps = g_psum[(size_t)warp*NJT + lane];
    }
    float m = pm;
    #pragma unroll
    for (int o = 8; o; o >>= 1) m = fmaxf(m, __shfl_xor_sync(0xFFFFFFFFu, m, o));
    float se = (lane < NJT) ? pe * __expf(pm - m) : 0.f;
    #pragma unroll
    for (int o = 8; o; o >>= 1) {
        se += __shfl_xor_sync(0xFFFFFFFFu, se, o);
        ps += __shfl_xor_sync(0xFFFFFFFFu, ps, o);
    }
    if (lane == 0)
        g_imp[warp] = m + logf(se) - 7.6246189861593985f - ps * (1.0f/2048.0f);
}

// ---------------- top-8 ----------------
__global__ void topk_kernel()
{
    int bh = blockIdx.x;
    const float* imp = g_imp + bh*Ls;
    __shared__ float bv[256];
    __shared__ int   bi[256];
    __shared__ int   chosen[NSEL];
    int t = threadIdx.x;
    for (int itu = 0; itu < NSEL; itu++) {
        float best = -INFINITY; int bidx = 0x7FFFFFFF;
        for (int j = t; j < Ls; j += 256) {
            bool skip = false;
            for (int c = 0; c < itu; c++) if (chosen[c] == j) skip = true;
            if (skip) continue;
            float vv = imp[j];
            if (vv > best || (vv == best && j < bidx)) { best = vv; bidx = j; }
        }
        bv[t] = best; bi[t] = bidx;
        __syncthreads();
        for (int s2 = 128; s2; s2 >>= 1) {
            if (t < s2) {
                if (bv[t+s2] > bv[t] || (bv[t+s2] == bv[t] && bi[t+s2] < bi[t])) {
                    bv[t] = bv[t+s2]; bi[t] = bi[t+s2];
                }
            }
            __syncthreads();
        }
        if (t == 0) { chosen[itu] = bi[0]; g_selidx[bh*NSEL + itu] = bi[0]; }
        __syncthreads();
    }
}

// =========================================================================
// fused flash attention, 128-row Q tiles, 8 warps all in M, with per-warp
// band-chunk skipping on the local path.
// =========================================================================
extern __shared__ char fsm2[];
__global__ void __launch_bounds__(256, 2) flash_mma_kernel(
    const __nv_bfloat16* __restrict__ Qh, const __nv_bfloat16* __restrict__ Ql,
    const __nv_bfloat16* __restrict__ Khg, const __nv_bfloat16* __restrict__ Klg,
    const __nv_bfloat16* __restrict__ Vhg, const __nv_bfloat16* __restrict__ Vlg,
    const __nv_bfloat16* __restrict__ Khc, const __nv_bfloat16* __restrict__ Klc,
    const __nv_bfloat16* __restrict__ Vhc, const __nv_bfloat16* __restrict__ Vlc,
    float* __restrict__ OutL, float* __restrict__ OutG)
{
    __nv_bfloat16* sQh = (__nv_bfloat16*)fsm2;   // [128][72]
    __nv_bfloat16* sQl = sQh + 128*72;
    __nv_bfloat16* sKh = sQl + 128*72;           // [64][72]
    __nv_bfloat16* sKl = sKh + 64*72;
    __nv_bfloat16* sVh = sKl + 64*72;            // natural [j][d]
    __nv_bfloat16* sVl = sVh + 64*72;

    const int z = blockIdx.z;
    const __nv_bfloat16* Kh = z ? Khc : Khg;
    const __nv_bfloat16* Kl = z ? Klc : Klg;
    const __nv_bfloat16* Vh = z ? Vhc : Vhg;
    const __nv_bfloat16* Vl = z ? Vlc : Vlg;
    float* Out = z ? OutG : OutL;
    const int LK = z ? LcC : Ls;
    const int nchunks = z ? 8 : 4;
    const int local = z ? 0 : 1;

    const int tid = threadIdx.x;
    const int lane = tid & 31, w = tid >> 5;
    const int qr = lane >> 2, qc = (lane & 3)*2;
    const int lrow = lane & 15, lkh = (lane >> 4)*8;
    const int bh = blockIdx.y;
    const int b = bh >> 3, h = bh & 7;
    const int i0 = blockIdx.x*128;
    const size_t hoff = (size_t)h*HDim;

    const uint32_t sb = smem_u32(fsm2);
    const uint32_t aQh = sb, aQl = sb + 18432;
    const uint32_t aKh = sb + 36864, aKl = sb + 46080;
    const uint32_t aVh = sb + 55296, aVl = sb + 64512;

    // load Q tile (row-major [i][d]): 128 rows, 2 threads/row
    {
        int row = tid >> 1, part = (tid & 1)*32;
        const uint4* ph = (const uint4*)(Qh + ((size_t)(b*Ls) + i0 + row)*Dm + hoff + part);
        const uint4* pl = (const uint4*)(Ql + ((size_t)(b*Ls) + i0 + row)*Dm + hoff + part);
        #pragma unroll
        for (int j = 0; j < 4; j++) {
            *(uint4*)&sQh[row*72 + part + j*8] = ph[j];
            *(uint4*)&sQl[row*72 + part + j*8] = pl[j];
        }
    }

    float accO[8][4] = {};
    float mr0 = -INFINITY, mr1 = -INFINITY;
    float lr0 = 0.f, lr1 = 0.f;
    const int ir0 = i0 + w*16 + qr, ir1 = ir0 + 8;

    for (int c = 0; c < nchunks; c++) {
        int jbase = (local ? i0 - 64 : 0) + c*64;
        __syncthreads();
        // load K and V chunks [j][d], vectorized (all threads cooperate)
        {
            int row = tid >> 2, c16 = (tid & 3)*16;
            int jg = jbase + row;
            uint4 kh0 = {0,0,0,0}, kh1 = {0,0,0,0}, kl0 = {0,0,0,0}, kl1 = {0,0,0,0};
            uint4 vh0 = {0,0,0,0}, vh1 = {0,0,0,0}, vl0 = {0,0,0,0}, vl1 = {0,0,0,0};
            if (jg >= 0 && jg < LK) {
                const uint4* ph = (const uint4*)(Kh + ((size_t)(b*LK) + jg)*Dm + hoff + c16);
                const uint4* pl = (const uint4*)(Kl + ((size_t)(b*LK) + jg)*Dm + hoff + c16);
                kh0 = ph[0]; kh1 = ph[1]; kl0 = pl[0]; kl1 = pl[1];
                ph = (const uint4*)(Vh + ((size_t)(b*LK) + jg)*Dm + hoff + c16);
                pl = (const uint4*)(Vl + ((size_t)(b*LK) + jg)*Dm + hoff + c16);
                vh0 = ph[0]; vh1 = ph[1]; vl0 = pl[0]; vl1 = pl[1];
            }
            *(uint4*)&sKh[row*72 + c16] = kh0; *(uint4*)&sKh[row*72 + c16 + 8] = kh1;
            *(uint4*)&sKl[row*72 + c16] = kl0; *(uint4*)&sKl[row*72 + c16 + 8] = kl1;
            *(uint4*)&sVh[row*72 + c16] = vh0; *(uint4*)&sVh[row*72 + c16 + 8] = vh1;
            *(uint4*)&sVl[row*72 + c16] = vl0; *(uint4*)&sVl[row*72 + c16 + 8] = vl1;
        }
        __syncthreads();

        // local path: skip chunk if warp's band doesn't intersect it.
        // warp band cols: [w*16-63 .. w*16+143] rel. jbase0; chunk c covers c*64..c*64+63 rel.
        if (local) {
            int c64 = c*64;
            if (c64 < w*16 - 63 || c64 > w*16 + 143) continue;
        }

        // QK^T: warp owns its 16 rows x all 64 cols  (8 n-tiles)
        float s[8][4] = {};
        #pragma unroll
        for (int kc = 0; kc < 4; kc++) {
            int ko = kc*16;
            uint32_t offA = ((w*16 + lrow)*72 + ko + lkh)*2;
            uint32_t ah[4], al[4];
            ldmx4(ah, aQh + offA);
            ldmx4(al, aQl + offA);
            #pragma unroll
            for (int ntp = 0; ntp < 4; ntp++) {
                uint32_t offB = ((ntp*16 + lrow)*72 + ko + lkh)*2;
                uint32_t kh4[4], kl4[4];
                ldmx4(kh4, aKh + offB);
                ldmx4(kl4, aKl + offB);
                uint32_t bhf0[2] = { kh4[0], kh4[2] }, bhf1[2] = { kh4[1], kh4[3] };
                uint32_t blf0[2] = { kl4[0], kl4[2] }, blf1[2] = { kl4[1], kl4[3] };
                mma16816(s[ntp*2],   ah, bhf0);
                mma16816(s[ntp*2],   ah, blf0);
                mma16816(s[ntp*2],   al, bhf0);
                mma16816(s[ntp*2+1], ah, bhf1);
                mma16816(s[ntp*2+1], ah, blf1);
                mma16816(s[ntp*2+1], al, bhf1);
            }
        }

        // scale + mask + row max (whole row inside quad — no smem)
        float m0 = -INFINITY, m1 = -INFINITY;
        #pragma unroll
        for (int nt = 0; nt < 8; nt++) {
            int jc0 = jbase + nt*8 + qc;
            int jc1 = jc0 + 1;
            #pragma unroll
            for (int rg = 0; rg < 4; rg++) s[nt][rg] *= 0.125f;
            bool ok00 = true, ok01 = true, ok10 = true, ok11 = true;
            if (local) {
                ok00 = (jc0 >= 0) & (jc0 < LK) & (jc0 >= ir0-64) & (jc0 <= ir0+64);
                ok01 = (jc1 >= 0) & (jc1 < LK) & (jc1 >= ir0-64) & (jc1 <= ir0+64);
                ok10 = (jc0 >= 0) & (jc0 < LK) & (jc0 >= ir1-64) & (jc0 <= ir1+64);
                ok11 = (jc1 >= 0) & (jc1 < LK) & (jc1 >= ir1-64) & (jc1 <= ir1+64);
            }
            if (ok00) m0 = fmaxf(m0, s[nt][0]);
            if (ok01) m0 = fmaxf(m0, s[nt][1]);
            if (ok10) m1 = fmaxf(m1, s[nt][2]);
            if (ok11) m1 = fmaxf(m1, s[nt][3]);
        }
        m0 = fmaxf(m0, __shfl_xor_sync(0xFFFFFFFFu, m0, 1));
        m0 = fmaxf(m0, __shfl_xor_sync(0xFFFFFFFFu, m0, 2));
        m1 = fmaxf(m1, __shfl_xor_sync(0xFFFFFFFFu, m1, 1));
        m1 = fmaxf(m1, __shfl_xor_sync(0xFFFFFFFFu, m1, 2));
        float mn0 = fmaxf(mr0, m0), mn1 = fmaxf(mr1, m1);
        float cf0 = (mn0 == -INFINITY) ? 1.f : __expf(mr0 - mn0);
        float cf1 = (mn1 == -INFINITY) ? 1.f : __expf(mr1 - mn1);
        mr0 = mn0; mr1 = mn1;

        // P = exp(s - m), row sums (quad shuffles only)
        float ps0 = 0.f, ps1 = 0.f;
        #pragma unroll
        for (int nt = 0; nt < 8; nt++) {
            int jc0 = jbase + nt*8 + qc;
            int jc1 = jc0 + 1;
            bool ok00 = true, ok01 = true, ok10 = true, ok11 = true;
            if (local) {
                ok00 = (jc0 >= 0) & (jc0 < LK) & (jc0 >= ir0-64) & (jc0 <= ir0+64);
                ok01 = (jc1 >= 0) & (jc1 < LK) & (jc1 >= ir0-64) & (jc1 <= ir0+64);
                ok10 = (jc0 >= 0) & (jc0 < LK) & (jc0 >= ir1-64) & (jc0 <= ir1+64);
                ok11 = (jc1 >= 0) & (jc1 < LK) & (jc1 >= ir1-64) & (jc1 <= ir1+64);
            }
            s[nt][0] = ok00 ? __expf(s[nt][0] - mn0) : 0.f;
            s[nt][1] = ok01 ? __expf(s[nt][1] - mn0) : 0.f;
            s[nt][2] = ok10 ? __expf(s[nt][2] - mn1) : 0.f;
            s[nt][3] = ok11 ? __expf(s[nt][3] - mn1) : 0.f;
            ps0 += s[nt][0] + s[nt][1];
            ps1 += s[nt][2] + s[nt][3];
        }
        ps0 += __shfl_xor_sync(0xFFFFFFFFu, ps0, 1); ps0 += __shfl_xor_sync(0xFFFFFFFFu, ps0, 2);
        ps1 += __shfl_xor_sync(0xFFFFFFFFu, ps1, 1); ps1 += __shfl_xor_sync(0xFFFFFFFFu, ps1, 2);
        lr0 = lr0*cf0 + ps0;
        lr1 = lr1*cf1 + ps1;

        // rescale accO
        #pragma unroll
        for (int ntd = 0; ntd < 8; ntd++) {
            accO[ntd][0] *= cf0; accO[ntd][1] *= cf0;
            accO[ntd][2] *= cf1; accO[ntd][3] *= cf1;
        }

        // PV: A = P (4 k16 chunks over 64 j), B = V via ldmatrix.trans
        #pragma unroll
        for (int kch = 0; kch < 4; kch++) {
            int nt0 = kch*2, nt1 = kch*2 + 1;
            uint32_t pah[4], pal[4];
            {
                float p00 = s[nt0][0], p01 = s[nt0][1], p02 = s[nt0][2], p03 = s[nt0][3];
                float p10 = s[nt1][0], p11 = s[nt1][1], p12 = s[nt1][2], p13 = s[nt1][3];
                pah[0] = packbf(p00, p01); pah[1] = packbf(p02, p03);
                pah[2] = packbf(p10, p11); pah[3] = packbf(p12, p13);
                float q00 = p00 - __bfloat162float(__float2bfloat16(p00));
                float q01 = p01 - __bfloat162float(__float2bfloat16(p01));
                float q02 = p02 - __bfloat162float(__float2bfloat16(p02));
                float q03 = p03 - __bfloat162float(__float2bfloat16(p03));
                float q10 = p10 - __bfloat162float(__float2bfloat16(p10));
                float q11 = p11 - __bfloat162float(__float2bfloat16(p11));
                float q12 = p12 - __bfloat162float(__float2bfloat16(p12));
                float q13 = p13 - __bfloat162float(__float2bfloat16(p13));
                pal[0] = packbf(q00, q01); pal[1] = packbf(q02, q03);
                pal[2] = packbf(q10, q11); pal[3] = packbf(q12, q13);
            }
            const int jo = kch*16;
            #pragma unroll
            for (int ntp = 0; ntp < 4; ntp++) {
                uint32_t offV = ((jo + lrow)*72 + ntp*16 + lkh)*2;
                uint32_t vh4[4], vl4[4];
                ldmx4t(vh4, aVh + offV);
                ldmx4t(vl4, aVl + offV);
                mma16816(accO[ntp*2],   pah, &vh4[0]);
                mma16816(accO[ntp*2],   pal, &vh4[0]);
                mma16816(accO[ntp*2],   pah, &vl4[0]);
                mma16816(accO[ntp*2+1], pah, &vh4[2]);
                mma16816(accO[ntp*2+1], pal, &vh4[2]);
                mma16816(accO[ntp*2+1], pah, &vl4[2]);
            }
        }
    }

    // epilogue: direct write
    float inv0 = 1.0f/lr0, inv1 = 1.0f/lr1;
    #pragma unroll
    for (int ntd = 0; ntd < 8; ntd++) {
        *(float2*)&Out[((size_t)(b*Ls) + ir0)*Dm + hoff + ntd*8 + qc] =
            make_float2(accO[ntd][0]*inv0, accO[ntd][1]*inv0);
        *(float2*)&Out[((size_t)(b*Ls) + ir1)*Dm + hoff + ntd*8 + qc] =
            make_float2(accO[ntd][2]*inv1, accO[ntd][3]*inv1);
    }
}

// ---------------- combine + split comb ----------------
__global__ void combine_kernel(const float* __restrict__ pm)
{
    float a0 = pm[0], a1 = pm[1], a2 = pm[2];
    float mx = fmaxf(a0, fmaxf(a1, a2));
    float e0 = expf(a0-mx), e1 = expf(a1-mx), e2 = expf(a2-mx);
    float den = e0+e1+e2;
    float pw0 = e0/den, pw1 = e1/den;
    int e = blockIdx.x*blockDim.x + threadIdx.x;
    float v = pw0*g_outg[e] + pw1*g_outl[e];
    g_comb[e] = v;
    bsplit(v, g_combh[e], g_combl[e]);
}

// ---------------- selection path ----------------
__global__ void attns_kernel(const float* __restrict__ pm)
{
    __shared__ float sc[Ls];
    __shared__ float qs[64];
    __shared__ float red[256];
    int blk = blockIdx.x;
    int bh  = blk / NSEL, si = blk % NSEL;
    int b = bh >> 3, h = bh & 7;
    int qi = g_selidx[bh*NSEL + si];
    int t = threadIdx.x;

    if (t < 16) {
        float4 v = *(const float4*)&g_q[((size_t)(b*Ls) + qi)*Dm + h*HDim + t*4];
        *(float4*)&qs[t*4] = v;
    }
    __syncthreads();

    const float* kb = g_k + ((size_t)(b*Ls))*Dm + h*HDim;
    for (int jj = 0; jj < 8; jj++) {
        int j = t*8 + jj;
        const float4* kr = (const float4*)&kb[(size_t)j*Dm];
        float dot = 0.f;
        #pragma unroll
        for (int d4 = 0; d4 < 16; d4++) {
            float4 kv = kr[d4];
            dot = fmaf(qs[d4*4+0], kv.x, dot);
            dot = fmaf(qs[d4*4+1], kv.y, dot);
            dot = fmaf(qs[d4*4+2], kv.z, dot);
            dot = fmaf(qs[d4*4+3], kv.w, dot);
        }
        sc[j] = dot * 0.125f;
    }
    __syncthreads();

    float m = -INFINITY;
    for (int j = t; j < Ls; j += 256) m = fmaxf(m, sc[j]);
    red[t] = m; __syncthreads();
    for (int s2 = 128; s2; s2 >>= 1) { if (t < s2) red[t] = fmaxf(red[t], red[t+s2]); __syncthreads(); }
    m = red[0]; __syncthreads();

    float s = 0.f;
    for (int j = t; j < Ls; j += 256) { float e = __expf(sc[j]-m); sc[j] = e; s += e; }
    red[t] = s; __syncthreads();
    for (int s2 = 128; s2; s2 >>= 1) { if (t < s2) red[t] += red[t+s2]; __syncthreads(); }
    s = red[0]; __syncthreads();

    int d = t & 63, qtr = t >> 6;
    const float* vb = g_v + ((size_t)b*Ls)*Dm + h*HDim + d;
    float acc = 0.f;
    for (int j = qtr*512; j < qtr*512 + 512; j++)
        acc = fmaf(sc[j], vb[(size_t)j*Dm], acc);
    red[t] = acc; __syncthreads();

    if (t < 64) {
        float tot = red[t] + red[t+64] + red[t+128] + red[t+192];
        float a0 = pm[0], a1 = pm[1], a2 = pm[2];
        float mx = fmaxf(a0, fmaxf(a1, a2));
        float e0 = expf(a0-mx), e1 = expf(a1-mx), e2 = expf(a2-mx);
        float pw2 = e2/(e0+e1+e2);
        size_t idx = ((size_t)b*Ls + qi)*Dm + h*HDim + t;
        float nv = g_comb[idx] + pw2 * tot / s;
        g_comb[idx] = nv;
        bsplit(nv, g_combh[idx], g_combl[idx]);
    }
}

// ---------------- launch ----------------
extern "C" void kernel_launch(void* const* d_in, const int* in_sizes, int n_in,
                              void* d_out, int out_size)
{
    const float* query = (const float*)d_in[0];
    const float* keyi  = (const float*)d_in[1];
    const float* vali  = (const float*)d_in[2];
    const float* Wq = (const float*)d_in[3];  const float* bq = (const float*)d_in[4];
    const float* Wk = (const float*)d_in[5];  const float* bk = (const float*)d_in[6];
    const float* Wv = (const float*)d_in[7];  const float* bv = (const float*)d_in[8];
    const float* Wo = (const float*)d_in[9];  const float* bo = (const float*)d_in[10];
    const float* Wc1 = (const float*)d_in[11]; const float* bc1 = (const float*)d_in[12];
    const float* Wc2 = (const float*)d_in[13]; const float* bc2 = (const float*)d_in[14];
    const float* pm  = (const float*)d_in[15];

    __nv_bfloat16 *kcpreh, *kcprel, *hidh, *hidl, *combh, *combl, *wth, *wtl;
    __nv_bfloat16 *qh, *ql, *kh, *kl, *vh, *vl, *kch, *kcl, *vch, *vcl;
    cudaGetSymbolAddress((void**)&kcpreh, g_kcpreh);
    cudaGetSymbolAddress((void**)&kcprel, g_kcprel);
    cudaGetSymbolAddress((void**)&hidh,  g_hidh);
    cudaGetSymbolAddress((void**)&hidl,  g_hidl);
    cudaGetSymbolAddress((void**)&combh, g_combh);
    cudaGetSymbolAddress((void**)&combl, g_combl);
    cudaGetSymbolAddress((void**)&wth,   g_wth);
    cudaGetSymbolAddress((void**)&wtl,   g_wtl);
    cudaGetSymbolAddress((void**)&qh,    g_qh);
    cudaGetSymbolAddress((void**)&ql,    g_ql);
    cudaGetSymbolAddress((void**)&kh,    g_kh);
    cudaGetSymbolAddress((void**)&kl,    g_kl);
    cudaGetSymbolAddress((void**)&vh,    g_vh);
    cudaGetSymbolAddress((void**)&vl,    g_vl);
    cudaGetSymbolAddress((void**)&kch,   g_kch);
    cudaGetSymbolAddress((void**)&kcl,   g_kcl);
    cudaGetSymbolAddress((void**)&vch,   g_vch);
    cudaGetSymbolAddress((void**)&vcl,   g_vcl);

    float *outg, *outl;
    cudaGetSymbolAddress((void**)&outg,  g_outg);
    cudaGetSymbolAddress((void**)&outl,  g_outl);

    const int FLASH_SMEM = (2*128*72 + 4*64*72)*2;   // 73728
    const int SCORES_SMEM = 4*128*72*2;              // 73728
    cudaFuncSetAttribute(flash_mma_kernel, cudaFuncAttributeMaxDynamicSharedMemorySize, FLASH_SMEM);
    cudaFuncSetAttribute(scores_stats_mma_kernel, cudaFuncAttributeMaxDynamicSharedMemorySize, SCORES_SMEM);

    // prep (weights only; input split fused into projections)
    split_w6_kernel<<<dim3(16,16,6), dim3(32,8)>>>(Wq, Wk, Wv, Wo, Wc1, Wc2);

    // projections (fused fp32->hi/lo A conversion)
    proj3_mma_kernel<<<dim3(4,32,3), 256>>>(query, keyi, vali, bq, bk, bv);

    // compression + MLP
    compress_kernel<<<512, 256>>>();
    mma_gemm_kernel<<<dim3(4,8), 256>>>(kcpreh, kcprel, wth + 4*(size_t)Dm*Dm, wtl + 4*(size_t)Dm*Dm,
                                        bc1, nullptr, hidh, hidl, Dm, Dm, 1);
    mma_gemm_kernel<<<dim3(4,8), 256>>>(hidh, hidl, wth + 5*(size_t)Dm*Dm, wtl + 5*(size_t)Dm*Dm,
                                        bc2, nullptr, kch, kcl, Dm, Dm, 0);

    // dense QK^T + fused stats
    scores_stats_mma_kernel<<<dim3(NJT,16,16), 256, SCORES_SMEM>>>(0.125f);
    impfinal_kernel<<<4096, 256>>>();
    topk_kernel<<<Bb*Hh, 256>>>();

    // attention paths (fused local+global, 128-row Q tiles, band chunk skip)
    flash_mma_kernel<<<dim3(16,16,2), 256, FLASH_SMEM>>>(
        qh, ql, kh, kl, vh, vl, kch, kcl, vch, vcl, outl, outg);

    // mix + selection
    combine_kernel<<<(Bb*Ls*Dm)/256, 256>>>(pm);
    attns_kernel<<<Bb*Hh*NSEL, 256>>>(pm);

    // output projection
    mma_gemm_kernel<<<dim3(4,32), 256>>>(combh, combl, wth + 3*(size_t)Dm*Dm, wtl + 3*(size_t)Dm*Dm,
                                         bo, (float*)d_out, nullptr, nullptr, Dm, Dm, 0);
}

// round 11
// speedup vs baseline: 2.4523x; 1.0603x over previous
#include <cuda_runtime.h>
#include <cuda_bf16.h>
#include <math.h>
#include <stdint.h>

#define Bb   2
#define Ls   2048
#define Dm   512
#define Hh   8
#define HDim 64
#define LcC  512
#define NSEL 8
#define NJT  16

// ---------------- fp32 scratch ----------------
static __device__ float g_q[Bb*Ls*Dm];
static __device__ float g_k[Bb*Ls*Dm];
static __device__ float g_v[Bb*Ls*Dm];
static __device__ float g_outg[Bb*Ls*Dm];
static __device__ float g_outl[Bb*Ls*Dm];
static __device__ float g_comb[Bb*Ls*Dm];
static __device__ float g_imp[Bb*Hh*Ls];
static __device__ int   g_selidx[Bb*Hh*NSEL];
static __device__ float g_pmax[Bb*Hh*Ls*NJT];
static __device__ float g_pse [Bb*Hh*Ls*NJT];
static __device__ float g_psum[Bb*Hh*Ls*NJT];

// ---------------- bf16 split scratch ----------------
static __device__ __nv_bfloat16 g_wth[6][Dm*Dm];   // transposed [N][K]
static __device__ __nv_bfloat16 g_wtl[6][Dm*Dm];
static __device__ __nv_bfloat16 g_qh[Bb*Ls*Dm], g_ql[Bb*Ls*Dm];
static __device__ __nv_bfloat16 g_kh[Bb*Ls*Dm], g_kl[Bb*Ls*Dm];
static __device__ __nv_bfloat16 g_vh[Bb*Ls*Dm], g_vl[Bb*Ls*Dm];
static __device__ __nv_bfloat16 g_kch[Bb*LcC*Dm], g_kcl[Bb*LcC*Dm];
static __device__ __nv_bfloat16 g_vch[Bb*LcC*Dm], g_vcl[Bb*LcC*Dm];
static __device__ __nv_bfloat16 g_kcpreh[Bb*LcC*Dm], g_kcprel[Bb*LcC*Dm];
static __device__ __nv_bfloat16 g_hidh[Bb*LcC*Dm], g_hidl[Bb*LcC*Dm];
static __device__ __nv_bfloat16 g_combh[Bb*Ls*Dm], g_combl[Bb*Ls*Dm];

__device__ __forceinline__ void bsplit(float x, __nv_bfloat16& h, __nv_bfloat16& l)
{
    h = __float2bfloat16(x);
    l = __float2bfloat16(x - __bfloat162float(h));
}

__device__ __forceinline__ uint32_t packbf(float x, float y)
{
    __nv_bfloat162 t = __floats2bfloat162_rn(x, y);
    return *(uint32_t*)&t;
}

__device__ __forceinline__ void split2(float a, float b, uint32_t& h2, uint32_t& l2)
{
    __nv_bfloat16 ha = __float2bfloat16(a), hb = __float2bfloat16(b);
    float la = a - __bfloat162float(ha), lb = b - __bfloat162float(hb);
    __nv_bfloat162 hp; hp.x = ha; hp.y = hb;
    h2 = *(uint32_t*)&hp;
    l2 = packbf(la, lb);
}

__device__ __forceinline__ void mma16816(float* c, const uint32_t* a, const uint32_t* b)
{
    asm volatile(
        "mma.sync.aligned.m16n8k16.row.col.f32.bf16.bf16.f32 "
        "{%0,%1,%2,%3}, {%4,%5,%6,%7}, {%8,%9}, {%0,%1,%2,%3};"
        : "+f"(c[0]), "+f"(c[1]), "+f"(c[2]), "+f"(c[3])
        : "r"(a[0]), "r"(a[1]), "r"(a[2]), "r"(a[3]), "r"(b[0]), "r"(b[1]));
}

__device__ __forceinline__ uint32_t smem_u32(const void* p)
{
    uint32_t a;
    asm("{ .reg .u64 t; cvta.to.shared.u64 t, %1; cvt.u32.u64 %0, t; }" : "=r"(a) : "l"(p));
    return a;
}

__device__ __forceinline__ void ldmx4(uint32_t* r, uint32_t a)
{
    asm volatile("ldmatrix.sync.aligned.m8n8.x4.shared.b16 {%0,%1,%2,%3}, [%4];"
        : "=r"(r[0]), "=r"(r[1]), "=r"(r[2]), "=r"(r[3]) : "r"(a));
}
__device__ __forceinline__ void ldmx4t(uint32_t* r, uint32_t a)
{
    asm volatile("ldmatrix.sync.aligned.m8n8.x4.trans.shared.b16 {%0,%1,%2,%3}, [%4];"
        : "=r"(r[0]), "=r"(r[1]), "=r"(r[2]), "=r"(r[3]) : "r"(a));
}

// ---------------- prep: split + transpose all 6 weights ----------------
__global__ void split_w6_kernel(const float* w0, const float* w1, const float* w2,
                                const float* w3, const float* w4, const float* w5)
{
    __shared__ float tl[32][33];
    int widx = blockIdx.z;
    const float* w = widx==0?w0 : widx==1?w1 : widx==2?w2 : widx==3?w3 : widx==4?w4 : w5;
    int tx = threadIdx.x, ty = threadIdx.y;
    int n0 = blockIdx.x*32, k0 = blockIdx.y*32;
    #pragma unroll
    for (int i = 0; i < 4; i++)
        tl[ty + i*8][tx] = w[(size_t)(k0 + ty + i*8)*Dm + n0 + tx];
    __syncthreads();
    #pragma unroll
    for (int i = 0; i < 4; i++) {
        float v = tl[tx][ty + i*8];
        size_t o = (size_t)(n0 + ty + i*8)*Dm + k0 + tx;
        bsplit(v, g_wth[widx][o], g_wtl[widx][o]);
    }
}

// =========================================================================
// 64x64-tile bf16x3 GEMM (for small-M / occupancy-bound GEMMs).
// 128 threads, warps 2(M)x2(N); same fragment mappings as the 128 kernel.
// =========================================================================
__global__ void __launch_bounds__(128, 4) mma_gemm64_kernel(
    const __nv_bfloat16* __restrict__ Ah, const __nv_bfloat16* __restrict__ Al,
    const __nv_bfloat16* __restrict__ Bh, const __nv_bfloat16* __restrict__ Bl,
    const float* __restrict__ bias, float* __restrict__ C,
    __nv_bfloat16* __restrict__ Ch, __nv_bfloat16* __restrict__ Cl,
    int N, int K, int gelu)
{
    __shared__ __nv_bfloat16 sAh[2][64*24], sAl[2][64*24];
    __shared__ __nv_bfloat16 sBh[2][64*24], sBl[2][64*24];
    const int tid = threadIdx.x;
    const int lane = tid & 31, warp = tid >> 5;
    const int wm = warp >> 1, wn = warp & 1;
    const int qr = lane >> 2, qc = (lane & 3)*2;
    const int lrow = lane & 15, lkh = (lane >> 4)*8;
    const int row0 = blockIdx.y*64, col0 = blockIdx.x*64;
    const int half = tid >> 6, r = tid & 63;

    const __nv_bfloat16* As = half ? Al : Ah;
    const __nv_bfloat16* Bs = half ? Bl : Bh;

    {
        const uint4* pa = (const uint4*)(As + (size_t)(row0 + r)*K);
        const uint4* pb = (const uint4*)(Bs + (size_t)(col0 + r)*K);
        uint4 a0 = pa[0], a1 = pa[1], b0 = pb[0], b1 = pb[1];
        __nv_bfloat16* dA = half ? sAl[0] : sAh[0];
        __nv_bfloat16* dB = half ? sBl[0] : sBh[0];
        *(uint4*)&dA[r*24]     = a0; *(uint4*)&dA[r*24 + 8] = a1;
        *(uint4*)&dB[r*24]     = b0; *(uint4*)&dB[r*24 + 8] = b1;
    }
    __syncthreads();

    float acc[2][4][4] = {};
    const int nk = K >> 4;
    for (int kc = 0; kc < nk; kc++) {
        const int buf = kc & 1;
        uint4 na0, na1, nb0, nb1;
        if (kc + 1 < nk) {
            int k0 = (kc + 1)*16;
            const uint4* pa = (const uint4*)(As + (size_t)(row0 + r)*K + k0);
            const uint4* pb = (const uint4*)(Bs + (size_t)(col0 + r)*K + k0);
            na0 = pa[0]; na1 = pa[1]; nb0 = pb[0]; nb1 = pb[1];
        }

        const uint32_t cAh = smem_u32(&sAh[buf][0]);
        const uint32_t cAl = smem_u32(&sAl[buf][0]);
        const uint32_t cBh = smem_u32(&sBh[buf][0]);
        const uint32_t cBl = smem_u32(&sBl[buf][0]);

        uint32_t bh[4][2], bl[4][2];
        #pragma unroll
        for (int ntp = 0; ntp < 2; ntp++) {
            uint32_t off = (uint32_t)(((wn*32 + ntp*16 + lrow)*24 + lkh)*2);
            uint32_t t4[4], u4[4];
            ldmx4(t4, cBh + off);
            ldmx4(u4, cBl + off);
            bh[ntp*2][0]   = t4[0]; bh[ntp*2][1]   = t4[2];
            bh[ntp*2+1][0] = t4[1]; bh[ntp*2+1][1] = t4[3];
            bl[ntp*2][0]   = u4[0]; bl[ntp*2][1]   = u4[2];
            bl[ntp*2+1][0] = u4[1]; bl[ntp*2+1][1] = u4[3];
        }
        #pragma unroll
        for (int mt = 0; mt < 2; mt++) {
            uint32_t offA = (uint32_t)(((wm*32 + mt*16 + lrow)*24 + lkh)*2);
            uint32_t ah[4], al[4];
            ldmx4(ah, cAh + offA);
            ldmx4(al, cAl + offA);
            #pragma unroll
            for (int nt = 0; nt < 4; nt++) {
                mma16816(acc[mt][nt], ah, bh[nt]);
                mma16816(acc[mt][nt], ah, bl[nt]);
                mma16816(acc[mt][nt], al, bh[nt]);
            }
        }

        if (kc + 1 < nk) {
            const int nb = buf ^ 1;
            __nv_bfloat16* dA = half ? sAl[nb] : sAh[nb];
            __nv_bfloat16* dB = half ? sBl[nb] : sBh[nb];
            *(uint4*)&dA[r*24]     = na0; *(uint4*)&dA[r*24 + 8] = na1;
            *(uint4*)&dB[r*24]     = nb0; *(uint4*)&dB[r*24 + 8] = nb1;
        }
        __syncthreads();
    }

    #pragma unroll
    for (int mt = 0; mt < 2; mt++) {
        int gr = row0 + wm*32 + mt*16 + qr;
        #pragma unroll
        for (int nt = 0; nt < 4; nt++) {
            int gc = col0 + wn*32 + nt*8 + qc;
            float v0 = acc[mt][nt][0] + bias[gc];
            float v1 = acc[mt][nt][1] + bias[gc+1];
            float v2 = acc[mt][nt][2] + bias[gc];
            float v3 = acc[mt][nt][3] + bias[gc+1];
            if (gelu) {
                v0 = 0.5f*v0*(1.0f + erff(v0*0.70710678118654752f));
                v1 = 0.5f*v1*(1.0f + erff(v1*0.70710678118654752f));
                v2 = 0.5f*v2*(1.0f + erff(v2*0.70710678118654752f));
                v3 = 0.5f*v3*(1.0f + erff(v3*0.70710678118654752f));
            }
            if (C) {
                *(float2*)&C[(size_t)gr*N + gc]     = make_float2(v0, v1);
                *(float2*)&C[(size_t)(gr+8)*N + gc] = make_float2(v2, v3);
            }
            if (Ch) {
                uint32_t h01, l01, h23, l23;
                split2(v0, v1, h01, l01);
                split2(v2, v3, h23, l23);
                *(uint32_t*)&Ch[(size_t)gr*N + gc]     = h01;
                *(uint32_t*)&Cl[(size_t)gr*N + gc]     = l01;
                *(uint32_t*)&Ch[(size_t)(gr+8)*N + gc] = h23;
                *(uint32_t*)&Cl[(size_t)(gr+8)*N + gc] = l23;
            }
        }
    }
}

// =========================================================================
// bf16x3 GEMM with fused fp32->hi/lo A conversion (projections), 128x128.
// =========================================================================
__device__ __forceinline__ void mma_gemm_f32A_body(
    const float* __restrict__ Afp,
    const __nv_bfloat16* __restrict__ Bh, const __nv_bfloat16* __restrict__ Bl,
    const float* __restrict__ bias, float* __restrict__ C,
    __nv_bfloat16* __restrict__ Ch, __nv_bfloat16* __restrict__ Cl,
    int N, int K)
{
    __shared__ __nv_bfloat16 sAh[2][128*24], sAl[2][128*24];
    __shared__ __nv_bfloat16 sBh[2][128*24], sBl[2][128*24];
    const int tid = threadIdx.x;
    const int lane = tid & 31, warp = tid >> 5;
    const int wm = warp >> 2, wn = warp & 3;
    const int qr = lane >> 2, qc = (lane & 3)*2;
    const int lrow = lane & 15, lkh = (lane >> 4)*8;
    const int row0 = blockIdx.y*128, col0 = blockIdx.x*128;
    const int half = tid >> 7, r = tid & 127;

    if (half == 0) {
        const float4* pa = (const float4*)(Afp + (size_t)(row0 + r)*K);
        float4 f0 = pa[0], f1 = pa[1], f2 = pa[2], f3 = pa[3];
        float fv[16] = {f0.x,f0.y,f0.z,f0.w, f1.x,f1.y,f1.z,f1.w,
                        f2.x,f2.y,f2.z,f2.w, f3.x,f3.y,f3.z,f3.w};
        #pragma unroll
        for (int c2 = 0; c2 < 8; c2++) {
            uint32_t h2, l2;
            split2(fv[c2*2], fv[c2*2+1], h2, l2);
            *(uint32_t*)&sAh[0][r*24 + c2*2] = h2;
            *(uint32_t*)&sAl[0][r*24 + c2*2] = l2;
        }
    } else {
        const uint4* pbh = (const uint4*)(Bh + (size_t)(col0 + r)*K);
        const uint4* pbl = (const uint4*)(Bl + (size_t)(col0 + r)*K);
        uint4 b0 = pbh[0], b1 = pbh[1], c0 = pbl[0], c1 = pbl[1];
        *(uint4*)&sBh[0][r*24]     = b0; *(uint4*)&sBh[0][r*24 + 8] = b1;
        *(uint4*)&sBl[0][r*24]     = c0; *(uint4*)&sBl[0][r*24 + 8] = c1;
    }
    __syncthreads();

    float acc[4][4][4] = {};
    const int nk = K >> 4;
    for (int kc = 0; kc < nk; kc++) {
        const int buf = kc & 1;
        float nfv[16];
        uint4 nb0, nb1, nc0, nc1;
        if (kc + 1 < nk) {
            int k0 = (kc + 1)*16;
            if (half == 0) {
                const float4* pa = (const float4*)(Afp + (size_t)(row0 + r)*K + k0);
                float4 f0 = pa[0], f1 = pa[1], f2 = pa[2], f3 = pa[3];
                nfv[0]=f0.x; nfv[1]=f0.y; nfv[2]=f0.z; nfv[3]=f0.w;
                nfv[4]=f1.x; nfv[5]=f1.y; nfv[6]=f1.z; nfv[7]=f1.w;
                nfv[8]=f2.x; nfv[9]=f2.y; nfv[10]=f2.z; nfv[11]=f2.w;
                nfv[12]=f3.x; nfv[13]=f3.y; nfv[14]=f3.z; nfv[15]=f3.w;
            } else {
                const uint4* pbh = (const uint4*)(Bh + (size_t)(col0 + r)*K + k0);
                const uint4* pbl = (const uint4*)(Bl + (size_t)(col0 + r)*K + k0);
                nb0 = pbh[0]; nb1 = pbh[1]; nc0 = pbl[0]; nc1 = pbl[1];
            }
        }

        const uint32_t cAh = smem_u32(&sAh[buf][0]);
        const uint32_t cAl = smem_u32(&sAl[buf][0]);
        const uint32_t cBh = smem_u32(&sBh[buf][0]);
        const uint32_t cBl = smem_u32(&sBl[buf][0]);

        uint32_t bh[4][2], bl[4][2];
        #pragma unroll
        for (int ntp = 0; ntp < 2; ntp++) {
            uint32_t off = (uint32_t)(((wn*32 + ntp*16 + lrow)*24 + lkh)*2);
            uint32_t t4[4], u4[4];
            ldmx4(t4, cBh + off);
            ldmx4(u4, cBl + off);
            bh[ntp*2][0]   = t4[0]; bh[ntp*2][1]   = t4[2];
            bh[ntp*2+1][0] = t4[1]; bh[ntp*2+1][1] = t4[3];
            bl[ntp*2][0]   = u4[0]; bl[ntp*2][1]   = u4[2];
            bl[ntp*2+1][0] = u4[1]; bl[ntp*2+1][1] = u4[3];
        }
        #pragma unroll
        for (int mt = 0; mt < 4; mt++) {
            uint32_t offA = (uint32_t)(((wm*64 + mt*16 + lrow)*24 + lkh)*2);
            uint32_t ah[4], al[4];
            ldmx4(ah, cAh + offA);
            ldmx4(al, cAl + offA);
            #pragma unroll
            for (int nt = 0; nt < 4; nt++) {
                mma16816(acc[mt][nt], ah, bh[nt]);
                mma16816(acc[mt][nt], ah, bl[nt]);
                mma16816(acc[mt][nt], al, bh[nt]);
            }
        }

        if (kc + 1 < nk) {
            const int nb = buf ^ 1;
            if (half == 0) {
                #pragma unroll
                for (int c2 = 0; c2 < 8; c2++) {
                    uint32_t h2, l2;
                    split2(nfv[c2*2], nfv[c2*2+1], h2, l2);
                    *(uint32_t*)&sAh[nb][r*24 + c2*2] = h2;
                    *(uint32_t*)&sAl[nb][r*24 + c2*2] = l2;
                }
            } else {
                *(uint4*)&sBh[nb][r*24]     = nb0; *(uint4*)&sBh[nb][r*24 + 8] = nb1;
                *(uint4*)&sBl[nb][r*24]     = nc0; *(uint4*)&sBl[nb][r*24 + 8] = nc1;
            }
        }
        __syncthreads();
    }

    #pragma unroll
    for (int mt = 0; mt < 4; mt++) {
        int gr = row0 + wm*64 + mt*16 + qr;
        #pragma unroll
        for (int nt = 0; nt < 4; nt++) {
            int gc = col0 + wn*32 + nt*8 + qc;
            float v0 = acc[mt][nt][0] + bias[gc];
            float v1 = acc[mt][nt][1] + bias[gc+1];
            float v2 = acc[mt][nt][2] + bias[gc];
            float v3 = acc[mt][nt][3] + bias[gc+1];
            if (C) {
                *(float2*)&C[(size_t)gr*N + gc]     = make_float2(v0, v1);
                *(float2*)&C[(size_t)(gr+8)*N + gc] = make_float2(v2, v3);
            }
            if (Ch) {
                uint32_t h01, l01, h23, l23;
                split2(v0, v1, h01, l01);
                split2(v2, v3, h23, l23);
                *(uint32_t*)&Ch[(size_t)gr*N + gc]     = h01;
                *(uint32_t*)&Cl[(size_t)gr*N + gc]     = l01;
                *(uint32_t*)&Ch[(size_t)(gr+8)*N + gc] = h23;
                *(uint32_t*)&Cl[(size_t)(gr+8)*N + gc] = l23;
            }
        }
    }
}

__global__ void __launch_bounds__(256, 2) proj3_mma_kernel(
    const float* q_in, const float* k_in, const float* v_in,
    const float* bq, const float* bk, const float* bv)
{
    int z = blockIdx.z;
    if (z == 0)
        mma_gemm_f32A_body(q_in, g_wth[0], g_wtl[0], bq, g_q, g_qh, g_ql, Dm, Dm);
    else if (z == 1)
        mma_gemm_f32A_body(k_in, g_wth[1], g_wtl[1], bk, g_k, g_kh, g_kl, Dm, Dm);
    else
        mma_gemm_f32A_body(v_in, g_wth[2], g_wtl[2], bv, g_v, g_vh, g_vl, Dm, Dm);
}

// =========================================================================
// dense QK^T (bf16x3 mma) + fused row stats, ldmatrix fragments (unchanged)
// =========================================================================
extern __shared__ __nv_bfloat16 scsm[];
__global__ void __launch_bounds__(256, 2) scores_stats_mma_kernel(float scale)
{
    __nv_bfloat16* sAh = scsm;
    __nv_bfloat16* sAl = scsm + 128*72;
    __nv_bfloat16* sBh = scsm + 2*128*72;
    __nv_bfloat16* sBl = scsm + 3*128*72;
    __shared__ float s4a[128][4], s4b[128][4], srm[128];

    const int tid = threadIdx.x;
    const int lane = tid & 31, warp = tid >> 5;
    const int wm = warp >> 2, wn = warp & 3;
    const int qr = lane >> 2;
    const int bh = blockIdx.z;
    const int b = bh >> 3, h = bh & 7;
    const int i0 = blockIdx.y*128, j0 = blockIdx.x*128;

    const __nv_bfloat16* Qhp = g_qh + ((size_t)(b*Ls) + i0)*Dm + h*HDim;
    const __nv_bfloat16* Qlp = g_ql + ((size_t)(b*Ls) + i0)*Dm + h*HDim;
    const __nv_bfloat16* Khp = g_kh + ((size_t)(b*Ls) + j0)*Dm + h*HDim;
    const __nv_bfloat16* Klp = g_kl + ((size_t)(b*Ls) + j0)*Dm + h*HDim;

    #pragma unroll
    for (int i = 0; i < 4; i++) {
        int slot = tid*4 + i;
        int row = slot >> 3, c = slot & 7;
        *(uint4*)&sAh[row*72 + c*8] = *(const uint4*)&Qhp[(size_t)row*Dm + c*8];
        *(uint4*)&sAl[row*72 + c*8] = *(const uint4*)&Qlp[(size_t)row*Dm + c*8];
        *(uint4*)&sBh[row*72 + c*8] = *(const uint4*)&Khp[(size_t)row*Dm + c*8];
        *(uint4*)&sBl[row*72 + c*8] = *(const uint4*)&Klp[(size_t)row*Dm + c*8];
    }
    __syncthreads();

    const uint32_t sc0 = smem_u32(scsm);
    const uint32_t aAh = sc0, aAl = sc0 + 128*72*2, aBh = sc0 + 2*128*72*2, aBl = sc0 + 3*128*72*2;
    const int lrow = lane & 15, lkh = (lane >> 4)*8;

    float acc[4][4][4] = {};
    #pragma unroll
    for (int kc = 0; kc < 4; kc++) {
        const int ko = kc*16;
        uint32_t Bh4[2][4], Bl4[2][4];
        #pragma unroll
        for (int ntp = 0; ntp < 2; ntp++) {
            uint32_t off = ((wn*32 + ntp*16 + lrow)*72 + ko + lkh)*2;
            ldmx4(Bh4[ntp], aBh + off);
            ldmx4(Bl4[ntp], aBl + off);
        }
        #pragma unroll
        for (int mt = 0; mt < 4; mt++) {
            uint32_t offA = ((wm*64 + mt*16 + lrow)*72 + ko + lkh)*2;
            uint32_t ah[4], al[4];
            ldmx4(ah, aAh + offA);
            ldmx4(al, aAl + offA);
            #pragma unroll
            for (int nt = 0; nt < 4; nt++) {
                uint32_t bhf[2] = { Bh4[nt>>1][nt&1], Bh4[nt>>1][(nt&1)+2] };
                uint32_t blf[2] = { Bl4[nt>>1][nt&1], Bl4[nt>>1][(nt&1)+2] };
                mma16816(acc[mt][nt], ah, bhf);
                mma16816(acc[mt][nt], ah, blf);
                mma16816(acc[mt][nt], al, bhf);
            }
        }
    }

    #pragma unroll
    for (int mt = 0; mt < 4; mt++) {
        float m0 = -INFINITY, m1 = -INFINITY;
        #pragma unroll
        for (int nt = 0; nt < 4; nt++) {
            m0 = fmaxf(m0, fmaxf(acc[mt][nt][0], acc[mt][nt][1]));
            m1 = fmaxf(m1, fmaxf(acc[mt][nt][2], acc[mt][nt][3]));
        }
        m0 = fmaxf(m0, __shfl_xor_sync(0xFFFFFFFFu, m0, 1));
        m0 = fmaxf(m0, __shfl_xor_sync(0xFFFFFFFFu, m0, 2));
        m1 = fmaxf(m1, __shfl_xor_sync(0xFFFFFFFFu, m1, 1));
        m1 = fmaxf(m1, __shfl_xor_sync(0xFFFFFFFFu, m1, 2));
        if ((lane & 3) == 0) {
            s4a[wm*64 + mt*16 + qr][wn]     = m0;
            s4a[wm*64 + mt*16 + 8 + qr][wn] = m1;
        }
    }
    __syncthreads();
    if (tid < 128)
        srm[tid] = fmaxf(fmaxf(s4a[tid][0], s4a[tid][1]), fmaxf(s4a[tid][2], s4a[tid][3]));
    __syncthreads();

    #pragma unroll
    for (int mt = 0; mt < 4; mt++) {
        int lr0 = wm*64 + mt*16 + qr, lr1 = lr0 + 8;
        float rm0 = srm[lr0]*scale, rm1 = srm[lr1]*scale;
        float se0 = 0.f, se1 = 0.f, ss0 = 0.f, ss1 = 0.f;
        #pragma unroll
        for (int nt = 0; nt < 4; nt++) {
            float x0 = acc[mt][nt][0]*scale, x1 = acc[mt][nt][1]*scale;
            float x2 = acc[mt][nt][2]*scale, x3 = acc[mt][nt][3]*scale;
            se0 += __expf(x0 - rm0) + __expf(x1 - rm0);
            se1 += __expf(x2 - rm1) + __expf(x3 - rm1);
            ss0 += x0 + x1; ss1 += x2 + x3;
        }
        se0 += __shfl_xor_sync(0xFFFFFFFFu, se0, 1); se0 += __shfl_xor_sync(0xFFFFFFFFu, se0, 2);
        se1 += __shfl_xor_sync(0xFFFFFFFFu, se1, 1); se1 += __shfl_xor_sync(0xFFFFFFFFu, se1, 2);
        ss0 += __shfl_xor_sync(0xFFFFFFFFu, ss0, 1); ss0 += __shfl_xor_sync(0xFFFFFFFFu, ss0, 2);
        ss1 += __shfl_xor_sync(0xFFFFFFFFu, ss1, 1); ss1 += __shfl_xor_sync(0xFFFFFFFFu, ss1, 2);
        if ((lane & 3) == 0) {
            s4b[lr0][wn] = se0; s4b[lr1][wn] = se1;
            s4a[lr0][wn] = ss0; s4a[lr1][wn] = ss1;
        }
    }
    __syncthreads();
    if (tid < 128) {
        int rowg = bh*Ls + i0 + tid;
        int jt = blockIdx.x;
        g_pmax[(size_t)rowg*NJT + jt] = srm[tid]*scale;
        g_pse [(size_t)rowg*NJT + jt] = s4b[tid][0]+s4b[tid][1]+s4b[tid][2]+s4b[tid][3];
        g_psum[(size_t)rowg*NJT + jt] = s4a[tid][0]+s4a[tid][1]+s4a[tid][2]+s4a[tid][3];
    }
}

// ---------------- compress: mean of 4 rows -> splits ----------------
__global__ void compress_kernel()
{
    int e4 = blockIdx.x*blockDim.x + threadIdx.x;
    int b = e4 / (LcC*Dm/4);
    int r = e4 % (LcC*Dm/4);
    int m = r / (Dm/4), d4 = r % (Dm/4);
    const float4* k4 = (const float4*)g_k;
    const float4* v4 = (const float4*)g_v;
    size_t base = ((size_t)(b*Ls + m*4)*Dm)/4 + d4;
    float4 a = k4[base], bb = k4[base+128], c = k4[base+256], d = k4[base+384];
    float ox = 0.25f*(a.x+bb.x+c.x+d.x), oy = 0.25f*(a.y+bb.y+c.y+d.y);
    float oz = 0.25f*(a.z+bb.z+c.z+d.z), ow = 0.25f*(a.w+bb.w+c.w+d.w);
    bsplit(ox, g_kcpreh[e4*4+0], g_kcprel[e4*4+0]);
    bsplit(oy, g_kcpreh[e4*4+1], g_kcprel[e4*4+1]);
    bsplit(oz, g_kcpreh[e4*4+2], g_kcprel[e4*4+2]);
    bsplit(ow, g_kcpreh[e4*4+3], g_kcprel[e4*4+3]);
    a = v4[base]; bb = v4[base+128]; c = v4[base+256]; d = v4[base+384];
    ox = 0.25f*(a.x+bb.x+c.x+d.x); oy = 0.25f*(a.y+bb.y+c.y+d.y);
    oz = 0.25f*(a.z+bb.z+c.z+d.z); ow = 0.25f*(a.w+bb.w+c.w+d.w);
    bsplit(ox, g_vch[e4*4+0], g_vcl[e4*4+0]);
    bsplit(oy, g_vch[e4*4+1], g_vcl[e4*4+1]);
    bsplit(oz, g_vch[e4*4+2], g_vcl[e4*4+2]);
    bsplit(ow, g_vch[e4*4+3], g_vcl[e4*4+3]);
}

// ---------------- importance merge ----------------
__global__ void impfinal_kernel()
{
    int warp = (blockIdx.x*blockDim.x + threadIdx.x) >> 5;
    int lane = threadIdx.x & 31;
    float pm = -INFINITY, pe = 0.f, ps = 0.f;
    if (lane < NJT) {
        pm = g_pmax[(size_t)warp*NJT + lane];
        pe = g_pse [(size_t)warp*NJT + lane];
        ps = g_psum[(size_t)warp*NJT + lane];
    }
    float m = pm;
    #pragma unroll
    for (int o = 8; o; o >>= 1) m = fmaxf(m, __shfl_xor_sync(0xFFFFFFFFu, m, o));
    float se = (lane < NJT) ? pe * __expf(pm - m) : 0.f;
    #pragma unroll
    for (int o = 8; o; o >>= 1) {
        se += __shfl_xor_sync(0xFFFFFFFFu, se, o);
        ps += __shfl_xor_sync(0xFFFFFFFFu, ps, o);
    }
    if (lane == 0)
        g_imp[warp] = m + logf(se) - 7.6246189861593985f - ps * (1.0f/2048.0f);
}

// ---------------- top-8 ----------------
__global__ void topk_kernel()
{
    int bh = blockIdx.x;
    const float* imp = g_imp + bh*Ls;
    __shared__ float bv[256];
    __shared__ int   bi[256];
    __shared__ int   chosen[NSEL];
    int t = threadIdx.x;
    for (int itu = 0; itu < NSEL; itu++) {
        float best = -INFINITY; int bidx = 0x7FFFFFFF;
        for (int j = t; j < Ls; j += 256) {
            bool skip = false;
            for (int c = 0; c < itu; c++) if (chosen[c] == j) skip = true;
            if (skip) continue;
            float vv = imp[j];
            if (vv > best || (vv == best && j < bidx)) { best = vv; bidx = j; }
        }
        bv[t] = best; bi[t] = bidx;
        __syncthreads();
        for (int s2 = 128; s2; s2 >>= 1) {
            if (t < s2) {
                if (bv[t+s2] > bv[t] || (bv[t+s2] == bv[t] && bi[t+s2] < bi[t])) {
                    bv[t] = bv[t+s2]; bi[t] = bi[t+s2];
                }
            }
            __syncthreads();
        }
        if (t == 0) { chosen[itu] = bi[0]; g_selidx[bh*NSEL + itu] = bi[0]; }
        __syncthreads();
    }
}

// =========================================================================
// fused flash attention, 128-row Q tiles, 8 warps all in M, band chunk skip.
// =========================================================================
extern __shared__ char fsm2[];
__global__ void __launch_bounds__(256, 2) flash_mma_kernel(
    const __nv_bfloat16* __restrict__ Qh, const __nv_bfloat16* __restrict__ Ql,
    const __nv_bfloat16* __restrict__ Khg, const __nv_bfloat16* __restrict__ Klg,
    const __nv_bfloat16* __restrict__ Vhg, const __nv_bfloat16* __restrict__ Vlg,
    const __nv_bfloat16* __restrict__ Khc, const __nv_bfloat16* __restrict__ Klc,
    const __nv_bfloat16* __restrict__ Vhc, const __nv_bfloat16* __restrict__ Vlc,
    float* __restrict__ OutL, float* __restrict__ OutG)
{
    __nv_bfloat16* sQh = (__nv_bfloat16*)fsm2;   // [128][72]
    __nv_bfloat16* sQl = sQh + 128*72;
    __nv_bfloat16* sKh = sQl + 128*72;           // [64][72]
    __nv_bfloat16* sKl = sKh + 64*72;
    __nv_bfloat16* sVh = sKl + 64*72;            // natural [j][d]
    __nv_bfloat16* sVl = sVh + 64*72;

    const int z = blockIdx.z;
    const __nv_bfloat16* Kh = z ? Khc : Khg;
    const __nv_bfloat16* Kl = z ? Klc : Klg;
    const __nv_bfloat16* Vh = z ? Vhc : Vhg;
    const __nv_bfloat16* Vl = z ? Vlc : Vlg;
    float* Out = z ? OutG : OutL;
    const int LK = z ? LcC : Ls;
    const int nchunks = z ? 8 : 4;
    const int local = z ? 0 : 1;

    const int tid = threadIdx.x;
    const int lane = tid & 31, w = tid >> 5;
    const int qr = lane >> 2, qc = (lane & 3)*2;
    const int lrow = lane & 15, lkh = (lane >> 4)*8;
    const int bh = blockIdx.y;
    const int b = bh >> 3, h = bh & 7;
    const int i0 = blockIdx.x*128;
    const size_t hoff = (size_t)h*HDim;

    const uint32_t sb = smem_u32(fsm2);
    const uint32_t aQh = sb, aQl = sb + 18432;
    const uint32_t aKh = sb + 36864, aKl = sb + 46080;
    const uint32_t aVh = sb + 55296, aVl = sb + 64512;

    {
        int row = tid >> 1, part = (tid & 1)*32;
        const uint4* ph = (const uint4*)(Qh + ((size_t)(b*Ls) + i0 + row)*Dm + hoff + part);
        const uint4* pl = (const uint4*)(Ql + ((size_t)(b*Ls) + i0 + row)*Dm + hoff + part);
        #pragma unroll
        for (int j = 0; j < 4; j++) {
            *(uint4*)&sQh[row*72 + part + j*8] = ph[j];
            *(uint4*)&sQl[row*72 + part + j*8] = pl[j];
        }
    }

    float accO[8][4] = {};
    float mr0 = -INFINITY, mr1 = -INFINITY;
    float lr0 = 0.f, lr1 = 0.f;
    const int ir0 = i0 + w*16 + qr, ir1 = ir0 + 8;

    for (int c = 0; c < nchunks; c++) {
        int jbase = (local ? i0 - 64 : 0) + c*64;
        __syncthreads();
        {
            int row = tid >> 2, c16 = (tid & 3)*16;
            int jg = jbase + row;
            uint4 kh0 = {0,0,0,0}, kh1 = {0,0,0,0}, kl0 = {0,0,0,0}, kl1 = {0,0,0,0};
            uint4 vh0 = {0,0,0,0}, vh1 = {0,0,0,0}, vl0 = {0,0,0,0}, vl1 = {0,0,0,0};
            if (jg >= 0 && jg < LK) {
                const uint4* ph = (const uint4*)(Kh + ((size_t)(b*LK) + jg)*Dm + hoff + c16);
                const uint4* pl = (const uint4*)(Kl + ((size_t)(b*LK) + jg)*Dm + hoff + c16);
                kh0 = ph[0]; kh1 = ph[1]; kl0 = pl[0]; kl1 = pl[1];
                ph = (const uint4*)(Vh + ((size_t)(b*LK) + jg)*Dm + hoff + c16);
                pl = (const uint4*)(Vl + ((size_t)(b*LK) + jg)*Dm + hoff + c16);
                vh0 = ph[0]; vh1 = ph[1]; vl0 = pl[0]; vl1 = pl[1];
            }
            *(uint4*)&sKh[row*72 + c16] = kh0; *(uint4*)&sKh[row*72 + c16 + 8] = kh1;
            *(uint4*)&sKl[row*72 + c16] = kl0; *(uint4*)&sKl[row*72 + c16 + 8] = kl1;
            *(uint4*)&sVh[row*72 + c16] = vh0; *(uint4*)&sVh[row*72 + c16 + 8] = vh1;
            *(uint4*)&sVl[row*72 + c16] = vl0; *(uint4*)&sVl[row*72 + c16 + 8] = vl1;
        }
        __syncthreads();

        if (local) {
            int c64 = c*64;
            if (c64 < w*16 - 63 || c64 > w*16 + 143) continue;
        }

        float s[8][4] = {};
        #pragma unroll
        for (int kc = 0; kc < 4; kc++) {
            int ko = kc*16;
            uint32_t offA = ((w*16 + lrow)*72 + ko + lkh)*2;
            uint32_t ah[4], al[4];
            ldmx4(ah, aQh + offA);
            ldmx4(al, aQl + offA);
            #pragma unroll
            for (int ntp = 0; ntp < 4; ntp++) {
                uint32_t offB = ((ntp*16 + lrow)*72 + ko + lkh)*2;
                uint32_t kh4[4], kl4[4];
                ldmx4(kh4, aKh + offB);
                ldmx4(kl4, aKl + offB);
                uint32_t bhf0[2] = { kh4[0], kh4[2] }, bhf1[2] = { kh4[1], kh4[3] };
                uint32_t blf0[2] = { kl4[0], kl4[2] }, blf1[2] = { kl4[1], kl4[3] };
                mma16816(s[ntp*2],   ah, bhf0);
                mma16816(s[ntp*2],   ah, blf0);
                mma16816(s[ntp*2],   al, bhf0);
                mma16816(s[ntp*2+1], ah, bhf1);
                mma16816(s[ntp*2+1], ah, blf1);
                mma16816(s[ntp*2+1], al, bhf1);
            }
        }

        float m0 = -INFINITY, m1 = -INFINITY;
        #pragma unroll
        for (int nt = 0; nt < 8; nt++) {
            int jc0 = jbase + nt*8 + qc;
            int jc1 = jc0 + 1;
            #pragma unroll
            for (int rg = 0; rg < 4; rg++) s[nt][rg] *= 0.125f;
            bool ok00 = true, ok01 = true, ok10 = true, ok11 = true;
            if (local) {
                ok00 = (jc0 >= 0) & (jc0 < LK) & (jc0 >= ir0-64) & (jc0 <= ir0+64);
                ok01 = (jc1 >= 0) & (jc1 < LK) & (jc1 >= ir0-64) & (jc1 <= ir0+64);
                ok10 = (jc0 >= 0) & (jc0 < LK) & (jc0 >= ir1-64) & (jc0 <= ir1+64);
                ok11 = (jc1 >= 0) & (jc1 < LK) & (jc1 >= ir1-64) & (jc1 <= ir1+64);
            }
            if (ok00) m0 = fmaxf(m0, s[nt][0]);
            if (ok01) m0 = fmaxf(m0, s[nt][1]);
            if (ok10) m1 = fmaxf(m1, s[nt][2]);
            if (ok11) m1 = fmaxf(m1, s[nt][3]);
        }
        m0 = fmaxf(m0, __shfl_xor_sync(0xFFFFFFFFu, m0, 1));
        m0 = fmaxf(m0, __shfl_xor_sync(0xFFFFFFFFu, m0, 2));
        m1 = fmaxf(m1, __shfl_xor_sync(0xFFFFFFFFu, m1, 1));
        m1 = fmaxf(m1, __shfl_xor_sync(0xFFFFFFFFu, m1, 2));
        float mn0 = fmaxf(mr0, m0), mn1 = fmaxf(mr1, m1);
        float cf0 = (mn0 == -INFINITY) ? 1.f : __expf(mr0 - mn0);
        float cf1 = (mn1 == -INFINITY) ? 1.f : __expf(mr1 - mn1);
        mr0 = mn0; mr1 = mn1;

        float ps0 = 0.f, ps1 = 0.f;
        #pragma unroll
        for (int nt = 0; nt < 8; nt++) {
            int jc0 = jbase + nt*8 + qc;
            int jc1 = jc0 + 1;
            bool ok00 = true, ok01 = true, ok10 = true, ok11 = true;
            if (local) {
                ok00 = (jc0 >= 0) & (jc0 < LK) & (jc0 >= ir0-64) & (jc0 <= ir0+64);
                ok01 = (jc1 >= 0) & (jc1 < LK) & (jc1 >= ir0-64) & (jc1 <= ir0+64);
                ok10 = (jc0 >= 0) & (jc0 < LK) & (jc0 >= ir1-64) & (jc0 <= ir1+64);
                ok11 = (jc1 >= 0) & (jc1 < LK) & (jc1 >= ir1-64) & (jc1 <= ir1+64);
            }
            s[nt][0] = ok00 ? __expf(s[nt][0] - mn0) : 0.f;
            s[nt][1] = ok01 ? __expf(s[nt][1] - mn0) : 0.f;
            s[nt][2] = ok10 ? __expf(s[nt][2] - mn1) : 0.f;
            s[nt][3] = ok11 ? __expf(s[nt][3] - mn1) : 0.f;
            ps0 += s[nt][0] + s[nt][1];
            ps1 += s[nt][2] + s[nt][3];
        }
        ps0 += __shfl_xor_sync(0xFFFFFFFFu, ps0, 1); ps0 += __shfl_xor_sync(0xFFFFFFFFu, ps0, 2);
        ps1 += __shfl_xor_sync(0xFFFFFFFFu, ps1, 1); ps1 += __shfl_xor_sync(0xFFFFFFFFu, ps1, 2);
        lr0 = lr0*cf0 + ps0;
        lr1 = lr1*cf1 + ps1;

        #pragma unroll
        for (int ntd = 0; ntd < 8; ntd++) {
            accO[ntd][0] *= cf0; accO[ntd][1] *= cf0;
            accO[ntd][2] *= cf1; accO[ntd][3] *= cf1;
        }

        #pragma unroll
        for (int kch = 0; kch < 4; kch++) {
            int nt0 = kch*2, nt1 = kch*2 + 1;
            uint32_t pah[4], pal[4];
            {
                float p00 = s[nt0][0], p01 = s[nt0][1], p02 = s[nt0][2], p03 = s[nt0][3];
                float p10 = s[nt1][0], p11 = s[nt1][1], p12 = s[nt1][2], p13 = s[nt1][3];
                pah[0] = packbf(p00, p01); pah[1] = packbf(p02, p03);
                pah[2] = packbf(p10, p11); pah[3] = packbf(p12, p13);
                float q00 = p00 - __bfloat162float(__float2bfloat16(p00));
                float q01 = p01 - __bfloat162float(__float2bfloat16(p01));
                float q02 = p02 - __bfloat162float(__float2bfloat16(p02));
                float q03 = p03 - __bfloat162float(__float2bfloat16(p03));
                float q10 = p10 - __bfloat162float(__float2bfloat16(p10));
                float q11 = p11 - __bfloat162float(__float2bfloat16(p11));
                float q12 = p12 - __bfloat162float(__float2bfloat16(p12));
                float q13 = p13 - __bfloat162float(__float2bfloat16(p13));
                pal[0] = packbf(q00, q01); pal[1] = packbf(q02, q03);
                pal[2] = packbf(q10, q11); pal[3] = packbf(q12, q13);
            }
            const int jo = kch*16;
            #pragma unroll
            for (int ntp = 0; ntp < 4; ntp++) {
                uint32_t offV = ((jo + lrow)*72 + ntp*16 + lkh)*2;
                uint32_t vh4[4], vl4[4];
                ldmx4t(vh4, aVh + offV);
                ldmx4t(vl4, aVl + offV);
                mma16816(accO[ntp*2],   pah, &vh4[0]);
                mma16816(accO[ntp*2],   pal, &vh4[0]);
                mma16816(accO[ntp*2],   pah, &vl4[0]);
                mma16816(accO[ntp*2+1], pah, &vh4[2]);
                mma16816(accO[ntp*2+1], pal, &vh4[2]);
                mma16816(accO[ntp*2+1], pah, &vl4[2]);
            }
        }
    }

    float inv0 = 1.0f/lr0, inv1 = 1.0f/lr1;
    #pragma unroll
    for (int ntd = 0; ntd < 8; ntd++) {
        *(float2*)&Out[((size_t)(b*Ls) + ir0)*Dm + hoff + ntd*8 + qc] =
            make_float2(accO[ntd][0]*inv0, accO[ntd][1]*inv0);
        *(float2*)&Out[((size_t)(b*Ls) + ir1)*Dm + hoff + ntd*8 + qc] =
            make_float2(accO[ntd][2]*inv1, accO[ntd][3]*inv1);
    }
}

// ---------------- combine + split comb ----------------
__global__ void combine_kernel(const float* __restrict__ pm)
{
    float a0 = pm[0], a1 = pm[1], a2 = pm[2];
    float mx = fmaxf(a0, fmaxf(a1, a2));
    float e0 = expf(a0-mx), e1 = expf(a1-mx), e2 = expf(a2-mx);
    float den = e0+e1+e2;
    float pw0 = e0/den, pw1 = e1/den;
    int e = blockIdx.x*blockDim.x + threadIdx.x;
    float v = pw0*g_outg[e] + pw1*g_outl[e];
    g_comb[e] = v;
    bsplit(v, g_combh[e], g_combl[e]);
}

// ---------------- selection path ----------------
__global__ void attns_kernel(const float* __restrict__ pm)
{
    __shared__ float sc[Ls];
    __shared__ float qs[64];
    __shared__ float red[256];
    int blk = blockIdx.x;
    int bh  = blk / NSEL, si = blk % NSEL;
    int b = bh >> 3, h = bh & 7;
    int qi = g_selidx[bh*NSEL + si];
    int t = threadIdx.x;

    if (t < 16) {
        float4 v = *(const float4*)&g_q[((size_t)(b*Ls) + qi)*Dm + h*HDim + t*4];
        *(float4*)&qs[t*4] = v;
    }
    __syncthreads();

    const float* kb = g_k + ((size_t)(b*Ls))*Dm + h*HDim;
    for (int jj = 0; jj < 8; jj++) {
        int j = t*8 + jj;
        const float4* kr = (const float4*)&kb[(size_t)j*Dm];
        float dot = 0.f;
        #pragma unroll
        for (int d4 = 0; d4 < 16; d4++) {
            float4 kv = kr[d4];
            dot = fmaf(qs[d4*4+0], kv.x, dot);
            dot = fmaf(qs[d4*4+1], kv.y, dot);
            dot = fmaf(qs[d4*4+2], kv.z, dot);
            dot = fmaf(qs[d4*4+3], kv.w, dot);
        }
        sc[j] = dot * 0.125f;
    }
    __syncthreads();

    float m = -INFINITY;
    for (int j = t; j < Ls; j += 256) m = fmaxf(m, sc[j]);
    red[t] = m; __syncthreads();
    for (int s2 = 128; s2; s2 >>= 1) { if (t < s2) red[t] = fmaxf(red[t], red[t+s2]); __syncthreads(); }
    m = red[0]; __syncthreads();

    float s = 0.f;
    for (int j = t; j < Ls; j += 256) { float e = __expf(sc[j]-m); sc[j] = e; s += e; }
    red[t] = s; __syncthreads();
    for (int s2 = 128; s2; s2 >>= 1) { if (t < s2) red[t] += red[t+s2]; __syncthreads(); }
    s = red[0]; __syncthreads();

    int d = t & 63, qtr = t >> 6;
    const float* vb = g_v + ((size_t)b*Ls)*Dm + h*HDim + d;
    float acc = 0.f;
    for (int j = qtr*512; j < qtr*512 + 512; j++)
        acc = fmaf(sc[j], vb[(size_t)j*Dm], acc);
    red[t] = acc; __syncthreads();

    if (t < 64) {
        float tot = red[t] + red[t+64] + red[t+128] + red[t+192];
        float a0 = pm[0], a1 = pm[1], a2 = pm[2];
        float mx = fmaxf(a0, fmaxf(a1, a2));
        float e0 = expf(a0-mx), e1 = expf(a1-mx), e2 = expf(a2-mx);
        float pw2 = e2/(e0+e1+e2);
        size_t idx = ((size_t)b*Ls + qi)*Dm + h*HDim + t;
        float nv = g_comb[idx] + pw2 * tot / s;
        g_comb[idx] = nv;
        bsplit(nv, g_combh[idx], g_combl[idx]);
    }
}

// ---------------- launch ----------------
extern "C" void kernel_launch(void* const* d_in, const int* in_sizes, int n_in,
                              void* d_out, int out_size)
{
    const float* query = (const float*)d_in[0];
    const float* keyi  = (const float*)d_in[1];
    const float* vali  = (const float*)d_in[2];
    const float* Wq = (const float*)d_in[3];  const float* bq = (const float*)d_in[4];
    const float* Wk = (const float*)d_in[5];  const float* bk = (const float*)d_in[6];
    const float* Wv = (const float*)d_in[7];  const float* bv = (const float*)d_in[8];
    const float* Wo = (const float*)d_in[9];  const float* bo = (const float*)d_in[10];
    const float* Wc1 = (const float*)d_in[11]; const float* bc1 = (const float*)d_in[12];
    const float* Wc2 = (const float*)d_in[13]; const float* bc2 = (const float*)d_in[14];
    const float* pm  = (const float*)d_in[15];

    __nv_bfloat16 *kcpreh, *kcprel, *hidh, *hidl, *combh, *combl, *wth, *wtl;
    __nv_bfloat16 *qh, *ql, *kh, *kl, *vh, *vl, *kch, *kcl, *vch, *vcl;
    cudaGetSymbolAddress((void**)&kcpreh, g_kcpreh);
    cudaGetSymbolAddress((void**)&kcprel, g_kcprel);
    cudaGetSymbolAddress((void**)&hidh,  g_hidh);
    cudaGetSymbolAddress((void**)&hidl,  g_hidl);
    cudaGetSymbolAddress((void**)&combh, g_combh);
    cudaGetSymbolAddress((void**)&combl, g_combl);
    cudaGetSymbolAddress((void**)&wth,   g_wth);
    cudaGetSymbolAddress((void**)&wtl,   g_wtl);
    cudaGetSymbolAddress((void**)&qh,    g_qh);
    cudaGetSymbolAddress((void**)&ql,    g_ql);
    cudaGetSymbolAddress((void**)&kh,    g_kh);
    cudaGetSymbolAddress((void**)&kl,    g_kl);
    cudaGetSymbolAddress((void**)&vh,    g_vh);
    cudaGetSymbolAddress((void**)&vl,    g_vl);
    cudaGetSymbolAddress((void**)&kch,   g_kch);
    cudaGetSymbolAddress((void**)&kcl,   g_kcl);
    cudaGetSymbolAddress((void**)&vch,   g_vch);
    cudaGetSymbolAddress((void**)&vcl,   g_vcl);

    float *outg, *outl;
    cudaGetSymbolAddress((void**)&outg,  g_outg);
    cudaGetSymbolAddress((void**)&outl,  g_outl);

    const int FLASH_SMEM = (2*128*72 + 4*64*72)*2;   // 73728
    const int SCORES_SMEM = 4*128*72*2;              // 73728
    cudaFuncSetAttribute(flash_mma_kernel, cudaFuncAttributeMaxDynamicSharedMemorySize, FLASH_SMEM);
    cudaFuncSetAttribute(scores_stats_mma_kernel, cudaFuncAttributeMaxDynamicSharedMemorySize, SCORES_SMEM);

    // prep (weights only; input split fused into projections)
    split_w6_kernel<<<dim3(16,16,6), dim3(32,8)>>>(Wq, Wk, Wv, Wo, Wc1, Wc2);

    // projections (fused fp32->hi/lo A conversion)
    proj3_mma_kernel<<<dim3(4,32,3), 256>>>(query, keyi, vali, bq, bk, bv);

    // compression + MLP (64x64-tile GEMMs for occupancy: 128 blocks each)
    compress_kernel<<<512, 256>>>();
    mma_gemm64_kernel<<<dim3(8,16), 128>>>(kcpreh, kcprel, wth + 4*(size_t)Dm*Dm, wtl + 4*(size_t)Dm*Dm,
                                           bc1, nullptr, hidh, hidl, Dm, Dm, 1);
    mma_gemm64_kernel<<<dim3(8,16), 128>>>(hidh, hidl, wth + 5*(size_t)Dm*Dm, wtl + 5*(size_t)Dm*Dm,
                                           bc2, nullptr, kch, kcl, Dm, Dm, 0);

    // dense QK^T + fused stats
    scores_stats_mma_kernel<<<dim3(NJT,16,16), 256, SCORES_SMEM>>>(0.125f);
    impfinal_kernel<<<4096, 256>>>();
    topk_kernel<<<Bb*Hh, 256>>>();

    // attention paths
    flash_mma_kernel<<<dim3(16,16,2), 256, FLASH_SMEM>>>(
        qh, ql, kh, kl, vh, vl, kch, kcl, vch, vcl, outl, outg);

    // mix + selection
    combine_kernel<<<(Bb*Ls*Dm)/256, 256>>>(pm);
    attns_kernel<<<Bb*Hh*NSEL, 256>>>(pm);

    // output projection (64x64 tiles: 512 blocks)
    mma_gemm64_kernel<<<dim3(8,64), 128>>>(combh, combl, wth + 3*(size_t)Dm*Dm, wtl + 3*(size_t)Dm*Dm,
                                           bo, (float*)d_out, nullptr, nullptr, Dm, Dm, 0);
}